// round 1
// baseline (speedup 1.0000x reference)
#include <cuda_runtime.h>
#include <math.h>

#define DM    1024
#define BATCH 8
#define NSEQ  1024
#define BN    (BATCH * NSEQ)      // 8192 rows
#define NH    16
#define DK    64
#define QSCALE 0.125f             // 1/sqrt(64)

// ---------------------------------------------------------------------------
// Scratch (device globals — no runtime allocation allowed)
// ---------------------------------------------------------------------------
__device__ float g_Q  [BN * DM];
__device__ float g_K  [BN * DM];
__device__ float g_V  [BN * DM];
__device__ float g_Vv [BN * DM];
__device__ float g_ctx[BN * DM];
__device__ float g_var[BN * DM];
__device__ float g_d2 [BATCH * NSEQ * NSEQ];
__device__ float g_Wvs2[DM * DM];
__device__ float g_Wos2[DM * DM];
__device__ float g_bvs2[DM];
__device__ float g_bos2[DM];

// ---------------------------------------------------------------------------
// softplus(x)^2 elementwise
// ---------------------------------------------------------------------------
__global__ void sig2_kernel(const float* __restrict__ in, float* __restrict__ out, int n) {
    int i = blockIdx.x * blockDim.x + threadIdx.x;
    if (i < n) {
        float x  = in[i];
        float sp = (x > 15.f) ? x : log1pf(__expf(x));
        out[i] = sp * sp;
    }
}

// ---------------------------------------------------------------------------
// dist2[b,n,m] = max(|x_n|^2 + |x_m|^2 - 2 x_n.x_m, 0),  x: [B,1024,16]
// grid: (16 n-tiles, 16 m-tiles, 8 batches), 256 threads, 64x64 tile
// ---------------------------------------------------------------------------
__global__ void dist2_kernel(const float* __restrict__ xr, float* __restrict__ d2) {
    __shared__ float xm[64][17];
    __shared__ float xn[64][17];
    __shared__ float x2m[64];
    __shared__ float x2n[64];

    const int t  = threadIdx.x;
    const int b  = blockIdx.z;
    const int mi = blockIdx.y * 64;
    const int nj = blockIdx.x * 64;

    for (int idx = t; idx < 64 * 4; idx += 256) {
        int r = idx >> 2, c = (idx & 3) * 4;
        float4 a = *(const float4*)(xr + ((size_t)b * NSEQ + mi + r) * 16 + c);
        xm[r][c] = a.x; xm[r][c+1] = a.y; xm[r][c+2] = a.z; xm[r][c+3] = a.w;
        float4 bb = *(const float4*)(xr + ((size_t)b * NSEQ + nj + r) * 16 + c);
        xn[r][c] = bb.x; xn[r][c+1] = bb.y; xn[r][c+2] = bb.z; xn[r][c+3] = bb.w;
    }
    __syncthreads();

    if (t < 64) {
        float s = 0.f;
        #pragma unroll
        for (int c = 0; c < 16; ++c) s += xm[t][c] * xm[t][c];
        x2m[t] = s;
    } else if (t < 128) {
        int r = t - 64;
        float s = 0.f;
        #pragma unroll
        for (int c = 0; c < 16; ++c) s += xn[r][c] * xn[r][c];
        x2n[r] = s;
    }
    __syncthreads();

    const int tx = t & 15, ty = t >> 4;
    #pragma unroll
    for (int i = 0; i < 4; ++i) {
        int row = ty * 4 + i;
        float out4[4];
        #pragma unroll
        for (int j = 0; j < 4; ++j) {
            int col = tx * 4 + j;
            float dot = 0.f;
            #pragma unroll
            for (int c = 0; c < 16; ++c) dot += xm[row][c] * xn[col][c];
            out4[j] = fmaxf(x2m[row] + x2n[col] - 2.f * dot, 0.f);
        }
        float4 v4 = make_float4(out4[0], out4[1], out4[2], out4[3]);
        *(float4*)(d2 + ((size_t)b * NSEQ + mi + row) * NSEQ + nj + tx * 4) = v4;
    }
}

// ---------------------------------------------------------------------------
// C[m,n] = sum_k Aop[m,k] * B[n,k] + bias[n] (+ add[m,n])
// A: [8192,1024] row-major, B: [1024,1024] row-major (k contiguous in both).
// 128x128 tile, K-step 8, 256 threads, 8x8 register tiles, double-buffered.
// SQ: square A elements on load (variance paths).
// ---------------------------------------------------------------------------
template<bool SQ, bool HASADD>
__global__ void __launch_bounds__(256)
gemm_kernel(const float* __restrict__ A, const float* __restrict__ B,
            const float* __restrict__ bias, const float* __restrict__ add,
            float* __restrict__ C) {
    __shared__ float As[2][8][132];
    __shared__ float Bs[2][8][132];

    const int t  = threadIdx.x;
    const int tx = t & 15, ty = t >> 4;
    const int mBase = blockIdx.y * 128;
    const int nBase = blockIdx.x * 128;

    // global-load assignment: each thread one float4 of A and of B per K-step
    const int lr = t >> 1;             // 0..127
    const int lc = (t & 1) * 4;        // 0 or 4
    const float* Ag = A + (size_t)(mBase + lr) * DM + lc;
    const float* Bg = B + (size_t)(nBase + lr) * DM + lc;

    float4 a4 = *(const float4*)Ag;
    float4 b4 = *(const float4*)Bg;

    float acc[8][8] = {};
    int buf = 0;

    for (int kt = 0; kt < DM / 8; ++kt) {
        if (SQ) { a4.x *= a4.x; a4.y *= a4.y; a4.z *= a4.z; a4.w *= a4.w; }
        As[buf][lc + 0][lr] = a4.x; As[buf][lc + 1][lr] = a4.y;
        As[buf][lc + 2][lr] = a4.z; As[buf][lc + 3][lr] = a4.w;
        Bs[buf][lc + 0][lr] = b4.x; Bs[buf][lc + 1][lr] = b4.y;
        Bs[buf][lc + 2][lr] = b4.z; Bs[buf][lc + 3][lr] = b4.w;
        __syncthreads();
        if (kt < DM / 8 - 1) {
            a4 = *(const float4*)(Ag + (kt + 1) * 8);
            b4 = *(const float4*)(Bg + (kt + 1) * 8);
        }
        #pragma unroll
        for (int kk = 0; kk < 8; ++kk) {
            float af[8], bf[8];
            #pragma unroll
            for (int i = 0; i < 8; ++i) af[i] = As[buf][kk][ty * 8 + i];
            #pragma unroll
            for (int j = 0; j < 8; ++j) bf[j] = Bs[buf][kk][tx * 8 + j];
            #pragma unroll
            for (int i = 0; i < 8; ++i)
                #pragma unroll
                for (int j = 0; j < 8; ++j)
                    acc[i][j] += af[i] * bf[j];
        }
        buf ^= 1;
    }

    float bv[8];
    #pragma unroll
    for (int j = 0; j < 8; ++j) bv[j] = bias[nBase + tx * 8 + j];

    #pragma unroll
    for (int i = 0; i < 8; ++i) {
        size_t row = (size_t)(mBase + ty * 8 + i) * DM + nBase + tx * 8;
        float o[8];
        #pragma unroll
        for (int j = 0; j < 8; ++j) o[j] = acc[i][j] + bv[j];
        if (HASADD) {
            float4 ad0 = *(const float4*)(add + row);
            float4 ad1 = *(const float4*)(add + row + 4);
            o[0] += ad0.x; o[1] += ad0.y; o[2] += ad0.z; o[3] += ad0.w;
            o[4] += ad1.x; o[5] += ad1.y; o[6] += ad1.z; o[7] += ad1.w;
        }
        *(float4*)(C + row)     = make_float4(o[0], o[1], o[2], o[3]);
        *(float4*)(C + row + 4) = make_float4(o[4], o[5], o[6], o[7]);
    }
}

// ---------------------------------------------------------------------------
// Flash attention with RBF bias; accumulates P@V and P^2@Vv simultaneously.
// grid: (16 q-tiles, 128 b*h), 256 threads. smem: 5 tiles of 64x65 floats.
// ---------------------------------------------------------------------------
__global__ void __launch_bounds__(256)
attn_kernel(const float* __restrict__ Q, const float* __restrict__ K,
            const float* __restrict__ V, const float* __restrict__ Vv,
            const float* __restrict__ d2g,
            const float* __restrict__ lsf, const float* __restrict__ lll,
            float* __restrict__ ctx, float* __restrict__ var) {
    extern __shared__ float sm[];
    float* Qs  = sm;               // 64*65
    float* Ks  = Qs  + 64 * 65;
    float* Vs  = Ks  + 64 * 65;
    float* Vvs = Vs  + 64 * 65;
    float* Ps  = Vvs + 64 * 65;

    const int t  = threadIdx.x;
    const int tx = t & 15, ty = t >> 4;
    const int bh = blockIdx.y;
    const int b  = bh >> 4, h = bh & 15;
    const int qb = blockIdx.x * 64;

    const float sigma_f2 = __expf(2.f * lsf[h]);
    const float coef     = 0.5f * __expf(-2.f * lll[h]);

    const size_t hoff = (size_t)h * DK;
    const float* Qg = Q + ((size_t)b * NSEQ + qb) * DM + hoff;

    for (int idx = t; idx < 64 * 16; idx += 256) {
        int r = idx >> 4, c = (idx & 15) * 4;
        float4 a = *(const float4*)(Qg + (size_t)r * DM + c);
        Qs[r * 65 + c] = a.x; Qs[r * 65 + c + 1] = a.y;
        Qs[r * 65 + c + 2] = a.z; Qs[r * 65 + c + 3] = a.w;
    }

    float accC[4][4] = {}, accV[4][4] = {};
    float rm[4], rl[4];
    #pragma unroll
    for (int i = 0; i < 4; ++i) { rm[i] = -1e30f; rl[i] = 0.f; }

    const int q0 = ty * 4;
    const int c0 = tx * 4;   // key column in S phase; head-dim column in PV phase

    for (int kt = 0; kt < 16; ++kt) {
        const int kb = kt * 64;
        __syncthreads();   // protect K/V/Vv/Ps from prior iteration's readers

        const float* Kg  = K  + ((size_t)b * NSEQ + kb) * DM + hoff;
        const float* Vg  = V  + ((size_t)b * NSEQ + kb) * DM + hoff;
        const float* Vvg = Vv + ((size_t)b * NSEQ + kb) * DM + hoff;
        for (int idx = t; idx < 64 * 16; idx += 256) {
            int r = idx >> 4, c = (idx & 15) * 4;
            float4 a = *(const float4*)(Kg + (size_t)r * DM + c);
            Ks[r * 65 + c] = a.x; Ks[r * 65 + c + 1] = a.y;
            Ks[r * 65 + c + 2] = a.z; Ks[r * 65 + c + 3] = a.w;
            float4 v2 = *(const float4*)(Vg + (size_t)r * DM + c);
            Vs[r * 65 + c] = v2.x; Vs[r * 65 + c + 1] = v2.y;
            Vs[r * 65 + c + 2] = v2.z; Vs[r * 65 + c + 3] = v2.w;
            float4 w2 = *(const float4*)(Vvg + (size_t)r * DM + c);
            Vvs[r * 65 + c] = w2.x; Vvs[r * 65 + c + 1] = w2.y;
            Vvs[r * 65 + c + 2] = w2.z; Vvs[r * 65 + c + 3] = w2.w;
        }
        __syncthreads();

        // ---- scores: qk^T * scale + rbf ----
        float qk[4][4] = {};
        #pragma unroll 8
        for (int d = 0; d < 64; ++d) {
            float qf[4], kf[4];
            #pragma unroll
            for (int i = 0; i < 4; ++i) qf[i] = Qs[(q0 + i) * 65 + d];
            #pragma unroll
            for (int j = 0; j < 4; ++j) kf[j] = Ks[(c0 + j) * 65 + d];
            #pragma unroll
            for (int i = 0; i < 4; ++i)
                #pragma unroll
                for (int j = 0; j < 4; ++j)
                    qk[i][j] += qf[i] * kf[j];
        }
        float s[4][4];
        #pragma unroll
        for (int i = 0; i < 4; ++i) {
            const float* d2row = d2g + (size_t)b * NSEQ * NSEQ
                                     + (size_t)(qb + q0 + i) * NSEQ + kb + c0;
            float4 dd = *(const float4*)d2row;
            s[i][0] = qk[i][0] * QSCALE + sigma_f2 * __expf(-dd.x * coef);
            s[i][1] = qk[i][1] * QSCALE + sigma_f2 * __expf(-dd.y * coef);
            s[i][2] = qk[i][2] * QSCALE + sigma_f2 * __expf(-dd.z * coef);
            s[i][3] = qk[i][3] * QSCALE + sigma_f2 * __expf(-dd.w * coef);
        }

        // ---- online softmax (row reduce over 16 lanes holding the row) ----
        float fscale[4];
        #pragma unroll
        for (int i = 0; i < 4; ++i) {
            float mx = fmaxf(fmaxf(s[i][0], s[i][1]), fmaxf(s[i][2], s[i][3]));
            mx = fmaxf(mx, __shfl_xor_sync(0xffffffffu, mx, 1));
            mx = fmaxf(mx, __shfl_xor_sync(0xffffffffu, mx, 2));
            mx = fmaxf(mx, __shfl_xor_sync(0xffffffffu, mx, 4));
            mx = fmaxf(mx, __shfl_xor_sync(0xffffffffu, mx, 8));
            float mnew = fmaxf(rm[i], mx);
            float f = __expf(rm[i] - mnew);
            float ssum = 0.f;
            #pragma unroll
            for (int j = 0; j < 4; ++j) {
                float p = __expf(s[i][j] - mnew);
                s[i][j] = p;
                ssum += p;
            }
            ssum += __shfl_xor_sync(0xffffffffu, ssum, 1);
            ssum += __shfl_xor_sync(0xffffffffu, ssum, 2);
            ssum += __shfl_xor_sync(0xffffffffu, ssum, 4);
            ssum += __shfl_xor_sync(0xffffffffu, ssum, 8);
            rl[i] = rl[i] * f + ssum;
            rm[i] = mnew;
            fscale[i] = f;
        }
        #pragma unroll
        for (int i = 0; i < 4; ++i) {
            float f = fscale[i], f2 = f * f;
            #pragma unroll
            for (int j = 0; j < 4; ++j) { accC[i][j] *= f; accV[i][j] *= f2; }
        }
        #pragma unroll
        for (int i = 0; i < 4; ++i)
            #pragma unroll
            for (int j = 0; j < 4; ++j)
                Ps[(q0 + i) * 65 + c0 + j] = s[i][j];
        __syncthreads();

        // ---- accumulate P@V and P^2@Vv ----
        #pragma unroll 8
        for (int kk = 0; kk < 64; ++kk) {
            float pf[4], vf[4], wf[4];
            #pragma unroll
            for (int i = 0; i < 4; ++i) pf[i] = Ps[(q0 + i) * 65 + kk];
            #pragma unroll
            for (int j = 0; j < 4; ++j) vf[j] = Vs[kk * 65 + c0 + j];
            #pragma unroll
            for (int j = 0; j < 4; ++j) wf[j] = Vvs[kk * 65 + c0 + j];
            #pragma unroll
            for (int i = 0; i < 4; ++i) {
                float p = pf[i], p2 = p * p;
                #pragma unroll
                for (int j = 0; j < 4; ++j) {
                    accC[i][j] += p  * vf[j];
                    accV[i][j] += p2 * wf[j];
                }
            }
        }
    }

    // ---- normalize and write context / var_attn (heads interleaved in DM) ----
    #pragma unroll
    for (int i = 0; i < 4; ++i) {
        float inv  = 1.f / rl[i];
        float inv2 = inv * inv;
        size_t row = ((size_t)b * NSEQ + qb + q0 + i) * DM + hoff + c0;
        *(float4*)(ctx + row) = make_float4(accC[i][0] * inv,  accC[i][1] * inv,
                                            accC[i][2] * inv,  accC[i][3] * inv);
        *(float4*)(var + row) = make_float4(accV[i][0] * inv2, accV[i][1] * inv2,
                                            accV[i][2] * inv2, accV[i][3] * inv2);
    }
}

// ---------------------------------------------------------------------------
// Launcher
// ---------------------------------------------------------------------------
extern "C" void kernel_launch(void* const* d_in, const int* in_sizes, int n_in,
                              void* d_out, int out_size) {
    const float* H      = (const float*)d_in[0];
    const float* xr     = (const float*)d_in[1];
    const float* Wq     = (const float*)d_in[2];
    const float* bq     = (const float*)d_in[4];
    const float* Wk     = (const float*)d_in[6];
    const float* bk     = (const float*)d_in[8];
    const float* Wv     = (const float*)d_in[10];
    const float* Wv_rho = (const float*)d_in[11];
    const float* bv     = (const float*)d_in[12];
    const float* bv_rho = (const float*)d_in[13];
    const float* Wo     = (const float*)d_in[14];
    const float* Wo_rho = (const float*)d_in[15];
    const float* bo     = (const float*)d_in[16];
    const float* bo_rho = (const float*)d_in[17];
    const float* lsf    = (const float*)d_in[18];
    const float* lll    = (const float*)d_in[19];

    float *Qp, *Kp, *Vp, *Vvp, *ctx, *var, *d2, *Wvs2, *Wos2, *bvs2, *bos2;
    cudaGetSymbolAddress((void**)&Qp,   g_Q);
    cudaGetSymbolAddress((void**)&Kp,   g_K);
    cudaGetSymbolAddress((void**)&Vp,   g_V);
    cudaGetSymbolAddress((void**)&Vvp,  g_Vv);
    cudaGetSymbolAddress((void**)&ctx,  g_ctx);
    cudaGetSymbolAddress((void**)&var,  g_var);
    cudaGetSymbolAddress((void**)&d2,   g_d2);
    cudaGetSymbolAddress((void**)&Wvs2, g_Wvs2);
    cudaGetSymbolAddress((void**)&Wos2, g_Wos2);
    cudaGetSymbolAddress((void**)&bvs2, g_bvs2);
    cudaGetSymbolAddress((void**)&bos2, g_bos2);

    // 1. softplus^2 prep
    sig2_kernel<<<DM * DM / 256, 256>>>(Wv_rho, Wvs2, DM * DM);
    sig2_kernel<<<DM * DM / 256, 256>>>(Wo_rho, Wos2, DM * DM);
    sig2_kernel<<<4, 256>>>(bv_rho, bvs2, DM);
    sig2_kernel<<<4, 256>>>(bo_rho, bos2, DM);

    // 2. pairwise squared distances (head-independent)
    dist2_kernel<<<dim3(16, 16, BATCH), 256>>>(xr, d2);

    // 3. projection GEMMs
    dim3 ggrid(DM / 128, BN / 128);
    gemm_kernel<false, false><<<ggrid, 256>>>(H, Wq, bq, nullptr, Qp);
    gemm_kernel<false, false><<<ggrid, 256>>>(H, Wk, bk, nullptr, Kp);
    gemm_kernel<false, false><<<ggrid, 256>>>(H, Wv, bv, nullptr, Vp);
    gemm_kernel<true,  false><<<ggrid, 256>>>(H, Wvs2, bvs2, nullptr, Vvp);

    // 4. attention (context + variance context)
    static const int attn_smem = 5 * 64 * 65 * sizeof(float);
    cudaFuncSetAttribute(attn_kernel, cudaFuncAttributeMaxDynamicSharedMemorySize, attn_smem);
    attn_kernel<<<dim3(NSEQ / 64, BATCH * NH), 256, attn_smem>>>(
        Qp, Kp, Vp, Vvp, d2, lsf, lll, ctx, var);

    // 5. output GEMMs -> d_out (mean at offset 0, var at offset B*N*D)
    float* out_mean = (float*)d_out;
    float* out_var  = out_mean + (size_t)BN * DM;
    gemm_kernel<false, false><<<ggrid, 256>>>(ctx, Wo, bo, nullptr, out_mean);
    gemm_kernel<true,  true ><<<ggrid, 256>>>(ctx, Wos2, bos2, var, out_var);
}

// round 4
// speedup vs baseline: 1.5097x; 1.5097x over previous
#include <cuda_runtime.h>
#include <cuda_bf16.h>
#include <math.h>
#include <stdint.h>

#define DM    1024
#define BATCH 8
#define NSEQ  1024
#define BN    (BATCH * NSEQ)      // 8192 rows
#define NH    16
#define DK    64
#define QSCALE 0.125f             // 1/sqrt(64)

#define K3      3072              // bf16x3 packed K
#define BK      64                // bf16 per K-chunk (128 bytes/row)
#define KITERS  (K3 / BK)         // 48
#define BM      128
#define BNT     128
#define STAGES  3
#define STAGE_BYTES ((BM + BNT) * 128)          // 32 KB
#define SMEM_GEMM (STAGES * STAGE_BYTES)        // 96 KB

// ---------------------------------------------------------------------------
// Scratch (device globals — no runtime allocation allowed)
// ---------------------------------------------------------------------------
__device__ float g_Q  [BN * DM];
__device__ float g_K  [BN * DM];
__device__ float g_V  [BN * DM];
__device__ float g_Vv [BN * DM];
__device__ float g_ctx[BN * DM];
__device__ float g_var[BN * DM];
__device__ float g_d2 [BATCH * NSEQ * NSEQ];
__device__ float g_bvs2[DM];
__device__ float g_bos2[DM];

__device__ __nv_bfloat16 g_A3H   [BN * K3];
__device__ __nv_bfloat16 g_A3H2  [BN * K3];
__device__ __nv_bfloat16 g_A3ctx [BN * K3];
__device__ __nv_bfloat16 g_A3ctx2[BN * K3];
__device__ __nv_bfloat16 g_B3q   [DM * K3];
__device__ __nv_bfloat16 g_B3k   [DM * K3];
__device__ __nv_bfloat16 g_B3v   [DM * K3];
__device__ __nv_bfloat16 g_B3vs2 [DM * K3];
__device__ __nv_bfloat16 g_B3o   [DM * K3];
__device__ __nv_bfloat16 g_B3os2 [DM * K3];

// ---------------------------------------------------------------------------
// PTX helpers (non-'a' features only: cp.async, ldmatrix, mma.sync)
// ---------------------------------------------------------------------------
__device__ __forceinline__ uint32_t smem_u32(const void* p) {
    uint32_t a;
    asm("{ .reg .u64 t; cvta.to.shared.u64 t, %1; cvt.u32.u64 %0, t; }"
        : "=r"(a) : "l"(p));
    return a;
}
#define SWZ(off) ((off) ^ (((off) >> 3) & 0x70))

__device__ __forceinline__ void cp16(uint32_t dst, const void* src) {
    asm volatile("cp.async.cg.shared.global [%0], [%1], 16;"
                 :: "r"(dst), "l"(src) : "memory");
}
#define CP_COMMIT() asm volatile("cp.async.commit_group;" ::: "memory")

__device__ __forceinline__ void ldsm4(uint32_t* r, uint32_t addr) {
    asm volatile("ldmatrix.sync.aligned.m8n8.x4.shared.b16 {%0,%1,%2,%3}, [%4];"
                 : "=r"(r[0]), "=r"(r[1]), "=r"(r[2]), "=r"(r[3]) : "r"(addr));
}
__device__ __forceinline__ void mma16816(float* c, const uint32_t* a, const uint32_t* b) {
    asm volatile("mma.sync.aligned.m16n8k16.row.col.f32.bf16.bf16.f32 "
                 "{%0,%1,%2,%3}, {%4,%5,%6,%7}, {%8,%9}, {%0,%1,%2,%3};"
                 : "+f"(c[0]), "+f"(c[1]), "+f"(c[2]), "+f"(c[3])
                 : "r"(a[0]), "r"(a[1]), "r"(a[2]), "r"(a[3]), "r"(b[0]), "r"(b[1]));
}

// ---------------------------------------------------------------------------
// softplus(x)^2 elementwise (biases)
// ---------------------------------------------------------------------------
__global__ void sig2_kernel(const float* __restrict__ in, float* __restrict__ out, int n) {
    int i = blockIdx.x * blockDim.x + threadIdx.x;
    if (i < n) {
        float x  = in[i];
        float sp = (x > 15.f) ? x : log1pf(__expf(x));
        out[i] = sp * sp;
    }
}

// ---------------------------------------------------------------------------
// fp32 -> bf16 hi/lo 3-way split packer.
// AFORM=1: [hi|lo|hi]  (A operand);  AFORM=0: [hi|hi|lo]  (B operand)
// PRE: 0 = identity, 1 = square, 2 = softplus^2
// ---------------------------------------------------------------------------
template<int AFORM, int PRE>
__global__ void split3_kernel(const float* __restrict__ X, __nv_bfloat16* __restrict__ Y,
                              int rows) {
    int idx = blockIdx.x * blockDim.x + threadIdx.x;   // one float4 per thread
    int r  = idx >> 8;
    int c4 = idx & 255;
    if (r >= rows) return;
    float4 x = *(const float4*)(X + (size_t)r * DM + c4 * 4);
    float v[4] = {x.x, x.y, x.z, x.w};
    #pragma unroll
    for (int i = 0; i < 4; ++i) {
        if (PRE == 1) v[i] = v[i] * v[i];
        if (PRE == 2) {
            float sp = (v[i] > 15.f) ? v[i] : log1pf(__expf(v[i]));
            v[i] = sp * sp;
        }
    }
    unsigned short hu[4], lu[4];
    #pragma unroll
    for (int i = 0; i < 4; ++i) {
        __nv_bfloat16 h = __float2bfloat16_rn(v[i]);
        float hr = __bfloat162float(h);
        __nv_bfloat16 l = __float2bfloat16_rn(v[i] - hr);
        hu[i] = __bfloat16_as_ushort(h);
        lu[i] = __bfloat16_as_ushort(l);
    }
    uint2 hp, lp;
    hp.x = (uint32_t)hu[0] | ((uint32_t)hu[1] << 16);
    hp.y = (uint32_t)hu[2] | ((uint32_t)hu[3] << 16);
    lp.x = (uint32_t)lu[0] | ((uint32_t)lu[1] << 16);
    lp.y = (uint32_t)lu[2] | ((uint32_t)lu[3] << 16);
    size_t ob = (size_t)r * K3 + c4 * 4;
    *(uint2*)(Y + ob) = hp;
    if (AFORM) {
        *(uint2*)(Y + ob + DM)     = lp;
        *(uint2*)(Y + ob + 2 * DM) = hp;
    } else {
        *(uint2*)(Y + ob + DM)     = hp;
        *(uint2*)(Y + ob + 2 * DM) = lp;
    }
}

// ---------------------------------------------------------------------------
// bf16 HMMA GEMM: C[8192,1024] = A3[8192,3072] . B3[1024,3072]^T
// + bias[n] (+ add[m,n]).  128x128 tile, BK=64, 3-stage cp.async, 8 warps.
// Warp grid 2(m) x 4(n); warp tile 64x32.
// ---------------------------------------------------------------------------
template<bool HASADD>
__global__ void __launch_bounds__(256, 2)
gemm_tc(const __nv_bfloat16* __restrict__ A3, const __nv_bfloat16* __restrict__ B3,
        const float* __restrict__ bias, const float* __restrict__ add,
        float* __restrict__ C) {
    extern __shared__ __align__(1024) char smem[];
    const uint32_t sb = smem_u32(smem);
    const int t    = threadIdx.x;
    const int wid  = t >> 5;
    const int lane = t & 31;
    const int wm   = wid & 1;          // 0..1
    const int wn   = wid >> 1;         // 0..3
    const int mBase = blockIdx.y * BM;
    const int nBase = blockIdx.x * BNT;

    // global-load mapping: row r = t>>1, 4 consecutive 16B units at (t&1)*4
    const int r  = t >> 1;
    const int uc = (t & 1) * 4;
    const __nv_bfloat16* aRow = A3 + (size_t)(mBase + r) * K3 + uc * 8;
    const __nv_bfloat16* bRow = B3 + (size_t)(nBase + r) * K3 + uc * 8;

    auto load_stage = [&](int buf, int c) {
        uint32_t sA = sb + buf * STAGE_BYTES;
        uint32_t sB = sA + BM * 128;
        const __nv_bfloat16* ga = aRow + c * BK;
        const __nv_bfloat16* gb = bRow + c * BK;
        #pragma unroll
        for (int i = 0; i < 4; ++i) {
            uint32_t bo = r * 128 + (uc + i) * 16;
            cp16(sA + SWZ(bo), ga + i * 8);
            cp16(sB + SWZ(bo), gb + i * 8);
        }
        CP_COMMIT();
    };

    // per-lane ldmatrix selectors
    const int aRowSel = (lane & 7) | (((lane >> 3) & 1) << 3);   // + row within 16
    const int aKSel   = (lane >> 4) << 4;                        // +0/+16 bytes (k half)
    const int bNSel   = (lane & 7) | ((lane >> 4) << 3);
    const int bKSel   = ((lane >> 3) & 1) << 4;

    float acc[4][4][4] = {};   // [mi][ni][reg]

    load_stage(0, 0);
    load_stage(1, 1);

    for (int kt = 0; kt < KITERS; ++kt) {
        const int buf = kt % STAGES;
        if (kt == KITERS - 1) asm volatile("cp.async.wait_group 0;" ::: "memory");
        else                  asm volatile("cp.async.wait_group 1;" ::: "memory");
        __syncthreads();

        if (kt + 2 < KITERS) load_stage((kt + 2) % STAGES, kt + 2);

        uint32_t sA = sb + buf * STAGE_BYTES;
        uint32_t sB = sA + BM * 128;
        #pragma unroll
        for (int ks = 0; ks < 4; ++ks) {
            uint32_t af[4][4], bf[2][4];
            #pragma unroll
            for (int mi = 0; mi < 4; ++mi) {
                uint32_t bo = (uint32_t)((wm * 64 + mi * 16 + aRowSel) * 128
                                         + ks * 32 + aKSel);
                ldsm4(af[mi], sA + SWZ(bo));
            }
            #pragma unroll
            for (int pi = 0; pi < 2; ++pi) {
                uint32_t bo = (uint32_t)((wn * 32 + pi * 16 + bNSel) * 128
                                         + ks * 32 + bKSel);
                ldsm4(bf[pi], sB + SWZ(bo));
            }
            #pragma unroll
            for (int mi = 0; mi < 4; ++mi)
                #pragma unroll
                for (int ni = 0; ni < 4; ++ni)
                    mma16816(acc[mi][ni], af[mi], &bf[ni >> 1][(ni & 1) * 2]);
        }
        __syncthreads();
    }

    // register epilogue: bias (+ add) then float2 stores
    const int lr = lane >> 2;
    const int lc = (lane & 3) * 2;
    const int rB = mBase + wm * 64;
    const int cB = nBase + wn * 32;
    #pragma unroll
    for (int mi = 0; mi < 4; ++mi) {
        #pragma unroll
        for (int ni = 0; ni < 4; ++ni) {
            int col  = cB + ni * 8 + lc;
            int row0 = rB + mi * 16 + lr;
            float2 bi = *(const float2*)(bias + col);
            float2 v0 = make_float2(acc[mi][ni][0] + bi.x, acc[mi][ni][1] + bi.y);
            float2 v1 = make_float2(acc[mi][ni][2] + bi.x, acc[mi][ni][3] + bi.y);
            size_t o0 = (size_t)row0 * DM + col;
            size_t o1 = (size_t)(row0 + 8) * DM + col;
            if (HASADD) {
                float2 a0 = *(const float2*)(add + o0);
                float2 a1 = *(const float2*)(add + o1);
                v0.x += a0.x; v0.y += a0.y; v1.x += a1.x; v1.y += a1.y;
            }
            *(float2*)(C + o0) = v0;
            *(float2*)(C + o1) = v1;
        }
    }
}

// ---------------------------------------------------------------------------
// dist2[b,n,m] = max(|x_n|^2 + |x_m|^2 - 2 x_n.x_m, 0),  x: [B,1024,16]
// ---------------------------------------------------------------------------
__global__ void dist2_kernel(const float* __restrict__ xr, float* __restrict__ d2) {
    __shared__ float xm[64][17];
    __shared__ float xn[64][17];
    __shared__ float x2m[64];
    __shared__ float x2n[64];

    const int t  = threadIdx.x;
    const int b  = blockIdx.z;
    const int mi = blockIdx.y * 64;
    const int nj = blockIdx.x * 64;

    for (int idx = t; idx < 64 * 4; idx += 256) {
        int r = idx >> 2, c = (idx & 3) * 4;
        float4 a = *(const float4*)(xr + ((size_t)b * NSEQ + mi + r) * 16 + c);
        xm[r][c] = a.x; xm[r][c+1] = a.y; xm[r][c+2] = a.z; xm[r][c+3] = a.w;
        float4 bb = *(const float4*)(xr + ((size_t)b * NSEQ + nj + r) * 16 + c);
        xn[r][c] = bb.x; xn[r][c+1] = bb.y; xn[r][c+2] = bb.z; xn[r][c+3] = bb.w;
    }
    __syncthreads();

    if (t < 64) {
        float s = 0.f;
        #pragma unroll
        for (int c = 0; c < 16; ++c) s += xm[t][c] * xm[t][c];
        x2m[t] = s;
    } else if (t < 128) {
        int r = t - 64;
        float s = 0.f;
        #pragma unroll
        for (int c = 0; c < 16; ++c) s += xn[r][c] * xn[r][c];
        x2n[r] = s;
    }
    __syncthreads();

    const int tx = t & 15, ty = t >> 4;
    #pragma unroll
    for (int i = 0; i < 4; ++i) {
        int row = ty * 4 + i;
        float out4[4];
        #pragma unroll
        for (int j = 0; j < 4; ++j) {
            int col = tx * 4 + j;
            float dot = 0.f;
            #pragma unroll
            for (int c = 0; c < 16; ++c) dot += xm[row][c] * xn[col][c];
            out4[j] = fmaxf(x2m[row] + x2n[col] - 2.f * dot, 0.f);
        }
        float4 v4 = make_float4(out4[0], out4[1], out4[2], out4[3]);
        *(float4*)(d2 + ((size_t)b * NSEQ + mi + row) * NSEQ + nj + tx * 4) = v4;
    }
}

// ---------------------------------------------------------------------------
// Flash attention with RBF bias; accumulates P@V and P^2@Vv simultaneously.
// ---------------------------------------------------------------------------
__global__ void __launch_bounds__(256)
attn_kernel(const float* __restrict__ Q, const float* __restrict__ K,
            const float* __restrict__ V, const float* __restrict__ Vv,
            const float* __restrict__ d2g,
            const float* __restrict__ lsf, const float* __restrict__ lll,
            float* __restrict__ ctx, float* __restrict__ var) {
    extern __shared__ float sm[];
    float* Qs  = sm;               // 64*65
    float* Ks  = Qs  + 64 * 65;
    float* Vs  = Ks  + 64 * 65;
    float* Vvs = Vs  + 64 * 65;
    float* Ps  = Vvs + 64 * 65;

    const int t  = threadIdx.x;
    const int tx = t & 15, ty = t >> 4;
    const int bh = blockIdx.y;
    const int b  = bh >> 4, h = bh & 15;
    const int qb = blockIdx.x * 64;

    const float sigma_f2 = __expf(2.f * lsf[h]);
    const float coef     = 0.5f * __expf(-2.f * lll[h]);

    const size_t hoff = (size_t)h * DK;
    const float* Qg = Q + ((size_t)b * NSEQ + qb) * DM + hoff;

    for (int idx = t; idx < 64 * 16; idx += 256) {
        int r = idx >> 4, c = (idx & 15) * 4;
        float4 a = *(const float4*)(Qg + (size_t)r * DM + c);
        Qs[r * 65 + c] = a.x; Qs[r * 65 + c + 1] = a.y;
        Qs[r * 65 + c + 2] = a.z; Qs[r * 65 + c + 3] = a.w;
    }

    float accC[4][4] = {}, accV[4][4] = {};
    float rm[4], rl[4];
    #pragma unroll
    for (int i = 0; i < 4; ++i) { rm[i] = -1e30f; rl[i] = 0.f; }

    const int q0 = ty * 4;
    const int c0 = tx * 4;

    for (int kt = 0; kt < 16; ++kt) {
        const int kb = kt * 64;
        __syncthreads();

        const float* Kg  = K  + ((size_t)b * NSEQ + kb) * DM + hoff;
        const float* Vg  = V  + ((size_t)b * NSEQ + kb) * DM + hoff;
        const float* Vvg = Vv + ((size_t)b * NSEQ + kb) * DM + hoff;
        for (int idx = t; idx < 64 * 16; idx += 256) {
            int r = idx >> 4, c = (idx & 15) * 4;
            float4 a = *(const float4*)(Kg + (size_t)r * DM + c);
            Ks[r * 65 + c] = a.x; Ks[r * 65 + c + 1] = a.y;
            Ks[r * 65 + c + 2] = a.z; Ks[r * 65 + c + 3] = a.w;
            float4 v2 = *(const float4*)(Vg + (size_t)r * DM + c);
            Vs[r * 65 + c] = v2.x; Vs[r * 65 + c + 1] = v2.y;
            Vs[r * 65 + c + 2] = v2.z; Vs[r * 65 + c + 3] = v2.w;
            float4 w2 = *(const float4*)(Vvg + (size_t)r * DM + c);
            Vvs[r * 65 + c] = w2.x; Vvs[r * 65 + c + 1] = w2.y;
            Vvs[r * 65 + c + 2] = w2.z; Vvs[r * 65 + c + 3] = w2.w;
        }
        __syncthreads();

        float qk[4][4] = {};
        #pragma unroll 8
        for (int d = 0; d < 64; ++d) {
            float qf[4], kf[4];
            #pragma unroll
            for (int i = 0; i < 4; ++i) qf[i] = Qs[(q0 + i) * 65 + d];
            #pragma unroll
            for (int j = 0; j < 4; ++j) kf[j] = Ks[(c0 + j) * 65 + d];
            #pragma unroll
            for (int i = 0; i < 4; ++i)
                #pragma unroll
                for (int j = 0; j < 4; ++j)
                    qk[i][j] += qf[i] * kf[j];
        }
        float s[4][4];
        #pragma unroll
        for (int i = 0; i < 4; ++i) {
            const float* d2row = d2g + (size_t)b * NSEQ * NSEQ
                                     + (size_t)(qb + q0 + i) * NSEQ + kb + c0;
            float4 dd = *(const float4*)d2row;
            s[i][0] = qk[i][0] * QSCALE + sigma_f2 * __expf(-dd.x * coef);
            s[i][1] = qk[i][1] * QSCALE + sigma_f2 * __expf(-dd.y * coef);
            s[i][2] = qk[i][2] * QSCALE + sigma_f2 * __expf(-dd.z * coef);
            s[i][3] = qk[i][3] * QSCALE + sigma_f2 * __expf(-dd.w * coef);
        }

        float fscale[4];
        #pragma unroll
        for (int i = 0; i < 4; ++i) {
            float mx = fmaxf(fmaxf(s[i][0], s[i][1]), fmaxf(s[i][2], s[i][3]));
            mx = fmaxf(mx, __shfl_xor_sync(0xffffffffu, mx, 1));
            mx = fmaxf(mx, __shfl_xor_sync(0xffffffffu, mx, 2));
            mx = fmaxf(mx, __shfl_xor_sync(0xffffffffu, mx, 4));
            mx = fmaxf(mx, __shfl_xor_sync(0xffffffffu, mx, 8));
            float mnew = fmaxf(rm[i], mx);
            float f = __expf(rm[i] - mnew);
            float ssum = 0.f;
            #pragma unroll
            for (int j = 0; j < 4; ++j) {
                float p = __expf(s[i][j] - mnew);
                s[i][j] = p;
                ssum += p;
            }
            ssum += __shfl_xor_sync(0xffffffffu, ssum, 1);
            ssum += __shfl_xor_sync(0xffffffffu, ssum, 2);
            ssum += __shfl_xor_sync(0xffffffffu, ssum, 4);
            ssum += __shfl_xor_sync(0xffffffffu, ssum, 8);
            rl[i] = rl[i] * f + ssum;
            rm[i] = mnew;
            fscale[i] = f;
        }
        #pragma unroll
        for (int i = 0; i < 4; ++i) {
            float f = fscale[i], f2 = f * f;
            #pragma unroll
            for (int j = 0; j < 4; ++j) { accC[i][j] *= f; accV[i][j] *= f2; }
        }
        #pragma unroll
        for (int i = 0; i < 4; ++i)
            #pragma unroll
            for (int j = 0; j < 4; ++j)
                Ps[(q0 + i) * 65 + c0 + j] = s[i][j];
        __syncthreads();

        #pragma unroll 8
        for (int kk = 0; kk < 64; ++kk) {
            float pf[4], vf[4], wf[4];
            #pragma unroll
            for (int i = 0; i < 4; ++i) pf[i] = Ps[(q0 + i) * 65 + kk];
            #pragma unroll
            for (int j = 0; j < 4; ++j) vf[j] = Vs[kk * 65 + c0 + j];
            #pragma unroll
            for (int j = 0; j < 4; ++j) wf[j] = Vvs[kk * 65 + c0 + j];
            #pragma unroll
            for (int i = 0; i < 4; ++i) {
                float p = pf[i], p2 = p * p;
                #pragma unroll
                for (int j = 0; j < 4; ++j) {
                    accC[i][j] += p  * vf[j];
                    accV[i][j] += p2 * wf[j];
                }
            }
        }
    }

    #pragma unroll
    for (int i = 0; i < 4; ++i) {
        float inv  = 1.f / rl[i];
        float inv2 = inv * inv;
        size_t row = ((size_t)b * NSEQ + qb + q0 + i) * DM + hoff + c0;
        *(float4*)(ctx + row) = make_float4(accC[i][0] * inv,  accC[i][1] * inv,
                                            accC[i][2] * inv,  accC[i][3] * inv);
        *(float4*)(var + row) = make_float4(accV[i][0] * inv2, accV[i][1] * inv2,
                                            accV[i][2] * inv2, accV[i][3] * inv2);
    }
}

// ---------------------------------------------------------------------------
// Launcher
// ---------------------------------------------------------------------------
extern "C" void kernel_launch(void* const* d_in, const int* in_sizes, int n_in,
                              void* d_out, int out_size) {
    const float* H      = (const float*)d_in[0];
    const float* xr     = (const float*)d_in[1];
    const float* Wq     = (const float*)d_in[2];
    const float* bq     = (const float*)d_in[4];
    const float* Wk     = (const float*)d_in[6];
    const float* bk     = (const float*)d_in[8];
    const float* Wv     = (const float*)d_in[10];
    const float* Wv_rho = (const float*)d_in[11];
    const float* bv     = (const float*)d_in[12];
    const float* bv_rho = (const float*)d_in[13];
    const float* Wo     = (const float*)d_in[14];
    const float* Wo_rho = (const float*)d_in[15];
    const float* bo     = (const float*)d_in[16];
    const float* bo_rho = (const float*)d_in[17];
    const float* lsf    = (const float*)d_in[18];
    const float* lll    = (const float*)d_in[19];

    float *Qp, *Kp, *Vp, *Vvp, *ctx, *var, *d2, *bvs2, *bos2;
    __nv_bfloat16 *a3h, *a3h2, *a3c, *a3c2, *b3q, *b3k, *b3v, *b3vs, *b3o, *b3os;
    cudaGetSymbolAddress((void**)&Qp,   g_Q);
    cudaGetSymbolAddress((void**)&Kp,   g_K);
    cudaGetSymbolAddress((void**)&Vp,   g_V);
    cudaGetSymbolAddress((void**)&Vvp,  g_Vv);
    cudaGetSymbolAddress((void**)&ctx,  g_ctx);
    cudaGetSymbolAddress((void**)&var,  g_var);
    cudaGetSymbolAddress((void**)&d2,   g_d2);
    cudaGetSymbolAddress((void**)&bvs2, g_bvs2);
    cudaGetSymbolAddress((void**)&bos2, g_bos2);
    cudaGetSymbolAddress((void**)&a3h,  g_A3H);
    cudaGetSymbolAddress((void**)&a3h2, g_A3H2);
    cudaGetSymbolAddress((void**)&a3c,  g_A3ctx);
    cudaGetSymbolAddress((void**)&a3c2, g_A3ctx2);
    cudaGetSymbolAddress((void**)&b3q,  g_B3q);
    cudaGetSymbolAddress((void**)&b3k,  g_B3k);
    cudaGetSymbolAddress((void**)&b3v,  g_B3v);
    cudaGetSymbolAddress((void**)&b3vs, g_B3vs2);
    cudaGetSymbolAddress((void**)&b3o,  g_B3o);
    cudaGetSymbolAddress((void**)&b3os, g_B3os2);

    cudaFuncSetAttribute(gemm_tc<false>, cudaFuncAttributeMaxDynamicSharedMemorySize, SMEM_GEMM);
    cudaFuncSetAttribute(gemm_tc<true>,  cudaFuncAttributeMaxDynamicSharedMemorySize, SMEM_GEMM);
    static const int attn_smem = 5 * 64 * 65 * sizeof(float);
    cudaFuncSetAttribute(attn_kernel, cudaFuncAttributeMaxDynamicSharedMemorySize, attn_smem);

    const dim3 ggrid(DM / BNT, BN / BM);       // (8, 64)
    const int splitA_grid = BN;                // rows * 256 threads
    const int splitB_grid = DM;

    // [0,1] bias softplus^2
    sig2_kernel<<<4, 256>>>(bv_rho, bvs2, DM);
    sig2_kernel<<<4, 256>>>(bo_rho, bos2, DM);
    // [2,3] A-operand splits of H and H^2
    split3_kernel<1, 0><<<splitA_grid, 256>>>(H, a3h,  BN);
    split3_kernel<1, 1><<<splitA_grid, 256>>>(H, a3h2, BN);
    // [4,5] Wq split + Q GEMM (GEMM lands at ncu -s 5)
    split3_kernel<0, 0><<<splitB_grid, 256>>>(Wq, b3q, DM);
    gemm_tc<false><<<ggrid, 256, SMEM_GEMM>>>(a3h, b3q, bq, nullptr, Qp);
    // [6,7] K
    split3_kernel<0, 0><<<splitB_grid, 256>>>(Wk, b3k, DM);
    gemm_tc<false><<<ggrid, 256, SMEM_GEMM>>>(a3h, b3k, bk, nullptr, Kp);
    // [8,9] V
    split3_kernel<0, 0><<<splitB_grid, 256>>>(Wv, b3v, DM);
    gemm_tc<false><<<ggrid, 256, SMEM_GEMM>>>(a3h, b3v, bv, nullptr, Vp);
    // [10,11] V variance: (H^2) @ softplus^2(Wv_rho)^T + softplus^2(bv_rho)
    split3_kernel<0, 2><<<splitB_grid, 256>>>(Wv_rho, b3vs, DM);
    gemm_tc<false><<<ggrid, 256, SMEM_GEMM>>>(a3h2, b3vs, bvs2, nullptr, Vvp);
    // [12] pairwise squared distances
    dist2_kernel<<<dim3(16, 16, BATCH), 256>>>(xr, d2);
    // [13] attention
    attn_kernel<<<dim3(NSEQ / 64, BATCH * NH), 256, attn_smem>>>(
        Qp, Kp, Vp, Vvp, d2, lsf, lll, ctx, var);
    // [14,15] ctx splits
    split3_kernel<1, 0><<<splitA_grid, 256>>>(ctx, a3c,  BN);
    split3_kernel<1, 1><<<splitA_grid, 256>>>(ctx, a3c2, BN);
    // [16..19] output GEMMs -> d_out (mean at 0, var at B*N*D)
    float* out_mean = (float*)d_out;
    float* out_var  = out_mean + (size_t)BN * DM;
    split3_kernel<0, 0><<<splitB_grid, 256>>>(Wo, b3o, DM);
    gemm_tc<false><<<ggrid, 256, SMEM_GEMM>>>(a3c, b3o, bo, nullptr, out_mean);
    split3_kernel<0, 2><<<splitB_grid, 256>>>(Wo_rho, b3os, DM);
    gemm_tc<true><<<ggrid, 256, SMEM_GEMM>>>(a3c2, b3os, bos2, var, out_var);
}

// round 6
// speedup vs baseline: 2.2520x; 1.4917x over previous
#include <cuda_runtime.h>
#include <cuda_bf16.h>
#include <math.h>
#include <stdint.h>

#define DM    1024
#define BATCH 8
#define NSEQ  1024
#define BN    (BATCH * NSEQ)      // 8192 rows
#define NH    16
#define DK    64
#define QSCALE 0.125f             // 1/sqrt(64)

#define K3      3072              // bf16x3 packed K
#define BK      64
#define KITERS  (K3 / BK)         // 48
#define BM      128
#define BNT     128
#define STAGES  3
#define STAGE_BYTES ((BM + BNT) * 128)          // 32 KB
#define SMEM_GEMM (STAGES * STAGE_BYTES)        // 96 KB

// attention tiling
#define QB 128                    // q rows per CTA
#define KT 64                     // keys per tile
// attention smem layout (bytes)
#define SM_Q   0                  // 3 chunks x 128 rows x 128B = 49152
#define SM_K   49152              // 2 bufs x 3 chunks x 64 x 128B = 49152
#define SM_V   98304              // 2 bufs x 64 x 256B = 32768
#define SM_VV  131072             // 2 bufs x 64 x 256B = 32768
#define ATTN_SMEM 163840

// ---------------------------------------------------------------------------
// Scratch (device globals — no runtime allocation allowed)
// ---------------------------------------------------------------------------
__device__ float g_Q  [BN * DM];
__device__ float g_K  [BN * DM];
__device__ float g_V  [BN * DM];
__device__ float g_Vv [BN * DM];
__device__ float g_ctx[BN * DM];
__device__ float g_var[BN * DM];
__device__ float g_d2 [BATCH * NSEQ * NSEQ];
__device__ float g_bvs2[DM];
__device__ float g_bos2[DM];

__device__ __nv_bfloat16 g_A3H   [BN * K3];
__device__ __nv_bfloat16 g_A3H2  [BN * K3];
__device__ __nv_bfloat16 g_A3ctx [BN * K3];
__device__ __nv_bfloat16 g_A3ctx2[BN * K3];
__device__ __nv_bfloat16 g_B3q   [DM * K3];
__device__ __nv_bfloat16 g_B3k   [DM * K3];
__device__ __nv_bfloat16 g_B3v   [DM * K3];
__device__ __nv_bfloat16 g_B3vs2 [DM * K3];
__device__ __nv_bfloat16 g_B3o   [DM * K3];
__device__ __nv_bfloat16 g_B3os2 [DM * K3];

// head-major split tensors for TC attention
__device__ __nv_bfloat16 g_q3 [BATCH * NH * NSEQ * 192];
__device__ __nv_bfloat16 g_k3 [BATCH * NH * NSEQ * 192];
__device__ __nv_bfloat16 g_v2 [BATCH * NH * NSEQ * 128];
__device__ __nv_bfloat16 g_vv2[BATCH * NH * NSEQ * 128];

// ---------------------------------------------------------------------------
// PTX helpers (non-'a' features only: cp.async, ldmatrix, mma.sync)
// ---------------------------------------------------------------------------
__device__ __forceinline__ uint32_t smem_u32(const void* p) {
    uint32_t a;
    asm("{ .reg .u64 t; cvta.to.shared.u64 t, %1; cvt.u32.u64 %0, t; }"
        : "=r"(a) : "l"(p));
    return a;
}
#define SWZ(off)    ((off) ^ (((off) >> 3) & 0x70))   // 128B-pitch rows
#define SWZ256(off) ((off) ^ (((off) >> 4) & 0x70))   // 256B-pitch rows

__device__ __forceinline__ void cp16(uint32_t dst, const void* src) {
    asm volatile("cp.async.cg.shared.global [%0], [%1], 16;"
                 :: "r"(dst), "l"(src) : "memory");
}
#define CP_COMMIT() asm volatile("cp.async.commit_group;" ::: "memory")

__device__ __forceinline__ void ldsm4(uint32_t* r, uint32_t addr) {
    asm volatile("ldmatrix.sync.aligned.m8n8.x4.shared.b16 {%0,%1,%2,%3}, [%4];"
                 : "=r"(r[0]), "=r"(r[1]), "=r"(r[2]), "=r"(r[3]) : "r"(addr));
}
__device__ __forceinline__ void ldsm4t(uint32_t* r, uint32_t addr) {
    asm volatile("ldmatrix.sync.aligned.m8n8.x4.trans.shared.b16 {%0,%1,%2,%3}, [%4];"
                 : "=r"(r[0]), "=r"(r[1]), "=r"(r[2]), "=r"(r[3]) : "r"(addr));
}
__device__ __forceinline__ void mma16816(float* c, const uint32_t* a, const uint32_t* b) {
    asm volatile("mma.sync.aligned.m16n8k16.row.col.f32.bf16.bf16.f32 "
                 "{%0,%1,%2,%3}, {%4,%5,%6,%7}, {%8,%9}, {%0,%1,%2,%3};"
                 : "+f"(c[0]), "+f"(c[1]), "+f"(c[2]), "+f"(c[3])
                 : "r"(a[0]), "r"(a[1]), "r"(a[2]), "r"(a[3]), "r"(b[0]), "r"(b[1]));
}
__device__ __forceinline__ uint32_t pack2(float lo, float hi) {
    uint32_t d;
    asm("cvt.rn.bf16x2.f32 %0, %1, %2;" : "=r"(d) : "f"(hi), "f"(lo));
    return d;
}
// split 8 fp32 into hi/lo bf16 A-fragments
__device__ __forceinline__ void frag_split(const float* p8, uint32_t* hi, uint32_t* lo) {
    float hf[8], lf[8];
    #pragma unroll
    for (int e = 0; e < 8; ++e) {
        float hv = __bfloat162float(__float2bfloat16_rn(p8[e]));
        hf[e] = hv; lf[e] = p8[e] - hv;
    }
    hi[0] = pack2(hf[0], hf[1]); hi[1] = pack2(hf[2], hf[3]);
    hi[2] = pack2(hf[4], hf[5]); hi[3] = pack2(hf[6], hf[7]);
    lo[0] = pack2(lf[0], lf[1]); lo[1] = pack2(lf[2], lf[3]);
    lo[2] = pack2(lf[4], lf[5]); lo[3] = pack2(lf[6], lf[7]);
}

// ---------------------------------------------------------------------------
// softplus(x)^2 elementwise (biases)
// ---------------------------------------------------------------------------
__global__ void sig2_kernel(const float* __restrict__ in, float* __restrict__ out, int n) {
    int i = blockIdx.x * blockDim.x + threadIdx.x;
    if (i < n) {
        float x  = in[i];
        float sp = (x > 15.f) ? x : log1pf(__expf(x));
        out[i] = sp * sp;
    }
}

// ---------------------------------------------------------------------------
// fp32 -> bf16 hi/lo 3-way split packer (GEMM operands, [rows,1024]->[rows,3072])
// AFORM=1: [hi|lo|hi]  (A operand);  AFORM=0: [hi|hi|lo]  (B operand)
// PRE: 0 = identity, 1 = square, 2 = softplus^2
// ---------------------------------------------------------------------------
template<int AFORM, int PRE>
__global__ void split3_kernel(const float* __restrict__ X, __nv_bfloat16* __restrict__ Y,
                              int rows) {
    int idx = blockIdx.x * blockDim.x + threadIdx.x;
    int r  = idx >> 8;
    int c4 = idx & 255;
    if (r >= rows) return;
    float4 x = *(const float4*)(X + (size_t)r * DM + c4 * 4);
    float v[4] = {x.x, x.y, x.z, x.w};
    #pragma unroll
    for (int i = 0; i < 4; ++i) {
        if (PRE == 1) v[i] = v[i] * v[i];
        if (PRE == 2) {
            float sp = (v[i] > 15.f) ? v[i] : log1pf(__expf(v[i]));
            v[i] = sp * sp;
        }
    }
    unsigned short hu[4], lu[4];
    #pragma unroll
    for (int i = 0; i < 4; ++i) {
        __nv_bfloat16 hb = __float2bfloat16_rn(v[i]);
        float hr = __bfloat162float(hb);
        __nv_bfloat16 lb = __float2bfloat16_rn(v[i] - hr);
        hu[i] = __bfloat16_as_ushort(hb);
        lu[i] = __bfloat16_as_ushort(lb);
    }
    uint2 hp, lp;
    hp.x = (uint32_t)hu[0] | ((uint32_t)hu[1] << 16);
    hp.y = (uint32_t)hu[2] | ((uint32_t)hu[3] << 16);
    lp.x = (uint32_t)lu[0] | ((uint32_t)lu[1] << 16);
    lp.y = (uint32_t)lu[2] | ((uint32_t)lu[3] << 16);
    size_t ob = (size_t)r * K3 + c4 * 4;
    *(uint2*)(Y + ob) = hp;
    if (AFORM) {
        *(uint2*)(Y + ob + DM)     = lp;
        *(uint2*)(Y + ob + 2 * DM) = hp;
    } else {
        *(uint2*)(Y + ob + DM)     = hp;
        *(uint2*)(Y + ob + 2 * DM) = lp;
    }
}

// ---------------------------------------------------------------------------
// head-major split for attention: [BN,1024] fp32 -> [B,H,N,NW] bf16
// NW=192 AFORM=1: [hi|lo|hi]; NW=192 AFORM=0: [hi|hi|lo]; NW=128: [hi|lo]
// grid = BN blocks x 256 threads (one float4 per thread)
// ---------------------------------------------------------------------------
template<int NW, int AFORM>
__global__ void head_split(const float* __restrict__ X, __nv_bfloat16* __restrict__ Y) {
    int row = blockIdx.x;
    int c4  = threadIdx.x;
    float4 x = *(const float4*)(X + (size_t)row * DM + c4 * 4);
    int hh = c4 >> 4, dl = (c4 & 15) * 4;
    int b = row >> 10, n = row & 1023;
    size_t base = ((size_t)(b * NH + hh) * NSEQ + n) * NW + dl;
    float v[4] = {x.x, x.y, x.z, x.w};
    unsigned short hu[4], lu[4];
    #pragma unroll
    for (int i = 0; i < 4; ++i) {
        __nv_bfloat16 hb = __float2bfloat16_rn(v[i]);
        float hr = __bfloat162float(hb);
        __nv_bfloat16 lb = __float2bfloat16_rn(v[i] - hr);
        hu[i] = __bfloat16_as_ushort(hb);
        lu[i] = __bfloat16_as_ushort(lb);
    }
    uint2 hp, lp;
    hp.x = (uint32_t)hu[0] | ((uint32_t)hu[1] << 16);
    hp.y = (uint32_t)hu[2] | ((uint32_t)hu[3] << 16);
    lp.x = (uint32_t)lu[0] | ((uint32_t)lu[1] << 16);
    lp.y = (uint32_t)lu[2] | ((uint32_t)lu[3] << 16);
    *(uint2*)(Y + base) = hp;
    if (NW == 192) {
        if (AFORM) { *(uint2*)(Y + base + 64) = lp; *(uint2*)(Y + base + 128) = hp; }
        else       { *(uint2*)(Y + base + 64) = hp; *(uint2*)(Y + base + 128) = lp; }
    } else {
        *(uint2*)(Y + base + 64) = lp;
    }
}

// ---------------------------------------------------------------------------
// bf16 HMMA GEMM (unchanged from round 4)
// ---------------------------------------------------------------------------
template<bool HASADD>
__global__ void __launch_bounds__(256, 2)
gemm_tc(const __nv_bfloat16* __restrict__ A3, const __nv_bfloat16* __restrict__ B3,
        const float* __restrict__ bias, const float* __restrict__ add,
        float* __restrict__ C) {
    extern __shared__ __align__(1024) char smem[];
    const uint32_t sb = smem_u32(smem);
    const int t    = threadIdx.x;
    const int wid  = t >> 5;
    const int lane = t & 31;
    const int wm   = wid & 1;
    const int wn   = wid >> 1;
    const int mBase = blockIdx.y * BM;
    const int nBase = blockIdx.x * BNT;

    const int r  = t >> 1;
    const int uc = (t & 1) * 4;
    const __nv_bfloat16* aRow = A3 + (size_t)(mBase + r) * K3 + uc * 8;
    const __nv_bfloat16* bRow = B3 + (size_t)(nBase + r) * K3 + uc * 8;

    auto load_stage = [&](int buf, int c) {
        uint32_t sA = sb + buf * STAGE_BYTES;
        uint32_t sB = sA + BM * 128;
        const __nv_bfloat16* ga = aRow + c * BK;
        const __nv_bfloat16* gb = bRow + c * BK;
        #pragma unroll
        for (int i = 0; i < 4; ++i) {
            uint32_t bo = r * 128 + (uc + i) * 16;
            cp16(sA + SWZ(bo), ga + i * 8);
            cp16(sB + SWZ(bo), gb + i * 8);
        }
        CP_COMMIT();
    };

    const int aRowSel = (lane & 7) | (((lane >> 3) & 1) << 3);
    const int aKSel   = (lane >> 4) << 4;
    const int bNSel   = (lane & 7) | ((lane >> 4) << 3);
    const int bKSel   = ((lane >> 3) & 1) << 4;

    float acc[4][4][4] = {};

    load_stage(0, 0);
    load_stage(1, 1);

    for (int kt = 0; kt < KITERS; ++kt) {
        const int buf = kt % STAGES;
        if (kt == KITERS - 1) asm volatile("cp.async.wait_group 0;" ::: "memory");
        else                  asm volatile("cp.async.wait_group 1;" ::: "memory");
        __syncthreads();

        if (kt + 2 < KITERS) load_stage((kt + 2) % STAGES, kt + 2);

        uint32_t sA = sb + buf * STAGE_BYTES;
        uint32_t sB = sA + BM * 128;
        #pragma unroll
        for (int ks = 0; ks < 4; ++ks) {
            uint32_t af[4][4], bfr[2][4];
            #pragma unroll
            for (int mi = 0; mi < 4; ++mi) {
                uint32_t bo = (uint32_t)((wm * 64 + mi * 16 + aRowSel) * 128
                                         + ks * 32 + aKSel);
                ldsm4(af[mi], sA + SWZ(bo));
            }
            #pragma unroll
            for (int pi = 0; pi < 2; ++pi) {
                uint32_t bo = (uint32_t)((wn * 32 + pi * 16 + bNSel) * 128
                                         + ks * 32 + bKSel);
                ldsm4(bfr[pi], sB + SWZ(bo));
            }
            #pragma unroll
            for (int mi = 0; mi < 4; ++mi)
                #pragma unroll
                for (int ni = 0; ni < 4; ++ni)
                    mma16816(acc[mi][ni], af[mi], &bfr[ni >> 1][(ni & 1) * 2]);
        }
        __syncthreads();
    }

    const int lr = lane >> 2;
    const int lc = (lane & 3) * 2;
    const int rB = mBase + wm * 64;
    const int cB = nBase + wn * 32;
    #pragma unroll
    for (int mi = 0; mi < 4; ++mi) {
        #pragma unroll
        for (int ni = 0; ni < 4; ++ni) {
            int col  = cB + ni * 8 + lc;
            int row0 = rB + mi * 16 + lr;
            float2 bi = *(const float2*)(bias + col);
            float2 v0 = make_float2(acc[mi][ni][0] + bi.x, acc[mi][ni][1] + bi.y);
            float2 v1 = make_float2(acc[mi][ni][2] + bi.x, acc[mi][ni][3] + bi.y);
            size_t o0 = (size_t)row0 * DM + col;
            size_t o1 = (size_t)(row0 + 8) * DM + col;
            if (HASADD) {
                float2 a0 = *(const float2*)(add + o0);
                float2 a1 = *(const float2*)(add + o1);
                v0.x += a0.x; v0.y += a0.y; v1.x += a1.x; v1.y += a1.y;
            }
            *(float2*)(C + o0) = v0;
            *(float2*)(C + o1) = v1;
        }
    }
}

// ---------------------------------------------------------------------------
// dist2 (unchanged)
// ---------------------------------------------------------------------------
__global__ void dist2_kernel(const float* __restrict__ xr, float* __restrict__ d2) {
    __shared__ float xm[64][17];
    __shared__ float xn[64][17];
    __shared__ float x2m[64];
    __shared__ float x2n[64];

    const int t  = threadIdx.x;
    const int b  = blockIdx.z;
    const int mi = blockIdx.y * 64;
    const int nj = blockIdx.x * 64;

    for (int idx = t; idx < 64 * 4; idx += 256) {
        int r = idx >> 2, c = (idx & 3) * 4;
        float4 a = *(const float4*)(xr + ((size_t)b * NSEQ + mi + r) * 16 + c);
        xm[r][c] = a.x; xm[r][c+1] = a.y; xm[r][c+2] = a.z; xm[r][c+3] = a.w;
        float4 bb = *(const float4*)(xr + ((size_t)b * NSEQ + nj + r) * 16 + c);
        xn[r][c] = bb.x; xn[r][c+1] = bb.y; xn[r][c+2] = bb.z; xn[r][c+3] = bb.w;
    }
    __syncthreads();

    if (t < 64) {
        float s = 0.f;
        #pragma unroll
        for (int c = 0; c < 16; ++c) s += xm[t][c] * xm[t][c];
        x2m[t] = s;
    } else if (t < 128) {
        int r = t - 64;
        float s = 0.f;
        #pragma unroll
        for (int c = 0; c < 16; ++c) s += xn[r][c] * xn[r][c];
        x2n[r] = s;
    }
    __syncthreads();

    const int tx = t & 15, ty = t >> 4;
    #pragma unroll
    for (int i = 0; i < 4; ++i) {
        int row = ty * 4 + i;
        float out4[4];
        #pragma unroll
        for (int j = 0; j < 4; ++j) {
            int col = tx * 4 + j;
            float dot = 0.f;
            #pragma unroll
            for (int c = 0; c < 16; ++c) dot += xm[row][c] * xn[col][c];
            out4[j] = fmaxf(x2m[row] + x2n[col] - 2.f * dot, 0.f);
        }
        float4 v4 = make_float4(out4[0], out4[1], out4[2], out4[3]);
        *(float4*)(d2 + ((size_t)b * NSEQ + mi + row) * NSEQ + nj + tx * 4) = v4;
    }
}

// ---------------------------------------------------------------------------
// Tensor-core flash attention with RBF bias, split-bf16 throughout.
// grid (NSEQ/QB=8, B*H=128), 256 threads (8 warps x 16 q-rows).
// ---------------------------------------------------------------------------
__global__ void __launch_bounds__(256, 1)
attn_tc(const __nv_bfloat16* __restrict__ q3, const __nv_bfloat16* __restrict__ k3,
        const __nv_bfloat16* __restrict__ v2, const __nv_bfloat16* __restrict__ vv2,
        const float* __restrict__ d2g,
        const float* __restrict__ lsf, const float* __restrict__ lll,
        float* __restrict__ ctx, float* __restrict__ var) {
    extern __shared__ __align__(1024) char smem[];
    const uint32_t sb = smem_u32(smem);
    const int t    = threadIdx.x;
    const int wid  = t >> 5;
    const int lane = t & 31;
    const int qb   = blockIdx.x * QB;
    const int bh   = blockIdx.y;
    const int b    = bh >> 4, hh = bh & 15;

    const float sigma_f2 = __expf(2.f * lsf[hh]);
    const float coef     = 0.5f * __expf(-2.f * lll[hh]);

    const __nv_bfloat16* Qg  = q3  + ((size_t)bh * NSEQ + qb) * 192;
    const __nv_bfloat16* Kg  = k3  + (size_t)bh * NSEQ * 192;
    const __nv_bfloat16* Vg  = v2  + (size_t)bh * NSEQ * 128;
    const __nv_bfloat16* VVg = vv2 + (size_t)bh * NSEQ * 128;

    // ---- Q tile load (once): 128 rows x 24 units -> 3 chunks ----
    for (int i = t; i < QB * 24; i += 256) {
        int row = i / 24, u = i % 24;
        cp16(sb + SM_Q + (u >> 3) * 16384 + SWZ((uint32_t)(row * 128 + (u & 7) * 16)),
             Qg + (size_t)row * 192 + u * 8);
    }

    auto load_kv = [&](int buf, int kt) {
        const __nv_bfloat16* kg = Kg + (size_t)kt * KT * 192;
        for (int i = t; i < KT * 24; i += 256) {
            int row = i / 24, u = i % 24;
            cp16(sb + SM_K + buf * 24576 + (u >> 3) * 8192
                    + SWZ((uint32_t)(row * 128 + (u & 7) * 16)),
                 kg + (size_t)row * 192 + u * 8);
        }
        const __nv_bfloat16* vg = Vg + (size_t)kt * KT * 128;
        const __nv_bfloat16* wg = VVg + (size_t)kt * KT * 128;
        for (int i = t; i < KT * 16; i += 256) {
            int row = i >> 4, u = i & 15;
            uint32_t so = SWZ256((uint32_t)(row * 256 + u * 16));
            cp16(sb + SM_V  + buf * 16384 + so, vg + (size_t)row * 128 + u * 8);
            cp16(sb + SM_VV + buf * 16384 + so, wg + (size_t)row * 128 + u * 8);
        }
        CP_COMMIT();
    };
    load_kv(0, 0);    // group 0 = Q + tile 0

    // per-lane ldsm selectors
    const int l15 = lane & 15;
    const int lHi = (lane >> 4) << 4;                // 0 / 16 bytes
    const uint32_t aRowOff = (uint32_t)((wid * 16 + l15) * 128 + lHi);
    const int g    = lane >> 3;
    const int keyl = ((g >> 1) << 3) + (lane & 7);
    const uint32_t kCol = (uint32_t)((g & 1) << 4);
    const int rr    = lane >> 2;                     // 0..7
    const int cpair = (lane & 3) * 2;

    float accC[8][4] = {}, accV[8][4] = {};
    float rm0 = -1e30f, rm1 = -1e30f, rl0 = 0.f, rl1 = 0.f;

    for (int kt = 0; kt < NSEQ / KT; ++kt) {
        if (kt + 1 < NSEQ / KT) { __syncthreads(); load_kv((kt + 1) & 1, kt + 1); }
        if (kt + 1 < NSEQ / KT) asm volatile("cp.async.wait_group 1;" ::: "memory");
        else                    asm volatile("cp.async.wait_group 0;" ::: "memory");
        __syncthreads();

        const int buf = kt & 1;
        const uint32_t kB  = sb + SM_K  + buf * 24576;
        const uint32_t vB  = sb + SM_V  + buf * 16384;
        const uint32_t vvB = sb + SM_VV + buf * 16384;

        // ---- S = Q3 . K3^T over 192 packed dims ----
        float sacc[8][4];
        #pragma unroll
        for (int j = 0; j < 8; ++j)
            #pragma unroll
            for (int e = 0; e < 4; ++e) sacc[j][e] = 0.f;

        #pragma unroll
        for (int ks = 0; ks < 12; ++ks) {
            uint32_t a[4];
            ldsm4(a, sb + SM_Q + (ks >> 2) * 16384 + SWZ(aRowOff + (ks & 3) * 32));
            #pragma unroll
            for (int n0 = 0; n0 < 4; ++n0) {
                uint32_t kb4[4];
                ldsm4(kb4, kB + (ks >> 2) * 8192
                         + SWZ((uint32_t)((n0 * 16 + keyl) * 128) + (ks & 3) * 32 + kCol));
                mma16816(sacc[2 * n0],     a, kb4);
                mma16816(sacc[2 * n0 + 1], a, kb4 + 2);
            }
        }

        // ---- rbf + online softmax (rows r, r+8 per lane) ----
        const int kb0 = kt * KT;
        const float* d2r0 = d2g + (size_t)b * NSEQ * NSEQ
                          + (size_t)(qb + wid * 16 + rr) * NSEQ + kb0;
        const float* d2r1 = d2r0 + 8 * NSEQ;
        #pragma unroll
        for (int j = 0; j < 8; ++j) {
            float2 da = *(const float2*)(d2r0 + j * 8 + cpair);
            float2 db = *(const float2*)(d2r1 + j * 8 + cpair);
            sacc[j][0] = sacc[j][0] * QSCALE + sigma_f2 * __expf(-da.x * coef);
            sacc[j][1] = sacc[j][1] * QSCALE + sigma_f2 * __expf(-da.y * coef);
            sacc[j][2] = sacc[j][2] * QSCALE + sigma_f2 * __expf(-db.x * coef);
            sacc[j][3] = sacc[j][3] * QSCALE + sigma_f2 * __expf(-db.y * coef);
        }
        float mx0 = -1e30f, mx1 = -1e30f;
        #pragma unroll
        for (int j = 0; j < 8; ++j) {
            mx0 = fmaxf(mx0, fmaxf(sacc[j][0], sacc[j][1]));
            mx1 = fmaxf(mx1, fmaxf(sacc[j][2], sacc[j][3]));
        }
        mx0 = fmaxf(mx0, __shfl_xor_sync(0xffffffffu, mx0, 1));
        mx0 = fmaxf(mx0, __shfl_xor_sync(0xffffffffu, mx0, 2));
        mx1 = fmaxf(mx1, __shfl_xor_sync(0xffffffffu, mx1, 1));
        mx1 = fmaxf(mx1, __shfl_xor_sync(0xffffffffu, mx1, 2));
        float m0n = fmaxf(rm0, mx0), m1n = fmaxf(rm1, mx1);
        float f0 = __expf(rm0 - m0n), f1 = __expf(rm1 - m1n);
        rm0 = m0n; rm1 = m1n;
        float sum0 = 0.f, sum1 = 0.f;
        #pragma unroll
        for (int j = 0; j < 8; ++j) {
            sacc[j][0] = __expf(sacc[j][0] - m0n); sum0 += sacc[j][0];
            sacc[j][1] = __expf(sacc[j][1] - m0n); sum0 += sacc[j][1];
            sacc[j][2] = __expf(sacc[j][2] - m1n); sum1 += sacc[j][2];
            sacc[j][3] = __expf(sacc[j][3] - m1n); sum1 += sacc[j][3];
        }
        sum0 += __shfl_xor_sync(0xffffffffu, sum0, 1);
        sum0 += __shfl_xor_sync(0xffffffffu, sum0, 2);
        sum1 += __shfl_xor_sync(0xffffffffu, sum1, 1);
        sum1 += __shfl_xor_sync(0xffffffffu, sum1, 2);
        rl0 = rl0 * f0 + sum0;
        rl1 = rl1 * f1 + sum1;
        float f02 = f0 * f0, f12 = f1 * f1;
        #pragma unroll
        for (int j = 0; j < 8; ++j) {
            accC[j][0] *= f0;  accC[j][1] *= f0;
            accC[j][2] *= f1;  accC[j][3] *= f1;
            accV[j][0] *= f02; accV[j][1] *= f02;
            accV[j][2] *= f12; accV[j][3] *= f12;
        }

        // ---- PV and P^2 Vv, split precision ----
        #pragma unroll
        for (int tt = 0; tt < 4; ++tt) {
            float p8[8], q8[8];
            #pragma unroll
            for (int e = 0; e < 4; ++e) {
                p8[e] = sacc[2 * tt][e]; p8[4 + e] = sacc[2 * tt + 1][e];
            }
            #pragma unroll
            for (int e = 0; e < 8; ++e) q8[e] = p8[e] * p8[e];
            uint32_t phi[4], plo[4], p2h[4], p2l[4];
            frag_split(p8, phi, plo);
            frag_split(q8, p2h, p2l);

            const uint32_t rowOff = (uint32_t)((tt * 16 + l15) * 256 + lHi);
            uint32_t vb[16];
            // V hi
            #pragma unroll
            for (int w = 0; w < 4; ++w) ldsm4t(vb + 4 * w, vB + SWZ256(rowOff + w * 32));
            #pragma unroll
            for (int j = 0; j < 8; ++j) {
                uint32_t* B = &vb[(j >> 1) * 4 + (j & 1) * 2];
                mma16816(accC[j], phi, B);
                mma16816(accC[j], plo, B);
            }
            // V lo
            #pragma unroll
            for (int w = 0; w < 4; ++w) ldsm4t(vb + 4 * w, vB + SWZ256(rowOff + 128 + w * 32));
            #pragma unroll
            for (int j = 0; j < 8; ++j)
                mma16816(accC[j], phi, &vb[(j >> 1) * 4 + (j & 1) * 2]);
            // Vv hi
            #pragma unroll
            for (int w = 0; w < 4; ++w) ldsm4t(vb + 4 * w, vvB + SWZ256(rowOff + w * 32));
            #pragma unroll
            for (int j = 0; j < 8; ++j) {
                uint32_t* B = &vb[(j >> 1) * 4 + (j & 1) * 2];
                mma16816(accV[j], p2h, B);
                mma16816(accV[j], p2l, B);
            }
            // Vv lo
            #pragma unroll
            for (int w = 0; w < 4; ++w) ldsm4t(vb + 4 * w, vvB + SWZ256(rowOff + 128 + w * 32));
            #pragma unroll
            for (int j = 0; j < 8; ++j)
                mma16816(accV[j], p2h, &vb[(j >> 1) * 4 + (j & 1) * 2]);
        }
    }

    // ---- normalize + write ctx/var in [bn, 1024] layout ----
    const float i0 = 1.f / rl0, i1 = 1.f / rl1;
    const float i02 = i0 * i0, i12 = i1 * i1;
    const int row0 = qb + wid * 16 + rr;
    const size_t base0 = ((size_t)b * NSEQ + row0) * DM + hh * 64;
    const size_t base1 = base0 + (size_t)8 * DM;
    #pragma unroll
    for (int j = 0; j < 8; ++j) {
        int off = j * 8 + cpair;
        *(float2*)(ctx + base0 + off) = make_float2(accC[j][0] * i0,  accC[j][1] * i0);
        *(float2*)(ctx + base1 + off) = make_float2(accC[j][2] * i1,  accC[j][3] * i1);
        *(float2*)(var + base0 + off) = make_float2(accV[j][0] * i02, accV[j][1] * i02);
        *(float2*)(var + base1 + off) = make_float2(accV[j][2] * i12, accV[j][3] * i12);
    }
}

// ---------------------------------------------------------------------------
// Launcher
// ---------------------------------------------------------------------------
extern "C" void kernel_launch(void* const* d_in, const int* in_sizes, int n_in,
                              void* d_out, int out_size) {
    const float* H      = (const float*)d_in[0];
    const float* xr     = (const float*)d_in[1];
    const float* Wq     = (const float*)d_in[2];
    const float* bq     = (const float*)d_in[4];
    const float* Wk     = (const float*)d_in[6];
    const float* bk     = (const float*)d_in[8];
    const float* Wv     = (const float*)d_in[10];
    const float* Wv_rho = (const float*)d_in[11];
    const float* bv     = (const float*)d_in[12];
    const float* bv_rho = (const float*)d_in[13];
    const float* Wo     = (const float*)d_in[14];
    const float* Wo_rho = (const float*)d_in[15];
    const float* bo     = (const float*)d_in[16];
    const float* bo_rho = (const float*)d_in[17];
    const float* lsf    = (const float*)d_in[18];
    const float* lll    = (const float*)d_in[19];

    float *Qp, *Kp, *Vp, *Vvp, *ctx, *var, *d2, *bvs2, *bos2;
    __nv_bfloat16 *a3h, *a3h2, *a3c, *a3c2, *b3q, *b3k, *b3v, *b3vs, *b3o, *b3os;
    __nv_bfloat16 *q3p, *k3p, *v2p, *vv2p;
    cudaGetSymbolAddress((void**)&Qp,   g_Q);
    cudaGetSymbolAddress((void**)&Kp,   g_K);
    cudaGetSymbolAddress((void**)&Vp,   g_V);
    cudaGetSymbolAddress((void**)&Vvp,  g_Vv);
    cudaGetSymbolAddress((void**)&ctx,  g_ctx);
    cudaGetSymbolAddress((void**)&var,  g_var);
    cudaGetSymbolAddress((void**)&d2,   g_d2);
    cudaGetSymbolAddress((void**)&bvs2, g_bvs2);
    cudaGetSymbolAddress((void**)&bos2, g_bos2);
    cudaGetSymbolAddress((void**)&a3h,  g_A3H);
    cudaGetSymbolAddress((void**)&a3h2, g_A3H2);
    cudaGetSymbolAddress((void**)&a3c,  g_A3ctx);
    cudaGetSymbolAddress((void**)&a3c2, g_A3ctx2);
    cudaGetSymbolAddress((void**)&b3q,  g_B3q);
    cudaGetSymbolAddress((void**)&b3k,  g_B3k);
    cudaGetSymbolAddress((void**)&b3v,  g_B3v);
    cudaGetSymbolAddress((void**)&b3vs, g_B3vs2);
    cudaGetSymbolAddress((void**)&b3o,  g_B3o);
    cudaGetSymbolAddress((void**)&b3os, g_B3os2);
    cudaGetSymbolAddress((void**)&q3p,  g_q3);
    cudaGetSymbolAddress((void**)&k3p,  g_k3);
    cudaGetSymbolAddress((void**)&v2p,  g_v2);
    cudaGetSymbolAddress((void**)&vv2p, g_vv2);

    cudaFuncSetAttribute(gemm_tc<false>, cudaFuncAttributeMaxDynamicSharedMemorySize, SMEM_GEMM);
    cudaFuncSetAttribute(gemm_tc<true>,  cudaFuncAttributeMaxDynamicSharedMemorySize, SMEM_GEMM);
    cudaFuncSetAttribute(attn_tc, cudaFuncAttributeMaxDynamicSharedMemorySize, ATTN_SMEM);

    const dim3 ggrid(DM / BNT, BN / BM);
    const int splitA_grid = BN;
    const int splitB_grid = DM;

    // [0,1] bias softplus^2
    sig2_kernel<<<4, 256>>>(bv_rho, bvs2, DM);
    sig2_kernel<<<4, 256>>>(bo_rho, bos2, DM);
    // [2,3] A-operand splits of H and H^2
    split3_kernel<1, 0><<<splitA_grid, 256>>>(H, a3h,  BN);
    split3_kernel<1, 1><<<splitA_grid, 256>>>(H, a3h2, BN);
    // [4..11] projection GEMMs
    split3_kernel<0, 0><<<splitB_grid, 256>>>(Wq, b3q, DM);
    gemm_tc<false><<<ggrid, 256, SMEM_GEMM>>>(a3h, b3q, bq, nullptr, Qp);
    split3_kernel<0, 0><<<splitB_grid, 256>>>(Wk, b3k, DM);
    gemm_tc<false><<<ggrid, 256, SMEM_GEMM>>>(a3h, b3k, bk, nullptr, Kp);
    split3_kernel<0, 0><<<splitB_grid, 256>>>(Wv, b3v, DM);
    gemm_tc<false><<<ggrid, 256, SMEM_GEMM>>>(a3h, b3v, bv, nullptr, Vp);
    split3_kernel<0, 2><<<splitB_grid, 256>>>(Wv_rho, b3vs, DM);
    gemm_tc<false><<<ggrid, 256, SMEM_GEMM>>>(a3h2, b3vs, bvs2, nullptr, Vvp);
    // [12..15] head-major splits for TC attention
    head_split<192, 1><<<BN, 256>>>(Qp,  q3p);
    head_split<192, 0><<<BN, 256>>>(Kp,  k3p);
    head_split<128, 1><<<BN, 256>>>(Vp,  v2p);
    head_split<128, 1><<<BN, 256>>>(Vvp, vv2p);
    // [16] pairwise squared distances
    dist2_kernel<<<dim3(16, 16, BATCH), 256>>>(xr, d2);
    // [17] tensor-core attention
    attn_tc<<<dim3(NSEQ / QB, BATCH * NH), 256, ATTN_SMEM>>>(
        q3p, k3p, v2p, vv2p, d2, lsf, lll, ctx, var);
    // [18,19] ctx splits
    split3_kernel<1, 0><<<splitA_grid, 256>>>(ctx, a3c,  BN);
    split3_kernel<1, 1><<<splitA_grid, 256>>>(ctx, a3c2, BN);
    // [20..23] output GEMMs -> d_out
    float* out_mean = (float*)d_out;
    float* out_var  = out_mean + (size_t)BN * DM;
    split3_kernel<0, 0><<<splitB_grid, 256>>>(Wo, b3o, DM);
    gemm_tc<false><<<ggrid, 256, SMEM_GEMM>>>(a3c, b3o, bo, nullptr, out_mean);
    split3_kernel<0, 2><<<splitB_grid, 256>>>(Wo_rho, b3os, DM);
    gemm_tc<true><<<ggrid, 256, SMEM_GEMM>>>(a3c2, b3os, bos2, var, out_var);
}

// round 7
// speedup vs baseline: 2.6983x; 1.1982x over previous
#include <cuda_runtime.h>
#include <cuda_bf16.h>
#include <cuda_fp16.h>
#include <math.h>
#include <stdint.h>

#define DM    1024
#define BATCH 8
#define NSEQ  1024
#define BN    (BATCH * NSEQ)      // 8192 rows
#define NH    16
#define DK    64
#define QSCALE 0.125f             // 1/sqrt(64)

#define K3      3072              // bf16x3 packed K
#define BK      64
#define KITERS  (K3 / BK)         // 48
#define KH      1024              // fp16 single-pass K (variance paths)
#define KITERS_H (KH / BK)        // 16
#define BM      128
#define BNT     128
#define STAGES  3
#define STAGE_BYTES ((BM + BNT) * 128)          // 32 KB
#define SMEM_GEMM (STAGES * STAGE_BYTES)        // 96 KB

// attention tiling
#define QB 128
#define KT 64
#define SM_Q   0
#define SM_K   49152
#define SM_V   98304
#define SM_VV  131072
#define ATTN_SMEM 163840

// ---------------------------------------------------------------------------
// Scratch (device globals — no runtime allocation allowed)
// ---------------------------------------------------------------------------
__device__ float g_Q  [BN * DM];
__device__ float g_K  [BN * DM];
__device__ float g_V  [BN * DM];
__device__ float g_Vv [BN * DM];
__device__ float g_ctx[BN * DM];
__device__ float g_var[BN * DM];
__device__ float g_d2 [BATCH * NSEQ * NSEQ];
__device__ float g_bvs2[DM];
__device__ float g_bos2[DM];

__device__ __nv_bfloat16 g_A3H   [BN * K3];
__device__ __nv_bfloat16 g_A3ctx [BN * K3];
__device__ __nv_bfloat16 g_B3q   [DM * K3];
__device__ __nv_bfloat16 g_B3k   [DM * K3];
__device__ __nv_bfloat16 g_B3v   [DM * K3];
__device__ __nv_bfloat16 g_B3o   [DM * K3];

// fp16 single-pass operands for the (positive-sum) variance GEMMs
__device__ __half g_hA_H2  [BN * DM];
__device__ __half g_hA_ctx2[BN * DM];
__device__ __half g_hB_vs2 [DM * DM];
__device__ __half g_hB_os2 [DM * DM];

// head-major split tensors for TC attention
__device__ __nv_bfloat16 g_q3 [BATCH * NH * NSEQ * 192];
__device__ __nv_bfloat16 g_k3 [BATCH * NH * NSEQ * 192];
__device__ __nv_bfloat16 g_v2 [BATCH * NH * NSEQ * 128];
__device__ __nv_bfloat16 g_vv2[BATCH * NH * NSEQ * 128];

// ---------------------------------------------------------------------------
// PTX helpers (non-'a' features only: cp.async, ldmatrix, mma.sync)
// ---------------------------------------------------------------------------
__device__ __forceinline__ uint32_t smem_u32(const void* p) {
    uint32_t a;
    asm("{ .reg .u64 t; cvta.to.shared.u64 t, %1; cvt.u32.u64 %0, t; }"
        : "=r"(a) : "l"(p));
    return a;
}
#define SWZ(off)    ((off) ^ (((off) >> 3) & 0x70))   // 128B-pitch rows
#define SWZ256(off) ((off) ^ (((off) >> 4) & 0x70))   // 256B-pitch rows

__device__ __forceinline__ void cp16(uint32_t dst, const void* src) {
    asm volatile("cp.async.cg.shared.global [%0], [%1], 16;"
                 :: "r"(dst), "l"(src) : "memory");
}
#define CP_COMMIT() asm volatile("cp.async.commit_group;" ::: "memory")

__device__ __forceinline__ void ldsm4(uint32_t* r, uint32_t addr) {
    asm volatile("ldmatrix.sync.aligned.m8n8.x4.shared.b16 {%0,%1,%2,%3}, [%4];"
                 : "=r"(r[0]), "=r"(r[1]), "=r"(r[2]), "=r"(r[3]) : "r"(addr));
}
__device__ __forceinline__ void ldsm4t(uint32_t* r, uint32_t addr) {
    asm volatile("ldmatrix.sync.aligned.m8n8.x4.trans.shared.b16 {%0,%1,%2,%3}, [%4];"
                 : "=r"(r[0]), "=r"(r[1]), "=r"(r[2]), "=r"(r[3]) : "r"(addr));
}
__device__ __forceinline__ void mma16816(float* c, const uint32_t* a, const uint32_t* b) {
    asm volatile("mma.sync.aligned.m16n8k16.row.col.f32.bf16.bf16.f32 "
                 "{%0,%1,%2,%3}, {%4,%5,%6,%7}, {%8,%9}, {%0,%1,%2,%3};"
                 : "+f"(c[0]), "+f"(c[1]), "+f"(c[2]), "+f"(c[3])
                 : "r"(a[0]), "r"(a[1]), "r"(a[2]), "r"(a[3]), "r"(b[0]), "r"(b[1]));
}
__device__ __forceinline__ void mma16816h(float* c, const uint32_t* a, const uint32_t* b) {
    asm volatile("mma.sync.aligned.m16n8k16.row.col.f32.f16.f16.f32 "
                 "{%0,%1,%2,%3}, {%4,%5,%6,%7}, {%8,%9}, {%0,%1,%2,%3};"
                 : "+f"(c[0]), "+f"(c[1]), "+f"(c[2]), "+f"(c[3])
                 : "r"(a[0]), "r"(a[1]), "r"(a[2]), "r"(a[3]), "r"(b[0]), "r"(b[1]));
}
__device__ __forceinline__ uint32_t pack2(float lo, float hi) {
    uint32_t d;
    asm("cvt.rn.bf16x2.f32 %0, %1, %2;" : "=r"(d) : "f"(hi), "f"(lo));
    return d;
}
__device__ __forceinline__ void frag_split(const float* p8, uint32_t* hi, uint32_t* lo) {
    float hf[8], lf[8];
    #pragma unroll
    for (int e = 0; e < 8; ++e) {
        float hv = __bfloat162float(__float2bfloat16_rn(p8[e]));
        hf[e] = hv; lf[e] = p8[e] - hv;
    }
    hi[0] = pack2(hf[0], hf[1]); hi[1] = pack2(hf[2], hf[3]);
    hi[2] = pack2(hf[4], hf[5]); hi[3] = pack2(hf[6], hf[7]);
    lo[0] = pack2(lf[0], lf[1]); lo[1] = pack2(lf[2], lf[3]);
    lo[2] = pack2(lf[4], lf[5]); lo[3] = pack2(lf[6], lf[7]);
}

// ---------------------------------------------------------------------------
// softplus(x)^2 elementwise (biases)
// ---------------------------------------------------------------------------
__global__ void sig2_kernel(const float* __restrict__ in, float* __restrict__ out, int n) {
    int i = blockIdx.x * blockDim.x + threadIdx.x;
    if (i < n) {
        float x  = in[i];
        float sp = (x > 15.f) ? x : log1pf(__expf(x));
        out[i] = sp * sp;
    }
}

// ---------------------------------------------------------------------------
// fp32 -> bf16 hi/lo 3-way split packer (mean-path GEMM operands)
// AFORM=1: [hi|lo|hi]  (A);  AFORM=0: [hi|hi|lo]  (B)
// ---------------------------------------------------------------------------
template<int AFORM>
__global__ void split3_kernel(const float* __restrict__ X, __nv_bfloat16* __restrict__ Y,
                              int rows) {
    int idx = blockIdx.x * blockDim.x + threadIdx.x;
    int r  = idx >> 8;
    int c4 = idx & 255;
    if (r >= rows) return;
    float4 x = *(const float4*)(X + (size_t)r * DM + c4 * 4);
    float v[4] = {x.x, x.y, x.z, x.w};
    unsigned short hu[4], lu[4];
    #pragma unroll
    for (int i = 0; i < 4; ++i) {
        __nv_bfloat16 hb = __float2bfloat16_rn(v[i]);
        float hr = __bfloat162float(hb);
        __nv_bfloat16 lb = __float2bfloat16_rn(v[i] - hr);
        hu[i] = __bfloat16_as_ushort(hb);
        lu[i] = __bfloat16_as_ushort(lb);
    }
    uint2 hp, lp;
    hp.x = (uint32_t)hu[0] | ((uint32_t)hu[1] << 16);
    hp.y = (uint32_t)hu[2] | ((uint32_t)hu[3] << 16);
    lp.x = (uint32_t)lu[0] | ((uint32_t)lu[1] << 16);
    lp.y = (uint32_t)lu[2] | ((uint32_t)lu[3] << 16);
    size_t ob = (size_t)r * K3 + c4 * 4;
    *(uint2*)(Y + ob) = hp;
    if (AFORM) {
        *(uint2*)(Y + ob + DM)     = lp;
        *(uint2*)(Y + ob + 2 * DM) = hp;
    } else {
        *(uint2*)(Y + ob + DM)     = hp;
        *(uint2*)(Y + ob + 2 * DM) = lp;
    }
}

// ---------------------------------------------------------------------------
// fp32 -> fp16 single convert (variance operands): PRE 1=square, 2=softplus^2
// grid = rows, 256 threads (one float4 each), out [rows, 1024] half
// ---------------------------------------------------------------------------
template<int PRE>
__global__ void f16conv_kernel(const float* __restrict__ X, __half* __restrict__ Y) {
    int row = blockIdx.x;
    int c4  = threadIdx.x;
    float4 x = *(const float4*)(X + (size_t)row * DM + c4 * 4);
    float v[4] = {x.x, x.y, x.z, x.w};
    #pragma unroll
    for (int i = 0; i < 4; ++i) {
        if (PRE == 1) v[i] = v[i] * v[i];
        if (PRE == 2) {
            float sp = (v[i] > 15.f) ? v[i] : log1pf(__expf(v[i]));
            v[i] = sp * sp;
        }
    }
    __half2 h0 = __floats2half2_rn(v[0], v[1]);
    __half2 h1 = __floats2half2_rn(v[2], v[3]);
    uint2 p;
    p.x = *(uint32_t*)&h0;
    p.y = *(uint32_t*)&h1;
    *(uint2*)(Y + (size_t)row * DM + c4 * 4) = p;
}

// ---------------------------------------------------------------------------
// head-major split for attention (unchanged)
// ---------------------------------------------------------------------------
template<int NW, int AFORM>
__global__ void head_split(const float* __restrict__ X, __nv_bfloat16* __restrict__ Y) {
    int row = blockIdx.x;
    int c4  = threadIdx.x;
    float4 x = *(const float4*)(X + (size_t)row * DM + c4 * 4);
    int hh = c4 >> 4, dl = (c4 & 15) * 4;
    int b = row >> 10, n = row & 1023;
    size_t base = ((size_t)(b * NH + hh) * NSEQ + n) * NW + dl;
    float v[4] = {x.x, x.y, x.z, x.w};
    unsigned short hu[4], lu[4];
    #pragma unroll
    for (int i = 0; i < 4; ++i) {
        __nv_bfloat16 hb = __float2bfloat16_rn(v[i]);
        float hr = __bfloat162float(hb);
        __nv_bfloat16 lb = __float2bfloat16_rn(v[i] - hr);
        hu[i] = __bfloat16_as_ushort(hb);
        lu[i] = __bfloat16_as_ushort(lb);
    }
    uint2 hp, lp;
    hp.x = (uint32_t)hu[0] | ((uint32_t)hu[1] << 16);
    hp.y = (uint32_t)hu[2] | ((uint32_t)hu[3] << 16);
    lp.x = (uint32_t)lu[0] | ((uint32_t)lu[1] << 16);
    lp.y = (uint32_t)lu[2] | ((uint32_t)lu[3] << 16);
    *(uint2*)(Y + base) = hp;
    if (NW == 192) {
        if (AFORM) { *(uint2*)(Y + base + 64) = lp; *(uint2*)(Y + base + 128) = hp; }
        else       { *(uint2*)(Y + base + 64) = hp; *(uint2*)(Y + base + 128) = lp; }
    } else {
        *(uint2*)(Y + base + 64) = lp;
    }
}

// ---------------------------------------------------------------------------
// bf16x3 HMMA GEMM core (macro-shaped as inline device function)
// ---------------------------------------------------------------------------
__device__ __forceinline__ void gemm_core_bf16(
    const __nv_bfloat16* __restrict__ A3, const __nv_bfloat16* __restrict__ B3,
    const float* __restrict__ bias, float* __restrict__ C,
    char* smem, int mBase, int nBase) {
    const uint32_t sb = smem_u32(smem);
    const int t    = threadIdx.x;
    const int wid  = t >> 5;
    const int lane = t & 31;
    const int wm   = wid & 1;
    const int wn   = wid >> 1;

    const int r  = t >> 1;
    const int uc = (t & 1) * 4;
    const __nv_bfloat16* aRow = A3 + (size_t)(mBase + r) * K3 + uc * 8;
    const __nv_bfloat16* bRow = B3 + (size_t)(nBase + r) * K3 + uc * 8;

    auto load_stage = [&](int buf, int c) {
        uint32_t sA = sb + buf * STAGE_BYTES;
        uint32_t sB = sA + BM * 128;
        const __nv_bfloat16* ga = aRow + c * BK;
        const __nv_bfloat16* gb = bRow + c * BK;
        #pragma unroll
        for (int i = 0; i < 4; ++i) {
            uint32_t bo = r * 128 + (uc + i) * 16;
            cp16(sA + SWZ(bo), ga + i * 8);
            cp16(sB + SWZ(bo), gb + i * 8);
        }
        CP_COMMIT();
    };

    const int aRowSel = (lane & 7) | (((lane >> 3) & 1) << 3);
    const int aKSel   = (lane >> 4) << 4;
    const int bNSel   = (lane & 7) | ((lane >> 4) << 3);
    const int bKSel   = ((lane >> 3) & 1) << 4;

    float acc[4][4][4] = {};

    load_stage(0, 0);
    load_stage(1, 1);

    for (int kt = 0; kt < KITERS; ++kt) {
        const int buf = kt % STAGES;
        if (kt == KITERS - 1) asm volatile("cp.async.wait_group 0;" ::: "memory");
        else                  asm volatile("cp.async.wait_group 1;" ::: "memory");
        __syncthreads();

        if (kt + 2 < KITERS) load_stage((kt + 2) % STAGES, kt + 2);

        uint32_t sA = sb + buf * STAGE_BYTES;
        uint32_t sB = sA + BM * 128;
        #pragma unroll
        for (int ks = 0; ks < 4; ++ks) {
            uint32_t af[4][4], bfr[2][4];
            #pragma unroll
            for (int mi = 0; mi < 4; ++mi) {
                uint32_t bo = (uint32_t)((wm * 64 + mi * 16 + aRowSel) * 128
                                         + ks * 32 + aKSel);
                ldsm4(af[mi], sA + SWZ(bo));
            }
            #pragma unroll
            for (int pi = 0; pi < 2; ++pi) {
                uint32_t bo = (uint32_t)((wn * 32 + pi * 16 + bNSel) * 128
                                         + ks * 32 + bKSel);
                ldsm4(bfr[pi], sB + SWZ(bo));
            }
            #pragma unroll
            for (int mi = 0; mi < 4; ++mi)
                #pragma unroll
                for (int ni = 0; ni < 4; ++ni)
                    mma16816(acc[mi][ni], af[mi], &bfr[ni >> 1][(ni & 1) * 2]);
        }
        __syncthreads();
    }

    const int lr = lane >> 2;
    const int lc = (lane & 3) * 2;
    const int rB = mBase + wm * 64;
    const int cB = nBase + wn * 32;
    #pragma unroll
    for (int mi = 0; mi < 4; ++mi) {
        #pragma unroll
        for (int ni = 0; ni < 4; ++ni) {
            int col  = cB + ni * 8 + lc;
            int row0 = rB + mi * 16 + lr;
            float2 bi = *(const float2*)(bias + col);
            float2 v0 = make_float2(acc[mi][ni][0] + bi.x, acc[mi][ni][1] + bi.y);
            float2 v1 = make_float2(acc[mi][ni][2] + bi.x, acc[mi][ni][3] + bi.y);
            size_t o0 = (size_t)row0 * DM + col;
            size_t o1 = (size_t)(row0 + 8) * DM + col;
            *(float2*)(C + o0) = v0;
            *(float2*)(C + o1) = v1;
        }
    }
}

// fused Q/K/V projection (z selects operand set; shared A3)
__global__ void __launch_bounds__(256, 2)
gemm_qkv(const __nv_bfloat16* __restrict__ A3,
         const __nv_bfloat16* __restrict__ B0, const __nv_bfloat16* __restrict__ B1,
         const __nv_bfloat16* __restrict__ B2,
         const float* __restrict__ bi0, const float* __restrict__ bi1,
         const float* __restrict__ bi2,
         float* __restrict__ C0, float* __restrict__ C1, float* __restrict__ C2) {
    extern __shared__ __align__(1024) char smem[];
    int z = blockIdx.z;
    const __nv_bfloat16* B3 = (z == 0) ? B0 : (z == 1) ? B1 : B2;
    const float* bias       = (z == 0) ? bi0 : (z == 1) ? bi1 : bi2;
    float* C                = (z == 0) ? C0 : (z == 1) ? C1 : C2;
    gemm_core_bf16(A3, B3, bias, C, smem, blockIdx.y * BM, blockIdx.x * BNT);
}

// single bf16x3 GEMM (out_mean)
__global__ void __launch_bounds__(256, 2)
gemm_tc(const __nv_bfloat16* __restrict__ A3, const __nv_bfloat16* __restrict__ B3,
        const float* __restrict__ bias, float* __restrict__ C) {
    extern __shared__ __align__(1024) char smem[];
    gemm_core_bf16(A3, B3, bias, C, smem, blockIdx.y * BM, blockIdx.x * BNT);
}

// ---------------------------------------------------------------------------
// fp16 single-pass GEMM (variance paths): C = A_h . B_h^T + bias (+ add)
// K = 1024, same tile/pipeline structure.
// ---------------------------------------------------------------------------
template<bool HASADD>
__global__ void __launch_bounds__(256, 2)
gemm_h(const __half* __restrict__ A, const __half* __restrict__ B,
       const float* __restrict__ bias, const float* __restrict__ add,
       float* __restrict__ C) {
    extern __shared__ __align__(1024) char smem[];
    const uint32_t sb = smem_u32(smem);
    const int t    = threadIdx.x;
    const int wid  = t >> 5;
    const int lane = t & 31;
    const int wm   = wid & 1;
    const int wn   = wid >> 1;
    const int mBase = blockIdx.y * BM;
    const int nBase = blockIdx.x * BNT;

    const int r  = t >> 1;
    const int uc = (t & 1) * 4;
    const __half* aRow = A + (size_t)(mBase + r) * KH + uc * 8;
    const __half* bRow = B + (size_t)(nBase + r) * KH + uc * 8;

    auto load_stage = [&](int buf, int c) {
        uint32_t sA = sb + buf * STAGE_BYTES;
        uint32_t sB = sA + BM * 128;
        const __half* ga = aRow + c * BK;
        const __half* gb = bRow + c * BK;
        #pragma unroll
        for (int i = 0; i < 4; ++i) {
            uint32_t bo = r * 128 + (uc + i) * 16;
            cp16(sA + SWZ(bo), ga + i * 8);
            cp16(sB + SWZ(bo), gb + i * 8);
        }
        CP_COMMIT();
    };

    const int aRowSel = (lane & 7) | (((lane >> 3) & 1) << 3);
    const int aKSel   = (lane >> 4) << 4;
    const int bNSel   = (lane & 7) | ((lane >> 4) << 3);
    const int bKSel   = ((lane >> 3) & 1) << 4;

    float acc[4][4][4] = {};

    load_stage(0, 0);
    load_stage(1, 1);

    for (int kt = 0; kt < KITERS_H; ++kt) {
        const int buf = kt % STAGES;
        if (kt == KITERS_H - 1) asm volatile("cp.async.wait_group 0;" ::: "memory");
        else                    asm volatile("cp.async.wait_group 1;" ::: "memory");
        __syncthreads();

        if (kt + 2 < KITERS_H) load_stage((kt + 2) % STAGES, kt + 2);

        uint32_t sA = sb + buf * STAGE_BYTES;
        uint32_t sB = sA + BM * 128;
        #pragma unroll
        for (int ks = 0; ks < 4; ++ks) {
            uint32_t af[4][4], bfr[2][4];
            #pragma unroll
            for (int mi = 0; mi < 4; ++mi) {
                uint32_t bo = (uint32_t)((wm * 64 + mi * 16 + aRowSel) * 128
                                         + ks * 32 + aKSel);
                ldsm4(af[mi], sA + SWZ(bo));
            }
            #pragma unroll
            for (int pi = 0; pi < 2; ++pi) {
                uint32_t bo = (uint32_t)((wn * 32 + pi * 16 + bNSel) * 128
                                         + ks * 32 + bKSel);
                ldsm4(bfr[pi], sB + SWZ(bo));
            }
            #pragma unroll
            for (int mi = 0; mi < 4; ++mi)
                #pragma unroll
                for (int ni = 0; ni < 4; ++ni)
                    mma16816h(acc[mi][ni], af[mi], &bfr[ni >> 1][(ni & 1) * 2]);
        }
        __syncthreads();
    }

    const int lr = lane >> 2;
    const int lc = (lane & 3) * 2;
    const int rB = mBase + wm * 64;
    const int cB = nBase + wn * 32;
    #pragma unroll
    for (int mi = 0; mi < 4; ++mi) {
        #pragma unroll
        for (int ni = 0; ni < 4; ++ni) {
            int col  = cB + ni * 8 + lc;
            int row0 = rB + mi * 16 + lr;
            float2 bi = *(const float2*)(bias + col);
            float2 v0 = make_float2(acc[mi][ni][0] + bi.x, acc[mi][ni][1] + bi.y);
            float2 v1 = make_float2(acc[mi][ni][2] + bi.x, acc[mi][ni][3] + bi.y);
            size_t o0 = (size_t)row0 * DM + col;
            size_t o1 = (size_t)(row0 + 8) * DM + col;
            if (HASADD) {
                float2 a0 = *(const float2*)(add + o0);
                float2 a1 = *(const float2*)(add + o1);
                v0.x += a0.x; v0.y += a0.y; v1.x += a1.x; v1.y += a1.y;
            }
            *(float2*)(C + o0) = v0;
            *(float2*)(C + o1) = v1;
        }
    }
}

// ---------------------------------------------------------------------------
// dist2 (unchanged)
// ---------------------------------------------------------------------------
__global__ void dist2_kernel(const float* __restrict__ xr, float* __restrict__ d2) {
    __shared__ float xm[64][17];
    __shared__ float xn[64][17];
    __shared__ float x2m[64];
    __shared__ float x2n[64];

    const int t  = threadIdx.x;
    const int b  = blockIdx.z;
    const int mi = blockIdx.y * 64;
    const int nj = blockIdx.x * 64;

    for (int idx = t; idx < 64 * 4; idx += 256) {
        int r = idx >> 2, c = (idx & 3) * 4;
        float4 a = *(const float4*)(xr + ((size_t)b * NSEQ + mi + r) * 16 + c);
        xm[r][c] = a.x; xm[r][c+1] = a.y; xm[r][c+2] = a.z; xm[r][c+3] = a.w;
        float4 bb = *(const float4*)(xr + ((size_t)b * NSEQ + nj + r) * 16 + c);
        xn[r][c] = bb.x; xn[r][c+1] = bb.y; xn[r][c+2] = bb.z; xn[r][c+3] = bb.w;
    }
    __syncthreads();

    if (t < 64) {
        float s = 0.f;
        #pragma unroll
        for (int c = 0; c < 16; ++c) s += xm[t][c] * xm[t][c];
        x2m[t] = s;
    } else if (t < 128) {
        int r = t - 64;
        float s = 0.f;
        #pragma unroll
        for (int c = 0; c < 16; ++c) s += xn[r][c] * xn[r][c];
        x2n[r] = s;
    }
    __syncthreads();

    const int tx = t & 15, ty = t >> 4;
    #pragma unroll
    for (int i = 0; i < 4; ++i) {
        int row = ty * 4 + i;
        float out4[4];
        #pragma unroll
        for (int j = 0; j < 4; ++j) {
            int col = tx * 4 + j;
            float dot = 0.f;
            #pragma unroll
            for (int c = 0; c < 16; ++c) dot += xm[row][c] * xn[col][c];
            out4[j] = fmaxf(x2m[row] + x2n[col] - 2.f * dot, 0.f);
        }
        float4 v4 = make_float4(out4[0], out4[1], out4[2], out4[3]);
        *(float4*)(d2 + ((size_t)b * NSEQ + mi + row) * NSEQ + nj + tx * 4) = v4;
    }
}

// ---------------------------------------------------------------------------
// Tensor-core flash attention (unchanged from round 6)
// ---------------------------------------------------------------------------
__global__ void __launch_bounds__(256, 1)
attn_tc(const __nv_bfloat16* __restrict__ q3, const __nv_bfloat16* __restrict__ k3,
        const __nv_bfloat16* __restrict__ v2, const __nv_bfloat16* __restrict__ vv2,
        const float* __restrict__ d2g,
        const float* __restrict__ lsf, const float* __restrict__ lll,
        float* __restrict__ ctx, float* __restrict__ var) {
    extern __shared__ __align__(1024) char smem[];
    const uint32_t sb = smem_u32(smem);
    const int t    = threadIdx.x;
    const int wid  = t >> 5;
    const int lane = t & 31;
    const int qb   = blockIdx.x * QB;
    const int bh   = blockIdx.y;
    const int b    = bh >> 4, hh = bh & 15;

    const float sigma_f2 = __expf(2.f * lsf[hh]);
    const float coef     = 0.5f * __expf(-2.f * lll[hh]);

    const __nv_bfloat16* Qg  = q3  + ((size_t)bh * NSEQ + qb) * 192;
    const __nv_bfloat16* Kg  = k3  + (size_t)bh * NSEQ * 192;
    const __nv_bfloat16* Vg  = v2  + (size_t)bh * NSEQ * 128;
    const __nv_bfloat16* VVg = vv2 + (size_t)bh * NSEQ * 128;

    for (int i = t; i < QB * 24; i += 256) {
        int row = i / 24, u = i % 24;
        cp16(sb + SM_Q + (u >> 3) * 16384 + SWZ((uint32_t)(row * 128 + (u & 7) * 16)),
             Qg + (size_t)row * 192 + u * 8);
    }

    auto load_kv = [&](int buf, int kt) {
        const __nv_bfloat16* kg = Kg + (size_t)kt * KT * 192;
        for (int i = t; i < KT * 24; i += 256) {
            int row = i / 24, u = i % 24;
            cp16(sb + SM_K + buf * 24576 + (u >> 3) * 8192
                    + SWZ((uint32_t)(row * 128 + (u & 7) * 16)),
                 kg + (size_t)row * 192 + u * 8);
        }
        const __nv_bfloat16* vg = Vg + (size_t)kt * KT * 128;
        const __nv_bfloat16* wg = VVg + (size_t)kt * KT * 128;
        for (int i = t; i < KT * 16; i += 256) {
            int row = i >> 4, u = i & 15;
            uint32_t so = SWZ256((uint32_t)(row * 256 + u * 16));
            cp16(sb + SM_V  + buf * 16384 + so, vg + (size_t)row * 128 + u * 8);
            cp16(sb + SM_VV + buf * 16384 + so, wg + (size_t)row * 128 + u * 8);
        }
        CP_COMMIT();
    };
    load_kv(0, 0);

    const int l15 = lane & 15;
    const int lHi = (lane >> 4) << 4;
    const uint32_t aRowOff = (uint32_t)((wid * 16 + l15) * 128 + lHi);
    const int g    = lane >> 3;
    const int keyl = ((g >> 1) << 3) + (lane & 7);
    const uint32_t kCol = (uint32_t)((g & 1) << 4);
    const int rr    = lane >> 2;
    const int cpair = (lane & 3) * 2;

    float accC[8][4] = {}, accV[8][4] = {};
    float rm0 = -1e30f, rm1 = -1e30f, rl0 = 0.f, rl1 = 0.f;

    for (int kt = 0; kt < NSEQ / KT; ++kt) {
        if (kt + 1 < NSEQ / KT) { __syncthreads(); load_kv((kt + 1) & 1, kt + 1); }
        if (kt + 1 < NSEQ / KT) asm volatile("cp.async.wait_group 1;" ::: "memory");
        else                    asm volatile("cp.async.wait_group 0;" ::: "memory");
        __syncthreads();

        const int buf = kt & 1;
        const uint32_t kB  = sb + SM_K  + buf * 24576;
        const uint32_t vB  = sb + SM_V  + buf * 16384;
        const uint32_t vvB = sb + SM_VV + buf * 16384;

        float sacc[8][4];
        #pragma unroll
        for (int j = 0; j < 8; ++j)
            #pragma unroll
            for (int e = 0; e < 4; ++e) sacc[j][e] = 0.f;

        #pragma unroll
        for (int ks = 0; ks < 12; ++ks) {
            uint32_t a[4];
            ldsm4(a, sb + SM_Q + (ks >> 2) * 16384 + SWZ(aRowOff + (ks & 3) * 32));
            #pragma unroll
            for (int n0 = 0; n0 < 4; ++n0) {
                uint32_t kb4[4];
                ldsm4(kb4, kB + (ks >> 2) * 8192
                         + SWZ((uint32_t)((n0 * 16 + keyl) * 128) + (ks & 3) * 32 + kCol));
                mma16816(sacc[2 * n0],     a, kb4);
                mma16816(sacc[2 * n0 + 1], a, kb4 + 2);
            }
        }

        const int kb0 = kt * KT;
        const float* d2r0 = d2g + (size_t)b * NSEQ * NSEQ
                          + (size_t)(qb + wid * 16 + rr) * NSEQ + kb0;
        const float* d2r1 = d2r0 + 8 * NSEQ;
        #pragma unroll
        for (int j = 0; j < 8; ++j) {
            float2 da = *(const float2*)(d2r0 + j * 8 + cpair);
            float2 db = *(const float2*)(d2r1 + j * 8 + cpair);
            sacc[j][0] = sacc[j][0] * QSCALE + sigma_f2 * __expf(-da.x * coef);
            sacc[j][1] = sacc[j][1] * QSCALE + sigma_f2 * __expf(-da.y * coef);
            sacc[j][2] = sacc[j][2] * QSCALE + sigma_f2 * __expf(-db.x * coef);
            sacc[j][3] = sacc[j][3] * QSCALE + sigma_f2 * __expf(-db.y * coef);
        }
        float mx0 = -1e30f, mx1 = -1e30f;
        #pragma unroll
        for (int j = 0; j < 8; ++j) {
            mx0 = fmaxf(mx0, fmaxf(sacc[j][0], sacc[j][1]));
            mx1 = fmaxf(mx1, fmaxf(sacc[j][2], sacc[j][3]));
        }
        mx0 = fmaxf(mx0, __shfl_xor_sync(0xffffffffu, mx0, 1));
        mx0 = fmaxf(mx0, __shfl_xor_sync(0xffffffffu, mx0, 2));
        mx1 = fmaxf(mx1, __shfl_xor_sync(0xffffffffu, mx1, 1));
        mx1 = fmaxf(mx1, __shfl_xor_sync(0xffffffffu, mx1, 2));
        float m0n = fmaxf(rm0, mx0), m1n = fmaxf(rm1, mx1);
        float f0 = __expf(rm0 - m0n), f1 = __expf(rm1 - m1n);
        rm0 = m0n; rm1 = m1n;
        float sum0 = 0.f, sum1 = 0.f;
        #pragma unroll
        for (int j = 0; j < 8; ++j) {
            sacc[j][0] = __expf(sacc[j][0] - m0n); sum0 += sacc[j][0];
            sacc[j][1] = __expf(sacc[j][1] - m0n); sum0 += sacc[j][1];
            sacc[j][2] = __expf(sacc[j][2] - m1n); sum1 += sacc[j][2];
            sacc[j][3] = __expf(sacc[j][3] - m1n); sum1 += sacc[j][3];
        }
        sum0 += __shfl_xor_sync(0xffffffffu, sum0, 1);
        sum0 += __shfl_xor_sync(0xffffffffu, sum0, 2);
        sum1 += __shfl_xor_sync(0xffffffffu, sum1, 1);
        sum1 += __shfl_xor_sync(0xffffffffu, sum1, 2);
        rl0 = rl0 * f0 + sum0;
        rl1 = rl1 * f1 + sum1;
        float f02 = f0 * f0, f12 = f1 * f1;
        #pragma unroll
        for (int j = 0; j < 8; ++j) {
            accC[j][0] *= f0;  accC[j][1] *= f0;
            accC[j][2] *= f1;  accC[j][3] *= f1;
            accV[j][0] *= f02; accV[j][1] *= f02;
            accV[j][2] *= f12; accV[j][3] *= f12;
        }

        #pragma unroll
        for (int tt = 0; tt < 4; ++tt) {
            float p8[8], q8[8];
            #pragma unroll
            for (int e = 0; e < 4; ++e) {
                p8[e] = sacc[2 * tt][e]; p8[4 + e] = sacc[2 * tt + 1][e];
            }
            #pragma unroll
            for (int e = 0; e < 8; ++e) q8[e] = p8[e] * p8[e];
            uint32_t phi[4], plo[4], p2h[4], p2l[4];
            frag_split(p8, phi, plo);
            frag_split(q8, p2h, p2l);

            const uint32_t rowOff = (uint32_t)((tt * 16 + l15) * 256 + lHi);
            uint32_t vb[16];
            #pragma unroll
            for (int w = 0; w < 4; ++w) ldsm4t(vb + 4 * w, vB + SWZ256(rowOff + w * 32));
            #pragma unroll
            for (int j = 0; j < 8; ++j) {
                uint32_t* B = &vb[(j >> 1) * 4 + (j & 1) * 2];
                mma16816(accC[j], phi, B);
                mma16816(accC[j], plo, B);
            }
            #pragma unroll
            for (int w = 0; w < 4; ++w) ldsm4t(vb + 4 * w, vB + SWZ256(rowOff + 128 + w * 32));
            #pragma unroll
            for (int j = 0; j < 8; ++j)
                mma16816(accC[j], phi, &vb[(j >> 1) * 4 + (j & 1) * 2]);
            #pragma unroll
            for (int w = 0; w < 4; ++w) ldsm4t(vb + 4 * w, vvB + SWZ256(rowOff + w * 32));
            #pragma unroll
            for (int j = 0; j < 8; ++j) {
                uint32_t* B = &vb[(j >> 1) * 4 + (j & 1) * 2];
                mma16816(accV[j], p2h, B);
                mma16816(accV[j], p2l, B);
            }
            #pragma unroll
            for (int w = 0; w < 4; ++w) ldsm4t(vb + 4 * w, vvB + SWZ256(rowOff + 128 + w * 32));
            #pragma unroll
            for (int j = 0; j < 8; ++j)
                mma16816(accV[j], p2h, &vb[(j >> 1) * 4 + (j & 1) * 2]);
        }
    }

    const float i0 = 1.f / rl0, i1 = 1.f / rl1;
    const float i02 = i0 * i0, i12 = i1 * i1;
    const int row0 = qb + wid * 16 + rr;
    const size_t base0 = ((size_t)b * NSEQ + row0) * DM + hh * 64;
    const size_t base1 = base0 + (size_t)8 * DM;
    #pragma unroll
    for (int j = 0; j < 8; ++j) {
        int off = j * 8 + cpair;
        *(float2*)(ctx + base0 + off) = make_float2(accC[j][0] * i0,  accC[j][1] * i0);
        *(float2*)(ctx + base1 + off) = make_float2(accC[j][2] * i1,  accC[j][3] * i1);
        *(float2*)(var + base0 + off) = make_float2(accV[j][0] * i02, accV[j][1] * i02);
        *(float2*)(var + base1 + off) = make_float2(accV[j][2] * i12, accV[j][3] * i12);
    }
}

// ---------------------------------------------------------------------------
// Launcher
// ---------------------------------------------------------------------------
extern "C" void kernel_launch(void* const* d_in, const int* in_sizes, int n_in,
                              void* d_out, int out_size) {
    const float* H      = (const float*)d_in[0];
    const float* xr     = (const float*)d_in[1];
    const float* Wq     = (const float*)d_in[2];
    const float* bq     = (const float*)d_in[4];
    const float* Wk     = (const float*)d_in[6];
    const float* bk     = (const float*)d_in[8];
    const float* Wv     = (const float*)d_in[10];
    const float* Wv_rho = (const float*)d_in[11];
    const float* bv     = (const float*)d_in[12];
    const float* bv_rho = (const float*)d_in[13];
    const float* Wo     = (const float*)d_in[14];
    const float* Wo_rho = (const float*)d_in[15];
    const float* bo     = (const float*)d_in[16];
    const float* bo_rho = (const float*)d_in[17];
    const float* lsf    = (const float*)d_in[18];
    const float* lll    = (const float*)d_in[19];

    float *Qp, *Kp, *Vp, *Vvp, *ctx, *var, *d2, *bvs2, *bos2;
    __nv_bfloat16 *a3h, *a3c, *b3q, *b3k, *b3v, *b3o;
    __half *hA2, *hC2, *hVs, *hOs;
    __nv_bfloat16 *q3p, *k3p, *v2p, *vv2p;
    cudaGetSymbolAddress((void**)&Qp,   g_Q);
    cudaGetSymbolAddress((void**)&Kp,   g_K);
    cudaGetSymbolAddress((void**)&Vp,   g_V);
    cudaGetSymbolAddress((void**)&Vvp,  g_Vv);
    cudaGetSymbolAddress((void**)&ctx,  g_ctx);
    cudaGetSymbolAddress((void**)&var,  g_var);
    cudaGetSymbolAddress((void**)&d2,   g_d2);
    cudaGetSymbolAddress((void**)&bvs2, g_bvs2);
    cudaGetSymbolAddress((void**)&bos2, g_bos2);
    cudaGetSymbolAddress((void**)&a3h,  g_A3H);
    cudaGetSymbolAddress((void**)&a3c,  g_A3ctx);
    cudaGetSymbolAddress((void**)&b3q,  g_B3q);
    cudaGetSymbolAddress((void**)&b3k,  g_B3k);
    cudaGetSymbolAddress((void**)&b3v,  g_B3v);
    cudaGetSymbolAddress((void**)&b3o,  g_B3o);
    cudaGetSymbolAddress((void**)&hA2,  g_hA_H2);
    cudaGetSymbolAddress((void**)&hC2,  g_hA_ctx2);
    cudaGetSymbolAddress((void**)&hVs,  g_hB_vs2);
    cudaGetSymbolAddress((void**)&hOs,  g_hB_os2);
    cudaGetSymbolAddress((void**)&q3p,  g_q3);
    cudaGetSymbolAddress((void**)&k3p,  g_k3);
    cudaGetSymbolAddress((void**)&v2p,  g_v2);
    cudaGetSymbolAddress((void**)&vv2p, g_vv2);

    cudaFuncSetAttribute(gemm_qkv,      cudaFuncAttributeMaxDynamicSharedMemorySize, SMEM_GEMM);
    cudaFuncSetAttribute(gemm_tc,       cudaFuncAttributeMaxDynamicSharedMemorySize, SMEM_GEMM);
    cudaFuncSetAttribute(gemm_h<false>, cudaFuncAttributeMaxDynamicSharedMemorySize, SMEM_GEMM);
    cudaFuncSetAttribute(gemm_h<true>,  cudaFuncAttributeMaxDynamicSharedMemorySize, SMEM_GEMM);
    cudaFuncSetAttribute(attn_tc,       cudaFuncAttributeMaxDynamicSharedMemorySize, ATTN_SMEM);

    const dim3 ggrid3(DM / BNT, BN / BM, 3);   // fused Q/K/V
    const dim3 ggrid (DM / BNT, BN / BM);
    const int splitA_grid = BN;
    const int splitB_grid = DM;

    // [0] bias softplus^2 (V)
    sig2_kernel<<<4, 256>>>(bv_rho, bvs2, DM);
    // [1] A-split of H
    split3_kernel<1><<<splitA_grid, 256>>>(H, a3h, BN);
    // [2..4] weight splits
    split3_kernel<0><<<splitB_grid, 256>>>(Wq, b3q, DM);
    split3_kernel<0><<<splitB_grid, 256>>>(Wk, b3k, DM);
    split3_kernel<0><<<splitB_grid, 256>>>(Wv, b3v, DM);
    // [5] fused Q/K/V projection GEMM
    gemm_qkv<<<ggrid3, 256, SMEM_GEMM>>>(a3h, b3q, b3k, b3v, bq, bk, bv, Qp, Kp, Vp);
    // [6,7] fp16 variance operands + [8] V-variance GEMM
    f16conv_kernel<1><<<BN, 256>>>(H, hA2);
    f16conv_kernel<2><<<DM, 256>>>(Wv_rho, hVs);
    gemm_h<false><<<ggrid, 256, SMEM_GEMM>>>(hA2, hVs, bvs2, nullptr, Vvp);
    // [9..12] head-major splits for TC attention
    head_split<192, 1><<<BN, 256>>>(Qp,  q3p);
    head_split<192, 0><<<BN, 256>>>(Kp,  k3p);
    head_split<128, 1><<<BN, 256>>>(Vp,  v2p);
    head_split<128, 1><<<BN, 256>>>(Vvp, vv2p);
    // [13] pairwise squared distances
    dist2_kernel<<<dim3(16, 16, BATCH), 256>>>(xr, d2);
    // [14] tensor-core attention
    attn_tc<<<dim3(NSEQ / QB, BATCH * NH), 256, ATTN_SMEM>>>(
        q3p, k3p, v2p, vv2p, d2, lsf, lll, ctx, var);
    // [15..17] output operand prep
    split3_kernel<1><<<splitA_grid, 256>>>(ctx, a3c, BN);
    split3_kernel<0><<<splitB_grid, 256>>>(Wo, b3o, DM);
    f16conv_kernel<1><<<BN, 256>>>(ctx, hC2);
    // [18] out_mean
    float* out_mean = (float*)d_out;
    float* out_var  = out_mean + (size_t)BN * DM;
    gemm_tc<<<ggrid, 256, SMEM_GEMM>>>(a3c, b3o, bo, out_mean);
    // [19..21] out_var (fp16 single + var_attn add)
    sig2_kernel<<<4, 256>>>(bo_rho, bos2, DM);
    f16conv_kernel<2><<<DM, 256>>>(Wo_rho, hOs);
    gemm_h<true><<<ggrid, 256, SMEM_GEMM>>>(hC2, hOs, bos2, var, out_var);
}

// round 8
// speedup vs baseline: 2.8818x; 1.0680x over previous
#include <cuda_runtime.h>
#include <cuda_bf16.h>
#include <cuda_fp16.h>
#include <math.h>
#include <stdint.h>

#define DM    1024
#define BATCH 8
#define NSEQ  1024
#define BN    (BATCH * NSEQ)
#define NH    16
#define DK    64
#define QSCALE 0.125f

#define K3      3072
#define BK      64
#define KITERS  (K3 / BK)         // 48
#define KH      1024
#define KITERS_H (KH / BK)        // 16
#define BM      128
#define BNT     128
#define STAGES  3
#define STAGE_BYTES ((BM + BNT) * 128)
#define SMEM_GEMM (STAGES * STAGE_BYTES)        // 96 KB

// attention tiling / smem
#define QB 128
#define KT 64
#define SM_Q   0                  // 3 x 128 x 128B = 49152
#define SM_K   49152              // 2 x 3 x 64 x 128B = 49152
#define SM_V   98304              // 2 x 64 x 128B = 16384
#define SM_VV  114688             // 16384
#define ATTN_SMEM 131072

// ---------------------------------------------------------------------------
// Scratch
// ---------------------------------------------------------------------------
__device__ float g_var [BN * DM];
__device__ float g_d2  [BATCH * NSEQ * NSEQ];
__device__ float g_bvs2[DM];
__device__ float g_bos2[DM];

__device__ __nv_bfloat16 g_A3H  [BN * K3];
__device__ __nv_bfloat16 g_A3ctx[BN * K3];
__device__ __nv_bfloat16 g_B3q  [DM * K3];
__device__ __nv_bfloat16 g_B3k  [DM * K3];
__device__ __nv_bfloat16 g_B3v  [DM * K3];
__device__ __nv_bfloat16 g_B3o  [DM * K3];

__device__ __half g_hA_H2  [BN * DM];
__device__ __half g_hC2    [BN * DM];
__device__ __half g_hB_vs2 [DM * DM];
__device__ __half g_hB_os2 [DM * DM];

__device__ __nv_bfloat16 g_q3 [BATCH * NH * NSEQ * 192];
__device__ __nv_bfloat16 g_k3 [BATCH * NH * NSEQ * 192];
__device__ __half        g_v2h [BATCH * NH * NSEQ * 64];
__device__ __half        g_vv2h[BATCH * NH * NSEQ * 64];

// ---------------------------------------------------------------------------
// PTX helpers
// ---------------------------------------------------------------------------
__device__ __forceinline__ uint32_t smem_u32(const void* p) {
    uint32_t a;
    asm("{ .reg .u64 t; cvta.to.shared.u64 t, %1; cvt.u32.u64 %0, t; }"
        : "=r"(a) : "l"(p));
    return a;
}
#define SWZ(off) ((off) ^ (((off) >> 3) & 0x70))

__device__ __forceinline__ void cp16(uint32_t dst, const void* src) {
    asm volatile("cp.async.cg.shared.global [%0], [%1], 16;"
                 :: "r"(dst), "l"(src) : "memory");
}
#define CP_COMMIT() asm volatile("cp.async.commit_group;" ::: "memory")

__device__ __forceinline__ void ldsm4(uint32_t* r, uint32_t addr) {
    asm volatile("ldmatrix.sync.aligned.m8n8.x4.shared.b16 {%0,%1,%2,%3}, [%4];"
                 : "=r"(r[0]), "=r"(r[1]), "=r"(r[2]), "=r"(r[3]) : "r"(addr));
}
__device__ __forceinline__ void ldsm4t(uint32_t* r, uint32_t addr) {
    asm volatile("ldmatrix.sync.aligned.m8n8.x4.trans.shared.b16 {%0,%1,%2,%3}, [%4];"
                 : "=r"(r[0]), "=r"(r[1]), "=r"(r[2]), "=r"(r[3]) : "r"(addr));
}
__device__ __forceinline__ void mma16816(float* c, const uint32_t* a, const uint32_t* b) {
    asm volatile("mma.sync.aligned.m16n8k16.row.col.f32.bf16.bf16.f32 "
                 "{%0,%1,%2,%3}, {%4,%5,%6,%7}, {%8,%9}, {%0,%1,%2,%3};"
                 : "+f"(c[0]), "+f"(c[1]), "+f"(c[2]), "+f"(c[3])
                 : "r"(a[0]), "r"(a[1]), "r"(a[2]), "r"(a[3]), "r"(b[0]), "r"(b[1]));
}
__device__ __forceinline__ void mma16816h(float* c, const uint32_t* a, const uint32_t* b) {
    asm volatile("mma.sync.aligned.m16n8k16.row.col.f32.f16.f16.f32 "
                 "{%0,%1,%2,%3}, {%4,%5,%6,%7}, {%8,%9}, {%0,%1,%2,%3};"
                 : "+f"(c[0]), "+f"(c[1]), "+f"(c[2]), "+f"(c[3])
                 : "r"(a[0]), "r"(a[1]), "r"(a[2]), "r"(a[3]), "r"(b[0]), "r"(b[1]));
}
__device__ __forceinline__ uint32_t pack2(float lo, float hi) {
    uint32_t d;
    asm("cvt.rn.bf16x2.f32 %0, %1, %2;" : "=r"(d) : "f"(hi), "f"(lo));
    return d;
}
__device__ __forceinline__ float bfr(float v) {
    return __bfloat162float(__float2bfloat16_rn(v));
}
// fp16 hi/lo split of 8 fp32 into A-fragments
__device__ __forceinline__ void frag_split_h(const float* p8, uint32_t* hi, uint32_t* lo) {
    float hf[8], lf[8];
    #pragma unroll
    for (int e = 0; e < 8; ++e) {
        float hv = __half2float(__float2half_rn(p8[e]));
        hf[e] = hv; lf[e] = p8[e] - hv;
    }
    #pragma unroll
    for (int e = 0; e < 4; ++e) {
        __half2 a = __floats2half2_rn(hf[2 * e], hf[2 * e + 1]);
        __half2 b = __floats2half2_rn(lf[2 * e], lf[2 * e + 1]);
        hi[e] = *(uint32_t*)&a;
        lo[e] = *(uint32_t*)&b;
    }
}

// ---------------------------------------------------------------------------
// small elementwise kernels
// ---------------------------------------------------------------------------
__global__ void sig2_kernel(const float* __restrict__ in, float* __restrict__ out, int n) {
    int i = blockIdx.x * blockDim.x + threadIdx.x;
    if (i < n) {
        float x  = in[i];
        float sp = (x > 15.f) ? x : log1pf(__expf(x));
        out[i] = sp * sp;
    }
}

template<int AFORM>
__global__ void split3_kernel(const float* __restrict__ X, __nv_bfloat16* __restrict__ Y,
                              int rows) {
    int idx = blockIdx.x * blockDim.x + threadIdx.x;
    int r  = idx >> 8;
    int c4 = idx & 255;
    if (r >= rows) return;
    float4 x = *(const float4*)(X + (size_t)r * DM + c4 * 4);
    float v[4] = {x.x, x.y, x.z, x.w};
    unsigned short hu[4], lu[4];
    #pragma unroll
    for (int i = 0; i < 4; ++i) {
        __nv_bfloat16 hb = __float2bfloat16_rn(v[i]);
        float hr = __bfloat162float(hb);
        __nv_bfloat16 lb = __float2bfloat16_rn(v[i] - hr);
        hu[i] = __bfloat16_as_ushort(hb);
        lu[i] = __bfloat16_as_ushort(lb);
    }
    uint2 hp, lp;
    hp.x = (uint32_t)hu[0] | ((uint32_t)hu[1] << 16);
    hp.y = (uint32_t)hu[2] | ((uint32_t)hu[3] << 16);
    lp.x = (uint32_t)lu[0] | ((uint32_t)lu[1] << 16);
    lp.y = (uint32_t)lu[2] | ((uint32_t)lu[3] << 16);
    size_t ob = (size_t)r * K3 + c4 * 4;
    *(uint2*)(Y + ob) = hp;
    if (AFORM) {
        *(uint2*)(Y + ob + DM)     = lp;
        *(uint2*)(Y + ob + 2 * DM) = hp;
    } else {
        *(uint2*)(Y + ob + DM)     = hp;
        *(uint2*)(Y + ob + 2 * DM) = lp;
    }
}

template<int PRE>
__global__ void f16conv_kernel(const float* __restrict__ X, __half* __restrict__ Y) {
    int row = blockIdx.x;
    int c4  = threadIdx.x;
    float4 x = *(const float4*)(X + (size_t)row * DM + c4 * 4);
    float v[4] = {x.x, x.y, x.z, x.w};
    #pragma unroll
    for (int i = 0; i < 4; ++i) {
        if (PRE == 1) v[i] = v[i] * v[i];
        if (PRE == 2) {
            float sp = (v[i] > 15.f) ? v[i] : log1pf(__expf(v[i]));
            v[i] = sp * sp;
        }
    }
    __half2 h0 = __floats2half2_rn(v[0], v[1]);
    __half2 h1 = __floats2half2_rn(v[2], v[3]);
    uint2 p;
    p.x = *(uint32_t*)&h0;
    p.y = *(uint32_t*)&h1;
    *(uint2*)(Y + (size_t)row * DM + c4 * 4) = p;
}

// ---------------------------------------------------------------------------
// bf16x3 HMMA mainloop (shared by gemm_qkv / gemm_tc)
// ---------------------------------------------------------------------------
__device__ __forceinline__ void gemm_main_bf16(
    const __nv_bfloat16* __restrict__ A3, const __nv_bfloat16* __restrict__ B3,
    char* smem, int mBase, int nBase, float acc[4][4][4]) {
    const uint32_t sb = smem_u32(smem);
    const int t    = threadIdx.x;
    const int wid  = t >> 5;
    const int lane = t & 31;
    const int wm   = wid & 1;
    const int wn   = wid >> 1;

    const int r  = t >> 1;
    const int uc = (t & 1) * 4;
    const __nv_bfloat16* aRow = A3 + (size_t)(mBase + r) * K3 + uc * 8;
    const __nv_bfloat16* bRow = B3 + (size_t)(nBase + r) * K3 + uc * 8;

    auto load_stage = [&](int buf, int c) {
        uint32_t sA = sb + buf * STAGE_BYTES;
        uint32_t sB = sA + BM * 128;
        const __nv_bfloat16* ga = aRow + c * BK;
        const __nv_bfloat16* gb = bRow + c * BK;
        #pragma unroll
        for (int i = 0; i < 4; ++i) {
            uint32_t bo = r * 128 + (uc + i) * 16;
            cp16(sA + SWZ(bo), ga + i * 8);
            cp16(sB + SWZ(bo), gb + i * 8);
        }
        CP_COMMIT();
    };

    const int aRowSel = (lane & 7) | (((lane >> 3) & 1) << 3);
    const int aKSel   = (lane >> 4) << 4;
    const int bNSel   = (lane & 7) | ((lane >> 4) << 3);
    const int bKSel   = ((lane >> 3) & 1) << 4;

    load_stage(0, 0);
    load_stage(1, 1);

    for (int kt = 0; kt < KITERS; ++kt) {
        const int buf = kt % STAGES;
        if (kt == KITERS - 1) asm volatile("cp.async.wait_group 0;" ::: "memory");
        else                  asm volatile("cp.async.wait_group 1;" ::: "memory");
        __syncthreads();

        if (kt + 2 < KITERS) load_stage((kt + 2) % STAGES, kt + 2);

        uint32_t sA = sb + buf * STAGE_BYTES;
        uint32_t sB = sA + BM * 128;
        #pragma unroll
        for (int ks = 0; ks < 4; ++ks) {
            uint32_t af[4][4], bfr2[2][4];
            #pragma unroll
            for (int mi = 0; mi < 4; ++mi) {
                uint32_t bo = (uint32_t)((wm * 64 + mi * 16 + aRowSel) * 128
                                         + ks * 32 + aKSel);
                ldsm4(af[mi], sA + SWZ(bo));
            }
            #pragma unroll
            for (int pi = 0; pi < 2; ++pi) {
                uint32_t bo = (uint32_t)((wn * 32 + pi * 16 + bNSel) * 128
                                         + ks * 32 + bKSel);
                ldsm4(bfr2[pi], sB + SWZ(bo));
            }
            #pragma unroll
            for (int mi = 0; mi < 4; ++mi)
                #pragma unroll
                for (int ni = 0; ni < 4; ++ni)
                    mma16816(acc[mi][ni], af[mi], &bfr2[ni >> 1][(ni & 1) * 2]);
        }
        __syncthreads();
    }
}

// fused Q/K/V projection; epilogue writes head-major split tensors directly
__global__ void __launch_bounds__(256, 2)
gemm_qkv(const __nv_bfloat16* __restrict__ A3,
         const __nv_bfloat16* __restrict__ B0, const __nv_bfloat16* __restrict__ B1,
         const __nv_bfloat16* __restrict__ B2,
         const float* __restrict__ bi0, const float* __restrict__ bi1,
         const float* __restrict__ bi2,
         __nv_bfloat16* __restrict__ q3, __nv_bfloat16* __restrict__ k3,
         __half* __restrict__ v2h) {
    extern __shared__ __align__(1024) char smem[];
    const int z = blockIdx.z;
    const __nv_bfloat16* B3 = (z == 0) ? B0 : (z == 1) ? B1 : B2;
    const float* bias       = (z == 0) ? bi0 : (z == 1) ? bi1 : bi2;
    const int mBase = blockIdx.y * BM;
    const int nBase = blockIdx.x * BNT;

    float acc[4][4][4] = {};
    gemm_main_bf16(A3, B3, smem, mBase, nBase, acc);

    const int wid  = threadIdx.x >> 5;
    const int lane = threadIdx.x & 31;
    const int lr = lane >> 2;
    const int lc = (lane & 3) * 2;
    const int rB = mBase + (wid & 1) * 64;
    const int cB = nBase + (wid >> 1) * 32;
    #pragma unroll
    for (int mi = 0; mi < 4; ++mi) {
        #pragma unroll
        for (int ni = 0; ni < 4; ++ni) {
            int col  = cB + ni * 8 + lc;
            int row0 = rB + mi * 16 + lr;
            int h = col >> 6, dl = col & 63;
            float2 bi = *(const float2*)(bias + col);
            float vx[2][2] = {{acc[mi][ni][0] + bi.x, acc[mi][ni][1] + bi.y},
                              {acc[mi][ni][2] + bi.x, acc[mi][ni][3] + bi.y}};
            #pragma unroll
            for (int rr2 = 0; rr2 < 2; ++rr2) {
                int row = row0 + rr2 * 8;
                int b = row >> 10, n = row & 1023;
                if (z == 2) {
                    __half2 hv = __floats2half2_rn(vx[rr2][0], vx[rr2][1]);
                    *(uint32_t*)(v2h + ((size_t)(b * NH + h) * NSEQ + n) * 64 + dl)
                        = *(uint32_t*)&hv;
                } else {
                    float h0 = bfr(vx[rr2][0]), h1 = bfr(vx[rr2][1]);
                    uint32_t hp = pack2(h0, h1);
                    uint32_t lp = pack2(vx[rr2][0] - h0, vx[rr2][1] - h1);
                    __nv_bfloat16* dst = ((z == 0) ? q3 : k3)
                        + ((size_t)(b * NH + h) * NSEQ + n) * 192 + dl;
                    *(uint32_t*)dst = hp;
                    if (z == 0) {
                        *(uint32_t*)(dst + 64)  = lp;
                        *(uint32_t*)(dst + 128) = hp;
                    } else {
                        *(uint32_t*)(dst + 64)  = hp;
                        *(uint32_t*)(dst + 128) = lp;
                    }
                }
            }
        }
    }
}

// bf16x3 GEMM with fp32 epilogue (out_mean)
__global__ void __launch_bounds__(256, 2)
gemm_tc(const __nv_bfloat16* __restrict__ A3, const __nv_bfloat16* __restrict__ B3,
        const float* __restrict__ bias, float* __restrict__ C) {
    extern __shared__ __align__(1024) char smem[];
    const int mBase = blockIdx.y * BM;
    const int nBase = blockIdx.x * BNT;
    float acc[4][4][4] = {};
    gemm_main_bf16(A3, B3, smem, mBase, nBase, acc);

    const int wid  = threadIdx.x >> 5;
    const int lane = threadIdx.x & 31;
    const int lr = lane >> 2;
    const int lc = (lane & 3) * 2;
    const int rB = mBase + (wid & 1) * 64;
    const int cB = nBase + (wid >> 1) * 32;
    #pragma unroll
    for (int mi = 0; mi < 4; ++mi) {
        #pragma unroll
        for (int ni = 0; ni < 4; ++ni) {
            int col  = cB + ni * 8 + lc;
            int row0 = rB + mi * 16 + lr;
            float2 bi = *(const float2*)(bias + col);
            *(float2*)(C + (size_t)row0 * DM + col) =
                make_float2(acc[mi][ni][0] + bi.x, acc[mi][ni][1] + bi.y);
            *(float2*)(C + (size_t)(row0 + 8) * DM + col) =
                make_float2(acc[mi][ni][2] + bi.x, acc[mi][ni][3] + bi.y);
        }
    }
}

// ---------------------------------------------------------------------------
// fp16 single-pass GEMM (variance paths)
// EPI=0: write head-major fp16 (vv2h). EPI=1: fp32 + add -> C.
// ---------------------------------------------------------------------------
template<int EPI>
__global__ void __launch_bounds__(256, 2)
gemm_h(const __half* __restrict__ A, const __half* __restrict__ B,
       const float* __restrict__ bias, const float* __restrict__ add,
       float* __restrict__ C, __half* __restrict__ Hout) {
    extern __shared__ __align__(1024) char smem[];
    const uint32_t sb = smem_u32(smem);
    const int t    = threadIdx.x;
    const int wid  = t >> 5;
    const int lane = t & 31;
    const int wm   = wid & 1;
    const int wn   = wid >> 1;
    const int mBase = blockIdx.y * BM;
    const int nBase = blockIdx.x * BNT;

    const int r  = t >> 1;
    const int uc = (t & 1) * 4;
    const __half* aRow = A + (size_t)(mBase + r) * KH + uc * 8;
    const __half* bRow = B + (size_t)(nBase + r) * KH + uc * 8;

    auto load_stage = [&](int buf, int c) {
        uint32_t sA = sb + buf * STAGE_BYTES;
        uint32_t sB = sA + BM * 128;
        const __half* ga = aRow + c * BK;
        const __half* gb = bRow + c * BK;
        #pragma unroll
        for (int i = 0; i < 4; ++i) {
            uint32_t bo = r * 128 + (uc + i) * 16;
            cp16(sA + SWZ(bo), ga + i * 8);
            cp16(sB + SWZ(bo), gb + i * 8);
        }
        CP_COMMIT();
    };

    const int aRowSel = (lane & 7) | (((lane >> 3) & 1) << 3);
    const int aKSel   = (lane >> 4) << 4;
    const int bNSel   = (lane & 7) | ((lane >> 4) << 3);
    const int bKSel   = ((lane >> 3) & 1) << 4;

    float acc[4][4][4] = {};

    load_stage(0, 0);
    load_stage(1, 1);

    for (int kt = 0; kt < KITERS_H; ++kt) {
        const int buf = kt % STAGES;
        if (kt == KITERS_H - 1) asm volatile("cp.async.wait_group 0;" ::: "memory");
        else                    asm volatile("cp.async.wait_group 1;" ::: "memory");
        __syncthreads();

        if (kt + 2 < KITERS_H) load_stage((kt + 2) % STAGES, kt + 2);

        uint32_t sA = sb + buf * STAGE_BYTES;
        uint32_t sB = sA + BM * 128;
        #pragma unroll
        for (int ks = 0; ks < 4; ++ks) {
            uint32_t af[4][4], bfr2[2][4];
            #pragma unroll
            for (int mi = 0; mi < 4; ++mi) {
                uint32_t bo = (uint32_t)((wm * 64 + mi * 16 + aRowSel) * 128
                                         + ks * 32 + aKSel);
                ldsm4(af[mi], sA + SWZ(bo));
            }
            #pragma unroll
            for (int pi = 0; pi < 2; ++pi) {
                uint32_t bo = (uint32_t)((wn * 32 + pi * 16 + bNSel) * 128
                                         + ks * 32 + bKSel);
                ldsm4(bfr2[pi], sB + SWZ(bo));
            }
            #pragma unroll
            for (int mi = 0; mi < 4; ++mi)
                #pragma unroll
                for (int ni = 0; ni < 4; ++ni)
                    mma16816h(acc[mi][ni], af[mi], &bfr2[ni >> 1][(ni & 1) * 2]);
        }
        __syncthreads();
    }

    const int lr = lane >> 2;
    const int lc = (lane & 3) * 2;
    const int rB = mBase + wm * 64;
    const int cB = nBase + wn * 32;
    #pragma unroll
    for (int mi = 0; mi < 4; ++mi) {
        #pragma unroll
        for (int ni = 0; ni < 4; ++ni) {
            int col  = cB + ni * 8 + lc;
            int row0 = rB + mi * 16 + lr;
            float2 bi = *(const float2*)(bias + col);
            float vx[2][2] = {{acc[mi][ni][0] + bi.x, acc[mi][ni][1] + bi.y},
                              {acc[mi][ni][2] + bi.x, acc[mi][ni][3] + bi.y}};
            #pragma unroll
            for (int rr2 = 0; rr2 < 2; ++rr2) {
                int row = row0 + rr2 * 8;
                if (EPI == 0) {
                    int b = row >> 10, n = row & 1023;
                    int h = col >> 6, dl = col & 63;
                    __half2 hv = __floats2half2_rn(vx[rr2][0], vx[rr2][1]);
                    *(uint32_t*)(Hout + ((size_t)(b * NH + h) * NSEQ + n) * 64 + dl)
                        = *(uint32_t*)&hv;
                } else {
                    size_t o = (size_t)row * DM + col;
                    float2 a2 = *(const float2*)(add + o);
                    *(float2*)(C + o) = make_float2(vx[rr2][0] + a2.x, vx[rr2][1] + a2.y);
                }
            }
        }
    }
}

// ---------------------------------------------------------------------------
// dist2 (unchanged)
// ---------------------------------------------------------------------------
__global__ void dist2_kernel(const float* __restrict__ xr, float* __restrict__ d2) {
    __shared__ float xm[64][17];
    __shared__ float xn[64][17];
    __shared__ float x2m[64];
    __shared__ float x2n[64];

    const int t  = threadIdx.x;
    const int b  = blockIdx.z;
    const int mi = blockIdx.y * 64;
    const int nj = blockIdx.x * 64;

    for (int idx = t; idx < 64 * 4; idx += 256) {
        int r = idx >> 2, c = (idx & 3) * 4;
        float4 a = *(const float4*)(xr + ((size_t)b * NSEQ + mi + r) * 16 + c);
        xm[r][c] = a.x; xm[r][c+1] = a.y; xm[r][c+2] = a.z; xm[r][c+3] = a.w;
        float4 bb = *(const float4*)(xr + ((size_t)b * NSEQ + nj + r) * 16 + c);
        xn[r][c] = bb.x; xn[r][c+1] = bb.y; xn[r][c+2] = bb.z; xn[r][c+3] = bb.w;
    }
    __syncthreads();

    if (t < 64) {
        float s = 0.f;
        #pragma unroll
        for (int c = 0; c < 16; ++c) s += xm[t][c] * xm[t][c];
        x2m[t] = s;
    } else if (t < 128) {
        int r = t - 64;
        float s = 0.f;
        #pragma unroll
        for (int c = 0; c < 16; ++c) s += xn[r][c] * xn[r][c];
        x2n[r] = s;
    }
    __syncthreads();

    const int tx = t & 15, ty = t >> 4;
    #pragma unroll
    for (int i = 0; i < 4; ++i) {
        int row = ty * 4 + i;
        float out4[4];
        #pragma unroll
        for (int j = 0; j < 4; ++j) {
            int col = tx * 4 + j;
            float dot = 0.f;
            #pragma unroll
            for (int c = 0; c < 16; ++c) dot += xm[row][c] * xn[col][c];
            out4[j] = fmaxf(x2m[row] + x2n[col] - 2.f * dot, 0.f);
        }
        float4 v4 = make_float4(out4[0], out4[1], out4[2], out4[3]);
        *(float4*)(d2 + ((size_t)b * NSEQ + mi + row) * NSEQ + nj + tx * 4) = v4;
    }
}

// ---------------------------------------------------------------------------
// Tensor-core flash attention: S bf16x3, PV / P^2 Vv fp16 2-term.
// Epilogue writes a3c (bf16x3), hC2 (fp16 ctx^2), var (fp32) directly.
// ---------------------------------------------------------------------------
__global__ void __launch_bounds__(256, 1)
attn_tc(const __nv_bfloat16* __restrict__ q3, const __nv_bfloat16* __restrict__ k3,
        const __half* __restrict__ v2h, const __half* __restrict__ vv2h,
        const float* __restrict__ d2g,
        const float* __restrict__ lsf, const float* __restrict__ lll,
        __nv_bfloat16* __restrict__ a3c, __half* __restrict__ hC2,
        float* __restrict__ var) {
    extern __shared__ __align__(1024) char smem[];
    const uint32_t sb = smem_u32(smem);
    const int t    = threadIdx.x;
    const int wid  = t >> 5;
    const int lane = t & 31;
    const int qb   = blockIdx.x * QB;
    const int bh   = blockIdx.y;
    const int b    = bh >> 4, hh = bh & 15;

    const float sigma_f2 = __expf(2.f * lsf[hh]);
    const float coef     = 0.5f * __expf(-2.f * lll[hh]);

    const __nv_bfloat16* Qg  = q3   + ((size_t)bh * NSEQ + qb) * 192;
    const __nv_bfloat16* Kg  = k3   + (size_t)bh * NSEQ * 192;
    const __half* Vg  = v2h  + (size_t)bh * NSEQ * 64;
    const __half* VVg = vv2h + (size_t)bh * NSEQ * 64;

    for (int i = t; i < QB * 24; i += 256) {
        int row = i / 24, u = i % 24;
        cp16(sb + SM_Q + (u >> 3) * 16384 + SWZ((uint32_t)(row * 128 + (u & 7) * 16)),
             Qg + (size_t)row * 192 + u * 8);
    }

    auto load_kv = [&](int buf, int kt) {
        const __nv_bfloat16* kg = Kg + (size_t)kt * KT * 192;
        for (int i = t; i < KT * 24; i += 256) {
            int row = i / 24, u = i % 24;
            cp16(sb + SM_K + buf * 24576 + (u >> 3) * 8192
                    + SWZ((uint32_t)(row * 128 + (u & 7) * 16)),
                 kg + (size_t)row * 192 + u * 8);
        }
        const __half* vg = Vg  + (size_t)kt * KT * 64;
        const __half* wg = VVg + (size_t)kt * KT * 64;
        for (int i = t; i < KT * 8; i += 256) {
            int row = i >> 3, u = i & 7;
            uint32_t so = SWZ((uint32_t)(row * 128 + u * 16));
            cp16(sb + SM_V  + buf * 8192 + so, vg + (size_t)row * 64 + u * 8);
            cp16(sb + SM_VV + buf * 8192 + so, wg + (size_t)row * 64 + u * 8);
        }
        CP_COMMIT();
    };
    load_kv(0, 0);

    const int l15 = lane & 15;
    const int lHi = (lane >> 4) << 4;
    const uint32_t aRowOff = (uint32_t)((wid * 16 + l15) * 128 + lHi);
    const int g    = lane >> 3;
    const int keyl = ((g >> 1) << 3) + (lane & 7);
    const uint32_t kCol = (uint32_t)((g & 1) << 4);
    const int rr    = lane >> 2;
    const int cpair = (lane & 3) * 2;

    float accC[8][4] = {}, accV[8][4] = {};
    float rm0 = -1e30f, rm1 = -1e30f, rl0 = 0.f, rl1 = 0.f;

    for (int kt = 0; kt < NSEQ / KT; ++kt) {
        if (kt + 1 < NSEQ / KT) { __syncthreads(); load_kv((kt + 1) & 1, kt + 1); }
        if (kt + 1 < NSEQ / KT) asm volatile("cp.async.wait_group 1;" ::: "memory");
        else                    asm volatile("cp.async.wait_group 0;" ::: "memory");
        __syncthreads();

        const int buf = kt & 1;
        const uint32_t kB  = sb + SM_K  + buf * 24576;
        const uint32_t vB  = sb + SM_V  + buf * 8192;
        const uint32_t vvB = sb + SM_VV + buf * 8192;

        float sacc[8][4];
        #pragma unroll
        for (int j = 0; j < 8; ++j)
            #pragma unroll
            for (int e = 0; e < 4; ++e) sacc[j][e] = 0.f;

        #pragma unroll
        for (int ks = 0; ks < 12; ++ks) {
            uint32_t a[4];
            ldsm4(a, sb + SM_Q + (ks >> 2) * 16384 + SWZ(aRowOff + (ks & 3) * 32));
            #pragma unroll
            for (int n0 = 0; n0 < 4; ++n0) {
                uint32_t kb4[4];
                ldsm4(kb4, kB + (ks >> 2) * 8192
                         + SWZ((uint32_t)((n0 * 16 + keyl) * 128) + (ks & 3) * 32 + kCol));
                mma16816(sacc[2 * n0],     a, kb4);
                mma16816(sacc[2 * n0 + 1], a, kb4 + 2);
            }
        }

        const int kb0 = kt * KT;
        const float* d2r0 = d2g + (size_t)b * NSEQ * NSEQ
                          + (size_t)(qb + wid * 16 + rr) * NSEQ + kb0;
        const float* d2r1 = d2r0 + 8 * NSEQ;
        #pragma unroll
        for (int j = 0; j < 8; ++j) {
            float2 da = *(const float2*)(d2r0 + j * 8 + cpair);
            float2 db = *(const float2*)(d2r1 + j * 8 + cpair);
            sacc[j][0] = sacc[j][0] * QSCALE + sigma_f2 * __expf(-da.x * coef);
            sacc[j][1] = sacc[j][1] * QSCALE + sigma_f2 * __expf(-da.y * coef);
            sacc[j][2] = sacc[j][2] * QSCALE + sigma_f2 * __expf(-db.x * coef);
            sacc[j][3] = sacc[j][3] * QSCALE + sigma_f2 * __expf(-db.y * coef);
        }
        float mx0 = -1e30f, mx1 = -1e30f;
        #pragma unroll
        for (int j = 0; j < 8; ++j) {
            mx0 = fmaxf(mx0, fmaxf(sacc[j][0], sacc[j][1]));
            mx1 = fmaxf(mx1, fmaxf(sacc[j][2], sacc[j][3]));
        }
        mx0 = fmaxf(mx0, __shfl_xor_sync(0xffffffffu, mx0, 1));
        mx0 = fmaxf(mx0, __shfl_xor_sync(0xffffffffu, mx0, 2));
        mx1 = fmaxf(mx1, __shfl_xor_sync(0xffffffffu, mx1, 1));
        mx1 = fmaxf(mx1, __shfl_xor_sync(0xffffffffu, mx1, 2));
        float m0n = fmaxf(rm0, mx0), m1n = fmaxf(rm1, mx1);
        float f0 = __expf(rm0 - m0n), f1 = __expf(rm1 - m1n);
        rm0 = m0n; rm1 = m1n;
        float sum0 = 0.f, sum1 = 0.f;
        #pragma unroll
        for (int j = 0; j < 8; ++j) {
            sacc[j][0] = __expf(sacc[j][0] - m0n); sum0 += sacc[j][0];
            sacc[j][1] = __expf(sacc[j][1] - m0n); sum0 += sacc[j][1];
            sacc[j][2] = __expf(sacc[j][2] - m1n); sum1 += sacc[j][2];
            sacc[j][3] = __expf(sacc[j][3] - m1n); sum1 += sacc[j][3];
        }
        sum0 += __shfl_xor_sync(0xffffffffu, sum0, 1);
        sum0 += __shfl_xor_sync(0xffffffffu, sum0, 2);
        sum1 += __shfl_xor_sync(0xffffffffu, sum1, 1);
        sum1 += __shfl_xor_sync(0xffffffffu, sum1, 2);
        rl0 = rl0 * f0 + sum0;
        rl1 = rl1 * f1 + sum1;
        float f02 = f0 * f0, f12 = f1 * f1;
        #pragma unroll
        for (int j = 0; j < 8; ++j) {
            accC[j][0] *= f0;  accC[j][1] *= f0;
            accC[j][2] *= f1;  accC[j][3] *= f1;
            accV[j][0] *= f02; accV[j][1] *= f02;
            accV[j][2] *= f12; accV[j][3] *= f12;
        }

        // ---- PV and P^2 Vv: fp16 2-term (P scaled x256, P^2 scaled x1024) ----
        #pragma unroll
        for (int tt = 0; tt < 4; ++tt) {
            float ps[8], q8[8];
            #pragma unroll
            for (int e = 0; e < 4; ++e) {
                float p0 = sacc[2 * tt][e], p1 = sacc[2 * tt + 1][e];
                ps[e]     = p0 * 256.f;
                ps[4 + e] = p1 * 256.f;
                q8[e]     = p0 * p0 * 1024.f;
                q8[4 + e] = p1 * p1 * 1024.f;
            }
            uint32_t phi[4], plo[4], p2h[4], p2l[4];
            frag_split_h(ps, phi, plo);
            frag_split_h(q8, p2h, p2l);

            const uint32_t rowOff = (uint32_t)((tt * 16 + l15) * 128 + lHi);
            uint32_t vb[16];
            #pragma unroll
            for (int w = 0; w < 4; ++w) ldsm4t(vb + 4 * w, vB + SWZ(rowOff + w * 32));
            #pragma unroll
            for (int j = 0; j < 8; ++j) {
                uint32_t* B = &vb[(j >> 1) * 4 + (j & 1) * 2];
                mma16816h(accC[j], phi, B);
                mma16816h(accC[j], plo, B);
            }
            #pragma unroll
            for (int w = 0; w < 4; ++w) ldsm4t(vb + 4 * w, vvB + SWZ(rowOff + w * 32));
            #pragma unroll
            for (int j = 0; j < 8; ++j) {
                uint32_t* B = &vb[(j >> 1) * 4 + (j & 1) * 2];
                mma16816h(accV[j], p2h, B);
                mma16816h(accV[j], p2l, B);
            }
        }
    }

    // ---- epilogue: write a3c (bf16x3), hC2 (fp16 ctx^2), var (fp32) ----
    const float i0 = 1.f / (256.f * rl0), i1 = 1.f / (256.f * rl1);
    const float w0 = 1.f / (1024.f * rl0 * rl0), w1 = 1.f / (1024.f * rl1 * rl1);
    const int row0 = qb + wid * 16 + rr;
    #pragma unroll
    for (int j = 0; j < 8; ++j) {
        int off = j * 8 + cpair;
        int col = hh * 64 + off;
        float cv[2][2] = {{accC[j][0] * i0, accC[j][1] * i0},
                          {accC[j][2] * i1, accC[j][3] * i1}};
        float uv[2][2] = {{accV[j][0] * w0, accV[j][1] * w0},
                          {accV[j][2] * w1, accV[j][3] * w1}};
        #pragma unroll
        for (int rr2 = 0; rr2 < 2; ++rr2) {
            size_t bn = (size_t)b * NSEQ + row0 + rr2 * 8;
            float c0 = cv[rr2][0], c1 = cv[rr2][1];
            float h0 = bfr(c0), h1 = bfr(c1);
            uint32_t hp = pack2(h0, h1);
            uint32_t lp = pack2(c0 - h0, c1 - h1);
            __nv_bfloat16* dst = a3c + bn * K3 + col;
            *(uint32_t*)dst          = hp;
            *(uint32_t*)(dst + 1024) = lp;
            *(uint32_t*)(dst + 2048) = hp;
            __half2 hc = __floats2half2_rn(c0 * c0, c1 * c1);
            *(uint32_t*)(hC2 + bn * DM + col) = *(uint32_t*)&hc;
            *(float2*)(var + bn * DM + col) = make_float2(uv[rr2][0], uv[rr2][1]);
        }
    }
}

// ---------------------------------------------------------------------------
// Launcher
// ---------------------------------------------------------------------------
extern "C" void kernel_launch(void* const* d_in, const int* in_sizes, int n_in,
                              void* d_out, int out_size) {
    const float* H      = (const float*)d_in[0];
    const float* xr     = (const float*)d_in[1];
    const float* Wq     = (const float*)d_in[2];
    const float* bq     = (const float*)d_in[4];
    const float* Wk     = (const float*)d_in[6];
    const float* bk     = (const float*)d_in[8];
    const float* Wv     = (const float*)d_in[10];
    const float* Wv_rho = (const float*)d_in[11];
    const float* bv     = (const float*)d_in[12];
    const float* bv_rho = (const float*)d_in[13];
    const float* Wo     = (const float*)d_in[14];
    const float* Wo_rho = (const float*)d_in[15];
    const float* bo     = (const float*)d_in[16];
    const float* bo_rho = (const float*)d_in[17];
    const float* lsf    = (const float*)d_in[18];
    const float* lll    = (const float*)d_in[19];

    float *var, *d2, *bvs2, *bos2;
    __nv_bfloat16 *a3h, *a3c, *b3q, *b3k, *b3v, *b3o, *q3p, *k3p;
    __half *hA2, *hC2, *hVs, *hOs, *v2hp, *vv2hp;
    cudaGetSymbolAddress((void**)&var,  g_var);
    cudaGetSymbolAddress((void**)&d2,   g_d2);
    cudaGetSymbolAddress((void**)&bvs2, g_bvs2);
    cudaGetSymbolAddress((void**)&bos2, g_bos2);
    cudaGetSymbolAddress((void**)&a3h,  g_A3H);
    cudaGetSymbolAddress((void**)&a3c,  g_A3ctx);
    cudaGetSymbolAddress((void**)&b3q,  g_B3q);
    cudaGetSymbolAddress((void**)&b3k,  g_B3k);
    cudaGetSymbolAddress((void**)&b3v,  g_B3v);
    cudaGetSymbolAddress((void**)&b3o,  g_B3o);
    cudaGetSymbolAddress((void**)&hA2,  g_hA_H2);
    cudaGetSymbolAddress((void**)&hC2,  g_hC2);
    cudaGetSymbolAddress((void**)&hVs,  g_hB_vs2);
    cudaGetSymbolAddress((void**)&hOs,  g_hB_os2);
    cudaGetSymbolAddress((void**)&q3p,  g_q3);
    cudaGetSymbolAddress((void**)&k3p,  g_k3);
    cudaGetSymbolAddress((void**)&v2hp, g_v2h);
    cudaGetSymbolAddress((void**)&vv2hp, g_vv2h);

    cudaFuncSetAttribute(gemm_qkv,  cudaFuncAttributeMaxDynamicSharedMemorySize, SMEM_GEMM);
    cudaFuncSetAttribute(gemm_tc,   cudaFuncAttributeMaxDynamicSharedMemorySize, SMEM_GEMM);
    cudaFuncSetAttribute(gemm_h<0>, cudaFuncAttributeMaxDynamicSharedMemorySize, SMEM_GEMM);
    cudaFuncSetAttribute(gemm_h<1>, cudaFuncAttributeMaxDynamicSharedMemorySize, SMEM_GEMM);
    cudaFuncSetAttribute(attn_tc,   cudaFuncAttributeMaxDynamicSharedMemorySize, ATTN_SMEM);

    const dim3 ggrid3(DM / BNT, BN / BM, 3);
    const dim3 ggrid (DM / BNT, BN / BM);

    // [0,1] bias softplus^2
    sig2_kernel<<<4, 256>>>(bv_rho, bvs2, DM);
    sig2_kernel<<<4, 256>>>(bo_rho, bos2, DM);
    // [2] A-split of H
    split3_kernel<1><<<BN, 256>>>(H, a3h, BN);
    // [3..5] weight splits
    split3_kernel<0><<<DM, 256>>>(Wq, b3q, DM);
    split3_kernel<0><<<DM, 256>>>(Wk, b3k, DM);
    split3_kernel<0><<<DM, 256>>>(Wv, b3v, DM);
    // [6] fused QKV GEMM -> q3 / k3 / v2h directly
    gemm_qkv<<<ggrid3, 256, SMEM_GEMM>>>(a3h, b3q, b3k, b3v, bq, bk, bv,
                                         q3p, k3p, v2hp);
    // [7,8] fp16 variance operands, [9] V-variance GEMM -> vv2h directly
    f16conv_kernel<1><<<BN, 256>>>(H, hA2);
    f16conv_kernel<2><<<DM, 256>>>(Wv_rho, hVs);
    gemm_h<0><<<ggrid, 256, SMEM_GEMM>>>(hA2, hVs, bvs2, nullptr, nullptr, vv2hp);
    // [10] pairwise squared distances
    dist2_kernel<<<dim3(16, 16, BATCH), 256>>>(xr, d2);
    // [11] attention -> a3c / hC2 / var directly
    attn_tc<<<dim3(NSEQ / QB, BATCH * NH), 256, ATTN_SMEM>>>(
        q3p, k3p, v2hp, vv2hp, d2, lsf, lll, a3c, hC2, var);
    // [12,13] output weight operands
    split3_kernel<0><<<DM, 256>>>(Wo, b3o, DM);
    f16conv_kernel<2><<<DM, 256>>>(Wo_rho, hOs);
    // [14,15] output GEMMs -> d_out
    float* out_mean = (float*)d_out;
    float* out_var  = out_mean + (size_t)BN * DM;
    gemm_tc<<<ggrid, 256, SMEM_GEMM>>>(a3c, b3o, bo, out_mean);
    gemm_h<1><<<ggrid, 256, SMEM_GEMM>>>(hC2, hOs, bos2, var, out_var, nullptr);
}

// round 9
// speedup vs baseline: 3.1608x; 1.0968x over previous
#include <cuda_runtime.h>
#include <cuda_bf16.h>
#include <cuda_fp16.h>
#include <math.h>
#include <stdint.h>

#define DM    1024
#define BATCH 8
#define NSEQ  1024
#define BN    (BATCH * NSEQ)
#define NH    16
#define DK    64
#define QSCALE 0.125f

#define K3      3072
#define BK      64
#define KITERS  (K3 / BK)         // 48
#define KH      1024
#define KITERS_H (KH / BK)        // 16
#define BM      128
#define BNT     128
#define STAGES  3
#define STAGE_BYTES ((BM + BNT) * 128)
#define SMEM_GEMM (STAGES * STAGE_BYTES)        // 96 KB

// attention tiling / smem
#define QB 128
#define KT 64
#define SM_Q   0                  // 3 x 128 x 128B = 49152
#define SM_K   49152              // 2 x 3 x 64 x 128B = 49152
#define SM_V   98304              // 2 x 64 x 128B = 16384
#define SM_VV  114688             // 16384
#define ATTN_SMEM 131072

// ---------------------------------------------------------------------------
// Scratch
// ---------------------------------------------------------------------------
__device__ float g_var [BN * DM];
__device__ float g_d2  [BATCH * NSEQ * NSEQ];
__device__ float g_bvs2[DM];
__device__ float g_bos2[DM];

__device__ __nv_bfloat16 g_A3H  [BN * K3];
__device__ __nv_bfloat16 g_A3ctx[BN * K3];
__device__ __nv_bfloat16 g_B3q  [DM * K3];
__device__ __nv_bfloat16 g_B3k  [DM * K3];
__device__ __nv_bfloat16 g_B3v  [DM * K3];
__device__ __nv_bfloat16 g_B3o  [DM * K3];

__device__ __half g_hA_H2  [BN * DM];
__device__ __half g_hC2    [BN * DM];
__device__ __half g_hB_vs2 [DM * DM];
__device__ __half g_hB_os2 [DM * DM];

__device__ __nv_bfloat16 g_q3 [BATCH * NH * NSEQ * 192];
__device__ __nv_bfloat16 g_k3 [BATCH * NH * NSEQ * 192];
__device__ __half        g_v2h [BATCH * NH * NSEQ * 64];
__device__ __half        g_vv2h[BATCH * NH * NSEQ * 64];

// ---------------------------------------------------------------------------
// PTX helpers
// ---------------------------------------------------------------------------
__device__ __forceinline__ uint32_t smem_u32(const void* p) {
    uint32_t a;
    asm("{ .reg .u64 t; cvta.to.shared.u64 t, %1; cvt.u32.u64 %0, t; }"
        : "=r"(a) : "l"(p));
    return a;
}
#define SWZ(off) ((off) ^ (((off) >> 3) & 0x70))

__device__ __forceinline__ void cp16(uint32_t dst, const void* src) {
    asm volatile("cp.async.cg.shared.global [%0], [%1], 16;"
                 :: "r"(dst), "l"(src) : "memory");
}
#define CP_COMMIT() asm volatile("cp.async.commit_group;" ::: "memory")

__device__ __forceinline__ void ldsm4(uint32_t* r, uint32_t addr) {
    asm volatile("ldmatrix.sync.aligned.m8n8.x4.shared.b16 {%0,%1,%2,%3}, [%4];"
                 : "=r"(r[0]), "=r"(r[1]), "=r"(r[2]), "=r"(r[3]) : "r"(addr));
}
__device__ __forceinline__ void ldsm4t(uint32_t* r, uint32_t addr) {
    asm volatile("ldmatrix.sync.aligned.m8n8.x4.trans.shared.b16 {%0,%1,%2,%3}, [%4];"
                 : "=r"(r[0]), "=r"(r[1]), "=r"(r[2]), "=r"(r[3]) : "r"(addr));
}
__device__ __forceinline__ void mma16816(float* c, const uint32_t* a, const uint32_t* b) {
    asm volatile("mma.sync.aligned.m16n8k16.row.col.f32.bf16.bf16.f32 "
                 "{%0,%1,%2,%3}, {%4,%5,%6,%7}, {%8,%9}, {%0,%1,%2,%3};"
                 : "+f"(c[0]), "+f"(c[1]), "+f"(c[2]), "+f"(c[3])
                 : "r"(a[0]), "r"(a[1]), "r"(a[2]), "r"(a[3]), "r"(b[0]), "r"(b[1]));
}
__device__ __forceinline__ void mma16816h(float* c, const uint32_t* a, const uint32_t* b) {
    asm volatile("mma.sync.aligned.m16n8k16.row.col.f32.f16.f16.f32 "
                 "{%0,%1,%2,%3}, {%4,%5,%6,%7}, {%8,%9}, {%0,%1,%2,%3};"
                 : "+f"(c[0]), "+f"(c[1]), "+f"(c[2]), "+f"(c[3])
                 : "r"(a[0]), "r"(a[1]), "r"(a[2]), "r"(a[3]), "r"(b[0]), "r"(b[1]));
}
__device__ __forceinline__ uint32_t pack2(float lo, float hi) {
    uint32_t d;
    asm("cvt.rn.bf16x2.f32 %0, %1, %2;" : "=r"(d) : "f"(hi), "f"(lo));
    return d;
}
__device__ __forceinline__ float bfr(float v) {
    return __bfloat162float(__float2bfloat16_rn(v));
}
// fp16 hi/lo split of 8 fp32 into A-fragments
__device__ __forceinline__ void frag_split_h(const float* p8, uint32_t* hi, uint32_t* lo) {
    float hf[8], lf[8];
    #pragma unroll
    for (int e = 0; e < 8; ++e) {
        float hv = __half2float(__float2half_rn(p8[e]));
        hf[e] = hv; lf[e] = p8[e] - hv;
    }
    #pragma unroll
    for (int e = 0; e < 4; ++e) {
        __half2 a = __floats2half2_rn(hf[2 * e], hf[2 * e + 1]);
        __half2 b = __floats2half2_rn(lf[2 * e], lf[2 * e + 1]);
        hi[e] = *(uint32_t*)&a;
        lo[e] = *(uint32_t*)&b;
    }
}

// ---------------------------------------------------------------------------
// elementwise prep kernels
// ---------------------------------------------------------------------------
// both bias softplus^2 arrays in one launch (grid 8 x 256)
__global__ void bias2_kernel(const float* __restrict__ a, const float* __restrict__ b,
                             float* __restrict__ oa, float* __restrict__ ob) {
    int i = blockIdx.x * 256 + threadIdx.x;
    const float* in  = (i < DM) ? a  : b;
    float*       out = (i < DM) ? oa : ob;
    int j = i & (DM - 1);
    float x  = in[j];
    float sp = (x > 15.f) ? x : log1pf(__expf(x));
    out[j] = sp * sp;
}

// bf16x3 A-split of H: [hi|lo|hi]
__global__ void splitA_kernel(const float* __restrict__ X, __nv_bfloat16* __restrict__ Y) {
    int r  = blockIdx.x;
    int c4 = threadIdx.x;
    float4 x = *(const float4*)(X + (size_t)r * DM + c4 * 4);
    float v[4] = {x.x, x.y, x.z, x.w};
    unsigned short hu[4], lu[4];
    #pragma unroll
    for (int i = 0; i < 4; ++i) {
        __nv_bfloat16 hb = __float2bfloat16_rn(v[i]);
        float hr = __bfloat162float(hb);
        __nv_bfloat16 lb = __float2bfloat16_rn(v[i] - hr);
        hu[i] = __bfloat16_as_ushort(hb);
        lu[i] = __bfloat16_as_ushort(lb);
    }
    uint2 hp, lp;
    hp.x = (uint32_t)hu[0] | ((uint32_t)hu[1] << 16);
    hp.y = (uint32_t)hu[2] | ((uint32_t)hu[3] << 16);
    lp.x = (uint32_t)lu[0] | ((uint32_t)lu[1] << 16);
    lp.y = (uint32_t)lu[2] | ((uint32_t)lu[3] << 16);
    size_t ob = (size_t)r * K3 + c4 * 4;
    *(uint2*)(Y + ob)          = hp;
    *(uint2*)(Y + ob + DM)     = lp;
    *(uint2*)(Y + ob + 2 * DM) = hp;
}

// bf16x3 B-split of 4 weight matrices ([hi|hi|lo]); grid (DM, 4)
__global__ void wsplit4_kernel(const float* __restrict__ W0, const float* __restrict__ W1,
                               const float* __restrict__ W2, const float* __restrict__ W3,
                               __nv_bfloat16* __restrict__ Y0, __nv_bfloat16* __restrict__ Y1,
                               __nv_bfloat16* __restrict__ Y2, __nv_bfloat16* __restrict__ Y3) {
    int z = blockIdx.y;
    const float* X = (z == 0) ? W0 : (z == 1) ? W1 : (z == 2) ? W2 : W3;
    __nv_bfloat16* Y = (z == 0) ? Y0 : (z == 1) ? Y1 : (z == 2) ? Y2 : Y3;
    int r  = blockIdx.x;
    int c4 = threadIdx.x;
    float4 x = *(const float4*)(X + (size_t)r * DM + c4 * 4);
    float v[4] = {x.x, x.y, x.z, x.w};
    unsigned short hu[4], lu[4];
    #pragma unroll
    for (int i = 0; i < 4; ++i) {
        __nv_bfloat16 hb = __float2bfloat16_rn(v[i]);
        float hr = __bfloat162float(hb);
        __nv_bfloat16 lb = __float2bfloat16_rn(v[i] - hr);
        hu[i] = __bfloat16_as_ushort(hb);
        lu[i] = __bfloat16_as_ushort(lb);
    }
    uint2 hp, lp;
    hp.x = (uint32_t)hu[0] | ((uint32_t)hu[1] << 16);
    hp.y = (uint32_t)hu[2] | ((uint32_t)hu[3] << 16);
    lp.x = (uint32_t)lu[0] | ((uint32_t)lu[1] << 16);
    lp.y = (uint32_t)lu[2] | ((uint32_t)lu[3] << 16);
    size_t ob = (size_t)r * K3 + c4 * 4;
    *(uint2*)(Y + ob)          = hp;
    *(uint2*)(Y + ob + DM)     = hp;
    *(uint2*)(Y + ob + 2 * DM) = lp;
}

// fp16 softplus^2 convert of both rho weights; grid (DM, 2)
__global__ void f16w2_kernel(const float* __restrict__ W0, const float* __restrict__ W1,
                             __half* __restrict__ Y0, __half* __restrict__ Y1) {
    int z = blockIdx.y;
    const float* X = (z == 0) ? W0 : W1;
    __half* Y      = (z == 0) ? Y0 : Y1;
    int row = blockIdx.x;
    int c4  = threadIdx.x;
    float4 x = *(const float4*)(X + (size_t)row * DM + c4 * 4);
    float v[4] = {x.x, x.y, x.z, x.w};
    #pragma unroll
    for (int i = 0; i < 4; ++i) {
        float sp = (v[i] > 15.f) ? v[i] : log1pf(__expf(v[i]));
        v[i] = sp * sp;
    }
    __half2 h0 = __floats2half2_rn(v[0], v[1]);
    __half2 h1 = __floats2half2_rn(v[2], v[3]);
    uint2 p;
    p.x = *(uint32_t*)&h0;
    p.y = *(uint32_t*)&h1;
    *(uint2*)(Y + (size_t)row * DM + c4 * 4) = p;
}

// fp16 square convert of H; grid BN
__global__ void f16sq_kernel(const float* __restrict__ X, __half* __restrict__ Y) {
    int row = blockIdx.x;
    int c4  = threadIdx.x;
    float4 x = *(const float4*)(X + (size_t)row * DM + c4 * 4);
    __half2 h0 = __floats2half2_rn(x.x * x.x, x.y * x.y);
    __half2 h1 = __floats2half2_rn(x.z * x.z, x.w * x.w);
    uint2 p;
    p.x = *(uint32_t*)&h0;
    p.y = *(uint32_t*)&h1;
    *(uint2*)(Y + (size_t)row * DM + c4 * 4) = p;
}

// ---------------------------------------------------------------------------
// GEMM mainloops (device functions)
// ---------------------------------------------------------------------------
__device__ __forceinline__ void gemm_main_bf16(
    const __nv_bfloat16* __restrict__ A3, const __nv_bfloat16* __restrict__ B3,
    char* smem, int mBase, int nBase, float acc[4][4][4]) {
    const uint32_t sb = smem_u32(smem);
    const int t    = threadIdx.x;
    const int wid  = t >> 5;
    const int lane = t & 31;
    const int wm   = wid & 1;
    const int wn   = wid >> 1;

    const int r  = t >> 1;
    const int uc = (t & 1) * 4;
    const __nv_bfloat16* aRow = A3 + (size_t)(mBase + r) * K3 + uc * 8;
    const __nv_bfloat16* bRow = B3 + (size_t)(nBase + r) * K3 + uc * 8;

    auto load_stage = [&](int buf, int c) {
        uint32_t sA = sb + buf * STAGE_BYTES;
        uint32_t sB = sA + BM * 128;
        const __nv_bfloat16* ga = aRow + c * BK;
        const __nv_bfloat16* gb = bRow + c * BK;
        #pragma unroll
        for (int i = 0; i < 4; ++i) {
            uint32_t bo = r * 128 + (uc + i) * 16;
            cp16(sA + SWZ(bo), ga + i * 8);
            cp16(sB + SWZ(bo), gb + i * 8);
        }
        CP_COMMIT();
    };

    const int aRowSel = (lane & 7) | (((lane >> 3) & 1) << 3);
    const int aKSel   = (lane >> 4) << 4;
    const int bNSel   = (lane & 7) | ((lane >> 4) << 3);
    const int bKSel   = ((lane >> 3) & 1) << 4;

    load_stage(0, 0);
    load_stage(1, 1);

    for (int kt = 0; kt < KITERS; ++kt) {
        const int buf = kt % STAGES;
        if (kt == KITERS - 1) asm volatile("cp.async.wait_group 0;" ::: "memory");
        else                  asm volatile("cp.async.wait_group 1;" ::: "memory");
        __syncthreads();

        if (kt + 2 < KITERS) load_stage((kt + 2) % STAGES, kt + 2);

        uint32_t sA = sb + buf * STAGE_BYTES;
        uint32_t sB = sA + BM * 128;
        #pragma unroll
        for (int ks = 0; ks < 4; ++ks) {
            uint32_t af[4][4], bfr2[2][4];
            #pragma unroll
            for (int mi = 0; mi < 4; ++mi) {
                uint32_t bo = (uint32_t)((wm * 64 + mi * 16 + aRowSel) * 128
                                         + ks * 32 + aKSel);
                ldsm4(af[mi], sA + SWZ(bo));
            }
            #pragma unroll
            for (int pi = 0; pi < 2; ++pi) {
                uint32_t bo = (uint32_t)((wn * 32 + pi * 16 + bNSel) * 128
                                         + ks * 32 + bKSel);
                ldsm4(bfr2[pi], sB + SWZ(bo));
            }
            #pragma unroll
            for (int mi = 0; mi < 4; ++mi)
                #pragma unroll
                for (int ni = 0; ni < 4; ++ni)
                    mma16816(acc[mi][ni], af[mi], &bfr2[ni >> 1][(ni & 1) * 2]);
        }
        __syncthreads();
    }
}

__device__ __forceinline__ void gemm_main_h(
    const __half* __restrict__ A, const __half* __restrict__ B,
    char* smem, int mBase, int nBase, float acc[4][4][4]) {
    const uint32_t sb = smem_u32(smem);
    const int t    = threadIdx.x;
    const int wid  = t >> 5;
    const int lane = t & 31;
    const int wm   = wid & 1;
    const int wn   = wid >> 1;

    const int r  = t >> 1;
    const int uc = (t & 1) * 4;
    const __half* aRow = A + (size_t)(mBase + r) * KH + uc * 8;
    const __half* bRow = B + (size_t)(nBase + r) * KH + uc * 8;

    auto load_stage = [&](int buf, int c) {
        uint32_t sA = sb + buf * STAGE_BYTES;
        uint32_t sB = sA + BM * 128;
        const __half* ga = aRow + c * BK;
        const __half* gb = bRow + c * BK;
        #pragma unroll
        for (int i = 0; i < 4; ++i) {
            uint32_t bo = r * 128 + (uc + i) * 16;
            cp16(sA + SWZ(bo), ga + i * 8);
            cp16(sB + SWZ(bo), gb + i * 8);
        }
        CP_COMMIT();
    };

    const int aRowSel = (lane & 7) | (((lane >> 3) & 1) << 3);
    const int aKSel   = (lane >> 4) << 4;
    const int bNSel   = (lane & 7) | ((lane >> 4) << 3);
    const int bKSel   = ((lane >> 3) & 1) << 4;

    load_stage(0, 0);
    load_stage(1, 1);

    for (int kt = 0; kt < KITERS_H; ++kt) {
        const int buf = kt % STAGES;
        if (kt == KITERS_H - 1) asm volatile("cp.async.wait_group 0;" ::: "memory");
        else                    asm volatile("cp.async.wait_group 1;" ::: "memory");
        __syncthreads();

        if (kt + 2 < KITERS_H) load_stage((kt + 2) % STAGES, kt + 2);

        uint32_t sA = sb + buf * STAGE_BYTES;
        uint32_t sB = sA + BM * 128;
        #pragma unroll
        for (int ks = 0; ks < 4; ++ks) {
            uint32_t af[4][4], bfr2[2][4];
            #pragma unroll
            for (int mi = 0; mi < 4; ++mi) {
                uint32_t bo = (uint32_t)((wm * 64 + mi * 16 + aRowSel) * 128
                                         + ks * 32 + aKSel);
                ldsm4(af[mi], sA + SWZ(bo));
            }
            #pragma unroll
            for (int pi = 0; pi < 2; ++pi) {
                uint32_t bo = (uint32_t)((wn * 32 + pi * 16 + bNSel) * 128
                                         + ks * 32 + bKSel);
                ldsm4(bfr2[pi], sB + SWZ(bo));
            }
            #pragma unroll
            for (int mi = 0; mi < 4; ++mi)
                #pragma unroll
                for (int ni = 0; ni < 4; ++ni)
                    mma16816h(acc[mi][ni], af[mi], &bfr2[ni >> 1][(ni & 1) * 2]);
        }
        __syncthreads();
    }
}

// ---------------------------------------------------------------------------
// fused projection GEMM: z=0/1/2 -> Q/K/V (bf16x3, head-major epilogue),
// z=3 -> V-variance (fp16, head-major fp16 epilogue). grid (8, 64, 4).
// ---------------------------------------------------------------------------
__global__ void __launch_bounds__(256, 2)
gemm_proj(const __nv_bfloat16* __restrict__ A3,
          const __nv_bfloat16* __restrict__ B3q, const __nv_bfloat16* __restrict__ B3k,
          const __nv_bfloat16* __restrict__ B3v,
          const __half* __restrict__ hA2, const __half* __restrict__ hVs,
          const float* __restrict__ bq, const float* __restrict__ bk,
          const float* __restrict__ bv, const float* __restrict__ bvs2,
          __nv_bfloat16* __restrict__ q3, __nv_bfloat16* __restrict__ k3,
          __half* __restrict__ v2h, __half* __restrict__ vv2h) {
    extern __shared__ __align__(1024) char smem[];
    const int z = blockIdx.z;
    const int mBase = blockIdx.y * BM;
    const int nBase = blockIdx.x * BNT;
    float acc[4][4][4] = {};

    if (z < 3) {
        const __nv_bfloat16* B3 = (z == 0) ? B3q : (z == 1) ? B3k : B3v;
        gemm_main_bf16(A3, B3, smem, mBase, nBase, acc);
    } else {
        gemm_main_h(hA2, hVs, smem, mBase, nBase, acc);
    }

    const float* bias = (z == 0) ? bq : (z == 1) ? bk : (z == 2) ? bv : bvs2;
    const int wid  = threadIdx.x >> 5;
    const int lane = threadIdx.x & 31;
    const int lr = lane >> 2;
    const int lc = (lane & 3) * 2;
    const int rB = mBase + (wid & 1) * 64;
    const int cB = nBase + (wid >> 1) * 32;
    #pragma unroll
    for (int mi = 0; mi < 4; ++mi) {
        #pragma unroll
        for (int ni = 0; ni < 4; ++ni) {
            int col  = cB + ni * 8 + lc;
            int row0 = rB + mi * 16 + lr;
            int h = col >> 6, dl = col & 63;
            float2 bi = *(const float2*)(bias + col);
            float vx[2][2] = {{acc[mi][ni][0] + bi.x, acc[mi][ni][1] + bi.y},
                              {acc[mi][ni][2] + bi.x, acc[mi][ni][3] + bi.y}};
            #pragma unroll
            for (int rr2 = 0; rr2 < 2; ++rr2) {
                int row = row0 + rr2 * 8;
                int b = row >> 10, n = row & 1023;
                if (z >= 2) {
                    __half* dst = (z == 2) ? v2h : vv2h;
                    __half2 hv = __floats2half2_rn(vx[rr2][0], vx[rr2][1]);
                    *(uint32_t*)(dst + ((size_t)(b * NH + h) * NSEQ + n) * 64 + dl)
                        = *(uint32_t*)&hv;
                } else {
                    float h0 = bfr(vx[rr2][0]), h1 = bfr(vx[rr2][1]);
                    uint32_t hp = pack2(h0, h1);
                    uint32_t lp = pack2(vx[rr2][0] - h0, vx[rr2][1] - h1);
                    __nv_bfloat16* dst = ((z == 0) ? q3 : k3)
                        + ((size_t)(b * NH + h) * NSEQ + n) * 192 + dl;
                    *(uint32_t*)dst = hp;
                    if (z == 0) {
                        *(uint32_t*)(dst + 64)  = lp;
                        *(uint32_t*)(dst + 128) = hp;
                    } else {
                        *(uint32_t*)(dst + 64)  = hp;
                        *(uint32_t*)(dst + 128) = lp;
                    }
                }
            }
        }
    }
}

// ---------------------------------------------------------------------------
// fused output GEMM: z=0 -> out_mean (bf16x3), z=1 -> out_var (fp16 + add).
// grid (8, 64, 2).
// ---------------------------------------------------------------------------
__global__ void __launch_bounds__(256, 2)
gemm_out(const __nv_bfloat16* __restrict__ a3c, const __nv_bfloat16* __restrict__ b3o,
         const float* __restrict__ bo,
         const __half* __restrict__ hC2, const __half* __restrict__ hOs,
         const float* __restrict__ bos2, const float* __restrict__ var,
         float* __restrict__ out_mean, float* __restrict__ out_var) {
    extern __shared__ __align__(1024) char smem[];
    const int z = blockIdx.z;
    const int mBase = blockIdx.y * BM;
    const int nBase = blockIdx.x * BNT;
    float acc[4][4][4] = {};

    if (z == 0) gemm_main_bf16(a3c, b3o, smem, mBase, nBase, acc);
    else        gemm_main_h(hC2, hOs, smem, mBase, nBase, acc);

    const float* bias = (z == 0) ? bo : bos2;
    float* C          = (z == 0) ? out_mean : out_var;
    const int wid  = threadIdx.x >> 5;
    const int lane = threadIdx.x & 31;
    const int lr = lane >> 2;
    const int lc = (lane & 3) * 2;
    const int rB = mBase + (wid & 1) * 64;
    const int cB = nBase + (wid >> 1) * 32;
    #pragma unroll
    for (int mi = 0; mi < 4; ++mi) {
        #pragma unroll
        for (int ni = 0; ni < 4; ++ni) {
            int col  = cB + ni * 8 + lc;
            int row0 = rB + mi * 16 + lr;
            float2 bi = *(const float2*)(bias + col);
            float vx[2][2] = {{acc[mi][ni][0] + bi.x, acc[mi][ni][1] + bi.y},
                              {acc[mi][ni][2] + bi.x, acc[mi][ni][3] + bi.y}};
            #pragma unroll
            for (int rr2 = 0; rr2 < 2; ++rr2) {
                size_t o = (size_t)(row0 + rr2 * 8) * DM + col;
                if (z == 1) {
                    float2 a2 = *(const float2*)(var + o);
                    vx[rr2][0] += a2.x; vx[rr2][1] += a2.y;
                }
                *(float2*)(C + o) = make_float2(vx[rr2][0], vx[rr2][1]);
            }
        }
    }
}

// ---------------------------------------------------------------------------
// dist2 (unchanged)
// ---------------------------------------------------------------------------
__global__ void dist2_kernel(const float* __restrict__ xr, float* __restrict__ d2) {
    __shared__ float xm[64][17];
    __shared__ float xn[64][17];
    __shared__ float x2m[64];
    __shared__ float x2n[64];

    const int t  = threadIdx.x;
    const int b  = blockIdx.z;
    const int mi = blockIdx.y * 64;
    const int nj = blockIdx.x * 64;

    for (int idx = t; idx < 64 * 4; idx += 256) {
        int r = idx >> 2, c = (idx & 3) * 4;
        float4 a = *(const float4*)(xr + ((size_t)b * NSEQ + mi + r) * 16 + c);
        xm[r][c] = a.x; xm[r][c+1] = a.y; xm[r][c+2] = a.z; xm[r][c+3] = a.w;
        float4 bb = *(const float4*)(xr + ((size_t)b * NSEQ + nj + r) * 16 + c);
        xn[r][c] = bb.x; xn[r][c+1] = bb.y; xn[r][c+2] = bb.z; xn[r][c+3] = bb.w;
    }
    __syncthreads();

    if (t < 64) {
        float s = 0.f;
        #pragma unroll
        for (int c = 0; c < 16; ++c) s += xm[t][c] * xm[t][c];
        x2m[t] = s;
    } else if (t < 128) {
        int r = t - 64;
        float s = 0.f;
        #pragma unroll
        for (int c = 0; c < 16; ++c) s += xn[r][c] * xn[r][c];
        x2n[r] = s;
    }
    __syncthreads();

    const int tx = t & 15, ty = t >> 4;
    #pragma unroll
    for (int i = 0; i < 4; ++i) {
        int row = ty * 4 + i;
        float out4[4];
        #pragma unroll
        for (int j = 0; j < 4; ++j) {
            int col = tx * 4 + j;
            float dot = 0.f;
            #pragma unroll
            for (int c = 0; c < 16; ++c) dot += xm[row][c] * xn[col][c];
            out4[j] = fmaxf(x2m[row] + x2n[col] - 2.f * dot, 0.f);
        }
        float4 v4 = make_float4(out4[0], out4[1], out4[2], out4[3]);
        *(float4*)(d2 + ((size_t)b * NSEQ + mi + row) * NSEQ + nj + tx * 4) = v4;
    }
}

// ---------------------------------------------------------------------------
// Tensor-core flash attention: S bf16x3, PV fp16 2-term, P^2 Vv fp16 1-term
// (P^2 scaled x1024 -> hi-term worst-case error <= 2^-12, positive sum).
// Epilogue writes a3c (bf16x3), hC2 (fp16 ctx^2), var (fp32) directly.
// ---------------------------------------------------------------------------
__global__ void __launch_bounds__(256, 1)
attn_tc(const __nv_bfloat16* __restrict__ q3, const __nv_bfloat16* __restrict__ k3,
        const __half* __restrict__ v2h, const __half* __restrict__ vv2h,
        const float* __restrict__ d2g,
        const float* __restrict__ lsf, const float* __restrict__ lll,
        __nv_bfloat16* __restrict__ a3c, __half* __restrict__ hC2,
        float* __restrict__ var) {
    extern __shared__ __align__(1024) char smem[];
    const uint32_t sb = smem_u32(smem);
    const int t    = threadIdx.x;
    const int wid  = t >> 5;
    const int lane = t & 31;
    const int qb   = blockIdx.x * QB;
    const int bh   = blockIdx.y;
    const int b    = bh >> 4, hh = bh & 15;

    const float sigma_f2 = __expf(2.f * lsf[hh]);
    const float coef     = 0.5f * __expf(-2.f * lll[hh]);

    const __nv_bfloat16* Qg  = q3   + ((size_t)bh * NSEQ + qb) * 192;
    const __nv_bfloat16* Kg  = k3   + (size_t)bh * NSEQ * 192;
    const __half* Vg  = v2h  + (size_t)bh * NSEQ * 64;
    const __half* VVg = vv2h + (size_t)bh * NSEQ * 64;

    for (int i = t; i < QB * 24; i += 256) {
        int row = i / 24, u = i % 24;
        cp16(sb + SM_Q + (u >> 3) * 16384 + SWZ((uint32_t)(row * 128 + (u & 7) * 16)),
             Qg + (size_t)row * 192 + u * 8);
    }

    auto load_kv = [&](int buf, int kt) {
        const __nv_bfloat16* kg = Kg + (size_t)kt * KT * 192;
        for (int i = t; i < KT * 24; i += 256) {
            int row = i / 24, u = i % 24;
            cp16(sb + SM_K + buf * 24576 + (u >> 3) * 8192
                    + SWZ((uint32_t)(row * 128 + (u & 7) * 16)),
                 kg + (size_t)row * 192 + u * 8);
        }
        const __half* vg = Vg  + (size_t)kt * KT * 64;
        const __half* wg = VVg + (size_t)kt * KT * 64;
        for (int i = t; i < KT * 8; i += 256) {
            int row = i >> 3, u = i & 7;
            uint32_t so = SWZ((uint32_t)(row * 128 + u * 16));
            cp16(sb + SM_V  + buf * 8192 + so, vg + (size_t)row * 64 + u * 8);
            cp16(sb + SM_VV + buf * 8192 + so, wg + (size_t)row * 64 + u * 8);
        }
        CP_COMMIT();
    };
    load_kv(0, 0);

    const int l15 = lane & 15;
    const int lHi = (lane >> 4) << 4;
    const uint32_t aRowOff = (uint32_t)((wid * 16 + l15) * 128 + lHi);
    const int g    = lane >> 3;
    const int keyl = ((g >> 1) << 3) + (lane & 7);
    const uint32_t kCol = (uint32_t)((g & 1) << 4);
    const int rr    = lane >> 2;
    const int cpair = (lane & 3) * 2;

    float accC[8][4] = {}, accV[8][4] = {};
    float rm0 = -1e30f, rm1 = -1e30f, rl0 = 0.f, rl1 = 0.f;

    for (int kt = 0; kt < NSEQ / KT; ++kt) {
        if (kt + 1 < NSEQ / KT) { __syncthreads(); load_kv((kt + 1) & 1, kt + 1); }
        if (kt + 1 < NSEQ / KT) asm volatile("cp.async.wait_group 1;" ::: "memory");
        else                    asm volatile("cp.async.wait_group 0;" ::: "memory");
        __syncthreads();

        const int buf = kt & 1;
        const uint32_t kB  = sb + SM_K  + buf * 24576;
        const uint32_t vB  = sb + SM_V  + buf * 8192;
        const uint32_t vvB = sb + SM_VV + buf * 8192;

        float sacc[8][4];
        #pragma unroll
        for (int j = 0; j < 8; ++j)
            #pragma unroll
            for (int e = 0; e < 4; ++e) sacc[j][e] = 0.f;

        #pragma unroll
        for (int ks = 0; ks < 12; ++ks) {
            uint32_t a[4];
            ldsm4(a, sb + SM_Q + (ks >> 2) * 16384 + SWZ(aRowOff + (ks & 3) * 32));
            #pragma unroll
            for (int n0 = 0; n0 < 4; ++n0) {
                uint32_t kb4[4];
                ldsm4(kb4, kB + (ks >> 2) * 8192
                         + SWZ((uint32_t)((n0 * 16 + keyl) * 128) + (ks & 3) * 32 + kCol));
                mma16816(sacc[2 * n0],     a, kb4);
                mma16816(sacc[2 * n0 + 1], a, kb4 + 2);
            }
        }

        const int kb0 = kt * KT;
        const float* d2r0 = d2g + (size_t)b * NSEQ * NSEQ
                          + (size_t)(qb + wid * 16 + rr) * NSEQ + kb0;
        const float* d2r1 = d2r0 + 8 * NSEQ;
        #pragma unroll
        for (int j = 0; j < 8; ++j) {
            float2 da = *(const float2*)(d2r0 + j * 8 + cpair);
            float2 db = *(const float2*)(d2r1 + j * 8 + cpair);
            sacc[j][0] = sacc[j][0] * QSCALE + sigma_f2 * __expf(-da.x * coef);
            sacc[j][1] = sacc[j][1] * QSCALE + sigma_f2 * __expf(-da.y * coef);
            sacc[j][2] = sacc[j][2] * QSCALE + sigma_f2 * __expf(-db.x * coef);
            sacc[j][3] = sacc[j][3] * QSCALE + sigma_f2 * __expf(-db.y * coef);
        }
        float mx0 = -1e30f, mx1 = -1e30f;
        #pragma unroll
        for (int j = 0; j < 8; ++j) {
            mx0 = fmaxf(mx0, fmaxf(sacc[j][0], sacc[j][1]));
            mx1 = fmaxf(mx1, fmaxf(sacc[j][2], sacc[j][3]));
        }
        mx0 = fmaxf(mx0, __shfl_xor_sync(0xffffffffu, mx0, 1));
        mx0 = fmaxf(mx0, __shfl_xor_sync(0xffffffffu, mx0, 2));
        mx1 = fmaxf(mx1, __shfl_xor_sync(0xffffffffu, mx1, 1));
        mx1 = fmaxf(mx1, __shfl_xor_sync(0xffffffffu, mx1, 2));
        float m0n = fmaxf(rm0, mx0), m1n = fmaxf(rm1, mx1);
        float f0 = __expf(rm0 - m0n), f1 = __expf(rm1 - m1n);
        rm0 = m0n; rm1 = m1n;
        float sum0 = 0.f, sum1 = 0.f;
        #pragma unroll
        for (int j = 0; j < 8; ++j) {
            sacc[j][0] = __expf(sacc[j][0] - m0n); sum0 += sacc[j][0];
            sacc[j][1] = __expf(sacc[j][1] - m0n); sum0 += sacc[j][1];
            sacc[j][2] = __expf(sacc[j][2] - m1n); sum1 += sacc[j][2];
            sacc[j][3] = __expf(sacc[j][3] - m1n); sum1 += sacc[j][3];
        }
        sum0 += __shfl_xor_sync(0xffffffffu, sum0, 1);
        sum0 += __shfl_xor_sync(0xffffffffu, sum0, 2);
        sum1 += __shfl_xor_sync(0xffffffffu, sum1, 1);
        sum1 += __shfl_xor_sync(0xffffffffu, sum1, 2);
        rl0 = rl0 * f0 + sum0;
        rl1 = rl1 * f1 + sum1;
        float f02 = f0 * f0, f12 = f1 * f1;
        #pragma unroll
        for (int j = 0; j < 8; ++j) {
            accC[j][0] *= f0;  accC[j][1] *= f0;
            accC[j][2] *= f1;  accC[j][3] *= f1;
            accV[j][0] *= f02; accV[j][1] *= f02;
            accV[j][2] *= f12; accV[j][3] *= f12;
        }

        // ---- PV (fp16 2-term, P x256) and P^2 Vv (fp16 hi-only, P^2 x1024) ----
        #pragma unroll
        for (int tt = 0; tt < 4; ++tt) {
            float ps[8], q8[8];
            #pragma unroll
            for (int e = 0; e < 4; ++e) {
                float p0 = sacc[2 * tt][e], p1 = sacc[2 * tt + 1][e];
                ps[e]     = p0 * 256.f;
                ps[4 + e] = p1 * 256.f;
                q8[e]     = p0 * p0 * 1024.f;
                q8[4 + e] = p1 * p1 * 1024.f;
            }
            uint32_t phi[4], plo[4], p2h[4];
            frag_split_h(ps, phi, plo);
            #pragma unroll
            for (int e = 0; e < 4; ++e) {
                __half2 a = __floats2half2_rn(q8[2 * e], q8[2 * e + 1]);
                p2h[e] = *(uint32_t*)&a;
            }

            const uint32_t rowOff = (uint32_t)((tt * 16 + l15) * 128 + lHi);
            uint32_t vb[16];
            #pragma unroll
            for (int w = 0; w < 4; ++w) ldsm4t(vb + 4 * w, vB + SWZ(rowOff + w * 32));
            #pragma unroll
            for (int j = 0; j < 8; ++j) {
                uint32_t* B = &vb[(j >> 1) * 4 + (j & 1) * 2];
                mma16816h(accC[j], phi, B);
                mma16816h(accC[j], plo, B);
            }
            #pragma unroll
            for (int w = 0; w < 4; ++w) ldsm4t(vb + 4 * w, vvB + SWZ(rowOff + w * 32));
            #pragma unroll
            for (int j = 0; j < 8; ++j)
                mma16816h(accV[j], p2h, &vb[(j >> 1) * 4 + (j & 1) * 2]);
        }
    }

    // ---- epilogue: write a3c (bf16x3), hC2 (fp16 ctx^2), var (fp32) ----
    const float i0 = 1.f / (256.f * rl0), i1 = 1.f / (256.f * rl1);
    const float w0 = 1.f / (1024.f * rl0 * rl0), w1 = 1.f / (1024.f * rl1 * rl1);
    const int row0 = qb + wid * 16 + rr;
    #pragma unroll
    for (int j = 0; j < 8; ++j) {
        int off = j * 8 + cpair;
        int col = hh * 64 + off;
        float cv[2][2] = {{accC[j][0] * i0, accC[j][1] * i0},
                          {accC[j][2] * i1, accC[j][3] * i1}};
        float uv[2][2] = {{accV[j][0] * w0, accV[j][1] * w0},
                          {accV[j][2] * w1, accV[j][3] * w1}};
        #pragma unroll
        for (int rr2 = 0; rr2 < 2; ++rr2) {
            size_t bn = (size_t)b * NSEQ + row0 + rr2 * 8;
            float c0 = cv[rr2][0], c1 = cv[rr2][1];
            float h0 = bfr(c0), h1 = bfr(c1);
            uint32_t hp = pack2(h0, h1);
            uint32_t lp = pack2(c0 - h0, c1 - h1);
            __nv_bfloat16* dst = a3c + bn * K3 + col;
            *(uint32_t*)dst          = hp;
            *(uint32_t*)(dst + 1024) = lp;
            *(uint32_t*)(dst + 2048) = hp;
            __half2 hc = __floats2half2_rn(c0 * c0, c1 * c1);
            *(uint32_t*)(hC2 + bn * DM + col) = *(uint32_t*)&hc;
            *(float2*)(var + bn * DM + col) = make_float2(uv[rr2][0], uv[rr2][1]);
        }
    }
}

// ---------------------------------------------------------------------------
// Launcher
// ---------------------------------------------------------------------------
extern "C" void kernel_launch(void* const* d_in, const int* in_sizes, int n_in,
                              void* d_out, int out_size) {
    const float* H      = (const float*)d_in[0];
    const float* xr     = (const float*)d_in[1];
    const float* Wq     = (const float*)d_in[2];
    const float* bq     = (const float*)d_in[4];
    const float* Wk     = (const float*)d_in[6];
    const float* bk     = (const float*)d_in[8];
    const float* Wv     = (const float*)d_in[10];
    const float* Wv_rho = (const float*)d_in[11];
    const float* bv     = (const float*)d_in[12];
    const float* bv_rho = (const float*)d_in[13];
    const float* Wo     = (const float*)d_in[14];
    const float* Wo_rho = (const float*)d_in[15];
    const float* bo     = (const float*)d_in[16];
    const float* bo_rho = (const float*)d_in[17];
    const float* lsf    = (const float*)d_in[18];
    const float* lll    = (const float*)d_in[19];

    float *var, *d2, *bvs2, *bos2;
    __nv_bfloat16 *a3h, *a3c, *b3q, *b3k, *b3v, *b3o, *q3p, *k3p;
    __half *hA2, *hC2, *hVs, *hOs, *v2hp, *vv2hp;
    cudaGetSymbolAddress((void**)&var,  g_var);
    cudaGetSymbolAddress((void**)&d2,   g_d2);
    cudaGetSymbolAddress((void**)&bvs2, g_bvs2);
    cudaGetSymbolAddress((void**)&bos2, g_bos2);
    cudaGetSymbolAddress((void**)&a3h,  g_A3H);
    cudaGetSymbolAddress((void**)&a3c,  g_A3ctx);
    cudaGetSymbolAddress((void**)&b3q,  g_B3q);
    cudaGetSymbolAddress((void**)&b3k,  g_B3k);
    cudaGetSymbolAddress((void**)&b3v,  g_B3v);
    cudaGetSymbolAddress((void**)&b3o,  g_B3o);
    cudaGetSymbolAddress((void**)&hA2,  g_hA_H2);
    cudaGetSymbolAddress((void**)&hC2,  g_hC2);
    cudaGetSymbolAddress((void**)&hVs,  g_hB_vs2);
    cudaGetSymbolAddress((void**)&hOs,  g_hB_os2);
    cudaGetSymbolAddress((void**)&q3p,  g_q3);
    cudaGetSymbolAddress((void**)&k3p,  g_k3);
    cudaGetSymbolAddress((void**)&v2hp, g_v2h);
    cudaGetSymbolAddress((void**)&vv2hp, g_vv2h);

    cudaFuncSetAttribute(gemm_proj, cudaFuncAttributeMaxDynamicSharedMemorySize, SMEM_GEMM);
    cudaFuncSetAttribute(gemm_out,  cudaFuncAttributeMaxDynamicSharedMemorySize, SMEM_GEMM);
    cudaFuncSetAttribute(attn_tc,   cudaFuncAttributeMaxDynamicSharedMemorySize, ATTN_SMEM);

    // [0] both bias softplus^2
    bias2_kernel<<<8, 256>>>(bv_rho, bo_rho, bvs2, bos2);
    // [1] bf16x3 A-split of H, [2] fp16 H^2
    splitA_kernel<<<BN, 256>>>(H, a3h);
    f16sq_kernel<<<BN, 256>>>(H, hA2);
    // [3] all 4 weight bf16x3 splits, [4] both fp16 rho converts
    wsplit4_kernel<<<dim3(DM, 4), 256>>>(Wq, Wk, Wv, Wo, b3q, b3k, b3v, b3o);
    f16w2_kernel<<<dim3(DM, 2), 256>>>(Wv_rho, Wo_rho, hVs, hOs);
    // [5] fused projection GEMM: Q/K/V (bf16x3) + Vv (fp16) -> head-major
    gemm_proj<<<dim3(DM / BNT, BN / BM, 4), 256, SMEM_GEMM>>>(
        a3h, b3q, b3k, b3v, hA2, hVs, bq, bk, bv, bvs2, q3p, k3p, v2hp, vv2hp);
    // [6] pairwise squared distances
    dist2_kernel<<<dim3(16, 16, BATCH), 256>>>(xr, d2);
    // [7] attention -> a3c / hC2 / var directly
    attn_tc<<<dim3(NSEQ / QB, BATCH * NH), 256, ATTN_SMEM>>>(
        q3p, k3p, v2hp, vv2hp, d2, lsf, lll, a3c, hC2, var);
    // [8] fused output GEMM: out_mean (bf16x3) + out_var (fp16 + var add)
    float* out_mean = (float*)d_out;
    float* out_var  = out_mean + (size_t)BN * DM;
    gemm_out<<<dim3(DM / BNT, BN / BM, 2), 256, SMEM_GEMM>>>(
        a3c, b3o, bo, hC2, hOs, bos2, var, out_mean, out_var);
}

// round 10
// speedup vs baseline: 3.3007x; 1.0443x over previous
#include <cuda_runtime.h>
#include <cuda_bf16.h>
#include <cuda_fp16.h>
#include <math.h>
#include <stdint.h>

#define DM    1024
#define BATCH 8
#define NSEQ  1024
#define BN    (BATCH * NSEQ)
#define NH    16
#define DK    64
#define QSCALE 0.125f

#define K3      3072
#define BK      64
#define KITERS  (K3 / BK)         // 48
#define KH      1024
#define KITERS_H (KH / BK)        // 16
#define BM      128
#define BNT     128
#define STAGES  3
#define STAGE_BYTES ((BM + BNT) * 128)
#define SMEM_GEMM (STAGES * STAGE_BYTES)        // 96 KB

// attention tiling / smem (KT=128 keys per softmax round)
#define QB 128
#define KT 128
#define SM_Q   0                  // 3 x 128 x 128B = 49152
#define SM_K   49152              // 2 bufs x 3 chunks x 128 x 128B = 98304
#define SM_V   147456             // 2 bufs x 128 x 128B = 32768
#define SM_VV  180224             // 32768
#define ATTN_SMEM 212992

// ---------------------------------------------------------------------------
// Scratch
// ---------------------------------------------------------------------------
__device__ float g_var [BN * DM];
__device__ float g_d2  [BATCH * NSEQ * NSEQ];
__device__ float g_bvs2[DM];
__device__ float g_bos2[DM];

__device__ __nv_bfloat16 g_A3H  [BN * K3];
__device__ __nv_bfloat16 g_A3ctx[BN * K3];
__device__ __nv_bfloat16 g_B3q  [DM * K3];
__device__ __nv_bfloat16 g_B3k  [DM * K3];
__device__ __nv_bfloat16 g_B3v  [DM * K3];
__device__ __nv_bfloat16 g_B3o  [DM * K3];

__device__ __half g_hA_H2  [BN * DM];
__device__ __half g_hC2    [BN * DM];
__device__ __half g_hB_vs2 [DM * DM];
__device__ __half g_hB_os2 [DM * DM];

__device__ __nv_bfloat16 g_q3 [BATCH * NH * NSEQ * 192];
__device__ __nv_bfloat16 g_k3 [BATCH * NH * NSEQ * 192];
__device__ __half        g_v2h [BATCH * NH * NSEQ * 64];
__device__ __half        g_vv2h[BATCH * NH * NSEQ * 64];

// ---------------------------------------------------------------------------
// PTX helpers
// ---------------------------------------------------------------------------
__device__ __forceinline__ uint32_t smem_u32(const void* p) {
    uint32_t a;
    asm("{ .reg .u64 t; cvta.to.shared.u64 t, %1; cvt.u32.u64 %0, t; }"
        : "=r"(a) : "l"(p));
    return a;
}
#define SWZ(off) ((off) ^ (((off) >> 3) & 0x70))

__device__ __forceinline__ void cp16(uint32_t dst, const void* src) {
    asm volatile("cp.async.cg.shared.global [%0], [%1], 16;"
                 :: "r"(dst), "l"(src) : "memory");
}
#define CP_COMMIT() asm volatile("cp.async.commit_group;" ::: "memory")

__device__ __forceinline__ void ldsm4(uint32_t* r, uint32_t addr) {
    asm volatile("ldmatrix.sync.aligned.m8n8.x4.shared.b16 {%0,%1,%2,%3}, [%4];"
                 : "=r"(r[0]), "=r"(r[1]), "=r"(r[2]), "=r"(r[3]) : "r"(addr));
}
__device__ __forceinline__ void ldsm4t(uint32_t* r, uint32_t addr) {
    asm volatile("ldmatrix.sync.aligned.m8n8.x4.trans.shared.b16 {%0,%1,%2,%3}, [%4];"
                 : "=r"(r[0]), "=r"(r[1]), "=r"(r[2]), "=r"(r[3]) : "r"(addr));
}
__device__ __forceinline__ void mma16816(float* c, const uint32_t* a, const uint32_t* b) {
    asm volatile("mma.sync.aligned.m16n8k16.row.col.f32.bf16.bf16.f32 "
                 "{%0,%1,%2,%3}, {%4,%5,%6,%7}, {%8,%9}, {%0,%1,%2,%3};"
                 : "+f"(c[0]), "+f"(c[1]), "+f"(c[2]), "+f"(c[3])
                 : "r"(a[0]), "r"(a[1]), "r"(a[2]), "r"(a[3]), "r"(b[0]), "r"(b[1]));
}
__device__ __forceinline__ void mma16816h(float* c, const uint32_t* a, const uint32_t* b) {
    asm volatile("mma.sync.aligned.m16n8k16.row.col.f32.f16.f16.f32 "
                 "{%0,%1,%2,%3}, {%4,%5,%6,%7}, {%8,%9}, {%0,%1,%2,%3};"
                 : "+f"(c[0]), "+f"(c[1]), "+f"(c[2]), "+f"(c[3])
                 : "r"(a[0]), "r"(a[1]), "r"(a[2]), "r"(a[3]), "r"(b[0]), "r"(b[1]));
}
__device__ __forceinline__ uint32_t pack2(float lo, float hi) {
    uint32_t d;
    asm("cvt.rn.bf16x2.f32 %0, %1, %2;" : "=r"(d) : "f"(hi), "f"(lo));
    return d;
}
__device__ __forceinline__ float bfr(float v) {
    return __bfloat162float(__float2bfloat16_rn(v));
}

// ---------------------------------------------------------------------------
// elementwise prep kernels
// ---------------------------------------------------------------------------
__global__ void bias2_kernel(const float* __restrict__ a, const float* __restrict__ b,
                             float* __restrict__ oa, float* __restrict__ ob) {
    int i = blockIdx.x * 256 + threadIdx.x;
    const float* in  = (i < DM) ? a  : b;
    float*       out = (i < DM) ? oa : ob;
    int j = i & (DM - 1);
    float x  = in[j];
    float sp = (x > 15.f) ? x : log1pf(__expf(x));
    out[j] = sp * sp;
}

// fused: bf16x3 A-split of H ([hi|lo|hi]) + fp16 H^2 (one read of H)
__global__ void splitAsq_kernel(const float* __restrict__ X,
                                __nv_bfloat16* __restrict__ Y, __half* __restrict__ Y2) {
    int r  = blockIdx.x;
    int c4 = threadIdx.x;
    float4 x = *(const float4*)(X + (size_t)r * DM + c4 * 4);
    float v[4] = {x.x, x.y, x.z, x.w};
    unsigned short hu[4], lu[4];
    #pragma unroll
    for (int i = 0; i < 4; ++i) {
        __nv_bfloat16 hb = __float2bfloat16_rn(v[i]);
        float hr = __bfloat162float(hb);
        __nv_bfloat16 lb = __float2bfloat16_rn(v[i] - hr);
        hu[i] = __bfloat16_as_ushort(hb);
        lu[i] = __bfloat16_as_ushort(lb);
    }
    uint2 hp, lp;
    hp.x = (uint32_t)hu[0] | ((uint32_t)hu[1] << 16);
    hp.y = (uint32_t)hu[2] | ((uint32_t)hu[3] << 16);
    lp.x = (uint32_t)lu[0] | ((uint32_t)lu[1] << 16);
    lp.y = (uint32_t)lu[2] | ((uint32_t)lu[3] << 16);
    size_t ob = (size_t)r * K3 + c4 * 4;
    *(uint2*)(Y + ob)          = hp;
    *(uint2*)(Y + ob + DM)     = lp;
    *(uint2*)(Y + ob + 2 * DM) = hp;
    __half2 h0 = __floats2half2_rn(v[0] * v[0], v[1] * v[1]);
    __half2 h1 = __floats2half2_rn(v[2] * v[2], v[3] * v[3]);
    uint2 p;
    p.x = *(uint32_t*)&h0;
    p.y = *(uint32_t*)&h1;
    *(uint2*)(Y2 + (size_t)r * DM + c4 * 4) = p;
}

// bf16x3 B-split of 4 weight matrices ([hi|hi|lo]); grid (DM, 4)
__global__ void wsplit4_kernel(const float* __restrict__ W0, const float* __restrict__ W1,
                               const float* __restrict__ W2, const float* __restrict__ W3,
                               __nv_bfloat16* __restrict__ Y0, __nv_bfloat16* __restrict__ Y1,
                               __nv_bfloat16* __restrict__ Y2, __nv_bfloat16* __restrict__ Y3) {
    int z = blockIdx.y;
    const float* X = (z == 0) ? W0 : (z == 1) ? W1 : (z == 2) ? W2 : W3;
    __nv_bfloat16* Y = (z == 0) ? Y0 : (z == 1) ? Y1 : (z == 2) ? Y2 : Y3;
    int r  = blockIdx.x;
    int c4 = threadIdx.x;
    float4 x = *(const float4*)(X + (size_t)r * DM + c4 * 4);
    float v[4] = {x.x, x.y, x.z, x.w};
    unsigned short hu[4], lu[4];
    #pragma unroll
    for (int i = 0; i < 4; ++i) {
        __nv_bfloat16 hb = __float2bfloat16_rn(v[i]);
        float hr = __bfloat162float(hb);
        __nv_bfloat16 lb = __float2bfloat16_rn(v[i] - hr);
        hu[i] = __bfloat16_as_ushort(hb);
        lu[i] = __bfloat16_as_ushort(lb);
    }
    uint2 hp, lp;
    hp.x = (uint32_t)hu[0] | ((uint32_t)hu[1] << 16);
    hp.y = (uint32_t)hu[2] | ((uint32_t)hu[3] << 16);
    lp.x = (uint32_t)lu[0] | ((uint32_t)lu[1] << 16);
    lp.y = (uint32_t)lu[2] | ((uint32_t)lu[3] << 16);
    size_t ob = (size_t)r * K3 + c4 * 4;
    *(uint2*)(Y + ob)          = hp;
    *(uint2*)(Y + ob + DM)     = hp;
    *(uint2*)(Y + ob + 2 * DM) = lp;
}

// fp16 softplus^2 convert of both rho weights; grid (DM, 2)
__global__ void f16w2_kernel(const float* __restrict__ W0, const float* __restrict__ W1,
                             __half* __restrict__ Y0, __half* __restrict__ Y1) {
    int z = blockIdx.y;
    const float* X = (z == 0) ? W0 : W1;
    __half* Y      = (z == 0) ? Y0 : Y1;
    int row = blockIdx.x;
    int c4  = threadIdx.x;
    float4 x = *(const float4*)(X + (size_t)row * DM + c4 * 4);
    float v[4] = {x.x, x.y, x.z, x.w};
    #pragma unroll
    for (int i = 0; i < 4; ++i) {
        float sp = (v[i] > 15.f) ? v[i] : log1pf(__expf(v[i]));
        v[i] = sp * sp;
    }
    __half2 h0 = __floats2half2_rn(v[0], v[1]);
    __half2 h1 = __floats2half2_rn(v[2], v[3]);
    uint2 p;
    p.x = *(uint32_t*)&h0;
    p.y = *(uint32_t*)&h1;
    *(uint2*)(Y + (size_t)row * DM + c4 * 4) = p;
}

// ---------------------------------------------------------------------------
// GEMM mainloops (device functions)
// ---------------------------------------------------------------------------
__device__ __forceinline__ void gemm_main_bf16(
    const __nv_bfloat16* __restrict__ A3, const __nv_bfloat16* __restrict__ B3,
    char* smem, int mBase, int nBase, float acc[4][4][4]) {
    const uint32_t sb = smem_u32(smem);
    const int t    = threadIdx.x;
    const int wid  = t >> 5;
    const int lane = t & 31;
    const int wm   = wid & 1;
    const int wn   = wid >> 1;

    const int r  = t >> 1;
    const int uc = (t & 1) * 4;
    const __nv_bfloat16* aRow = A3 + (size_t)(mBase + r) * K3 + uc * 8;
    const __nv_bfloat16* bRow = B3 + (size_t)(nBase + r) * K3 + uc * 8;

    auto load_stage = [&](int buf, int c) {
        uint32_t sA = sb + buf * STAGE_BYTES;
        uint32_t sB = sA + BM * 128;
        const __nv_bfloat16* ga = aRow + c * BK;
        const __nv_bfloat16* gb = bRow + c * BK;
        #pragma unroll
        for (int i = 0; i < 4; ++i) {
            uint32_t bo = r * 128 + (uc + i) * 16;
            cp16(sA + SWZ(bo), ga + i * 8);
            cp16(sB + SWZ(bo), gb + i * 8);
        }
        CP_COMMIT();
    };

    const int aRowSel = (lane & 7) | (((lane >> 3) & 1) << 3);
    const int aKSel   = (lane >> 4) << 4;
    const int bNSel   = (lane & 7) | ((lane >> 4) << 3);
    const int bKSel   = ((lane >> 3) & 1) << 4;

    load_stage(0, 0);
    load_stage(1, 1);

    for (int kt = 0; kt < KITERS; ++kt) {
        const int buf = kt % STAGES;
        if (kt == KITERS - 1) asm volatile("cp.async.wait_group 0;" ::: "memory");
        else                  asm volatile("cp.async.wait_group 1;" ::: "memory");
        __syncthreads();

        if (kt + 2 < KITERS) load_stage((kt + 2) % STAGES, kt + 2);

        uint32_t sA = sb + buf * STAGE_BYTES;
        uint32_t sB = sA + BM * 128;
        #pragma unroll
        for (int ks = 0; ks < 4; ++ks) {
            uint32_t af[4][4], bfr2[2][4];
            #pragma unroll
            for (int mi = 0; mi < 4; ++mi) {
                uint32_t bo = (uint32_t)((wm * 64 + mi * 16 + aRowSel) * 128
                                         + ks * 32 + aKSel);
                ldsm4(af[mi], sA + SWZ(bo));
            }
            #pragma unroll
            for (int pi = 0; pi < 2; ++pi) {
                uint32_t bo = (uint32_t)((wn * 32 + pi * 16 + bNSel) * 128
                                         + ks * 32 + bKSel);
                ldsm4(bfr2[pi], sB + SWZ(bo));
            }
            #pragma unroll
            for (int mi = 0; mi < 4; ++mi)
                #pragma unroll
                for (int ni = 0; ni < 4; ++ni)
                    mma16816(acc[mi][ni], af[mi], &bfr2[ni >> 1][(ni & 1) * 2]);
        }
        __syncthreads();
    }
}

__device__ __forceinline__ void gemm_main_h(
    const __half* __restrict__ A, const __half* __restrict__ B,
    char* smem, int mBase, int nBase, float acc[4][4][4]) {
    const uint32_t sb = smem_u32(smem);
    const int t    = threadIdx.x;
    const int wid  = t >> 5;
    const int lane = t & 31;
    const int wm   = wid & 1;
    const int wn   = wid >> 1;

    const int r  = t >> 1;
    const int uc = (t & 1) * 4;
    const __half* aRow = A + (size_t)(mBase + r) * KH + uc * 8;
    const __half* bRow = B + (size_t)(nBase + r) * KH + uc * 8;

    auto load_stage = [&](int buf, int c) {
        uint32_t sA = sb + buf * STAGE_BYTES;
        uint32_t sB = sA + BM * 128;
        const __half* ga = aRow + c * BK;
        const __half* gb = bRow + c * BK;
        #pragma unroll
        for (int i = 0; i < 4; ++i) {
            uint32_t bo = r * 128 + (uc + i) * 16;
            cp16(sA + SWZ(bo), ga + i * 8);
            cp16(sB + SWZ(bo), gb + i * 8);
        }
        CP_COMMIT();
    };

    const int aRowSel = (lane & 7) | (((lane >> 3) & 1) << 3);
    const int aKSel   = (lane >> 4) << 4;
    const int bNSel   = (lane & 7) | ((lane >> 4) << 3);
    const int bKSel   = ((lane >> 3) & 1) << 4;

    load_stage(0, 0);
    load_stage(1, 1);

    for (int kt = 0; kt < KITERS_H; ++kt) {
        const int buf = kt % STAGES;
        if (kt == KITERS_H - 1) asm volatile("cp.async.wait_group 0;" ::: "memory");
        else                    asm volatile("cp.async.wait_group 1;" ::: "memory");
        __syncthreads();

        if (kt + 2 < KITERS_H) load_stage((kt + 2) % STAGES, kt + 2);

        uint32_t sA = sb + buf * STAGE_BYTES;
        uint32_t sB = sA + BM * 128;
        #pragma unroll
        for (int ks = 0; ks < 4; ++ks) {
            uint32_t af[4][4], bfr2[2][4];
            #pragma unroll
            for (int mi = 0; mi < 4; ++mi) {
                uint32_t bo = (uint32_t)((wm * 64 + mi * 16 + aRowSel) * 128
                                         + ks * 32 + aKSel);
                ldsm4(af[mi], sA + SWZ(bo));
            }
            #pragma unroll
            for (int pi = 0; pi < 2; ++pi) {
                uint32_t bo = (uint32_t)((wn * 32 + pi * 16 + bNSel) * 128
                                         + ks * 32 + bKSel);
                ldsm4(bfr2[pi], sB + SWZ(bo));
            }
            #pragma unroll
            for (int mi = 0; mi < 4; ++mi)
                #pragma unroll
                for (int ni = 0; ni < 4; ++ni)
                    mma16816h(acc[mi][ni], af[mi], &bfr2[ni >> 1][(ni & 1) * 2]);
        }
        __syncthreads();
    }
}

// ---------------------------------------------------------------------------
// fused projection GEMM: z=0/1/2 -> Q/K/V (bf16x3), z=3 -> V-variance (fp16).
// ---------------------------------------------------------------------------
__global__ void __launch_bounds__(256, 2)
gemm_proj(const __nv_bfloat16* __restrict__ A3,
          const __nv_bfloat16* __restrict__ B3q, const __nv_bfloat16* __restrict__ B3k,
          const __nv_bfloat16* __restrict__ B3v,
          const __half* __restrict__ hA2, const __half* __restrict__ hVs,
          const float* __restrict__ bq, const float* __restrict__ bk,
          const float* __restrict__ bv, const float* __restrict__ bvs2,
          __nv_bfloat16* __restrict__ q3, __nv_bfloat16* __restrict__ k3,
          __half* __restrict__ v2h, __half* __restrict__ vv2h) {
    extern __shared__ __align__(1024) char smem[];
    const int z = blockIdx.z;
    const int mBase = blockIdx.y * BM;
    const int nBase = blockIdx.x * BNT;
    float acc[4][4][4] = {};

    if (z < 3) {
        const __nv_bfloat16* B3 = (z == 0) ? B3q : (z == 1) ? B3k : B3v;
        gemm_main_bf16(A3, B3, smem, mBase, nBase, acc);
    } else {
        gemm_main_h(hA2, hVs, smem, mBase, nBase, acc);
    }

    const float* bias = (z == 0) ? bq : (z == 1) ? bk : (z == 2) ? bv : bvs2;
    const int wid  = threadIdx.x >> 5;
    const int lane = threadIdx.x & 31;
    const int lr = lane >> 2;
    const int lc = (lane & 3) * 2;
    const int rB = mBase + (wid & 1) * 64;
    const int cB = nBase + (wid >> 1) * 32;
    #pragma unroll
    for (int mi = 0; mi < 4; ++mi) {
        #pragma unroll
        for (int ni = 0; ni < 4; ++ni) {
            int col  = cB + ni * 8 + lc;
            int row0 = rB + mi * 16 + lr;
            int h = col >> 6, dl = col & 63;
            float2 bi = *(const float2*)(bias + col);
            float vx[2][2] = {{acc[mi][ni][0] + bi.x, acc[mi][ni][1] + bi.y},
                              {acc[mi][ni][2] + bi.x, acc[mi][ni][3] + bi.y}};
            #pragma unroll
            for (int rr2 = 0; rr2 < 2; ++rr2) {
                int row = row0 + rr2 * 8;
                int b = row >> 10, n = row & 1023;
                if (z >= 2) {
                    __half* dst = (z == 2) ? v2h : vv2h;
                    __half2 hv = __floats2half2_rn(vx[rr2][0], vx[rr2][1]);
                    *(uint32_t*)(dst + ((size_t)(b * NH + h) * NSEQ + n) * 64 + dl)
                        = *(uint32_t*)&hv;
                } else {
                    float h0 = bfr(vx[rr2][0]), h1 = bfr(vx[rr2][1]);
                    uint32_t hp = pack2(h0, h1);
                    uint32_t lp = pack2(vx[rr2][0] - h0, vx[rr2][1] - h1);
                    __nv_bfloat16* dst = ((z == 0) ? q3 : k3)
                        + ((size_t)(b * NH + h) * NSEQ + n) * 192 + dl;
                    *(uint32_t*)dst = hp;
                    if (z == 0) {
                        *(uint32_t*)(dst + 64)  = lp;
                        *(uint32_t*)(dst + 128) = hp;
                    } else {
                        *(uint32_t*)(dst + 64)  = hp;
                        *(uint32_t*)(dst + 128) = lp;
                    }
                }
            }
        }
    }
}

// ---------------------------------------------------------------------------
// fused output GEMM: z=0 -> out_mean (bf16x3), z=1 -> out_var (fp16 + add).
// ---------------------------------------------------------------------------
__global__ void __launch_bounds__(256, 2)
gemm_out(const __nv_bfloat16* __restrict__ a3c, const __nv_bfloat16* __restrict__ b3o,
         const float* __restrict__ bo,
         const __half* __restrict__ hC2, const __half* __restrict__ hOs,
         const float* __restrict__ bos2, const float* __restrict__ var,
         float* __restrict__ out_mean, float* __restrict__ out_var) {
    extern __shared__ __align__(1024) char smem[];
    const int z = blockIdx.z;
    const int mBase = blockIdx.y * BM;
    const int nBase = blockIdx.x * BNT;
    float acc[4][4][4] = {};

    if (z == 0) gemm_main_bf16(a3c, b3o, smem, mBase, nBase, acc);
    else        gemm_main_h(hC2, hOs, smem, mBase, nBase, acc);

    const float* bias = (z == 0) ? bo : bos2;
    float* C          = (z == 0) ? out_mean : out_var;
    const int wid  = threadIdx.x >> 5;
    const int lane = threadIdx.x & 31;
    const int lr = lane >> 2;
    const int lc = (lane & 3) * 2;
    const int rB = mBase + (wid & 1) * 64;
    const int cB = nBase + (wid >> 1) * 32;
    #pragma unroll
    for (int mi = 0; mi < 4; ++mi) {
        #pragma unroll
        for (int ni = 0; ni < 4; ++ni) {
            int col  = cB + ni * 8 + lc;
            int row0 = rB + mi * 16 + lr;
            float2 bi = *(const float2*)(bias + col);
            float vx[2][2] = {{acc[mi][ni][0] + bi.x, acc[mi][ni][1] + bi.y},
                              {acc[mi][ni][2] + bi.x, acc[mi][ni][3] + bi.y}};
            #pragma unroll
            for (int rr2 = 0; rr2 < 2; ++rr2) {
                size_t o = (size_t)(row0 + rr2 * 8) * DM + col;
                if (z == 1) {
                    float2 a2 = *(const float2*)(var + o);
                    vx[rr2][0] += a2.x; vx[rr2][1] += a2.y;
                }
                *(float2*)(C + o) = make_float2(vx[rr2][0], vx[rr2][1]);
            }
        }
    }
}

// ---------------------------------------------------------------------------
// dist2 (unchanged)
// ---------------------------------------------------------------------------
__global__ void dist2_kernel(const float* __restrict__ xr, float* __restrict__ d2) {
    __shared__ float xm[64][17];
    __shared__ float xn[64][17];
    __shared__ float x2m[64];
    __shared__ float x2n[64];

    const int t  = threadIdx.x;
    const int b  = blockIdx.z;
    const int mi = blockIdx.y * 64;
    const int nj = blockIdx.x * 64;

    for (int idx = t; idx < 64 * 4; idx += 256) {
        int r = idx >> 2, c = (idx & 3) * 4;
        float4 a = *(const float4*)(xr + ((size_t)b * NSEQ + mi + r) * 16 + c);
        xm[r][c] = a.x; xm[r][c+1] = a.y; xm[r][c+2] = a.z; xm[r][c+3] = a.w;
        float4 bb = *(const float4*)(xr + ((size_t)b * NSEQ + nj + r) * 16 + c);
        xn[r][c] = bb.x; xn[r][c+1] = bb.y; xn[r][c+2] = bb.z; xn[r][c+3] = bb.w;
    }
    __syncthreads();

    if (t < 64) {
        float s = 0.f;
        #pragma unroll
        for (int c = 0; c < 16; ++c) s += xm[t][c] * xm[t][c];
        x2m[t] = s;
    } else if (t < 128) {
        int r = t - 64;
        float s = 0.f;
        #pragma unroll
        for (int c = 0; c < 16; ++c) s += xn[r][c] * xn[r][c];
        x2n[r] = s;
    }
    __syncthreads();

    const int tx = t & 15, ty = t >> 4;
    #pragma unroll
    for (int i = 0; i < 4; ++i) {
        int row = ty * 4 + i;
        float out4[4];
        #pragma unroll
        for (int j = 0; j < 4; ++j) {
            int col = tx * 4 + j;
            float dot = 0.f;
            #pragma unroll
            for (int c = 0; c < 16; ++c) dot += xm[row][c] * xn[col][c];
            out4[j] = fmaxf(x2m[row] + x2n[col] - 2.f * dot, 0.f);
        }
        float4 v4 = make_float4(out4[0], out4[1], out4[2], out4[3]);
        *(float4*)(d2 + ((size_t)b * NSEQ + mi + row) * NSEQ + nj + tx * 4) = v4;
    }
}

// ---------------------------------------------------------------------------
// Tensor-core flash attention, KT=128 keys per softmax round.
// S bf16x3; PV fp16 hi-only (P x256); P^2 Vv fp16 hi-only (P^2 x1024).
// Epilogue writes a3c (bf16x3), hC2 (fp16 ctx^2), var (fp32).
// ---------------------------------------------------------------------------
__global__ void __launch_bounds__(256, 1)
attn_tc(const __nv_bfloat16* __restrict__ q3, const __nv_bfloat16* __restrict__ k3,
        const __half* __restrict__ v2h, const __half* __restrict__ vv2h,
        const float* __restrict__ d2g,
        const float* __restrict__ lsf, const float* __restrict__ lll,
        __nv_bfloat16* __restrict__ a3c, __half* __restrict__ hC2,
        float* __restrict__ var) {
    extern __shared__ __align__(1024) char smem[];
    const uint32_t sb = smem_u32(smem);
    const int t    = threadIdx.x;
    const int wid  = t >> 5;
    const int lane = t & 31;
    const int qb   = blockIdx.x * QB;
    const int bh   = blockIdx.y;
    const int b    = bh >> 4, hh = bh & 15;

    const float sigma_f2 = __expf(2.f * lsf[hh]);
    const float coef     = 0.5f * __expf(-2.f * lll[hh]);

    const __nv_bfloat16* Qg  = q3   + ((size_t)bh * NSEQ + qb) * 192;
    const __nv_bfloat16* Kg  = k3   + (size_t)bh * NSEQ * 192;
    const __half* Vg  = v2h  + (size_t)bh * NSEQ * 64;
    const __half* VVg = vv2h + (size_t)bh * NSEQ * 64;

    for (int i = t; i < QB * 24; i += 256) {
        int row = i / 24, u = i % 24;
        cp16(sb + SM_Q + (u >> 3) * 16384 + SWZ((uint32_t)(row * 128 + (u & 7) * 16)),
             Qg + (size_t)row * 192 + u * 8);
    }

    auto load_kv = [&](int buf, int kt) {
        const __nv_bfloat16* kg = Kg + (size_t)kt * KT * 192;
        for (int i = t; i < KT * 24; i += 256) {
            int row = i / 24, u = i % 24;
            cp16(sb + SM_K + buf * 49152 + (u >> 3) * 16384
                    + SWZ((uint32_t)(row * 128 + (u & 7) * 16)),
                 kg + (size_t)row * 192 + u * 8);
        }
        const __half* vg = Vg  + (size_t)kt * KT * 64;
        const __half* wg = VVg + (size_t)kt * KT * 64;
        for (int i = t; i < KT * 8; i += 256) {
            int row = i >> 3, u = i & 7;
            uint32_t so = SWZ((uint32_t)(row * 128 + u * 16));
            cp16(sb + SM_V  + buf * 16384 + so, vg + (size_t)row * 64 + u * 8);
            cp16(sb + SM_VV + buf * 16384 + so, wg + (size_t)row * 64 + u * 8);
        }
        CP_COMMIT();
    };
    load_kv(0, 0);

    const int l15 = lane & 15;
    const int lHi = (lane >> 4) << 4;
    const uint32_t aRowOff = (uint32_t)((wid * 16 + l15) * 128 + lHi);
    const int g    = lane >> 3;
    const int keyl = ((g >> 1) << 3) + (lane & 7);
    const uint32_t kCol = (uint32_t)((g & 1) << 4);
    const int rr    = lane >> 2;
    const int cpair = (lane & 3) * 2;

    float accC[8][4] = {}, accV[8][4] = {};
    float rm0 = -1e30f, rm1 = -1e30f, rl0 = 0.f, rl1 = 0.f;

    for (int kt = 0; kt < NSEQ / KT; ++kt) {
        if (kt + 1 < NSEQ / KT) { __syncthreads(); load_kv((kt + 1) & 1, kt + 1); }
        if (kt + 1 < NSEQ / KT) asm volatile("cp.async.wait_group 1;" ::: "memory");
        else                    asm volatile("cp.async.wait_group 0;" ::: "memory");
        __syncthreads();

        const int buf = kt & 1;
        const uint32_t kB  = sb + SM_K  + buf * 49152;
        const uint32_t vB  = sb + SM_V  + buf * 16384;
        const uint32_t vvB = sb + SM_VV + buf * 16384;

        float sacc[16][4];
        #pragma unroll
        for (int j = 0; j < 16; ++j)
            #pragma unroll
            for (int e = 0; e < 4; ++e) sacc[j][e] = 0.f;

        #pragma unroll
        for (int ks = 0; ks < 12; ++ks) {
            uint32_t a[4];
            ldsm4(a, sb + SM_Q + (ks >> 2) * 16384 + SWZ(aRowOff + (ks & 3) * 32));
            #pragma unroll
            for (int n0 = 0; n0 < 8; ++n0) {
                uint32_t kb4[4];
                ldsm4(kb4, kB + (ks >> 2) * 16384
                         + SWZ((uint32_t)((n0 * 16 + keyl) * 128) + (ks & 3) * 32 + kCol));
                mma16816(sacc[2 * n0],     a, kb4);
                mma16816(sacc[2 * n0 + 1], a, kb4 + 2);
            }
        }

        const int kb0 = kt * KT;
        const float* d2r0 = d2g + (size_t)b * NSEQ * NSEQ
                          + (size_t)(qb + wid * 16 + rr) * NSEQ + kb0;
        const float* d2r1 = d2r0 + 8 * NSEQ;
        #pragma unroll
        for (int j = 0; j < 16; ++j) {
            float2 da = *(const float2*)(d2r0 + j * 8 + cpair);
            float2 db = *(const float2*)(d2r1 + j * 8 + cpair);
            sacc[j][0] = sacc[j][0] * QSCALE + sigma_f2 * __expf(-da.x * coef);
            sacc[j][1] = sacc[j][1] * QSCALE + sigma_f2 * __expf(-da.y * coef);
            sacc[j][2] = sacc[j][2] * QSCALE + sigma_f2 * __expf(-db.x * coef);
            sacc[j][3] = sacc[j][3] * QSCALE + sigma_f2 * __expf(-db.y * coef);
        }
        float mx0 = -1e30f, mx1 = -1e30f;
        #pragma unroll
        for (int j = 0; j < 16; ++j) {
            mx0 = fmaxf(mx0, fmaxf(sacc[j][0], sacc[j][1]));
            mx1 = fmaxf(mx1, fmaxf(sacc[j][2], sacc[j][3]));
        }
        mx0 = fmaxf(mx0, __shfl_xor_sync(0xffffffffu, mx0, 1));
        mx0 = fmaxf(mx0, __shfl_xor_sync(0xffffffffu, mx0, 2));
        mx1 = fmaxf(mx1, __shfl_xor_sync(0xffffffffu, mx1, 1));
        mx1 = fmaxf(mx1, __shfl_xor_sync(0xffffffffu, mx1, 2));
        float m0n = fmaxf(rm0, mx0), m1n = fmaxf(rm1, mx1);
        float f0 = __expf(rm0 - m0n), f1 = __expf(rm1 - m1n);
        rm0 = m0n; rm1 = m1n;
        float sum0 = 0.f, sum1 = 0.f;
        #pragma unroll
        for (int j = 0; j < 16; ++j) {
            sacc[j][0] = __expf(sacc[j][0] - m0n); sum0 += sacc[j][0];
            sacc[j][1] = __expf(sacc[j][1] - m0n); sum0 += sacc[j][1];
            sacc[j][2] = __expf(sacc[j][2] - m1n); sum1 += sacc[j][2];
            sacc[j][3] = __expf(sacc[j][3] - m1n); sum1 += sacc[j][3];
        }
        sum0 += __shfl_xor_sync(0xffffffffu, sum0, 1);
        sum0 += __shfl_xor_sync(0xffffffffu, sum0, 2);
        sum1 += __shfl_xor_sync(0xffffffffu, sum1, 1);
        sum1 += __shfl_xor_sync(0xffffffffu, sum1, 2);
        rl0 = rl0 * f0 + sum0;
        rl1 = rl1 * f1 + sum1;
        float f02 = f0 * f0, f12 = f1 * f1;
        #pragma unroll
        for (int j = 0; j < 8; ++j) {
            accC[j][0] *= f0;  accC[j][1] *= f0;
            accC[j][2] *= f1;  accC[j][3] *= f1;
            accV[j][0] *= f02; accV[j][1] *= f02;
            accV[j][2] *= f12; accV[j][3] *= f12;
        }

        // ---- PV and P^2 Vv: fp16 hi-only (P x256, P^2 x1024) ----
        #pragma unroll
        for (int tt = 0; tt < 8; ++tt) {
            uint32_t phi[4], p2h[4];
            #pragma unroll
            for (int e = 0; e < 4; ++e) {
                float p0 = sacc[2 * tt][e], p1 = sacc[2 * tt + 1][e];
                float2 pe = make_float2(p0 * 256.f, p1 * 256.f);
                float2 qe = make_float2(p0 * p0 * 1024.f, p1 * p1 * 1024.f);
                // fragment element pairs: (e<2 ? rows rr/rr+8 k-lo : k-hi)
                // pack per original order: elements [e] and [4+e] of the 8-vector
                // map to half2 lanes of phi[e]: (sacc[2tt][e], sacc[2tt+1][e])
                __half2 ph = __floats2half2_rn(pe.x, pe.y);
                __half2 qh = __floats2half2_rn(qe.x, qe.y);
                phi[e] = *(uint32_t*)&ph;
                p2h[e] = *(uint32_t*)&qh;
            }
            // NOTE: A-fragment needs pairs (p8[0],p8[1]) etc. Rebuild properly:
            {
                float p8[8], q8[8];
                #pragma unroll
                for (int e = 0; e < 4; ++e) {
                    float p0 = sacc[2 * tt][e], p1 = sacc[2 * tt + 1][e];
                    p8[e]     = p0 * 256.f;
                    p8[4 + e] = p1 * 256.f;
                    q8[e]     = p0 * p0 * 1024.f;
                    q8[4 + e] = p1 * p1 * 1024.f;
                }
                #pragma unroll
                for (int e = 0; e < 4; ++e) {
                    __half2 a = __floats2half2_rn(p8[2 * e], p8[2 * e + 1]);
                    __half2 c = __floats2half2_rn(q8[2 * e], q8[2 * e + 1]);
                    phi[e] = *(uint32_t*)&a;
                    p2h[e] = *(uint32_t*)&c;
                }
            }

            const uint32_t rowOff = (uint32_t)((tt * 16 + l15) * 128 + lHi);
            uint32_t vb[16];
            #pragma unroll
            for (int w = 0; w < 4; ++w) ldsm4t(vb + 4 * w, vB + SWZ(rowOff + w * 32));
            #pragma unroll
            for (int j = 0; j < 8; ++j)
                mma16816h(accC[j], phi, &vb[(j >> 1) * 4 + (j & 1) * 2]);
            #pragma unroll
            for (int w = 0; w < 4; ++w) ldsm4t(vb + 4 * w, vvB + SWZ(rowOff + w * 32));
            #pragma unroll
            for (int j = 0; j < 8; ++j)
                mma16816h(accV[j], p2h, &vb[(j >> 1) * 4 + (j & 1) * 2]);
        }
    }

    // ---- epilogue: write a3c (bf16x3), hC2 (fp16 ctx^2), var (fp32) ----
    const float i0 = 1.f / (256.f * rl0), i1 = 1.f / (256.f * rl1);
    const float w0 = 1.f / (1024.f * rl0 * rl0), w1 = 1.f / (1024.f * rl1 * rl1);
    const int row0 = qb + wid * 16 + rr;
    #pragma unroll
    for (int j = 0; j < 8; ++j) {
        int off = j * 8 + cpair;
        int col = hh * 64 + off;
        float cv[2][2] = {{accC[j][0] * i0, accC[j][1] * i0},
                          {accC[j][2] * i1, accC[j][3] * i1}};
        float uv[2][2] = {{accV[j][0] * w0, accV[j][1] * w0},
                          {accV[j][2] * w1, accV[j][3] * w1}};
        #pragma unroll
        for (int rr2 = 0; rr2 < 2; ++rr2) {
            size_t bn = (size_t)b * NSEQ + row0 + rr2 * 8;
            float c0 = cv[rr2][0], c1 = cv[rr2][1];
            float h0 = bfr(c0), h1 = bfr(c1);
            uint32_t hp = pack2(h0, h1);
            uint32_t lp = pack2(c0 - h0, c1 - h1);
            __nv_bfloat16* dst = a3c + bn * K3 + col;
            *(uint32_t*)dst          = hp;
            *(uint32_t*)(dst + 1024) = lp;
            *(uint32_t*)(dst + 2048) = hp;
            __half2 hc = __floats2half2_rn(c0 * c0, c1 * c1);
            *(uint32_t*)(hC2 + bn * DM + col) = *(uint32_t*)&hc;
            *(float2*)(var + bn * DM + col) = make_float2(uv[rr2][0], uv[rr2][1]);
        }
    }
}

// ---------------------------------------------------------------------------
// Launcher
// ---------------------------------------------------------------------------
extern "C" void kernel_launch(void* const* d_in, const int* in_sizes, int n_in,
                              void* d_out, int out_size) {
    const float* H      = (const float*)d_in[0];
    const float* xr     = (const float*)d_in[1];
    const float* Wq     = (const float*)d_in[2];
    const float* bq     = (const float*)d_in[4];
    const float* Wk     = (const float*)d_in[6];
    const float* bk     = (const float*)d_in[8];
    const float* Wv     = (const float*)d_in[10];
    const float* Wv_rho = (const float*)d_in[11];
    const float* bv     = (const float*)d_in[12];
    const float* bv_rho = (const float*)d_in[13];
    const float* Wo     = (const float*)d_in[14];
    const float* Wo_rho = (const float*)d_in[15];
    const float* bo     = (const float*)d_in[16];
    const float* bo_rho = (const float*)d_in[17];
    const float* lsf    = (const float*)d_in[18];
    const float* lll    = (const float*)d_in[19];

    float *var, *d2, *bvs2, *bos2;
    __nv_bfloat16 *a3h, *a3c, *b3q, *b3k, *b3v, *b3o, *q3p, *k3p;
    __half *hA2, *hC2, *hVs, *hOs, *v2hp, *vv2hp;
    cudaGetSymbolAddress((void**)&var,  g_var);
    cudaGetSymbolAddress((void**)&d2,   g_d2);
    cudaGetSymbolAddress((void**)&bvs2, g_bvs2);
    cudaGetSymbolAddress((void**)&bos2, g_bos2);
    cudaGetSymbolAddress((void**)&a3h,  g_A3H);
    cudaGetSymbolAddress((void**)&a3c,  g_A3ctx);
    cudaGetSymbolAddress((void**)&b3q,  g_B3q);
    cudaGetSymbolAddress((void**)&b3k,  g_B3k);
    cudaGetSymbolAddress((void**)&b3v,  g_B3v);
    cudaGetSymbolAddress((void**)&b3o,  g_B3o);
    cudaGetSymbolAddress((void**)&hA2,  g_hA_H2);
    cudaGetSymbolAddress((void**)&hC2,  g_hC2);
    cudaGetSymbolAddress((void**)&hVs,  g_hB_vs2);
    cudaGetSymbolAddress((void**)&hOs,  g_hB_os2);
    cudaGetSymbolAddress((void**)&q3p,  g_q3);
    cudaGetSymbolAddress((void**)&k3p,  g_k3);
    cudaGetSymbolAddress((void**)&v2hp, g_v2h);
    cudaGetSymbolAddress((void**)&vv2hp, g_vv2h);

    cudaFuncSetAttribute(gemm_proj, cudaFuncAttributeMaxDynamicSharedMemorySize, SMEM_GEMM);
    cudaFuncSetAttribute(gemm_out,  cudaFuncAttributeMaxDynamicSharedMemorySize, SMEM_GEMM);
    cudaFuncSetAttribute(attn_tc,   cudaFuncAttributeMaxDynamicSharedMemorySize, ATTN_SMEM);

    // [0] both bias softplus^2
    bias2_kernel<<<8, 256>>>(bv_rho, bo_rho, bvs2, bos2);
    // [1] fused bf16x3 A-split + fp16 H^2 (one read of H)
    splitAsq_kernel<<<BN, 256>>>(H, a3h, hA2);
    // [2] all 4 weight bf16x3 splits, [3] both fp16 rho converts
    wsplit4_kernel<<<dim3(DM, 4), 256>>>(Wq, Wk, Wv, Wo, b3q, b3k, b3v, b3o);
    f16w2_kernel<<<dim3(DM, 2), 256>>>(Wv_rho, Wo_rho, hVs, hOs);
    // [4] fused projection GEMM: Q/K/V (bf16x3) + Vv (fp16) -> head-major
    gemm_proj<<<dim3(DM / BNT, BN / BM, 4), 256, SMEM_GEMM>>>(
        a3h, b3q, b3k, b3v, hA2, hVs, bq, bk, bv, bvs2, q3p, k3p, v2hp, vv2hp);
    // [5] pairwise squared distances
    dist2_kernel<<<dim3(16, 16, BATCH), 256>>>(xr, d2);
    // [6] attention -> a3c / hC2 / var directly
    attn_tc<<<dim3(NSEQ / QB, BATCH * NH), 256, ATTN_SMEM>>>(
        q3p, k3p, v2hp, vv2hp, d2, lsf, lll, a3c, hC2, var);
    // [7] fused output GEMM: out_mean (bf16x3) + out_var (fp16 + var add)
    float* out_mean = (float*)d_out;
    float* out_var  = out_mean + (size_t)BN * DM;
    gemm_out<<<dim3(DM / BNT, BN / BM, 2), 256, SMEM_GEMM>>>(
        a3c, b3o, bo, hC2, hOs, bos2, var, out_mean, out_var);
}

// round 11
// speedup vs baseline: 3.6033x; 1.0917x over previous
#include <cuda_runtime.h>
#include <cuda_bf16.h>
#include <cuda_fp16.h>
#include <math.h>
#include <stdint.h>

#define DM    1024
#define BATCH 8
#define NSEQ  1024
#define BN    (BATCH * NSEQ)
#define NH    16
#define DK    64
#define QSCALE 0.125f

#define K3      3072              // bf16x3 packed K (Q/K projections)
#define K2      2048              // fp16x2 packed K (V, out_mean)
#define BK      64
#define KITERS  (K3 / BK)         // 48
#define BM      128
#define BNT     128
#define STAGES  3
#define STAGE_BYTES ((BM + BNT) * 128)
#define SMEM_GEMM (STAGES * STAGE_BYTES)        // 96 KB

// attention tiling / smem (KT=128)
#define QB 128
#define KT 128
#define SM_Q   0                  // 3 x 128 x 128B = 49152
#define SM_K   49152              // 2 bufs x 3 chunks x 128 x 128B = 98304
#define SM_V   147456             // 2 bufs x 128 x 128B = 32768
#define SM_VV  180224             // 32768
#define ATTN_SMEM 212992

// ---------------------------------------------------------------------------
// Scratch
// ---------------------------------------------------------------------------
__device__ float g_var [BN * DM];
__device__ float g_d2  [BATCH * NSEQ * NSEQ];
__device__ float g_bvs2[DM];
__device__ float g_bos2[DM];

__device__ __nv_bfloat16 g_A3H [BN * K3];   // H bf16x3 [hi|lo|hi]
__device__ __nv_bfloat16 g_B3q [DM * K3];
__device__ __nv_bfloat16 g_B3k [DM * K3];

__device__ __half g_hH2  [BN * K2];         // H fp16x2 [hi|lo] (V GEMM A)
__device__ __half g_a2h  [BN * K2];         // ctx fp16x2 [hi|lo] (out_mean A)
__device__ __half g_hWv2 [DM * K2];         // Wv fp16 dup [hi|hi]
__device__ __half g_hWo2 [DM * K2];         // Wo fp16 dup [hi|hi]
__device__ __half g_hA_H2[BN * DM];         // fp16 H^2 (Vv A)
__device__ __half g_hC2  [BN * DM];         // fp16 ctx^2 (out_var A)
__device__ __half g_hB_vs2[DM * DM];        // fp16 softplus^2(Wv_rho)
__device__ __half g_hB_os2[DM * DM];        // fp16 softplus^2(Wo_rho)

__device__ __nv_bfloat16 g_q3 [BATCH * NH * NSEQ * 192];
__device__ __nv_bfloat16 g_k3 [BATCH * NH * NSEQ * 192];
__device__ __half        g_v2h [BATCH * NH * NSEQ * 64];
__device__ __half        g_vv2h[BATCH * NH * NSEQ * 64];

// ---------------------------------------------------------------------------
// PTX helpers
// ---------------------------------------------------------------------------
__device__ __forceinline__ uint32_t smem_u32(const void* p) {
    uint32_t a;
    asm("{ .reg .u64 t; cvta.to.shared.u64 t, %1; cvt.u32.u64 %0, t; }"
        : "=r"(a) : "l"(p));
    return a;
}
#define SWZ(off) ((off) ^ (((off) >> 3) & 0x70))

__device__ __forceinline__ void cp16(uint32_t dst, const void* src) {
    asm volatile("cp.async.cg.shared.global [%0], [%1], 16;"
                 :: "r"(dst), "l"(src) : "memory");
}
#define CP_COMMIT() asm volatile("cp.async.commit_group;" ::: "memory")

__device__ __forceinline__ void ldsm4(uint32_t* r, uint32_t addr) {
    asm volatile("ldmatrix.sync.aligned.m8n8.x4.shared.b16 {%0,%1,%2,%3}, [%4];"
                 : "=r"(r[0]), "=r"(r[1]), "=r"(r[2]), "=r"(r[3]) : "r"(addr));
}
__device__ __forceinline__ void ldsm4t(uint32_t* r, uint32_t addr) {
    asm volatile("ldmatrix.sync.aligned.m8n8.x4.trans.shared.b16 {%0,%1,%2,%3}, [%4];"
                 : "=r"(r[0]), "=r"(r[1]), "=r"(r[2]), "=r"(r[3]) : "r"(addr));
}
__device__ __forceinline__ void mma16816(float* c, const uint32_t* a, const uint32_t* b) {
    asm volatile("mma.sync.aligned.m16n8k16.row.col.f32.bf16.bf16.f32 "
                 "{%0,%1,%2,%3}, {%4,%5,%6,%7}, {%8,%9}, {%0,%1,%2,%3};"
                 : "+f"(c[0]), "+f"(c[1]), "+f"(c[2]), "+f"(c[3])
                 : "r"(a[0]), "r"(a[1]), "r"(a[2]), "r"(a[3]), "r"(b[0]), "r"(b[1]));
}
__device__ __forceinline__ void mma16816h(float* c, const uint32_t* a, const uint32_t* b) {
    asm volatile("mma.sync.aligned.m16n8k16.row.col.f32.f16.f16.f32 "
                 "{%0,%1,%2,%3}, {%4,%5,%6,%7}, {%8,%9}, {%0,%1,%2,%3};"
                 : "+f"(c[0]), "+f"(c[1]), "+f"(c[2]), "+f"(c[3])
                 : "r"(a[0]), "r"(a[1]), "r"(a[2]), "r"(a[3]), "r"(b[0]), "r"(b[1]));
}
__device__ __forceinline__ uint32_t pack2(float lo, float hi) {
    uint32_t d;
    asm("cvt.rn.bf16x2.f32 %0, %1, %2;" : "=r"(d) : "f"(hi), "f"(lo));
    return d;
}
__device__ __forceinline__ float bfr(float v) {
    return __bfloat162float(__float2bfloat16_rn(v));
}

// ---------------------------------------------------------------------------
// elementwise prep kernels
// ---------------------------------------------------------------------------
__global__ void bias2_kernel(const float* __restrict__ a, const float* __restrict__ b,
                             float* __restrict__ oa, float* __restrict__ ob) {
    int i = blockIdx.x * 256 + threadIdx.x;
    const float* in  = (i < DM) ? a  : b;
    float*       out = (i < DM) ? oa : ob;
    int j = i & (DM - 1);
    float x  = in[j];
    float sp = (x > 15.f) ? x : log1pf(__expf(x));
    out[j] = sp * sp;
}

// fused H prep: bf16x3 [hi|lo|hi] + fp16x2 [hi|lo] + fp16 H^2 (one read of H)
__global__ void splitH_kernel(const float* __restrict__ X,
                              __nv_bfloat16* __restrict__ Y3,
                              __half* __restrict__ Y2, __half* __restrict__ Ysq) {
    int r  = blockIdx.x;
    int c4 = threadIdx.x;
    float4 x = *(const float4*)(X + (size_t)r * DM + c4 * 4);
    float v[4] = {x.x, x.y, x.z, x.w};
    // bf16x3
    unsigned short hu[4], lu[4];
    #pragma unroll
    for (int i = 0; i < 4; ++i) {
        __nv_bfloat16 hb = __float2bfloat16_rn(v[i]);
        float hr = __bfloat162float(hb);
        __nv_bfloat16 lb = __float2bfloat16_rn(v[i] - hr);
        hu[i] = __bfloat16_as_ushort(hb);
        lu[i] = __bfloat16_as_ushort(lb);
    }
    uint2 hp, lp;
    hp.x = (uint32_t)hu[0] | ((uint32_t)hu[1] << 16);
    hp.y = (uint32_t)hu[2] | ((uint32_t)hu[3] << 16);
    lp.x = (uint32_t)lu[0] | ((uint32_t)lu[1] << 16);
    lp.y = (uint32_t)lu[2] | ((uint32_t)lu[3] << 16);
    size_t ob3 = (size_t)r * K3 + c4 * 4;
    *(uint2*)(Y3 + ob3)          = hp;
    *(uint2*)(Y3 + ob3 + DM)     = lp;
    *(uint2*)(Y3 + ob3 + 2 * DM) = hp;
    // fp16x2 [hi|lo]
    float hh[4], ll[4];
    #pragma unroll
    for (int i = 0; i < 4; ++i) {
        hh[i] = __half2float(__float2half_rn(v[i]));
        ll[i] = v[i] - hh[i];
    }
    __half2 fh0 = __floats2half2_rn(hh[0], hh[1]);
    __half2 fh1 = __floats2half2_rn(hh[2], hh[3]);
    __half2 fl0 = __floats2half2_rn(ll[0], ll[1]);
    __half2 fl1 = __floats2half2_rn(ll[2], ll[3]);
    uint2 fp, fl;
    fp.x = *(uint32_t*)&fh0; fp.y = *(uint32_t*)&fh1;
    fl.x = *(uint32_t*)&fl0; fl.y = *(uint32_t*)&fl1;
    size_t ob2 = (size_t)r * K2 + c4 * 4;
    *(uint2*)(Y2 + ob2)      = fp;
    *(uint2*)(Y2 + ob2 + DM) = fl;
    // fp16 H^2
    __half2 s0 = __floats2half2_rn(v[0] * v[0], v[1] * v[1]);
    __half2 s1 = __floats2half2_rn(v[2] * v[2], v[3] * v[3]);
    uint2 sq;
    sq.x = *(uint32_t*)&s0;
    sq.y = *(uint32_t*)&s1;
    *(uint2*)(Ysq + (size_t)r * DM + c4 * 4) = sq;
}

// bf16x3 B-split of Wq / Wk ([hi|hi|lo]); grid (DM, 2)
__global__ void wsplit2_kernel(const float* __restrict__ W0, const float* __restrict__ W1,
                               __nv_bfloat16* __restrict__ Y0, __nv_bfloat16* __restrict__ Y1) {
    int z = blockIdx.y;
    const float* X = (z == 0) ? W0 : W1;
    __nv_bfloat16* Y = (z == 0) ? Y0 : Y1;
    int r  = blockIdx.x;
    int c4 = threadIdx.x;
    float4 x = *(const float4*)(X + (size_t)r * DM + c4 * 4);
    float v[4] = {x.x, x.y, x.z, x.w};
    unsigned short hu[4], lu[4];
    #pragma unroll
    for (int i = 0; i < 4; ++i) {
        __nv_bfloat16 hb = __float2bfloat16_rn(v[i]);
        float hr = __bfloat162float(hb);
        __nv_bfloat16 lb = __float2bfloat16_rn(v[i] - hr);
        hu[i] = __bfloat16_as_ushort(hb);
        lu[i] = __bfloat16_as_ushort(lb);
    }
    uint2 hp, lp;
    hp.x = (uint32_t)hu[0] | ((uint32_t)hu[1] << 16);
    hp.y = (uint32_t)hu[2] | ((uint32_t)hu[3] << 16);
    lp.x = (uint32_t)lu[0] | ((uint32_t)lu[1] << 16);
    lp.y = (uint32_t)lu[2] | ((uint32_t)lu[3] << 16);
    size_t ob = (size_t)r * K3 + c4 * 4;
    *(uint2*)(Y + ob)          = hp;
    *(uint2*)(Y + ob + DM)     = hp;
    *(uint2*)(Y + ob + 2 * DM) = lp;
}

// fp16 dup-convert of Wv / Wo to [hi|hi] (K2 wide); grid (DM, 2)
__global__ void wdup2_kernel(const float* __restrict__ W0, const float* __restrict__ W1,
                             __half* __restrict__ Y0, __half* __restrict__ Y1) {
    int z = blockIdx.y;
    const float* X = (z == 0) ? W0 : W1;
    __half* Y      = (z == 0) ? Y0 : Y1;
    int r  = blockIdx.x;
    int c4 = threadIdx.x;
    float4 x = *(const float4*)(X + (size_t)r * DM + c4 * 4);
    __half2 h0 = __floats2half2_rn(x.x, x.y);
    __half2 h1 = __floats2half2_rn(x.z, x.w);
    uint2 p;
    p.x = *(uint32_t*)&h0;
    p.y = *(uint32_t*)&h1;
    size_t ob = (size_t)r * K2 + c4 * 4;
    *(uint2*)(Y + ob)      = p;
    *(uint2*)(Y + ob + DM) = p;
}

// fp16 softplus^2 convert of both rho weights; grid (DM, 2)
__global__ void f16w2_kernel(const float* __restrict__ W0, const float* __restrict__ W1,
                             __half* __restrict__ Y0, __half* __restrict__ Y1) {
    int z = blockIdx.y;
    const float* X = (z == 0) ? W0 : W1;
    __half* Y      = (z == 0) ? Y0 : Y1;
    int row = blockIdx.x;
    int c4  = threadIdx.x;
    float4 x = *(const float4*)(X + (size_t)row * DM + c4 * 4);
    float v[4] = {x.x, x.y, x.z, x.w};
    #pragma unroll
    for (int i = 0; i < 4; ++i) {
        float sp = (v[i] > 15.f) ? v[i] : log1pf(__expf(v[i]));
        v[i] = sp * sp;
    }
    __half2 h0 = __floats2half2_rn(v[0], v[1]);
    __half2 h1 = __floats2half2_rn(v[2], v[3]);
    uint2 p;
    p.x = *(uint32_t*)&h0;
    p.y = *(uint32_t*)&h1;
    *(uint2*)(Y + (size_t)row * DM + c4 * 4) = p;
}

// ---------------------------------------------------------------------------
// GEMM mainloops (device functions)
// ---------------------------------------------------------------------------
__device__ __forceinline__ void gemm_main_bf16(
    const __nv_bfloat16* __restrict__ A3, const __nv_bfloat16* __restrict__ B3,
    char* smem, int mBase, int nBase, float acc[4][4][4]) {
    const uint32_t sb = smem_u32(smem);
    const int t    = threadIdx.x;
    const int wid  = t >> 5;
    const int lane = t & 31;
    const int wm   = wid & 1;
    const int wn   = wid >> 1;

    const int r  = t >> 1;
    const int uc = (t & 1) * 4;
    const __nv_bfloat16* aRow = A3 + (size_t)(mBase + r) * K3 + uc * 8;
    const __nv_bfloat16* bRow = B3 + (size_t)(nBase + r) * K3 + uc * 8;

    auto load_stage = [&](int buf, int c) {
        uint32_t sA = sb + buf * STAGE_BYTES;
        uint32_t sB = sA + BM * 128;
        const __nv_bfloat16* ga = aRow + c * BK;
        const __nv_bfloat16* gb = bRow + c * BK;
        #pragma unroll
        for (int i = 0; i < 4; ++i) {
            uint32_t bo = r * 128 + (uc + i) * 16;
            cp16(sA + SWZ(bo), ga + i * 8);
            cp16(sB + SWZ(bo), gb + i * 8);
        }
        CP_COMMIT();
    };

    const int aRowSel = (lane & 7) | (((lane >> 3) & 1) << 3);
    const int aKSel   = (lane >> 4) << 4;
    const int bNSel   = (lane & 7) | ((lane >> 4) << 3);
    const int bKSel   = ((lane >> 3) & 1) << 4;

    load_stage(0, 0);
    load_stage(1, 1);

    for (int kt = 0; kt < KITERS; ++kt) {
        const int buf = kt % STAGES;
        if (kt == KITERS - 1) asm volatile("cp.async.wait_group 0;" ::: "memory");
        else                  asm volatile("cp.async.wait_group 1;" ::: "memory");
        __syncthreads();

        if (kt + 2 < KITERS) load_stage((kt + 2) % STAGES, kt + 2);

        uint32_t sA = sb + buf * STAGE_BYTES;
        uint32_t sB = sA + BM * 128;
        #pragma unroll
        for (int ks = 0; ks < 4; ++ks) {
            uint32_t af[4][4], bfr2[2][4];
            #pragma unroll
            for (int mi = 0; mi < 4; ++mi) {
                uint32_t bo = (uint32_t)((wm * 64 + mi * 16 + aRowSel) * 128
                                         + ks * 32 + aKSel);
                ldsm4(af[mi], sA + SWZ(bo));
            }
            #pragma unroll
            for (int pi = 0; pi < 2; ++pi) {
                uint32_t bo = (uint32_t)((wn * 32 + pi * 16 + bNSel) * 128
                                         + ks * 32 + bKSel);
                ldsm4(bfr2[pi], sB + SWZ(bo));
            }
            #pragma unroll
            for (int mi = 0; mi < 4; ++mi)
                #pragma unroll
                for (int ni = 0; ni < 4; ++ni)
                    mma16816(acc[mi][ni], af[mi], &bfr2[ni >> 1][(ni & 1) * 2]);
        }
        __syncthreads();
    }
}

// fp16 mainloop with NITER k-chunks (stride NITER*BK per row)
template<int NITER>
__device__ __forceinline__ void gemm_main_h(
    const __half* __restrict__ A, const __half* __restrict__ B,
    char* smem, int mBase, int nBase, float acc[4][4][4]) {
    const uint32_t sb = smem_u32(smem);
    const int t    = threadIdx.x;
    const int wid  = t >> 5;
    const int lane = t & 31;
    const int wm   = wid & 1;
    const int wn   = wid >> 1;
    const int STRIDE = NITER * BK;

    const int r  = t >> 1;
    const int uc = (t & 1) * 4;
    const __half* aRow = A + (size_t)(mBase + r) * STRIDE + uc * 8;
    const __half* bRow = B + (size_t)(nBase + r) * STRIDE + uc * 8;

    auto load_stage = [&](int buf, int c) {
        uint32_t sA = sb + buf * STAGE_BYTES;
        uint32_t sB = sA + BM * 128;
        const __half* ga = aRow + c * BK;
        const __half* gb = bRow + c * BK;
        #pragma unroll
        for (int i = 0; i < 4; ++i) {
            uint32_t bo = r * 128 + (uc + i) * 16;
            cp16(sA + SWZ(bo), ga + i * 8);
            cp16(sB + SWZ(bo), gb + i * 8);
        }
        CP_COMMIT();
    };

    const int aRowSel = (lane & 7) | (((lane >> 3) & 1) << 3);
    const int aKSel   = (lane >> 4) << 4;
    const int bNSel   = (lane & 7) | ((lane >> 4) << 3);
    const int bKSel   = ((lane >> 3) & 1) << 4;

    load_stage(0, 0);
    load_stage(1, 1);

    for (int kt = 0; kt < NITER; ++kt) {
        const int buf = kt % STAGES;
        if (kt == NITER - 1) asm volatile("cp.async.wait_group 0;" ::: "memory");
        else                 asm volatile("cp.async.wait_group 1;" ::: "memory");
        __syncthreads();

        if (kt + 2 < NITER) load_stage((kt + 2) % STAGES, kt + 2);

        uint32_t sA = sb + buf * STAGE_BYTES;
        uint32_t sB = sA + BM * 128;
        #pragma unroll
        for (int ks = 0; ks < 4; ++ks) {
            uint32_t af[4][4], bfr2[2][4];
            #pragma unroll
            for (int mi = 0; mi < 4; ++mi) {
                uint32_t bo = (uint32_t)((wm * 64 + mi * 16 + aRowSel) * 128
                                         + ks * 32 + aKSel);
                ldsm4(af[mi], sA + SWZ(bo));
            }
            #pragma unroll
            for (int pi = 0; pi < 2; ++pi) {
                uint32_t bo = (uint32_t)((wn * 32 + pi * 16 + bNSel) * 128
                                         + ks * 32 + bKSel);
                ldsm4(bfr2[pi], sB + SWZ(bo));
            }
            #pragma unroll
            for (int mi = 0; mi < 4; ++mi)
                #pragma unroll
                for (int ni = 0; ni < 4; ++ni)
                    mma16816h(acc[mi][ni], af[mi], &bfr2[ni >> 1][(ni & 1) * 2]);
        }
        __syncthreads();
    }
}

// ---------------------------------------------------------------------------
// fused projection GEMM: z=0/1 -> Q/K (bf16x3), z=2 -> V (fp16x2),
// z=3 -> V-variance (fp16x1). grid (8, 64, 4).
// ---------------------------------------------------------------------------
__global__ void __launch_bounds__(256, 2)
gemm_proj(const __nv_bfloat16* __restrict__ A3,
          const __nv_bfloat16* __restrict__ B3q, const __nv_bfloat16* __restrict__ B3k,
          const __half* __restrict__ hH2, const __half* __restrict__ hWv2,
          const __half* __restrict__ hA2, const __half* __restrict__ hVs,
          const float* __restrict__ bq, const float* __restrict__ bk,
          const float* __restrict__ bv, const float* __restrict__ bvs2,
          __nv_bfloat16* __restrict__ q3, __nv_bfloat16* __restrict__ k3,
          __half* __restrict__ v2h, __half* __restrict__ vv2h) {
    extern __shared__ __align__(1024) char smem[];
    const int z = blockIdx.z;
    const int mBase = blockIdx.y * BM;
    const int nBase = blockIdx.x * BNT;
    float acc[4][4][4] = {};

    if (z < 2) {
        gemm_main_bf16(A3, (z == 0) ? B3q : B3k, smem, mBase, nBase, acc);
    } else if (z == 2) {
        gemm_main_h<32>(hH2, hWv2, smem, mBase, nBase, acc);
    } else {
        gemm_main_h<16>(hA2, hVs, smem, mBase, nBase, acc);
    }

    const float* bias = (z == 0) ? bq : (z == 1) ? bk : (z == 2) ? bv : bvs2;
    const int wid  = threadIdx.x >> 5;
    const int lane = threadIdx.x & 31;
    const int lr = lane >> 2;
    const int lc = (lane & 3) * 2;
    const int rB = mBase + (wid & 1) * 64;
    const int cB = nBase + (wid >> 1) * 32;
    #pragma unroll
    for (int mi = 0; mi < 4; ++mi) {
        #pragma unroll
        for (int ni = 0; ni < 4; ++ni) {
            int col  = cB + ni * 8 + lc;
            int row0 = rB + mi * 16 + lr;
            int h = col >> 6, dl = col & 63;
            float2 bi = *(const float2*)(bias + col);
            float vx[2][2] = {{acc[mi][ni][0] + bi.x, acc[mi][ni][1] + bi.y},
                              {acc[mi][ni][2] + bi.x, acc[mi][ni][3] + bi.y}};
            #pragma unroll
            for (int rr2 = 0; rr2 < 2; ++rr2) {
                int row = row0 + rr2 * 8;
                int b = row >> 10, n = row & 1023;
                if (z >= 2) {
                    __half* dst = (z == 2) ? v2h : vv2h;
                    __half2 hv = __floats2half2_rn(vx[rr2][0], vx[rr2][1]);
                    *(uint32_t*)(dst + ((size_t)(b * NH + h) * NSEQ + n) * 64 + dl)
                        = *(uint32_t*)&hv;
                } else {
                    float h0 = bfr(vx[rr2][0]), h1 = bfr(vx[rr2][1]);
                    uint32_t hp = pack2(h0, h1);
                    uint32_t lp = pack2(vx[rr2][0] - h0, vx[rr2][1] - h1);
                    __nv_bfloat16* dst = ((z == 0) ? q3 : k3)
                        + ((size_t)(b * NH + h) * NSEQ + n) * 192 + dl;
                    *(uint32_t*)dst = hp;
                    if (z == 0) {
                        *(uint32_t*)(dst + 64)  = lp;
                        *(uint32_t*)(dst + 128) = hp;
                    } else {
                        *(uint32_t*)(dst + 64)  = hp;
                        *(uint32_t*)(dst + 128) = lp;
                    }
                }
            }
        }
    }
}

// ---------------------------------------------------------------------------
// fused output GEMM: z=0 -> out_mean (fp16x2), z=1 -> out_var (fp16x1 + add).
// grid (8, 64, 2).
// ---------------------------------------------------------------------------
__global__ void __launch_bounds__(256, 2)
gemm_out(const __half* __restrict__ a2h, const __half* __restrict__ hWo2,
         const float* __restrict__ bo,
         const __half* __restrict__ hC2, const __half* __restrict__ hOs,
         const float* __restrict__ bos2, const float* __restrict__ var,
         float* __restrict__ out_mean, float* __restrict__ out_var) {
    extern __shared__ __align__(1024) char smem[];
    const int z = blockIdx.z;
    const int mBase = blockIdx.y * BM;
    const int nBase = blockIdx.x * BNT;
    float acc[4][4][4] = {};

    if (z == 0) gemm_main_h<32>(a2h, hWo2, smem, mBase, nBase, acc);
    else        gemm_main_h<16>(hC2, hOs, smem, mBase, nBase, acc);

    const float* bias = (z == 0) ? bo : bos2;
    float* C          = (z == 0) ? out_mean : out_var;
    const int wid  = threadIdx.x >> 5;
    const int lane = threadIdx.x & 31;
    const int lr = lane >> 2;
    const int lc = (lane & 3) * 2;
    const int rB = mBase + (wid & 1) * 64;
    const int cB = nBase + (wid >> 1) * 32;
    #pragma unroll
    for (int mi = 0; mi < 4; ++mi) {
        #pragma unroll
        for (int ni = 0; ni < 4; ++ni) {
            int col  = cB + ni * 8 + lc;
            int row0 = rB + mi * 16 + lr;
            float2 bi = *(const float2*)(bias + col);
            float vx[2][2] = {{acc[mi][ni][0] + bi.x, acc[mi][ni][1] + bi.y},
                              {acc[mi][ni][2] + bi.x, acc[mi][ni][3] + bi.y}};
            #pragma unroll
            for (int rr2 = 0; rr2 < 2; ++rr2) {
                size_t o = (size_t)(row0 + rr2 * 8) * DM + col;
                if (z == 1) {
                    float2 a2 = *(const float2*)(var + o);
                    vx[rr2][0] += a2.x; vx[rr2][1] += a2.y;
                }
                *(float2*)(C + o) = make_float2(vx[rr2][0], vx[rr2][1]);
            }
        }
    }
}

// ---------------------------------------------------------------------------
// dist2 (unchanged)
// ---------------------------------------------------------------------------
__global__ void dist2_kernel(const float* __restrict__ xr, float* __restrict__ d2) {
    __shared__ float xm[64][17];
    __shared__ float xn[64][17];
    __shared__ float x2m[64];
    __shared__ float x2n[64];

    const int t  = threadIdx.x;
    const int b  = blockIdx.z;
    const int mi = blockIdx.y * 64;
    const int nj = blockIdx.x * 64;

    for (int idx = t; idx < 64 * 4; idx += 256) {
        int r = idx >> 2, c = (idx & 3) * 4;
        float4 a = *(const float4*)(xr + ((size_t)b * NSEQ + mi + r) * 16 + c);
        xm[r][c] = a.x; xm[r][c+1] = a.y; xm[r][c+2] = a.z; xm[r][c+3] = a.w;
        float4 bb = *(const float4*)(xr + ((size_t)b * NSEQ + nj + r) * 16 + c);
        xn[r][c] = bb.x; xn[r][c+1] = bb.y; xn[r][c+2] = bb.z; xn[r][c+3] = bb.w;
    }
    __syncthreads();

    if (t < 64) {
        float s = 0.f;
        #pragma unroll
        for (int c = 0; c < 16; ++c) s += xm[t][c] * xm[t][c];
        x2m[t] = s;
    } else if (t < 128) {
        int r = t - 64;
        float s = 0.f;
        #pragma unroll
        for (int c = 0; c < 16; ++c) s += xn[r][c] * xn[r][c];
        x2n[r] = s;
    }
    __syncthreads();

    const int tx = t & 15, ty = t >> 4;
    #pragma unroll
    for (int i = 0; i < 4; ++i) {
        int row = ty * 4 + i;
        float out4[4];
        #pragma unroll
        for (int j = 0; j < 4; ++j) {
            int col = tx * 4 + j;
            float dot = 0.f;
            #pragma unroll
            for (int c = 0; c < 16; ++c) dot += xm[row][c] * xn[col][c];
            out4[j] = fmaxf(x2m[row] + x2n[col] - 2.f * dot, 0.f);
        }
        float4 v4 = make_float4(out4[0], out4[1], out4[2], out4[3]);
        *(float4*)(d2 + ((size_t)b * NSEQ + mi + row) * NSEQ + nj + tx * 4) = v4;
    }
}

// ---------------------------------------------------------------------------
// Tensor-core flash attention, KT=128. S bf16x3; PV fp16 hi-only (P x256);
// P^2 Vv fp16 hi-only (P^2 x1024).
// Epilogue writes a2h (fp16x2 ctx), hC2 (fp16 ctx^2), var (fp32).
// ---------------------------------------------------------------------------
__global__ void __launch_bounds__(256, 1)
attn_tc(const __nv_bfloat16* __restrict__ q3, const __nv_bfloat16* __restrict__ k3,
        const __half* __restrict__ v2h, const __half* __restrict__ vv2h,
        const float* __restrict__ d2g,
        const float* __restrict__ lsf, const float* __restrict__ lll,
        __half* __restrict__ a2h, __half* __restrict__ hC2,
        float* __restrict__ var) {
    extern __shared__ __align__(1024) char smem[];
    const uint32_t sb = smem_u32(smem);
    const int t    = threadIdx.x;
    const int wid  = t >> 5;
    const int lane = t & 31;
    const int qb   = blockIdx.x * QB;
    const int bh   = blockIdx.y;
    const int b    = bh >> 4, hh = bh & 15;

    const float sigma_f2 = __expf(2.f * lsf[hh]);
    const float coef     = 0.5f * __expf(-2.f * lll[hh]);

    const __nv_bfloat16* Qg  = q3   + ((size_t)bh * NSEQ + qb) * 192;
    const __nv_bfloat16* Kg  = k3   + (size_t)bh * NSEQ * 192;
    const __half* Vg  = v2h  + (size_t)bh * NSEQ * 64;
    const __half* VVg = vv2h + (size_t)bh * NSEQ * 64;

    for (int i = t; i < QB * 24; i += 256) {
        int row = i / 24, u = i % 24;
        cp16(sb + SM_Q + (u >> 3) * 16384 + SWZ((uint32_t)(row * 128 + (u & 7) * 16)),
             Qg + (size_t)row * 192 + u * 8);
    }

    auto load_kv = [&](int buf, int kt) {
        const __nv_bfloat16* kg = Kg + (size_t)kt * KT * 192;
        for (int i = t; i < KT * 24; i += 256) {
            int row = i / 24, u = i % 24;
            cp16(sb + SM_K + buf * 49152 + (u >> 3) * 16384
                    + SWZ((uint32_t)(row * 128 + (u & 7) * 16)),
                 kg + (size_t)row * 192 + u * 8);
        }
        const __half* vg = Vg  + (size_t)kt * KT * 64;
        const __half* wg = VVg + (size_t)kt * KT * 64;
        for (int i = t; i < KT * 8; i += 256) {
            int row = i >> 3, u = i & 7;
            uint32_t so = SWZ((uint32_t)(row * 128 + u * 16));
            cp16(sb + SM_V  + buf * 16384 + so, vg + (size_t)row * 64 + u * 8);
            cp16(sb + SM_VV + buf * 16384 + so, wg + (size_t)row * 64 + u * 8);
        }
        CP_COMMIT();
    };
    load_kv(0, 0);

    const int l15 = lane & 15;
    const int lHi = (lane >> 4) << 4;
    const uint32_t aRowOff = (uint32_t)((wid * 16 + l15) * 128 + lHi);
    const int g    = lane >> 3;
    const int keyl = ((g >> 1) << 3) + (lane & 7);
    const uint32_t kCol = (uint32_t)((g & 1) << 4);
    const int rr    = lane >> 2;
    const int cpair = (lane & 3) * 2;

    float accC[8][4] = {}, accV[8][4] = {};
    float rm0 = -1e30f, rm1 = -1e30f, rl0 = 0.f, rl1 = 0.f;

    for (int kt = 0; kt < NSEQ / KT; ++kt) {
        if (kt + 1 < NSEQ / KT) { __syncthreads(); load_kv((kt + 1) & 1, kt + 1); }
        if (kt + 1 < NSEQ / KT) asm volatile("cp.async.wait_group 1;" ::: "memory");
        else                    asm volatile("cp.async.wait_group 0;" ::: "memory");
        __syncthreads();

        const int buf = kt & 1;
        const uint32_t kB  = sb + SM_K  + buf * 49152;
        const uint32_t vB  = sb + SM_V  + buf * 16384;
        const uint32_t vvB = sb + SM_VV + buf * 16384;

        float sacc[16][4];
        #pragma unroll
        for (int j = 0; j < 16; ++j)
            #pragma unroll
            for (int e = 0; e < 4; ++e) sacc[j][e] = 0.f;

        #pragma unroll
        for (int ks = 0; ks < 12; ++ks) {
            uint32_t a[4];
            ldsm4(a, sb + SM_Q + (ks >> 2) * 16384 + SWZ(aRowOff + (ks & 3) * 32));
            #pragma unroll
            for (int n0 = 0; n0 < 8; ++n0) {
                uint32_t kb4[4];
                ldsm4(kb4, kB + (ks >> 2) * 16384
                         + SWZ((uint32_t)((n0 * 16 + keyl) * 128) + (ks & 3) * 32 + kCol));
                mma16816(sacc[2 * n0],     a, kb4);
                mma16816(sacc[2 * n0 + 1], a, kb4 + 2);
            }
        }

        const int kb0 = kt * KT;
        const float* d2r0 = d2g + (size_t)b * NSEQ * NSEQ
                          + (size_t)(qb + wid * 16 + rr) * NSEQ + kb0;
        const float* d2r1 = d2r0 + 8 * NSEQ;
        #pragma unroll
        for (int j = 0; j < 16; ++j) {
            float2 da = *(const float2*)(d2r0 + j * 8 + cpair);
            float2 db = *(const float2*)(d2r1 + j * 8 + cpair);
            sacc[j][0] = sacc[j][0] * QSCALE + sigma_f2 * __expf(-da.x * coef);
            sacc[j][1] = sacc[j][1] * QSCALE + sigma_f2 * __expf(-da.y * coef);
            sacc[j][2] = sacc[j][2] * QSCALE + sigma_f2 * __expf(-db.x * coef);
            sacc[j][3] = sacc[j][3] * QSCALE + sigma_f2 * __expf(-db.y * coef);
        }
        float mx0 = -1e30f, mx1 = -1e30f;
        #pragma unroll
        for (int j = 0; j < 16; ++j) {
            mx0 = fmaxf(mx0, fmaxf(sacc[j][0], sacc[j][1]));
            mx1 = fmaxf(mx1, fmaxf(sacc[j][2], sacc[j][3]));
        }
        mx0 = fmaxf(mx0, __shfl_xor_sync(0xffffffffu, mx0, 1));
        mx0 = fmaxf(mx0, __shfl_xor_sync(0xffffffffu, mx0, 2));
        mx1 = fmaxf(mx1, __shfl_xor_sync(0xffffffffu, mx1, 1));
        mx1 = fmaxf(mx1, __shfl_xor_sync(0xffffffffu, mx1, 2));
        float m0n = fmaxf(rm0, mx0), m1n = fmaxf(rm1, mx1);
        float f0 = __expf(rm0 - m0n), f1 = __expf(rm1 - m1n);
        rm0 = m0n; rm1 = m1n;
        float sum0 = 0.f, sum1 = 0.f;
        #pragma unroll
        for (int j = 0; j < 16; ++j) {
            sacc[j][0] = __expf(sacc[j][0] - m0n); sum0 += sacc[j][0];
            sacc[j][1] = __expf(sacc[j][1] - m0n); sum0 += sacc[j][1];
            sacc[j][2] = __expf(sacc[j][2] - m1n); sum1 += sacc[j][2];
            sacc[j][3] = __expf(sacc[j][3] - m1n); sum1 += sacc[j][3];
        }
        sum0 += __shfl_xor_sync(0xffffffffu, sum0, 1);
        sum0 += __shfl_xor_sync(0xffffffffu, sum0, 2);
        sum1 += __shfl_xor_sync(0xffffffffu, sum1, 1);
        sum1 += __shfl_xor_sync(0xffffffffu, sum1, 2);
        rl0 = rl0 * f0 + sum0;
        rl1 = rl1 * f1 + sum1;
        float f02 = f0 * f0, f12 = f1 * f1;
        #pragma unroll
        for (int j = 0; j < 8; ++j) {
            accC[j][0] *= f0;  accC[j][1] *= f0;
            accC[j][2] *= f1;  accC[j][3] *= f1;
            accV[j][0] *= f02; accV[j][1] *= f02;
            accV[j][2] *= f12; accV[j][3] *= f12;
        }

        // ---- PV and P^2 Vv: fp16 hi-only (P x256, P^2 x1024) ----
        #pragma unroll
        for (int tt = 0; tt < 8; ++tt) {
            float p8[8], q8[8];
            #pragma unroll
            for (int e = 0; e < 4; ++e) {
                float p0 = sacc[2 * tt][e], p1 = sacc[2 * tt + 1][e];
                p8[e]     = p0 * 256.f;
                p8[4 + e] = p1 * 256.f;
                q8[e]     = p0 * p0 * 1024.f;
                q8[4 + e] = p1 * p1 * 1024.f;
            }
            uint32_t phi[4], p2h[4];
            #pragma unroll
            for (int e = 0; e < 4; ++e) {
                __half2 a = __floats2half2_rn(p8[2 * e], p8[2 * e + 1]);
                __half2 c = __floats2half2_rn(q8[2 * e], q8[2 * e + 1]);
                phi[e] = *(uint32_t*)&a;
                p2h[e] = *(uint32_t*)&c;
            }

            const uint32_t rowOff = (uint32_t)((tt * 16 + l15) * 128 + lHi);
            uint32_t vb[16];
            #pragma unroll
            for (int w = 0; w < 4; ++w) ldsm4t(vb + 4 * w, vB + SWZ(rowOff + w * 32));
            #pragma unroll
            for (int j = 0; j < 8; ++j)
                mma16816h(accC[j], phi, &vb[(j >> 1) * 4 + (j & 1) * 2]);
            #pragma unroll
            for (int w = 0; w < 4; ++w) ldsm4t(vb + 4 * w, vvB + SWZ(rowOff + w * 32));
            #pragma unroll
            for (int j = 0; j < 8; ++j)
                mma16816h(accV[j], p2h, &vb[(j >> 1) * 4 + (j & 1) * 2]);
        }
    }

    // ---- epilogue: write a2h (fp16x2 ctx), hC2 (fp16 ctx^2), var (fp32) ----
    const float i0 = 1.f / (256.f * rl0), i1 = 1.f / (256.f * rl1);
    const float w0 = 1.f / (1024.f * rl0 * rl0), w1 = 1.f / (1024.f * rl1 * rl1);
    const int row0 = qb + wid * 16 + rr;
    #pragma unroll
    for (int j = 0; j < 8; ++j) {
        int off = j * 8 + cpair;
        int col = hh * 64 + off;
        float cv[2][2] = {{accC[j][0] * i0, accC[j][1] * i0},
                          {accC[j][2] * i1, accC[j][3] * i1}};
        float uv[2][2] = {{accV[j][0] * w0, accV[j][1] * w0},
                          {accV[j][2] * w1, accV[j][3] * w1}};
        #pragma unroll
        for (int rr2 = 0; rr2 < 2; ++rr2) {
            size_t bn = (size_t)b * NSEQ + row0 + rr2 * 8;
            float c0 = cv[rr2][0], c1 = cv[rr2][1];
            float h0 = __half2float(__float2half_rn(c0));
            float h1 = __half2float(__float2half_rn(c1));
            __half2 hpk = __floats2half2_rn(h0, h1);
            __half2 lpk = __floats2half2_rn(c0 - h0, c1 - h1);
            __half* dst = a2h + bn * K2 + col;
            *(uint32_t*)dst          = *(uint32_t*)&hpk;
            *(uint32_t*)(dst + 1024) = *(uint32_t*)&lpk;
            __half2 hc = __floats2half2_rn(c0 * c0, c1 * c1);
            *(uint32_t*)(hC2 + bn * DM + col) = *(uint32_t*)&hc;
            *(float2*)(var + bn * DM + col) = make_float2(uv[rr2][0], uv[rr2][1]);
        }
    }
}

// ---------------------------------------------------------------------------
// Launcher
// ---------------------------------------------------------------------------
extern "C" void kernel_launch(void* const* d_in, const int* in_sizes, int n_in,
                              void* d_out, int out_size) {
    const float* H      = (const float*)d_in[0];
    const float* xr     = (const float*)d_in[1];
    const float* Wq     = (const float*)d_in[2];
    const float* bq     = (const float*)d_in[4];
    const float* Wk     = (const float*)d_in[6];
    const float* bk     = (const float*)d_in[8];
    const float* Wv     = (const float*)d_in[10];
    const float* Wv_rho = (const float*)d_in[11];
    const float* bv     = (const float*)d_in[12];
    const float* bv_rho = (const float*)d_in[13];
    const float* Wo     = (const float*)d_in[14];
    const float* Wo_rho = (const float*)d_in[15];
    const float* bo     = (const float*)d_in[16];
    const float* bo_rho = (const float*)d_in[17];
    const float* lsf    = (const float*)d_in[18];
    const float* lll    = (const float*)d_in[19];

    float *var, *d2, *bvs2, *bos2;
    __nv_bfloat16 *a3h, *b3q, *b3k, *q3p, *k3p;
    __half *hH2, *a2hp, *hWv2, *hWo2, *hA2, *hC2, *hVs, *hOs, *v2hp, *vv2hp;
    cudaGetSymbolAddress((void**)&var,  g_var);
    cudaGetSymbolAddress((void**)&d2,   g_d2);
    cudaGetSymbolAddress((void**)&bvs2, g_bvs2);
    cudaGetSymbolAddress((void**)&bos2, g_bos2);
    cudaGetSymbolAddress((void**)&a3h,  g_A3H);
    cudaGetSymbolAddress((void**)&b3q,  g_B3q);
    cudaGetSymbolAddress((void**)&b3k,  g_B3k);
    cudaGetSymbolAddress((void**)&hH2,  g_hH2);
    cudaGetSymbolAddress((void**)&a2hp, g_a2h);
    cudaGetSymbolAddress((void**)&hWv2, g_hWv2);
    cudaGetSymbolAddress((void**)&hWo2, g_hWo2);
    cudaGetSymbolAddress((void**)&hA2,  g_hA_H2);
    cudaGetSymbolAddress((void**)&hC2,  g_hC2);
    cudaGetSymbolAddress((void**)&hVs,  g_hB_vs2);
    cudaGetSymbolAddress((void**)&hOs,  g_hB_os2);
    cudaGetSymbolAddress((void**)&q3p,  g_q3);
    cudaGetSymbolAddress((void**)&k3p,  g_k3);
    cudaGetSymbolAddress((void**)&v2hp, g_v2h);
    cudaGetSymbolAddress((void**)&vv2hp, g_vv2h);

    cudaFuncSetAttribute(gemm_proj, cudaFuncAttributeMaxDynamicSharedMemorySize, SMEM_GEMM);
    cudaFuncSetAttribute(gemm_out,  cudaFuncAttributeMaxDynamicSharedMemorySize, SMEM_GEMM);
    cudaFuncSetAttribute(attn_tc,   cudaFuncAttributeMaxDynamicSharedMemorySize, ATTN_SMEM);

    // [0] both bias softplus^2
    bias2_kernel<<<8, 256>>>(bv_rho, bo_rho, bvs2, bos2);
    // [1] fused H prep: bf16x3 + fp16x2 + fp16 H^2 (one read)
    splitH_kernel<<<BN, 256>>>(H, a3h, hH2, hA2);
    // [2] Wq/Wk bf16x3 splits, [3] Wv/Wo fp16 dup, [4] rho fp16 converts
    wsplit2_kernel<<<dim3(DM, 2), 256>>>(Wq, Wk, b3q, b3k);
    wdup2_kernel<<<dim3(DM, 2), 256>>>(Wv, Wo, hWv2, hWo2);
    f16w2_kernel<<<dim3(DM, 2), 256>>>(Wv_rho, Wo_rho, hVs, hOs);
    // [5] fused projection GEMM: Q/K bf16x3, V fp16x2, Vv fp16x1
    gemm_proj<<<dim3(DM / BNT, BN / BM, 4), 256, SMEM_GEMM>>>(
        a3h, b3q, b3k, hH2, hWv2, hA2, hVs, bq, bk, bv, bvs2,
        q3p, k3p, v2hp, vv2hp);
    // [6] pairwise squared distances
    dist2_kernel<<<dim3(16, 16, BATCH), 256>>>(xr, d2);
    // [7] attention -> a2h / hC2 / var directly
    attn_tc<<<dim3(NSEQ / QB, BATCH * NH), 256, ATTN_SMEM>>>(
        q3p, k3p, v2hp, vv2hp, d2, lsf, lll, a2hp, hC2, var);
    // [8] fused output GEMM: out_mean fp16x2, out_var fp16x1 + var add
    float* out_mean = (float*)d_out;
    float* out_var  = out_mean + (size_t)BN * DM;
    gemm_out<<<dim3(DM / BNT, BN / BM, 2), 256, SMEM_GEMM>>>(
        a2hp, hWo2, bo, hC2, hOs, bos2, var, out_mean, out_var);
}

// round 13
// speedup vs baseline: 3.8954x; 1.0811x over previous
#include <cuda_runtime.h>
#include <cuda_bf16.h>
#include <cuda_fp16.h>
#include <math.h>
#include <stdint.h>

#define DM    1024
#define BATCH 8
#define NSEQ  1024
#define BN    (BATCH * NSEQ)
#define NH    16
#define DK    64
#define QSCALE 0.125f

#define K3      3072              // bf16x3 packed K (Q/K projections)
#define K2      2048              // fp16x2 packed K (V, out_mean)
#define BK      64
#define KITERS  (K3 / BK)         // 48
#define BM      128
#define BNT     128
#define STAGES  3
#define STAGE_BYTES ((BM + BNT) * 128)
#define SMEM_GEMM (STAGES * STAGE_BYTES)        // 96 KB

// attention tiling / smem (KT=128; Q/K fp16 128-wide = 2 chunks of 64)
#define QB 128
#define KT 128
#define SM_Q   0                  // 2 chunks x 128 x 128B = 32768
#define SM_K   32768              // 2 bufs x 2 chunks x 128 x 128B = 65536
#define SM_V   98304              // 2 bufs x 128 x 128B = 32768
#define SM_VV  131072             // 32768
#define ATTN_SMEM 163840

// ---------------------------------------------------------------------------
// Scratch
// ---------------------------------------------------------------------------
__device__ float g_var [BN * DM];
__device__ float g_d2  [BATCH * NSEQ * NSEQ];
__device__ float g_bvs2[DM];
__device__ float g_bos2[DM];

__device__ __nv_bfloat16 g_A3H [BN * K3];   // H bf16x3 [hi|lo|hi]
__device__ __nv_bfloat16 g_B3q [DM * K3];
__device__ __nv_bfloat16 g_B3k [DM * K3];

__device__ __half g_hH2  [BN * K2];         // H fp16x2 [hi|lo] (V GEMM A)
__device__ __half g_a2h  [BN * K2];         // ctx fp16x2 [hi|lo] (out_mean A)
__device__ __half g_hWv2 [DM * K2];         // Wv fp16 dup [hi|hi]
__device__ __half g_hWo2 [DM * K2];         // Wo fp16 dup [hi|hi]
__device__ __half g_hA_H2[BN * DM];         // fp16 H^2 (Vv A)
__device__ __half g_hC2  [BN * DM];         // fp16 ctx^2 (out_var A)
__device__ __half g_hB_vs2[DM * DM];        // fp16 softplus^2(Wv_rho)
__device__ __half g_hB_os2[DM * DM];        // fp16 softplus^2(Wo_rho)

__device__ __half g_q2 [BATCH * NH * NSEQ * 128];   // Q fp16 [hi|lo] head-major
__device__ __half g_k2 [BATCH * NH * NSEQ * 128];   // K fp16 [hi|hi] head-major
__device__ __half g_v2h [BATCH * NH * NSEQ * 64];
__device__ __half g_vv2h[BATCH * NH * NSEQ * 64];

// ---------------------------------------------------------------------------
// PTX helpers
// ---------------------------------------------------------------------------
__device__ __forceinline__ uint32_t smem_u32(const void* p) {
    uint32_t a;
    asm("{ .reg .u64 t; cvta.to.shared.u64 t, %1; cvt.u32.u64 %0, t; }"
        : "=r"(a) : "l"(p));
    return a;
}
#define SWZ(off) ((off) ^ (((off) >> 3) & 0x70))

__device__ __forceinline__ void cp16(uint32_t dst, const void* src) {
    asm volatile("cp.async.cg.shared.global [%0], [%1], 16;"
                 :: "r"(dst), "l"(src) : "memory");
}
#define CP_COMMIT() asm volatile("cp.async.commit_group;" ::: "memory")

__device__ __forceinline__ void ldsm4(uint32_t* r, uint32_t addr) {
    asm volatile("ldmatrix.sync.aligned.m8n8.x4.shared.b16 {%0,%1,%2,%3}, [%4];"
                 : "=r"(r[0]), "=r"(r[1]), "=r"(r[2]), "=r"(r[3]) : "r"(addr));
}
__device__ __forceinline__ void ldsm4t(uint32_t* r, uint32_t addr) {
    asm volatile("ldmatrix.sync.aligned.m8n8.x4.trans.shared.b16 {%0,%1,%2,%3}, [%4];"
                 : "=r"(r[0]), "=r"(r[1]), "=r"(r[2]), "=r"(r[3]) : "r"(addr));
}
__device__ __forceinline__ void mma16816(float* c, const uint32_t* a, const uint32_t* b) {
    asm volatile("mma.sync.aligned.m16n8k16.row.col.f32.bf16.bf16.f32 "
                 "{%0,%1,%2,%3}, {%4,%5,%6,%7}, {%8,%9}, {%0,%1,%2,%3};"
                 : "+f"(c[0]), "+f"(c[1]), "+f"(c[2]), "+f"(c[3])
                 : "r"(a[0]), "r"(a[1]), "r"(a[2]), "r"(a[3]), "r"(b[0]), "r"(b[1]));
}
__device__ __forceinline__ void mma16816h(float* c, const uint32_t* a, const uint32_t* b) {
    asm volatile("mma.sync.aligned.m16n8k16.row.col.f32.f16.f16.f32 "
                 "{%0,%1,%2,%3}, {%4,%5,%6,%7}, {%8,%9}, {%0,%1,%2,%3};"
                 : "+f"(c[0]), "+f"(c[1]), "+f"(c[2]), "+f"(c[3])
                 : "r"(a[0]), "r"(a[1]), "r"(a[2]), "r"(a[3]), "r"(b[0]), "r"(b[1]));
}
__device__ __forceinline__ uint32_t pack2(float lo, float hi) {
    uint32_t d;
    asm("cvt.rn.bf16x2.f32 %0, %1, %2;" : "=r"(d) : "f"(hi), "f"(lo));
    return d;
}

// ---------------------------------------------------------------------------
// elementwise prep kernels
// ---------------------------------------------------------------------------
__global__ void bias2_kernel(const float* __restrict__ a, const float* __restrict__ b,
                             float* __restrict__ oa, float* __restrict__ ob) {
    int i = blockIdx.x * 256 + threadIdx.x;
    const float* in  = (i < DM) ? a  : b;
    float*       out = (i < DM) ? oa : ob;
    int j = i & (DM - 1);
    float x  = in[j];
    float sp = (x > 15.f) ? x : log1pf(__expf(x));
    out[j] = sp * sp;
}

// fused H prep: bf16x3 [hi|lo|hi] + fp16x2 [hi|lo] + fp16 H^2 (one read of H)
__global__ void splitH_kernel(const float* __restrict__ X,
                              __nv_bfloat16* __restrict__ Y3,
                              __half* __restrict__ Y2, __half* __restrict__ Ysq) {
    int r  = blockIdx.x;
    int c4 = threadIdx.x;
    float4 x = *(const float4*)(X + (size_t)r * DM + c4 * 4);
    float v[4] = {x.x, x.y, x.z, x.w};
    unsigned short hu[4], lu[4];
    #pragma unroll
    for (int i = 0; i < 4; ++i) {
        __nv_bfloat16 hb = __float2bfloat16_rn(v[i]);
        float hr = __bfloat162float(hb);
        __nv_bfloat16 lb = __float2bfloat16_rn(v[i] - hr);
        hu[i] = __bfloat16_as_ushort(hb);
        lu[i] = __bfloat16_as_ushort(lb);
    }
    uint2 hp, lp;
    hp.x = (uint32_t)hu[0] | ((uint32_t)hu[1] << 16);
    hp.y = (uint32_t)hu[2] | ((uint32_t)hu[3] << 16);
    lp.x = (uint32_t)lu[0] | ((uint32_t)lu[1] << 16);
    lp.y = (uint32_t)lu[2] | ((uint32_t)lu[3] << 16);
    size_t ob3 = (size_t)r * K3 + c4 * 4;
    *(uint2*)(Y3 + ob3)          = hp;
    *(uint2*)(Y3 + ob3 + DM)     = lp;
    *(uint2*)(Y3 + ob3 + 2 * DM) = hp;
    float hh[4], ll[4];
    #pragma unroll
    for (int i = 0; i < 4; ++i) {
        hh[i] = __half2float(__float2half_rn(v[i]));
        ll[i] = v[i] - hh[i];
    }
    __half2 fh0 = __floats2half2_rn(hh[0], hh[1]);
    __half2 fh1 = __floats2half2_rn(hh[2], hh[3]);
    __half2 fl0 = __floats2half2_rn(ll[0], ll[1]);
    __half2 fl1 = __floats2half2_rn(ll[2], ll[3]);
    uint2 fp, fl;
    fp.x = *(uint32_t*)&fh0; fp.y = *(uint32_t*)&fh1;
    fl.x = *(uint32_t*)&fl0; fl.y = *(uint32_t*)&fl1;
    size_t ob2 = (size_t)r * K2 + c4 * 4;
    *(uint2*)(Y2 + ob2)      = fp;
    *(uint2*)(Y2 + ob2 + DM) = fl;
    __half2 s0 = __floats2half2_rn(v[0] * v[0], v[1] * v[1]);
    __half2 s1 = __floats2half2_rn(v[2] * v[2], v[3] * v[3]);
    uint2 sq;
    sq.x = *(uint32_t*)&s0;
    sq.y = *(uint32_t*)&s1;
    *(uint2*)(Ysq + (size_t)r * DM + c4 * 4) = sq;
}

// bf16x3 B-split of Wq / Wk ([hi|hi|lo]); grid (DM, 2)
__global__ void wsplit2_kernel(const float* __restrict__ W0, const float* __restrict__ W1,
                               __nv_bfloat16* __restrict__ Y0, __nv_bfloat16* __restrict__ Y1) {
    int z = blockIdx.y;
    const float* X = (z == 0) ? W0 : W1;
    __nv_bfloat16* Y = (z == 0) ? Y0 : Y1;
    int r  = blockIdx.x;
    int c4 = threadIdx.x;
    float4 x = *(const float4*)(X + (size_t)r * DM + c4 * 4);
    float v[4] = {x.x, x.y, x.z, x.w};
    unsigned short hu[4], lu[4];
    #pragma unroll
    for (int i = 0; i < 4; ++i) {
        __nv_bfloat16 hb = __float2bfloat16_rn(v[i]);
        float hr = __bfloat162float(hb);
        __nv_bfloat16 lb = __float2bfloat16_rn(v[i] - hr);
        hu[i] = __bfloat16_as_ushort(hb);
        lu[i] = __bfloat16_as_ushort(lb);
    }
    uint2 hp, lp;
    hp.x = (uint32_t)hu[0] | ((uint32_t)hu[1] << 16);
    hp.y = (uint32_t)hu[2] | ((uint32_t)hu[3] << 16);
    lp.x = (uint32_t)lu[0] | ((uint32_t)lu[1] << 16);
    lp.y = (uint32_t)lu[2] | ((uint32_t)lu[3] << 16);
    size_t ob = (size_t)r * K3 + c4 * 4;
    *(uint2*)(Y + ob)          = hp;
    *(uint2*)(Y + ob + DM)     = hp;
    *(uint2*)(Y + ob + 2 * DM) = lp;
}

// fp16 dup-convert of Wv / Wo to [hi|hi] (K2 wide); grid (DM, 2)
__global__ void wdup2_kernel(const float* __restrict__ W0, const float* __restrict__ W1,
                             __half* __restrict__ Y0, __half* __restrict__ Y1) {
    int z = blockIdx.y;
    const float* X = (z == 0) ? W0 : W1;
    __half* Y      = (z == 0) ? Y0 : Y1;
    int r  = blockIdx.x;
    int c4 = threadIdx.x;
    float4 x = *(const float4*)(X + (size_t)r * DM + c4 * 4);
    __half2 h0 = __floats2half2_rn(x.x, x.y);
    __half2 h1 = __floats2half2_rn(x.z, x.w);
    uint2 p;
    p.x = *(uint32_t*)&h0;
    p.y = *(uint32_t*)&h1;
    size_t ob = (size_t)r * K2 + c4 * 4;
    *(uint2*)(Y + ob)      = p;
    *(uint2*)(Y + ob + DM) = p;
}

// fp16 softplus^2 convert of both rho weights; grid (DM, 2)
__global__ void f16w2_kernel(const float* __restrict__ W0, const float* __restrict__ W1,
                             __half* __restrict__ Y0, __half* __restrict__ Y1) {
    int z = blockIdx.y;
    const float* X = (z == 0) ? W0 : W1;
    __half* Y      = (z == 0) ? Y0 : Y1;
    int row = blockIdx.x;
    int c4  = threadIdx.x;
    float4 x = *(const float4*)(X + (size_t)row * DM + c4 * 4);
    float v[4] = {x.x, x.y, x.z, x.w};
    #pragma unroll
    for (int i = 0; i < 4; ++i) {
        float sp = (v[i] > 15.f) ? v[i] : log1pf(__expf(v[i]));
        v[i] = sp * sp;
    }
    __half2 h0 = __floats2half2_rn(v[0], v[1]);
    __half2 h1 = __floats2half2_rn(v[2], v[3]);
    uint2 p;
    p.x = *(uint32_t*)&h0;
    p.y = *(uint32_t*)&h1;
    *(uint2*)(Y + (size_t)row * DM + c4 * 4) = p;
}

// ---------------------------------------------------------------------------
// GEMM mainloops (device functions)
// ---------------------------------------------------------------------------
__device__ __forceinline__ void gemm_main_bf16(
    const __nv_bfloat16* __restrict__ A3, const __nv_bfloat16* __restrict__ B3,
    char* smem, int mBase, int nBase, float acc[4][4][4]) {
    const uint32_t sb = smem_u32(smem);
    const int t    = threadIdx.x;
    const int wid  = t >> 5;
    const int lane = t & 31;
    const int wm   = wid & 1;
    const int wn   = wid >> 1;

    const int r  = t >> 1;
    const int uc = (t & 1) * 4;
    const __nv_bfloat16* aRow = A3 + (size_t)(mBase + r) * K3 + uc * 8;
    const __nv_bfloat16* bRow = B3 + (size_t)(nBase + r) * K3 + uc * 8;

    auto load_stage = [&](int buf, int c) {
        uint32_t sA = sb + buf * STAGE_BYTES;
        uint32_t sB = sA + BM * 128;
        const __nv_bfloat16* ga = aRow + c * BK;
        const __nv_bfloat16* gb = bRow + c * BK;
        #pragma unroll
        for (int i = 0; i < 4; ++i) {
            uint32_t bo = r * 128 + (uc + i) * 16;
            cp16(sA + SWZ(bo), ga + i * 8);
            cp16(sB + SWZ(bo), gb + i * 8);
        }
        CP_COMMIT();
    };

    const int aRowSel = (lane & 7) | (((lane >> 3) & 1) << 3);
    const int aKSel   = (lane >> 4) << 4;
    const int bNSel   = (lane & 7) | ((lane >> 4) << 3);
    const int bKSel   = ((lane >> 3) & 1) << 4;

    load_stage(0, 0);
    load_stage(1, 1);

    for (int kt = 0; kt < KITERS; ++kt) {
        const int buf = kt % STAGES;
        if (kt == KITERS - 1) asm volatile("cp.async.wait_group 0;" ::: "memory");
        else                  asm volatile("cp.async.wait_group 1;" ::: "memory");
        __syncthreads();

        if (kt + 2 < KITERS) load_stage((kt + 2) % STAGES, kt + 2);

        uint32_t sA = sb + buf * STAGE_BYTES;
        uint32_t sB = sA + BM * 128;
        #pragma unroll
        for (int ks = 0; ks < 4; ++ks) {
            uint32_t af[4][4], bfr2[2][4];
            #pragma unroll
            for (int mi = 0; mi < 4; ++mi) {
                uint32_t bo = (uint32_t)((wm * 64 + mi * 16 + aRowSel) * 128
                                         + ks * 32 + aKSel);
                ldsm4(af[mi], sA + SWZ(bo));
            }
            #pragma unroll
            for (int pi = 0; pi < 2; ++pi) {
                uint32_t bo = (uint32_t)((wn * 32 + pi * 16 + bNSel) * 128
                                         + ks * 32 + bKSel);
                ldsm4(bfr2[pi], sB + SWZ(bo));
            }
            #pragma unroll
            for (int mi = 0; mi < 4; ++mi)
                #pragma unroll
                for (int ni = 0; ni < 4; ++ni)
                    mma16816(acc[mi][ni], af[mi], &bfr2[ni >> 1][(ni & 1) * 2]);
        }
        __syncthreads();
    }
}

// fp16 mainloop with NITER k-chunks (stride NITER*BK per row)
template<int NITER>
__device__ __forceinline__ void gemm_main_h(
    const __half* __restrict__ A, const __half* __restrict__ B,
    char* smem, int mBase, int nBase, float acc[4][4][4]) {
    const uint32_t sb = smem_u32(smem);
    const int t    = threadIdx.x;
    const int wid  = t >> 5;
    const int lane = t & 31;
    const int wm   = wid & 1;
    const int wn   = wid >> 1;
    const int STRIDE = NITER * BK;

    const int r  = t >> 1;
    const int uc = (t & 1) * 4;
    const __half* aRow = A + (size_t)(mBase + r) * STRIDE + uc * 8;
    const __half* bRow = B + (size_t)(nBase + r) * STRIDE + uc * 8;

    auto load_stage = [&](int buf, int c) {
        uint32_t sA = sb + buf * STAGE_BYTES;
        uint32_t sB = sA + BM * 128;
        const __half* ga = aRow + c * BK;
        const __half* gb = bRow + c * BK;
        #pragma unroll
        for (int i = 0; i < 4; ++i) {
            uint32_t bo = r * 128 + (uc + i) * 16;
            cp16(sA + SWZ(bo), ga + i * 8);
            cp16(sB + SWZ(bo), gb + i * 8);
        }
        CP_COMMIT();
    };

    const int aRowSel = (lane & 7) | (((lane >> 3) & 1) << 3);
    const int aKSel   = (lane >> 4) << 4;
    const int bNSel   = (lane & 7) | ((lane >> 4) << 3);
    const int bKSel   = ((lane >> 3) & 1) << 4;

    load_stage(0, 0);
    load_stage(1, 1);

    for (int kt = 0; kt < NITER; ++kt) {
        const int buf = kt % STAGES;
        if (kt == NITER - 1) asm volatile("cp.async.wait_group 0;" ::: "memory");
        else                 asm volatile("cp.async.wait_group 1;" ::: "memory");
        __syncthreads();

        if (kt + 2 < NITER) load_stage((kt + 2) % STAGES, kt + 2);

        uint32_t sA = sb + buf * STAGE_BYTES;
        uint32_t sB = sA + BM * 128;
        #pragma unroll
        for (int ks = 0; ks < 4; ++ks) {
            uint32_t af[4][4], bfr2[2][4];
            #pragma unroll
            for (int mi = 0; mi < 4; ++mi) {
                uint32_t bo = (uint32_t)((wm * 64 + mi * 16 + aRowSel) * 128
                                         + ks * 32 + aKSel);
                ldsm4(af[mi], sA + SWZ(bo));
            }
            #pragma unroll
            for (int pi = 0; pi < 2; ++pi) {
                uint32_t bo = (uint32_t)((wn * 32 + pi * 16 + bNSel) * 128
                                         + ks * 32 + bKSel);
                ldsm4(bfr2[pi], sB + SWZ(bo));
            }
            #pragma unroll
            for (int mi = 0; mi < 4; ++mi)
                #pragma unroll
                for (int ni = 0; ni < 4; ++ni)
                    mma16816h(acc[mi][ni], af[mi], &bfr2[ni >> 1][(ni & 1) * 2]);
        }
        __syncthreads();
    }
}

// ---------------------------------------------------------------------------
// fused projection GEMM: z=0/1 -> Q/K (bf16x3, fp16 head-major epilogue),
// z=2 -> V (fp16x2), z=3 -> V-variance (fp16x1). grid (8, 64, 4).
// ---------------------------------------------------------------------------
__global__ void __launch_bounds__(256, 2)
gemm_proj(const __nv_bfloat16* __restrict__ A3,
          const __nv_bfloat16* __restrict__ B3q, const __nv_bfloat16* __restrict__ B3k,
          const __half* __restrict__ hH2, const __half* __restrict__ hWv2,
          const __half* __restrict__ hA2, const __half* __restrict__ hVs,
          const float* __restrict__ bq, const float* __restrict__ bk,
          const float* __restrict__ bv, const float* __restrict__ bvs2,
          __half* __restrict__ q2, __half* __restrict__ k2,
          __half* __restrict__ v2h, __half* __restrict__ vv2h) {
    extern __shared__ __align__(1024) char smem[];
    const int z = blockIdx.z;
    const int mBase = blockIdx.y * BM;
    const int nBase = blockIdx.x * BNT;
    float acc[4][4][4] = {};

    if (z < 2) {
        gemm_main_bf16(A3, (z == 0) ? B3q : B3k, smem, mBase, nBase, acc);
    } else if (z == 2) {
        gemm_main_h<32>(hH2, hWv2, smem, mBase, nBase, acc);
    } else {
        gemm_main_h<16>(hA2, hVs, smem, mBase, nBase, acc);
    }

    const float* bias = (z == 0) ? bq : (z == 1) ? bk : (z == 2) ? bv : bvs2;
    const int wid  = threadIdx.x >> 5;
    const int lane = threadIdx.x & 31;
    const int lr = lane >> 2;
    const int lc = (lane & 3) * 2;
    const int rB = mBase + (wid & 1) * 64;
    const int cB = nBase + (wid >> 1) * 32;
    #pragma unroll
    for (int mi = 0; mi < 4; ++mi) {
        #pragma unroll
        for (int ni = 0; ni < 4; ++ni) {
            int col  = cB + ni * 8 + lc;
            int row0 = rB + mi * 16 + lr;
            int h = col >> 6, dl = col & 63;
            float2 bi = *(const float2*)(bias + col);
            float vx[2][2] = {{acc[mi][ni][0] + bi.x, acc[mi][ni][1] + bi.y},
                              {acc[mi][ni][2] + bi.x, acc[mi][ni][3] + bi.y}};
            #pragma unroll
            for (int rr2 = 0; rr2 < 2; ++rr2) {
                int row = row0 + rr2 * 8;
                int b = row >> 10, n = row & 1023;
                if (z >= 2) {
                    __half* dst = (z == 2) ? v2h : vv2h;
                    __half2 hv = __floats2half2_rn(vx[rr2][0], vx[rr2][1]);
                    *(uint32_t*)(dst + ((size_t)(b * NH + h) * NSEQ + n) * 64 + dl)
                        = *(uint32_t*)&hv;
                } else {
                    float h0 = __half2float(__float2half_rn(vx[rr2][0]));
                    float h1 = __half2float(__float2half_rn(vx[rr2][1]));
                    __half2 hpk = __floats2half2_rn(h0, h1);
                    __half* dst = ((z == 0) ? q2 : k2)
                        + ((size_t)(b * NH + h) * NSEQ + n) * 128 + dl;
                    *(uint32_t*)dst = *(uint32_t*)&hpk;
                    if (z == 0) {
                        __half2 lpk = __floats2half2_rn(vx[rr2][0] - h0, vx[rr2][1] - h1);
                        *(uint32_t*)(dst + 64) = *(uint32_t*)&lpk;
                    } else {
                        *(uint32_t*)(dst + 64) = *(uint32_t*)&hpk;
                    }
                }
            }
        }
    }
}

// ---------------------------------------------------------------------------
// fused output GEMM: z=0 -> out_mean (fp16x2), z=1 -> out_var (fp16x1 + add).
// ---------------------------------------------------------------------------
__global__ void __launch_bounds__(256, 2)
gemm_out(const __half* __restrict__ a2h, const __half* __restrict__ hWo2,
         const float* __restrict__ bo,
         const __half* __restrict__ hC2, const __half* __restrict__ hOs,
         const float* __restrict__ bos2, const float* __restrict__ var,
         float* __restrict__ out_mean, float* __restrict__ out_var) {
    extern __shared__ __align__(1024) char smem[];
    const int z = blockIdx.z;
    const int mBase = blockIdx.y * BM;
    const int nBase = blockIdx.x * BNT;
    float acc[4][4][4] = {};

    if (z == 0) gemm_main_h<32>(a2h, hWo2, smem, mBase, nBase, acc);
    else        gemm_main_h<16>(hC2, hOs, smem, mBase, nBase, acc);

    const float* bias = (z == 0) ? bo : bos2;
    float* C          = (z == 0) ? out_mean : out_var;
    const int wid  = threadIdx.x >> 5;
    const int lane = threadIdx.x & 31;
    const int lr = lane >> 2;
    const int lc = (lane & 3) * 2;
    const int rB = mBase + (wid & 1) * 64;
    const int cB = nBase + (wid >> 1) * 32;
    #pragma unroll
    for (int mi = 0; mi < 4; ++mi) {
        #pragma unroll
        for (int ni = 0; ni < 4; ++ni) {
            int col  = cB + ni * 8 + lc;
            int row0 = rB + mi * 16 + lr;
            float2 bi = *(const float2*)(bias + col);
            float vx[2][2] = {{acc[mi][ni][0] + bi.x, acc[mi][ni][1] + bi.y},
                              {acc[mi][ni][2] + bi.x, acc[mi][ni][3] + bi.y}};
            #pragma unroll
            for (int rr2 = 0; rr2 < 2; ++rr2) {
                size_t o = (size_t)(row0 + rr2 * 8) * DM + col;
                if (z == 1) {
                    float2 a2 = *(const float2*)(var + o);
                    vx[rr2][0] += a2.x; vx[rr2][1] += a2.y;
                }
                *(float2*)(C + o) = make_float2(vx[rr2][0], vx[rr2][1]);
            }
        }
    }
}

// ---------------------------------------------------------------------------
// dist2 (unchanged)
// ---------------------------------------------------------------------------
__global__ void dist2_kernel(const float* __restrict__ xr, float* __restrict__ d2) {
    __shared__ float xm[64][17];
    __shared__ float xn[64][17];
    __shared__ float x2m[64];
    __shared__ float x2n[64];

    const int t  = threadIdx.x;
    const int b  = blockIdx.z;
    const int mi = blockIdx.y * 64;
    const int nj = blockIdx.x * 64;

    for (int idx = t; idx < 64 * 4; idx += 256) {
        int r = idx >> 2, c = (idx & 3) * 4;
        float4 a = *(const float4*)(xr + ((size_t)b * NSEQ + mi + r) * 16 + c);
        xm[r][c] = a.x; xm[r][c+1] = a.y; xm[r][c+2] = a.z; xm[r][c+3] = a.w;
        float4 bb = *(const float4*)(xr + ((size_t)b * NSEQ + nj + r) * 16 + c);
        xn[r][c] = bb.x; xn[r][c+1] = bb.y; xn[r][c+2] = bb.z; xn[r][c+3] = bb.w;
    }
    __syncthreads();

    if (t < 64) {
        float s = 0.f;
        #pragma unroll
        for (int c = 0; c < 16; ++c) s += xm[t][c] * xm[t][c];
        x2m[t] = s;
    } else if (t < 128) {
        int r = t - 64;
        float s = 0.f;
        #pragma unroll
        for (int c = 0; c < 16; ++c) s += xn[r][c] * xn[r][c];
        x2n[r] = s;
    }
    __syncthreads();

    const int tx = t & 15, ty = t >> 4;
    #pragma unroll
    for (int i = 0; i < 4; ++i) {
        int row = ty * 4 + i;
        float out4[4];
        #pragma unroll
        for (int j = 0; j < 4; ++j) {
            int col = tx * 4 + j;
            float dot = 0.f;
            #pragma unroll
            for (int c = 0; c < 16; ++c) dot += xm[row][c] * xn[col][c];
            out4[j] = fmaxf(x2m[row] + x2n[col] - 2.f * dot, 0.f);
        }
        float4 v4 = make_float4(out4[0], out4[1], out4[2], out4[3]);
        *(float4*)(d2 + ((size_t)b * NSEQ + mi + row) * NSEQ + nj + tx * 4) = v4;
    }
}

// ---------------------------------------------------------------------------
// Tensor-core flash attention, KT=128. S fp16x2 (Q [hi|lo] x K [hi|hi]);
// PV fp16 hi-only (P x256); P^2 Vv fp16 hi-only (P^2 x1024).
// Epilogue writes a2h (fp16x2 ctx), hC2 (fp16 ctx^2), var (fp32).
// ---------------------------------------------------------------------------
__global__ void __launch_bounds__(256, 1)
attn_tc(const __half* __restrict__ q2, const __half* __restrict__ k2,
        const __half* __restrict__ v2h, const __half* __restrict__ vv2h,
        const float* __restrict__ d2g,
        const float* __restrict__ lsf, const float* __restrict__ lll,
        __half* __restrict__ a2h, __half* __restrict__ hC2,
        float* __restrict__ var) {
    extern __shared__ __align__(1024) char smem[];
    const uint32_t sb = smem_u32(smem);
    const int t    = threadIdx.x;
    const int wid  = t >> 5;
    const int lane = t & 31;
    const int qb   = blockIdx.x * QB;
    const int bh   = blockIdx.y;
    const int b    = bh >> 4, hh = bh & 15;

    const float sigma_f2 = __expf(2.f * lsf[hh]);
    const float coef     = 0.5f * __expf(-2.f * lll[hh]);

    const __half* Qg  = q2   + ((size_t)bh * NSEQ + qb) * 128;
    const __half* Kg  = k2   + (size_t)bh * NSEQ * 128;
    const __half* Vg  = v2h  + (size_t)bh * NSEQ * 64;
    const __half* VVg = vv2h + (size_t)bh * NSEQ * 64;

    // Q load: 128 rows x 16 units (2 chunks of 64 fp16)
    for (int i = t; i < QB * 16; i += 256) {
        int row = i >> 4, u = i & 15;
        cp16(sb + SM_Q + (u >> 3) * 16384 + SWZ((uint32_t)(row * 128 + (u & 7) * 16)),
             Qg + (size_t)row * 128 + u * 8);
    }

    auto load_kv = [&](int buf, int kt) {
        const __half* kg = Kg + (size_t)kt * KT * 128;
        for (int i = t; i < KT * 16; i += 256) {
            int row = i >> 4, u = i & 15;
            cp16(sb + SM_K + buf * 32768 + (u >> 3) * 16384
                    + SWZ((uint32_t)(row * 128 + (u & 7) * 16)),
                 kg + (size_t)row * 128 + u * 8);
        }
        const __half* vg = Vg  + (size_t)kt * KT * 64;
        const __half* wg = VVg + (size_t)kt * KT * 64;
        for (int i = t; i < KT * 8; i += 256) {
            int row = i >> 3, u = i & 7;
            uint32_t so = SWZ((uint32_t)(row * 128 + u * 16));
            cp16(sb + SM_V  + buf * 16384 + so, vg + (size_t)row * 64 + u * 8);
            cp16(sb + SM_VV + buf * 16384 + so, wg + (size_t)row * 64 + u * 8);
        }
        CP_COMMIT();
    };
    load_kv(0, 0);

    const int l15 = lane & 15;
    const int lHi = (lane >> 4) << 4;
    const uint32_t aRowOff = (uint32_t)((wid * 16 + l15) * 128 + lHi);
    const int g    = lane >> 3;
    const int keyl = ((g >> 1) << 3) + (lane & 7);
    const uint32_t kCol = (uint32_t)((g & 1) << 4);
    const int rr    = lane >> 2;
    const int cpair = (lane & 3) * 2;

    float accC[8][4] = {}, accV[8][4] = {};
    float rm0 = -1e30f, rm1 = -1e30f, rl0 = 0.f, rl1 = 0.f;

    for (int kt = 0; kt < NSEQ / KT; ++kt) {
        if (kt + 1 < NSEQ / KT) { __syncthreads(); load_kv((kt + 1) & 1, kt + 1); }
        if (kt + 1 < NSEQ / KT) asm volatile("cp.async.wait_group 1;" ::: "memory");
        else                    asm volatile("cp.async.wait_group 0;" ::: "memory");
        __syncthreads();

        const int buf = kt & 1;
        const uint32_t kB  = sb + SM_K  + buf * 32768;
        const uint32_t vB  = sb + SM_V  + buf * 16384;
        const uint32_t vvB = sb + SM_VV + buf * 16384;

        float sacc[16][4];
        #pragma unroll
        for (int j = 0; j < 16; ++j)
            #pragma unroll
            for (int e = 0; e < 4; ++e) sacc[j][e] = 0.f;

        // ---- S = Q2 . K2^T over 128 packed fp16 dims ----
        #pragma unroll
        for (int ks = 0; ks < 8; ++ks) {
            uint32_t a[4];
            ldsm4(a, sb + SM_Q + (ks >> 2) * 16384 + SWZ(aRowOff + (ks & 3) * 32));
            #pragma unroll
            for (int n0 = 0; n0 < 8; ++n0) {
                uint32_t kb4[4];
                ldsm4(kb4, kB + (ks >> 2) * 16384
                         + SWZ((uint32_t)((n0 * 16 + keyl) * 128) + (ks & 3) * 32 + kCol));
                mma16816h(sacc[2 * n0],     a, kb4);
                mma16816h(sacc[2 * n0 + 1], a, kb4 + 2);
            }
        }

        const int kb0 = kt * KT;
        const float* d2r0 = d2g + (size_t)b * NSEQ * NSEQ
                          + (size_t)(qb + wid * 16 + rr) * NSEQ + kb0;
        const float* d2r1 = d2r0 + 8 * NSEQ;
        #pragma unroll
        for (int j = 0; j < 16; ++j) {
            float2 da = *(const float2*)(d2r0 + j * 8 + cpair);
            float2 db = *(const float2*)(d2r1 + j * 8 + cpair);
            sacc[j][0] = sacc[j][0] * QSCALE + sigma_f2 * __expf(-da.x * coef);
            sacc[j][1] = sacc[j][1] * QSCALE + sigma_f2 * __expf(-da.y * coef);
            sacc[j][2] = sacc[j][2] * QSCALE + sigma_f2 * __expf(-db.x * coef);
            sacc[j][3] = sacc[j][3] * QSCALE + sigma_f2 * __expf(-db.y * coef);
        }
        float mx0 = -1e30f, mx1 = -1e30f;
        #pragma unroll
        for (int j = 0; j < 16; ++j) {
            mx0 = fmaxf(mx0, fmaxf(sacc[j][0], sacc[j][1]));
            mx1 = fmaxf(mx1, fmaxf(sacc[j][2], sacc[j][3]));
        }
        mx0 = fmaxf(mx0, __shfl_xor_sync(0xffffffffu, mx0, 1));
        mx0 = fmaxf(mx0, __shfl_xor_sync(0xffffffffu, mx0, 2));
        mx1 = fmaxf(mx1, __shfl_xor_sync(0xffffffffu, mx1, 1));
        mx1 = fmaxf(mx1, __shfl_xor_sync(0xffffffffu, mx1, 2));
        float m0n = fmaxf(rm0, mx0), m1n = fmaxf(rm1, mx1);
        float f0 = __expf(rm0 - m0n), f1 = __expf(rm1 - m1n);
        rm0 = m0n; rm1 = m1n;
        float sum0 = 0.f, sum1 = 0.f;
        #pragma unroll
        for (int j = 0; j < 16; ++j) {
            sacc[j][0] = __expf(sacc[j][0] - m0n); sum0 += sacc[j][0];
            sacc[j][1] = __expf(sacc[j][1] - m0n); sum0 += sacc[j][1];
            sacc[j][2] = __expf(sacc[j][2] - m1n); sum1 += sacc[j][2];
            sacc[j][3] = __expf(sacc[j][3] - m1n); sum1 += sacc[j][3];
        }
        sum0 += __shfl_xor_sync(0xffffffffu, sum0, 1);
        sum0 += __shfl_xor_sync(0xffffffffu, sum0, 2);
        sum1 += __shfl_xor_sync(0xffffffffu, sum1, 1);
        sum1 += __shfl_xor_sync(0xffffffffu, sum1, 2);
        rl0 = rl0 * f0 + sum0;
        rl1 = rl1 * f1 + sum1;
        float f02 = f0 * f0, f12 = f1 * f1;
        #pragma unroll
        for (int j = 0; j < 8; ++j) {
            accC[j][0] *= f0;  accC[j][1] *= f0;
            accC[j][2] *= f1;  accC[j][3] *= f1;
            accV[j][0] *= f02; accV[j][1] *= f02;
            accV[j][2] *= f12; accV[j][3] *= f12;
        }

        // ---- PV and P^2 Vv: fp16 hi-only (P x256, P^2 x1024) ----
        #pragma unroll
        for (int tt = 0; tt < 8; ++tt) {
            float p8[8], q8[8];
            #pragma unroll
            for (int e = 0; e < 4; ++e) {
                float p0 = sacc[2 * tt][e], p1 = sacc[2 * tt + 1][e];
                p8[e]     = p0 * 256.f;
                p8[4 + e] = p1 * 256.f;
                q8[e]     = p0 * p0 * 1024.f;
                q8[4 + e] = p1 * p1 * 1024.f;
            }
            uint32_t phi[4], p2h[4];
            #pragma unroll
            for (int e = 0; e < 4; ++e) {
                __half2 a = __floats2half2_rn(p8[2 * e], p8[2 * e + 1]);
                __half2 c = __floats2half2_rn(q8[2 * e], q8[2 * e + 1]);
                phi[e] = *(uint32_t*)&a;
                p2h[e] = *(uint32_t*)&c;
            }

            const uint32_t rowOff = (uint32_t)((tt * 16 + l15) * 128 + lHi);
            uint32_t vb[16];
            #pragma unroll
            for (int w = 0; w < 4; ++w) ldsm4t(vb + 4 * w, vB + SWZ(rowOff + w * 32));
            #pragma unroll
            for (int j = 0; j < 8; ++j)
                mma16816h(accC[j], phi, &vb[(j >> 1) * 4 + (j & 1) * 2]);
            #pragma unroll
            for (int w = 0; w < 4; ++w) ldsm4t(vb + 4 * w, vvB + SWZ(rowOff + w * 32));
            #pragma unroll
            for (int j = 0; j < 8; ++j)
                mma16816h(accV[j], p2h, &vb[(j >> 1) * 4 + (j & 1) * 2]);
        }
    }

    // ---- epilogue: write a2h (fp16x2 ctx), hC2 (fp16 ctx^2), var (fp32) ----
    const float i0 = 1.f / (256.f * rl0), i1 = 1.f / (256.f * rl1);
    const float w0 = 1.f / (1024.f * rl0 * rl0), w1 = 1.f / (1024.f * rl1 * rl1);
    const int row0 = qb + wid * 16 + rr;
    #pragma unroll
    for (int j = 0; j < 8; ++j) {
        int off = j * 8 + cpair;
        int col = hh * 64 + off;
        float cv[2][2] = {{accC[j][0] * i0, accC[j][1] * i0},
                          {accC[j][2] * i1, accC[j][3] * i1}};
        float uv[2][2] = {{accV[j][0] * w0, accV[j][1] * w0},
                          {accV[j][2] * w1, accV[j][3] * w1}};
        #pragma unroll
        for (int rr2 = 0; rr2 < 2; ++rr2) {
            size_t bn = (size_t)b * NSEQ + row0 + rr2 * 8;
            float c0 = cv[rr2][0], c1 = cv[rr2][1];
            float h0 = __half2float(__float2half_rn(c0));
            float h1 = __half2float(__float2half_rn(c1));
            __half2 hpk = __floats2half2_rn(h0, h1);
            __half2 lpk = __floats2half2_rn(c0 - h0, c1 - h1);
            __half* dst = a2h + bn * K2 + col;
            *(uint32_t*)dst          = *(uint32_t*)&hpk;
            *(uint32_t*)(dst + 1024) = *(uint32_t*)&lpk;
            __half2 hc = __floats2half2_rn(c0 * c0, c1 * c1);
            *(uint32_t*)(hC2 + bn * DM + col) = *(uint32_t*)&hc;
            *(float2*)(var + bn * DM + col) = make_float2(uv[rr2][0], uv[rr2][1]);
        }
    }
}

// ---------------------------------------------------------------------------
// Launcher
// ---------------------------------------------------------------------------
extern "C" void kernel_launch(void* const* d_in, const int* in_sizes, int n_in,
                              void* d_out, int out_size) {
    const float* H      = (const float*)d_in[0];
    const float* xr     = (const float*)d_in[1];
    const float* Wq     = (const float*)d_in[2];
    const float* bq     = (const float*)d_in[4];
    const float* Wk     = (const float*)d_in[6];
    const float* bk     = (const float*)d_in[8];
    const float* Wv     = (const float*)d_in[10];
    const float* Wv_rho = (const float*)d_in[11];
    const float* bv     = (const float*)d_in[12];
    const float* bv_rho = (const float*)d_in[13];
    const float* Wo     = (const float*)d_in[14];
    const float* Wo_rho = (const float*)d_in[15];
    const float* bo     = (const float*)d_in[16];
    const float* bo_rho = (const float*)d_in[17];
    const float* lsf    = (const float*)d_in[18];
    const float* lll    = (const float*)d_in[19];

    float *var, *d2, *bvs2, *bos2;
    __nv_bfloat16 *a3h, *b3q, *b3k;
    __half *hH2, *a2hp, *hWv2, *hWo2, *hA2, *hC2, *hVs, *hOs;
    __half *q2p, *k2p, *v2hp, *vv2hp;
    cudaGetSymbolAddress((void**)&var,  g_var);
    cudaGetSymbolAddress((void**)&d2,   g_d2);
    cudaGetSymbolAddress((void**)&bvs2, g_bvs2);
    cudaGetSymbolAddress((void**)&bos2, g_bos2);
    cudaGetSymbolAddress((void**)&a3h,  g_A3H);
    cudaGetSymbolAddress((void**)&b3q,  g_B3q);
    cudaGetSymbolAddress((void**)&b3k,  g_B3k);
    cudaGetSymbolAddress((void**)&hH2,  g_hH2);
    cudaGetSymbolAddress((void**)&a2hp, g_a2h);
    cudaGetSymbolAddress((void**)&hWv2, g_hWv2);
    cudaGetSymbolAddress((void**)&hWo2, g_hWo2);
    cudaGetSymbolAddress((void**)&hA2,  g_hA_H2);
    cudaGetSymbolAddress((void**)&hC2,  g_hC2);
    cudaGetSymbolAddress((void**)&hVs,  g_hB_vs2);
    cudaGetSymbolAddress((void**)&hOs,  g_hB_os2);
    cudaGetSymbolAddress((void**)&q2p,  g_q2);
    cudaGetSymbolAddress((void**)&k2p,  g_k2);
    cudaGetSymbolAddress((void**)&v2hp, g_v2h);
    cudaGetSymbolAddress((void**)&vv2hp, g_vv2h);

    cudaFuncSetAttribute(gemm_proj, cudaFuncAttributeMaxDynamicSharedMemorySize, SMEM_GEMM);
    cudaFuncSetAttribute(gemm_out,  cudaFuncAttributeMaxDynamicSharedMemorySize, SMEM_GEMM);
    cudaFuncSetAttribute(attn_tc,   cudaFuncAttributeMaxDynamicSharedMemorySize, ATTN_SMEM);

    // [0] both bias softplus^2
    bias2_kernel<<<8, 256>>>(bv_rho, bo_rho, bvs2, bos2);
    // [1] fused H prep: bf16x3 + fp16x2 + fp16 H^2 (one read)
    splitH_kernel<<<BN, 256>>>(H, a3h, hH2, hA2);
    // [2] Wq/Wk bf16x3 splits, [3] Wv/Wo fp16 dup, [4] rho fp16 converts
    wsplit2_kernel<<<dim3(DM, 2), 256>>>(Wq, Wk, b3q, b3k);
    wdup2_kernel<<<dim3(DM, 2), 256>>>(Wv, Wo, hWv2, hWo2);
    f16w2_kernel<<<dim3(DM, 2), 256>>>(Wv_rho, Wo_rho, hVs, hOs);
    // [5] fused projection GEMM: Q/K bf16x3 -> fp16 head-major, V fp16x2, Vv fp16x1
    gemm_proj<<<dim3(DM / BNT, BN / BM, 4), 256, SMEM_GEMM>>>(
        a3h, b3q, b3k, hH2, hWv2, hA2, hVs, bq, bk, bv, bvs2,
        q2p, k2p, v2hp, vv2hp);
    // [6] pairwise squared distances
    dist2_kernel<<<dim3(16, 16, BATCH), 256>>>(xr, d2);
    // [7] attention -> a2h / hC2 / var directly
    attn_tc<<<dim3(NSEQ / QB, BATCH * NH), 256, ATTN_SMEM>>>(
        q2p, k2p, v2hp, vv2hp, d2, lsf, lll, a2hp, hC2, var);
    // [8] fused output GEMM: out_mean fp16x2, out_var fp16x1 + var add
    float* out_mean = (float*)d_out;
    float* out_var  = out_mean + (size_t)BN * DM;
    gemm_out<<<dim3(DM / BNT, BN / BM, 2), 256, SMEM_GEMM>>>(
        a2hp, hWo2, bo, hC2, hOs, bos2, var, out_mean, out_var);
}

// round 14
// speedup vs baseline: 4.3765x; 1.1235x over previous
#include <cuda_runtime.h>
#include <cuda_fp16.h>
#include <math.h>
#include <stdint.h>

#define DM    1024
#define BATCH 8
#define NSEQ  1024
#define BN    (BATCH * NSEQ)
#define NH    16
#define DK    64
#define QSCALE 0.125f

#define K2      2048              // fp16x2 packed K
#define BK      64
#define BM      128
#define BNT     128
#define STAGES  3
#define STAGE_BYTES ((BM + BNT) * 128)
#define SMEM_GEMM (STAGES * STAGE_BYTES)        // 96 KB

// attention tiling / smem (KT=128; Q/K fp16 128-wide = 2 chunks of 64)
#define QB 128
#define KT 128
#define SM_Q   0                  // 2 chunks x 128 x 128B = 32768
#define SM_K   32768              // 2 bufs x 2 chunks x 128 x 128B = 65536
#define SM_V   98304              // 2 bufs x 128 x 128B = 32768
#define SM_VV  131072             // 32768
#define ATTN_SMEM 163840

// ---------------------------------------------------------------------------
// Scratch
// ---------------------------------------------------------------------------
__device__ float g_var [BN * DM];
__device__ float g_d2  [BATCH * NSEQ * NSEQ];
__device__ float g_bvs2[DM];
__device__ float g_bos2[DM];

__device__ __half g_hH2  [BN * K2];         // H fp16x2 [hi|lo] (Q/K/V GEMM A)
__device__ __half g_a2h  [BN * K2];         // ctx fp16x2 [hi|lo] (out_mean A)
__device__ __half g_hWq2 [DM * K2];         // Wq fp16 dup [hi|hi]
__device__ __half g_hWk2 [DM * K2];         // Wk fp16 dup [hi|hi]
__device__ __half g_hWv2 [DM * K2];         // Wv fp16 dup [hi|hi]
__device__ __half g_hWo2 [DM * K2];         // Wo fp16 dup [hi|hi]
__device__ __half g_hA_H2[BN * DM];         // fp16 H^2 (Vv A)
__device__ __half g_hC2  [BN * DM];         // fp16 ctx^2 (out_var A)
__device__ __half g_hB_vs2[DM * DM];        // fp16 softplus^2(Wv_rho)
__device__ __half g_hB_os2[DM * DM];        // fp16 softplus^2(Wo_rho)

__device__ __half g_q2 [BATCH * NH * NSEQ * 128];   // Q fp16 [hi|lo] head-major
__device__ __half g_k2 [BATCH * NH * NSEQ * 128];   // K fp16 [hi|hi] head-major
__device__ __half g_v2h [BATCH * NH * NSEQ * 64];
__device__ __half g_vv2h[BATCH * NH * NSEQ * 64];

// ---------------------------------------------------------------------------
// PTX helpers
// ---------------------------------------------------------------------------
__device__ __forceinline__ uint32_t smem_u32(const void* p) {
    uint32_t a;
    asm("{ .reg .u64 t; cvta.to.shared.u64 t, %1; cvt.u32.u64 %0, t; }"
        : "=r"(a) : "l"(p));
    return a;
}
#define SWZ(off) ((off) ^ (((off) >> 3) & 0x70))

__device__ __forceinline__ void cp16(uint32_t dst, const void* src) {
    asm volatile("cp.async.cg.shared.global [%0], [%1], 16;"
                 :: "r"(dst), "l"(src) : "memory");
}
#define CP_COMMIT() asm volatile("cp.async.commit_group;" ::: "memory")

__device__ __forceinline__ void ldsm4(uint32_t* r, uint32_t addr) {
    asm volatile("ldmatrix.sync.aligned.m8n8.x4.shared.b16 {%0,%1,%2,%3}, [%4];"
                 : "=r"(r[0]), "=r"(r[1]), "=r"(r[2]), "=r"(r[3]) : "r"(addr));
}
__device__ __forceinline__ void ldsm4t(uint32_t* r, uint32_t addr) {
    asm volatile("ldmatrix.sync.aligned.m8n8.x4.trans.shared.b16 {%0,%1,%2,%3}, [%4];"
                 : "=r"(r[0]), "=r"(r[1]), "=r"(r[2]), "=r"(r[3]) : "r"(addr));
}
__device__ __forceinline__ void mma16816h(float* c, const uint32_t* a, const uint32_t* b) {
    asm volatile("mma.sync.aligned.m16n8k16.row.col.f32.f16.f16.f32 "
                 "{%0,%1,%2,%3}, {%4,%5,%6,%7}, {%8,%9}, {%0,%1,%2,%3};"
                 : "+f"(c[0]), "+f"(c[1]), "+f"(c[2]), "+f"(c[3])
                 : "r"(a[0]), "r"(a[1]), "r"(a[2]), "r"(a[3]), "r"(b[0]), "r"(b[1]));
}

// ---------------------------------------------------------------------------
// elementwise prep kernels
// ---------------------------------------------------------------------------
__global__ void bias2_kernel(const float* __restrict__ a, const float* __restrict__ b,
                             float* __restrict__ oa, float* __restrict__ ob) {
    int i = blockIdx.x * 256 + threadIdx.x;
    const float* in  = (i < DM) ? a  : b;
    float*       out = (i < DM) ? oa : ob;
    int j = i & (DM - 1);
    float x  = in[j];
    float sp = (x > 15.f) ? x : log1pf(__expf(x));
    out[j] = sp * sp;
}

// fused H prep: fp16x2 [hi|lo] + fp16 H^2 (one read of H)
__global__ void splitH_kernel(const float* __restrict__ X,
                              __half* __restrict__ Y2, __half* __restrict__ Ysq) {
    int r  = blockIdx.x;
    int c4 = threadIdx.x;
    float4 x = *(const float4*)(X + (size_t)r * DM + c4 * 4);
    float v[4] = {x.x, x.y, x.z, x.w};
    float hh[4], ll[4];
    #pragma unroll
    for (int i = 0; i < 4; ++i) {
        hh[i] = __half2float(__float2half_rn(v[i]));
        ll[i] = v[i] - hh[i];
    }
    __half2 fh0 = __floats2half2_rn(hh[0], hh[1]);
    __half2 fh1 = __floats2half2_rn(hh[2], hh[3]);
    __half2 fl0 = __floats2half2_rn(ll[0], ll[1]);
    __half2 fl1 = __floats2half2_rn(ll[2], ll[3]);
    uint2 fp, fl;
    fp.x = *(uint32_t*)&fh0; fp.y = *(uint32_t*)&fh1;
    fl.x = *(uint32_t*)&fl0; fl.y = *(uint32_t*)&fl1;
    size_t ob2 = (size_t)r * K2 + c4 * 4;
    *(uint2*)(Y2 + ob2)      = fp;
    *(uint2*)(Y2 + ob2 + DM) = fl;
    __half2 s0 = __floats2half2_rn(v[0] * v[0], v[1] * v[1]);
    __half2 s1 = __floats2half2_rn(v[2] * v[2], v[3] * v[3]);
    uint2 sq;
    sq.x = *(uint32_t*)&s0;
    sq.y = *(uint32_t*)&s1;
    *(uint2*)(Ysq + (size_t)r * DM + c4 * 4) = sq;
}

// fp16 dup-convert of 4 weight matrices to [hi|hi] (K2 wide); grid (DM, 4)
__global__ void wdup4_kernel(const float* __restrict__ W0, const float* __restrict__ W1,
                             const float* __restrict__ W2, const float* __restrict__ W3,
                             __half* __restrict__ Y0, __half* __restrict__ Y1,
                             __half* __restrict__ Y2, __half* __restrict__ Y3) {
    int z = blockIdx.y;
    const float* X = (z == 0) ? W0 : (z == 1) ? W1 : (z == 2) ? W2 : W3;
    __half* Y      = (z == 0) ? Y0 : (z == 1) ? Y1 : (z == 2) ? Y2 : Y3;
    int r  = blockIdx.x;
    int c4 = threadIdx.x;
    float4 x = *(const float4*)(X + (size_t)r * DM + c4 * 4);
    __half2 h0 = __floats2half2_rn(x.x, x.y);
    __half2 h1 = __floats2half2_rn(x.z, x.w);
    uint2 p;
    p.x = *(uint32_t*)&h0;
    p.y = *(uint32_t*)&h1;
    size_t ob = (size_t)r * K2 + c4 * 4;
    *(uint2*)(Y + ob)      = p;
    *(uint2*)(Y + ob + DM) = p;
}

// fp16 softplus^2 convert of both rho weights; grid (DM, 2)
__global__ void f16w2_kernel(const float* __restrict__ W0, const float* __restrict__ W1,
                             __half* __restrict__ Y0, __half* __restrict__ Y1) {
    int z = blockIdx.y;
    const float* X = (z == 0) ? W0 : W1;
    __half* Y      = (z == 0) ? Y0 : Y1;
    int row = blockIdx.x;
    int c4  = threadIdx.x;
    float4 x = *(const float4*)(X + (size_t)row * DM + c4 * 4);
    float v[4] = {x.x, x.y, x.z, x.w};
    #pragma unroll
    for (int i = 0; i < 4; ++i) {
        float sp = (v[i] > 15.f) ? v[i] : log1pf(__expf(v[i]));
        v[i] = sp * sp;
    }
    __half2 h0 = __floats2half2_rn(v[0], v[1]);
    __half2 h1 = __floats2half2_rn(v[2], v[3]);
    uint2 p;
    p.x = *(uint32_t*)&h0;
    p.y = *(uint32_t*)&h1;
    *(uint2*)(Y + (size_t)row * DM + c4 * 4) = p;
}

// ---------------------------------------------------------------------------
// fp16 GEMM mainloop with NITER k-chunks (stride NITER*BK per row)
// ---------------------------------------------------------------------------
template<int NITER>
__device__ __forceinline__ void gemm_main_h(
    const __half* __restrict__ A, const __half* __restrict__ B,
    char* smem, int mBase, int nBase, float acc[4][4][4]) {
    const uint32_t sb = smem_u32(smem);
    const int t    = threadIdx.x;
    const int wid  = t >> 5;
    const int lane = t & 31;
    const int wm   = wid & 1;
    const int wn   = wid >> 1;
    const int STRIDE = NITER * BK;

    const int r  = t >> 1;
    const int uc = (t & 1) * 4;
    const __half* aRow = A + (size_t)(mBase + r) * STRIDE + uc * 8;
    const __half* bRow = B + (size_t)(nBase + r) * STRIDE + uc * 8;

    auto load_stage = [&](int buf, int c) {
        uint32_t sA = sb + buf * STAGE_BYTES;
        uint32_t sB = sA + BM * 128;
        const __half* ga = aRow + c * BK;
        const __half* gb = bRow + c * BK;
        #pragma unroll
        for (int i = 0; i < 4; ++i) {
            uint32_t bo = r * 128 + (uc + i) * 16;
            cp16(sA + SWZ(bo), ga + i * 8);
            cp16(sB + SWZ(bo), gb + i * 8);
        }
        CP_COMMIT();
    };

    const int aRowSel = (lane & 7) | (((lane >> 3) & 1) << 3);
    const int aKSel   = (lane >> 4) << 4;
    const int bNSel   = (lane & 7) | ((lane >> 4) << 3);
    const int bKSel   = ((lane >> 3) & 1) << 4;

    load_stage(0, 0);
    load_stage(1, 1);

    for (int kt = 0; kt < NITER; ++kt) {
        const int buf = kt % STAGES;
        if (kt == NITER - 1) asm volatile("cp.async.wait_group 0;" ::: "memory");
        else                 asm volatile("cp.async.wait_group 1;" ::: "memory");
        __syncthreads();

        if (kt + 2 < NITER) load_stage((kt + 2) % STAGES, kt + 2);

        uint32_t sA = sb + buf * STAGE_BYTES;
        uint32_t sB = sA + BM * 128;
        #pragma unroll
        for (int ks = 0; ks < 4; ++ks) {
            uint32_t af[4][4], bfr2[2][4];
            #pragma unroll
            for (int mi = 0; mi < 4; ++mi) {
                uint32_t bo = (uint32_t)((wm * 64 + mi * 16 + aRowSel) * 128
                                         + ks * 32 + aKSel);
                ldsm4(af[mi], sA + SWZ(bo));
            }
            #pragma unroll
            for (int pi = 0; pi < 2; ++pi) {
                uint32_t bo = (uint32_t)((wn * 32 + pi * 16 + bNSel) * 128
                                         + ks * 32 + bKSel);
                ldsm4(bfr2[pi], sB + SWZ(bo));
            }
            #pragma unroll
            for (int mi = 0; mi < 4; ++mi)
                #pragma unroll
                for (int ni = 0; ni < 4; ++ni)
                    mma16816h(acc[mi][ni], af[mi], &bfr2[ni >> 1][(ni & 1) * 2]);
        }
        __syncthreads();
    }
}

// ---------------------------------------------------------------------------
// fused projection GEMM (all fp16): z=0/1 -> Q/K (fp16x2, fp16 head-major
// epilogue), z=2 -> V (fp16x2), z=3 -> V-variance (fp16x1). grid (8, 64, 4).
// ---------------------------------------------------------------------------
__global__ void __launch_bounds__(256, 2)
gemm_proj(const __half* __restrict__ hH2,
          const __half* __restrict__ hWq2, const __half* __restrict__ hWk2,
          const __half* __restrict__ hWv2,
          const __half* __restrict__ hA2, const __half* __restrict__ hVs,
          const float* __restrict__ bq, const float* __restrict__ bk,
          const float* __restrict__ bv, const float* __restrict__ bvs2,
          __half* __restrict__ q2, __half* __restrict__ k2,
          __half* __restrict__ v2h, __half* __restrict__ vv2h) {
    extern __shared__ __align__(1024) char smem[];
    const int z = blockIdx.z;
    const int mBase = blockIdx.y * BM;
    const int nBase = blockIdx.x * BNT;
    float acc[4][4][4] = {};

    if (z == 0)      gemm_main_h<32>(hH2, hWq2, smem, mBase, nBase, acc);
    else if (z == 1) gemm_main_h<32>(hH2, hWk2, smem, mBase, nBase, acc);
    else if (z == 2) gemm_main_h<32>(hH2, hWv2, smem, mBase, nBase, acc);
    else             gemm_main_h<16>(hA2, hVs, smem, mBase, nBase, acc);

    const float* bias = (z == 0) ? bq : (z == 1) ? bk : (z == 2) ? bv : bvs2;
    const int wid  = threadIdx.x >> 5;
    const int lane = threadIdx.x & 31;
    const int lr = lane >> 2;
    const int lc = (lane & 3) * 2;
    const int rB = mBase + (wid & 1) * 64;
    const int cB = nBase + (wid >> 1) * 32;
    #pragma unroll
    for (int mi = 0; mi < 4; ++mi) {
        #pragma unroll
        for (int ni = 0; ni < 4; ++ni) {
            int col  = cB + ni * 8 + lc;
            int row0 = rB + mi * 16 + lr;
            int h = col >> 6, dl = col & 63;
            float2 bi = *(const float2*)(bias + col);
            float vx[2][2] = {{acc[mi][ni][0] + bi.x, acc[mi][ni][1] + bi.y},
                              {acc[mi][ni][2] + bi.x, acc[mi][ni][3] + bi.y}};
            #pragma unroll
            for (int rr2 = 0; rr2 < 2; ++rr2) {
                int row = row0 + rr2 * 8;
                int b = row >> 10, n = row & 1023;
                if (z >= 2) {
                    __half* dst = (z == 2) ? v2h : vv2h;
                    __half2 hv = __floats2half2_rn(vx[rr2][0], vx[rr2][1]);
                    *(uint32_t*)(dst + ((size_t)(b * NH + h) * NSEQ + n) * 64 + dl)
                        = *(uint32_t*)&hv;
                } else {
                    float h0 = __half2float(__float2half_rn(vx[rr2][0]));
                    float h1 = __half2float(__float2half_rn(vx[rr2][1]));
                    __half2 hpk = __floats2half2_rn(h0, h1);
                    __half* dst = ((z == 0) ? q2 : k2)
                        + ((size_t)(b * NH + h) * NSEQ + n) * 128 + dl;
                    *(uint32_t*)dst = *(uint32_t*)&hpk;
                    if (z == 0) {
                        __half2 lpk = __floats2half2_rn(vx[rr2][0] - h0, vx[rr2][1] - h1);
                        *(uint32_t*)(dst + 64) = *(uint32_t*)&lpk;
                    } else {
                        *(uint32_t*)(dst + 64) = *(uint32_t*)&hpk;
                    }
                }
            }
        }
    }
}

// ---------------------------------------------------------------------------
// fused output GEMM: z=0 -> out_mean (fp16x2), z=1 -> out_var (fp16x1 + add).
// ---------------------------------------------------------------------------
__global__ void __launch_bounds__(256, 2)
gemm_out(const __half* __restrict__ a2h, const __half* __restrict__ hWo2,
         const float* __restrict__ bo,
         const __half* __restrict__ hC2, const __half* __restrict__ hOs,
         const float* __restrict__ bos2, const float* __restrict__ var,
         float* __restrict__ out_mean, float* __restrict__ out_var) {
    extern __shared__ __align__(1024) char smem[];
    const int z = blockIdx.z;
    const int mBase = blockIdx.y * BM;
    const int nBase = blockIdx.x * BNT;
    float acc[4][4][4] = {};

    if (z == 0) gemm_main_h<32>(a2h, hWo2, smem, mBase, nBase, acc);
    else        gemm_main_h<16>(hC2, hOs, smem, mBase, nBase, acc);

    const float* bias = (z == 0) ? bo : bos2;
    float* C          = (z == 0) ? out_mean : out_var;
    const int wid  = threadIdx.x >> 5;
    const int lane = threadIdx.x & 31;
    const int lr = lane >> 2;
    const int lc = (lane & 3) * 2;
    const int rB = mBase + (wid & 1) * 64;
    const int cB = nBase + (wid >> 1) * 32;
    #pragma unroll
    for (int mi = 0; mi < 4; ++mi) {
        #pragma unroll
        for (int ni = 0; ni < 4; ++ni) {
            int col  = cB + ni * 8 + lc;
            int row0 = rB + mi * 16 + lr;
            float2 bi = *(const float2*)(bias + col);
            float vx[2][2] = {{acc[mi][ni][0] + bi.x, acc[mi][ni][1] + bi.y},
                              {acc[mi][ni][2] + bi.x, acc[mi][ni][3] + bi.y}};
            #pragma unroll
            for (int rr2 = 0; rr2 < 2; ++rr2) {
                size_t o = (size_t)(row0 + rr2 * 8) * DM + col;
                if (z == 1) {
                    float2 a2 = *(const float2*)(var + o);
                    vx[rr2][0] += a2.x; vx[rr2][1] += a2.y;
                }
                *(float2*)(C + o) = make_float2(vx[rr2][0], vx[rr2][1]);
            }
        }
    }
}

// ---------------------------------------------------------------------------
// dist2 (unchanged)
// ---------------------------------------------------------------------------
__global__ void dist2_kernel(const float* __restrict__ xr, float* __restrict__ d2) {
    __shared__ float xm[64][17];
    __shared__ float xn[64][17];
    __shared__ float x2m[64];
    __shared__ float x2n[64];

    const int t  = threadIdx.x;
    const int b  = blockIdx.z;
    const int mi = blockIdx.y * 64;
    const int nj = blockIdx.x * 64;

    for (int idx = t; idx < 64 * 4; idx += 256) {
        int r = idx >> 2, c = (idx & 3) * 4;
        float4 a = *(const float4*)(xr + ((size_t)b * NSEQ + mi + r) * 16 + c);
        xm[r][c] = a.x; xm[r][c+1] = a.y; xm[r][c+2] = a.z; xm[r][c+3] = a.w;
        float4 bb = *(const float4*)(xr + ((size_t)b * NSEQ + nj + r) * 16 + c);
        xn[r][c] = bb.x; xn[r][c+1] = bb.y; xn[r][c+2] = bb.z; xn[r][c+3] = bb.w;
    }
    __syncthreads();

    if (t < 64) {
        float s = 0.f;
        #pragma unroll
        for (int c = 0; c < 16; ++c) s += xm[t][c] * xm[t][c];
        x2m[t] = s;
    } else if (t < 128) {
        int r = t - 64;
        float s = 0.f;
        #pragma unroll
        for (int c = 0; c < 16; ++c) s += xn[r][c] * xn[r][c];
        x2n[r] = s;
    }
    __syncthreads();

    const int tx = t & 15, ty = t >> 4;
    #pragma unroll
    for (int i = 0; i < 4; ++i) {
        int row = ty * 4 + i;
        float out4[4];
        #pragma unroll
        for (int j = 0; j < 4; ++j) {
            int col = tx * 4 + j;
            float dot = 0.f;
            #pragma unroll
            for (int c = 0; c < 16; ++c) dot += xm[row][c] * xn[col][c];
            out4[j] = fmaxf(x2m[row] + x2n[col] - 2.f * dot, 0.f);
        }
        float4 v4 = make_float4(out4[0], out4[1], out4[2], out4[3]);
        *(float4*)(d2 + ((size_t)b * NSEQ + mi + row) * NSEQ + nj + tx * 4) = v4;
    }
}

// ---------------------------------------------------------------------------
// Tensor-core flash attention, KT=128. S fp16x2 (Q [hi|lo] x K [hi|hi]);
// PV fp16 hi-only (P x256); P^2 Vv fp16 hi-only (P^2 x1024).
// Epilogue writes a2h (fp16x2 ctx), hC2 (fp16 ctx^2), var (fp32).
// ---------------------------------------------------------------------------
__global__ void __launch_bounds__(256, 1)
attn_tc(const __half* __restrict__ q2, const __half* __restrict__ k2,
        const __half* __restrict__ v2h, const __half* __restrict__ vv2h,
        const float* __restrict__ d2g,
        const float* __restrict__ lsf, const float* __restrict__ lll,
        __half* __restrict__ a2h, __half* __restrict__ hC2,
        float* __restrict__ var) {
    extern __shared__ __align__(1024) char smem[];
    const uint32_t sb = smem_u32(smem);
    const int t    = threadIdx.x;
    const int wid  = t >> 5;
    const int lane = t & 31;
    const int qb   = blockIdx.x * QB;
    const int bh   = blockIdx.y;
    const int b    = bh >> 4, hh = bh & 15;

    const float sigma_f2 = __expf(2.f * lsf[hh]);
    const float coef     = 0.5f * __expf(-2.f * lll[hh]);

    const __half* Qg  = q2   + ((size_t)bh * NSEQ + qb) * 128;
    const __half* Kg  = k2   + (size_t)bh * NSEQ * 128;
    const __half* Vg  = v2h  + (size_t)bh * NSEQ * 64;
    const __half* VVg = vv2h + (size_t)bh * NSEQ * 64;

    // Q load: 128 rows x 16 units (2 chunks of 64 fp16)
    for (int i = t; i < QB * 16; i += 256) {
        int row = i >> 4, u = i & 15;
        cp16(sb + SM_Q + (u >> 3) * 16384 + SWZ((uint32_t)(row * 128 + (u & 7) * 16)),
             Qg + (size_t)row * 128 + u * 8);
    }

    auto load_kv = [&](int buf, int kt) {
        const __half* kg = Kg + (size_t)kt * KT * 128;
        for (int i = t; i < KT * 16; i += 256) {
            int row = i >> 4, u = i & 15;
            cp16(sb + SM_K + buf * 32768 + (u >> 3) * 16384
                    + SWZ((uint32_t)(row * 128 + (u & 7) * 16)),
                 kg + (size_t)row * 128 + u * 8);
        }
        const __half* vg = Vg  + (size_t)kt * KT * 64;
        const __half* wg = VVg + (size_t)kt * KT * 64;
        for (int i = t; i < KT * 8; i += 256) {
            int row = i >> 3, u = i & 7;
            uint32_t so = SWZ((uint32_t)(row * 128 + u * 16));
            cp16(sb + SM_V  + buf * 16384 + so, vg + (size_t)row * 64 + u * 8);
            cp16(sb + SM_VV + buf * 16384 + so, wg + (size_t)row * 64 + u * 8);
        }
        CP_COMMIT();
    };
    load_kv(0, 0);

    const int l15 = lane & 15;
    const int lHi = (lane >> 4) << 4;
    const uint32_t aRowOff = (uint32_t)((wid * 16 + l15) * 128 + lHi);
    const int g    = lane >> 3;
    const int keyl = ((g >> 1) << 3) + (lane & 7);
    const uint32_t kCol = (uint32_t)((g & 1) << 4);
    const int rr    = lane >> 2;
    const int cpair = (lane & 3) * 2;

    float accC[8][4] = {}, accV[8][4] = {};
    float rm0 = -1e30f, rm1 = -1e30f, rl0 = 0.f, rl1 = 0.f;

    for (int kt = 0; kt < NSEQ / KT; ++kt) {
        if (kt + 1 < NSEQ / KT) { __syncthreads(); load_kv((kt + 1) & 1, kt + 1); }
        if (kt + 1 < NSEQ / KT) asm volatile("cp.async.wait_group 1;" ::: "memory");
        else                    asm volatile("cp.async.wait_group 0;" ::: "memory");
        __syncthreads();

        const int buf = kt & 1;
        const uint32_t kB  = sb + SM_K  + buf * 32768;
        const uint32_t vB  = sb + SM_V  + buf * 16384;
        const uint32_t vvB = sb + SM_VV + buf * 16384;

        float sacc[16][4];
        #pragma unroll
        for (int j = 0; j < 16; ++j)
            #pragma unroll
            for (int e = 0; e < 4; ++e) sacc[j][e] = 0.f;

        // ---- S = Q2 . K2^T over 128 packed fp16 dims ----
        #pragma unroll
        for (int ks = 0; ks < 8; ++ks) {
            uint32_t a[4];
            ldsm4(a, sb + SM_Q + (ks >> 2) * 16384 + SWZ(aRowOff + (ks & 3) * 32));
            #pragma unroll
            for (int n0 = 0; n0 < 8; ++n0) {
                uint32_t kb4[4];
                ldsm4(kb4, kB + (ks >> 2) * 16384
                         + SWZ((uint32_t)((n0 * 16 + keyl) * 128) + (ks & 3) * 32 + kCol));
                mma16816h(sacc[2 * n0],     a, kb4);
                mma16816h(sacc[2 * n0 + 1], a, kb4 + 2);
            }
        }

        const int kb0 = kt * KT;
        const float* d2r0 = d2g + (size_t)b * NSEQ * NSEQ
                          + (size_t)(qb + wid * 16 + rr) * NSEQ + kb0;
        const float* d2r1 = d2r0 + 8 * NSEQ;
        #pragma unroll
        for (int j = 0; j < 16; ++j) {
            float2 da = *(const float2*)(d2r0 + j * 8 + cpair);
            float2 db = *(const float2*)(d2r1 + j * 8 + cpair);
            sacc[j][0] = sacc[j][0] * QSCALE + sigma_f2 * __expf(-da.x * coef);
            sacc[j][1] = sacc[j][1] * QSCALE + sigma_f2 * __expf(-da.y * coef);
            sacc[j][2] = sacc[j][2] * QSCALE + sigma_f2 * __expf(-db.x * coef);
            sacc[j][3] = sacc[j][3] * QSCALE + sigma_f2 * __expf(-db.y * coef);
        }
        float mx0 = -1e30f, mx1 = -1e30f;
        #pragma unroll
        for (int j = 0; j < 16; ++j) {
            mx0 = fmaxf(mx0, fmaxf(sacc[j][0], sacc[j][1]));
            mx1 = fmaxf(mx1, fmaxf(sacc[j][2], sacc[j][3]));
        }
        mx0 = fmaxf(mx0, __shfl_xor_sync(0xffffffffu, mx0, 1));
        mx0 = fmaxf(mx0, __shfl_xor_sync(0xffffffffu, mx0, 2));
        mx1 = fmaxf(mx1, __shfl_xor_sync(0xffffffffu, mx1, 1));
        mx1 = fmaxf(mx1, __shfl_xor_sync(0xffffffffu, mx1, 2));
        float m0n = fmaxf(rm0, mx0), m1n = fmaxf(rm1, mx1);
        float f0 = __expf(rm0 - m0n), f1 = __expf(rm1 - m1n);
        rm0 = m0n; rm1 = m1n;
        float sum0 = 0.f, sum1 = 0.f;
        #pragma unroll
        for (int j = 0; j < 16; ++j) {
            sacc[j][0] = __expf(sacc[j][0] - m0n); sum0 += sacc[j][0];
            sacc[j][1] = __expf(sacc[j][1] - m0n); sum0 += sacc[j][1];
            sacc[j][2] = __expf(sacc[j][2] - m1n); sum1 += sacc[j][2];
            sacc[j][3] = __expf(sacc[j][3] - m1n); sum1 += sacc[j][3];
        }
        sum0 += __shfl_xor_sync(0xffffffffu, sum0, 1);
        sum0 += __shfl_xor_sync(0xffffffffu, sum0, 2);
        sum1 += __shfl_xor_sync(0xffffffffu, sum1, 1);
        sum1 += __shfl_xor_sync(0xffffffffu, sum1, 2);
        rl0 = rl0 * f0 + sum0;
        rl1 = rl1 * f1 + sum1;
        float f02 = f0 * f0, f12 = f1 * f1;
        #pragma unroll
        for (int j = 0; j < 8; ++j) {
            accC[j][0] *= f0;  accC[j][1] *= f0;
            accC[j][2] *= f1;  accC[j][3] *= f1;
            accV[j][0] *= f02; accV[j][1] *= f02;
            accV[j][2] *= f12; accV[j][3] *= f12;
        }

        // ---- PV and P^2 Vv: fp16 hi-only (P x256, P^2 x1024) ----
        #pragma unroll
        for (int tt = 0; tt < 8; ++tt) {
            float p8[8], q8[8];
            #pragma unroll
            for (int e = 0; e < 4; ++e) {
                float p0 = sacc[2 * tt][e], p1 = sacc[2 * tt + 1][e];
                p8[e]     = p0 * 256.f;
                p8[4 + e] = p1 * 256.f;
                q8[e]     = p0 * p0 * 1024.f;
                q8[4 + e] = p1 * p1 * 1024.f;
            }
            uint32_t phi[4], p2h[4];
            #pragma unroll
            for (int e = 0; e < 4; ++e) {
                __half2 a = __floats2half2_rn(p8[2 * e], p8[2 * e + 1]);
                __half2 c = __floats2half2_rn(q8[2 * e], q8[2 * e + 1]);
                phi[e] = *(uint32_t*)&a;
                p2h[e] = *(uint32_t*)&c;
            }

            const uint32_t rowOff = (uint32_t)((tt * 16 + l15) * 128 + lHi);
            uint32_t vb[16];
            #pragma unroll
            for (int w = 0; w < 4; ++w) ldsm4t(vb + 4 * w, vB + SWZ(rowOff + w * 32));
            #pragma unroll
            for (int j = 0; j < 8; ++j)
                mma16816h(accC[j], phi, &vb[(j >> 1) * 4 + (j & 1) * 2]);
            #pragma unroll
            for (int w = 0; w < 4; ++w) ldsm4t(vb + 4 * w, vvB + SWZ(rowOff + w * 32));
            #pragma unroll
            for (int j = 0; j < 8; ++j)
                mma16816h(accV[j], p2h, &vb[(j >> 1) * 4 + (j & 1) * 2]);
        }
    }

    // ---- epilogue: write a2h (fp16x2 ctx), hC2 (fp16 ctx^2), var (fp32) ----
    const float i0 = 1.f / (256.f * rl0), i1 = 1.f / (256.f * rl1);
    const float w0 = 1.f / (1024.f * rl0 * rl0), w1 = 1.f / (1024.f * rl1 * rl1);
    const int row0 = qb + wid * 16 + rr;
    #pragma unroll
    for (int j = 0; j < 8; ++j) {
        int off = j * 8 + cpair;
        int col = hh * 64 + off;
        float cv[2][2] = {{accC[j][0] * i0, accC[j][1] * i0},
                          {accC[j][2] * i1, accC[j][3] * i1}};
        float uv[2][2] = {{accV[j][0] * w0, accV[j][1] * w0},
                          {accV[j][2] * w1, accV[j][3] * w1}};
        #pragma unroll
        for (int rr2 = 0; rr2 < 2; ++rr2) {
            size_t bn = (size_t)b * NSEQ + row0 + rr2 * 8;
            float c0 = cv[rr2][0], c1 = cv[rr2][1];
            float h0 = __half2float(__float2half_rn(c0));
            float h1 = __half2float(__float2half_rn(c1));
            __half2 hpk = __floats2half2_rn(h0, h1);
            __half2 lpk = __floats2half2_rn(c0 - h0, c1 - h1);
            __half* dst = a2h + bn * K2 + col;
            *(uint32_t*)dst          = *(uint32_t*)&hpk;
            *(uint32_t*)(dst + 1024) = *(uint32_t*)&lpk;
            __half2 hc = __floats2half2_rn(c0 * c0, c1 * c1);
            *(uint32_t*)(hC2 + bn * DM + col) = *(uint32_t*)&hc;
            *(float2*)(var + bn * DM + col) = make_float2(uv[rr2][0], uv[rr2][1]);
        }
    }
}

// ---------------------------------------------------------------------------
// Launcher
// ---------------------------------------------------------------------------
extern "C" void kernel_launch(void* const* d_in, const int* in_sizes, int n_in,
                              void* d_out, int out_size) {
    const float* H      = (const float*)d_in[0];
    const float* xr     = (const float*)d_in[1];
    const float* Wq     = (const float*)d_in[2];
    const float* bq     = (const float*)d_in[4];
    const float* Wk     = (const float*)d_in[6];
    const float* bk     = (const float*)d_in[8];
    const float* Wv     = (const float*)d_in[10];
    const float* Wv_rho = (const float*)d_in[11];
    const float* bv     = (const float*)d_in[12];
    const float* bv_rho = (const float*)d_in[13];
    const float* Wo     = (const float*)d_in[14];
    const float* Wo_rho = (const float*)d_in[15];
    const float* bo     = (const float*)d_in[16];
    const float* bo_rho = (const float*)d_in[17];
    const float* lsf    = (const float*)d_in[18];
    const float* lll    = (const float*)d_in[19];

    float *var, *d2, *bvs2, *bos2;
    __half *hH2, *a2hp, *hWq2, *hWk2, *hWv2, *hWo2, *hA2, *hC2, *hVs, *hOs;
    __half *q2p, *k2p, *v2hp, *vv2hp;
    cudaGetSymbolAddress((void**)&var,  g_var);
    cudaGetSymbolAddress((void**)&d2,   g_d2);
    cudaGetSymbolAddress((void**)&bvs2, g_bvs2);
    cudaGetSymbolAddress((void**)&bos2, g_bos2);
    cudaGetSymbolAddress((void**)&hH2,  g_hH2);
    cudaGetSymbolAddress((void**)&a2hp, g_a2h);
    cudaGetSymbolAddress((void**)&hWq2, g_hWq2);
    cudaGetSymbolAddress((void**)&hWk2, g_hWk2);
    cudaGetSymbolAddress((void**)&hWv2, g_hWv2);
    cudaGetSymbolAddress((void**)&hWo2, g_hWo2);
    cudaGetSymbolAddress((void**)&hA2,  g_hA_H2);
    cudaGetSymbolAddress((void**)&hC2,  g_hC2);
    cudaGetSymbolAddress((void**)&hVs,  g_hB_vs2);
    cudaGetSymbolAddress((void**)&hOs,  g_hB_os2);
    cudaGetSymbolAddress((void**)&q2p,  g_q2);
    cudaGetSymbolAddress((void**)&k2p,  g_k2);
    cudaGetSymbolAddress((void**)&v2hp, g_v2h);
    cudaGetSymbolAddress((void**)&vv2hp, g_vv2h);

    cudaFuncSetAttribute(gemm_proj, cudaFuncAttributeMaxDynamicSharedMemorySize, SMEM_GEMM);
    cudaFuncSetAttribute(gemm_out,  cudaFuncAttributeMaxDynamicSharedMemorySize, SMEM_GEMM);
    cudaFuncSetAttribute(attn_tc,   cudaFuncAttributeMaxDynamicSharedMemorySize, ATTN_SMEM);

    // [0] both bias softplus^2
    bias2_kernel<<<8, 256>>>(bv_rho, bo_rho, bvs2, bos2);
    // [1] fused H prep: fp16x2 + fp16 H^2 (one read)
    splitH_kernel<<<BN, 256>>>(H, hH2, hA2);
    // [2] Wq/Wk/Wv/Wo fp16 dup, [3] rho fp16 converts
    wdup4_kernel<<<dim3(DM, 4), 256>>>(Wq, Wk, Wv, Wo, hWq2, hWk2, hWv2, hWo2);
    f16w2_kernel<<<dim3(DM, 2), 256>>>(Wv_rho, Wo_rho, hVs, hOs);
    // [4] fused projection GEMM (all fp16): Q/K/V fp16x2, Vv fp16x1
    gemm_proj<<<dim3(DM / BNT, BN / BM, 4), 256, SMEM_GEMM>>>(
        hH2, hWq2, hWk2, hWv2, hA2, hVs, bq, bk, bv, bvs2,
        q2p, k2p, v2hp, vv2hp);
    // [5] pairwise squared distances
    dist2_kernel<<<dim3(16, 16, BATCH), 256>>>(xr, d2);
    // [6] attention -> a2h / hC2 / var directly
    attn_tc<<<dim3(NSEQ / QB, BATCH * NH), 256, ATTN_SMEM>>>(
        q2p, k2p, v2hp, vv2hp, d2, lsf, lll, a2hp, hC2, var);
    // [7] fused output GEMM: out_mean fp16x2, out_var fp16x1 + var add
    float* out_mean = (float*)d_out;
    float* out_var  = out_mean + (size_t)BN * DM;
    gemm_out<<<dim3(DM / BNT, BN / BM, 2), 256, SMEM_GEMM>>>(
        a2hp, hWo2, bo, hC2, hOs, bos2, var, out_mean, out_var);
}

// round 15
// speedup vs baseline: 4.7184x; 1.0781x over previous
#include <cuda_runtime.h>
#include <cuda_fp16.h>
#include <math.h>
#include <stdint.h>

#define DM    1024
#define BATCH 8
#define NSEQ  1024
#define BN    (BATCH * NSEQ)
#define NH    16
#define DK    64
#define QSCALE 0.125f

#define K2      2048              // fp16x2 packed K
#define BK      64
#define BM      128
#define BNT     128
#define STAGES  3
#define STAGE_BYTES ((BM + BNT) * 128)
#define SMEM_GEMM (STAGES * STAGE_BYTES)        // 96 KB

// attention tiling / smem (KT=128; Q/K fp16 64-wide = 1 chunk)
#define QB 128
#define KT 128
#define SM_Q   0                  // 128 x 128B = 16384
#define SM_K   16384              // 2 bufs x 128 x 128B = 32768
#define SM_V   49152              // 2 bufs x 128 x 128B = 32768
#define SM_VV  81920              // 32768
#define ATTN_SMEM 114688

// ---------------------------------------------------------------------------
// Scratch
// ---------------------------------------------------------------------------
__device__ float  g_var [BN * DM];
__device__ __half g_d2  [BATCH * NSEQ * NSEQ];
__device__ float  g_bvs2[DM];
__device__ float  g_bos2[DM];

__device__ __half g_hH2  [BN * K2];         // H fp16x2 [hi|lo] (Q/K/V GEMM A)
__device__ __half g_a2h  [BN * K2];         // ctx fp16x2 [hi|lo] (out_mean A)
__device__ __half g_hWq2 [DM * K2];         // Wq fp16 dup [hi|hi]
__device__ __half g_hWk2 [DM * K2];         // Wk fp16 dup [hi|hi]
__device__ __half g_hWv2 [DM * K2];         // Wv fp16 dup [hi|hi]
__device__ __half g_hWo2 [DM * K2];         // Wo fp16 dup [hi|hi]
__device__ __half g_hA_H2[BN * DM];         // fp16 H^2 (Vv A)
__device__ __half g_hC2  [BN * DM];         // fp16 ctx^2 (out_var A)
__device__ __half g_hB_vs2[DM * DM];        // fp16 softplus^2(Wv_rho)
__device__ __half g_hB_os2[DM * DM];        // fp16 softplus^2(Wo_rho)

__device__ __half g_q2 [BATCH * NH * NSEQ * 64];    // Q fp16 head-major
__device__ __half g_k2 [BATCH * NH * NSEQ * 64];    // K fp16 head-major
__device__ __half g_v2h [BATCH * NH * NSEQ * 64];
__device__ __half g_vv2h[BATCH * NH * NSEQ * 64];

// ---------------------------------------------------------------------------
// PTX helpers
// ---------------------------------------------------------------------------
__device__ __forceinline__ uint32_t smem_u32(const void* p) {
    uint32_t a;
    asm("{ .reg .u64 t; cvta.to.shared.u64 t, %1; cvt.u32.u64 %0, t; }"
        : "=r"(a) : "l"(p));
    return a;
}
#define SWZ(off) ((off) ^ (((off) >> 3) & 0x70))

__device__ __forceinline__ void cp16(uint32_t dst, const void* src) {
    asm volatile("cp.async.cg.shared.global [%0], [%1], 16;"
                 :: "r"(dst), "l"(src) : "memory");
}
#define CP_COMMIT() asm volatile("cp.async.commit_group;" ::: "memory")

__device__ __forceinline__ void ldsm4(uint32_t* r, uint32_t addr) {
    asm volatile("ldmatrix.sync.aligned.m8n8.x4.shared.b16 {%0,%1,%2,%3}, [%4];"
                 : "=r"(r[0]), "=r"(r[1]), "=r"(r[2]), "=r"(r[3]) : "r"(addr));
}
__device__ __forceinline__ void ldsm4t(uint32_t* r, uint32_t addr) {
    asm volatile("ldmatrix.sync.aligned.m8n8.x4.trans.shared.b16 {%0,%1,%2,%3}, [%4];"
                 : "=r"(r[0]), "=r"(r[1]), "=r"(r[2]), "=r"(r[3]) : "r"(addr));
}
__device__ __forceinline__ void mma16816h(float* c, const uint32_t* a, const uint32_t* b) {
    asm volatile("mma.sync.aligned.m16n8k16.row.col.f32.f16.f16.f32 "
                 "{%0,%1,%2,%3}, {%4,%5,%6,%7}, {%8,%9}, {%0,%1,%2,%3};"
                 : "+f"(c[0]), "+f"(c[1]), "+f"(c[2]), "+f"(c[3])
                 : "r"(a[0]), "r"(a[1]), "r"(a[2]), "r"(a[3]), "r"(b[0]), "r"(b[1]));
}

// ---------------------------------------------------------------------------
// elementwise prep kernels
// ---------------------------------------------------------------------------
__global__ void bias2_kernel(const float* __restrict__ a, const float* __restrict__ b,
                             float* __restrict__ oa, float* __restrict__ ob) {
    int i = blockIdx.x * 256 + threadIdx.x;
    const float* in  = (i < DM) ? a  : b;
    float*       out = (i < DM) ? oa : ob;
    int j = i & (DM - 1);
    float x  = in[j];
    float sp = (x > 15.f) ? x : log1pf(__expf(x));
    out[j] = sp * sp;
}

// fused H prep: fp16x2 [hi|lo] + fp16 H^2 (one read of H)
__global__ void splitH_kernel(const float* __restrict__ X,
                              __half* __restrict__ Y2, __half* __restrict__ Ysq) {
    int r  = blockIdx.x;
    int c4 = threadIdx.x;
    float4 x = *(const float4*)(X + (size_t)r * DM + c4 * 4);
    float v[4] = {x.x, x.y, x.z, x.w};
    float hh[4], ll[4];
    #pragma unroll
    for (int i = 0; i < 4; ++i) {
        hh[i] = __half2float(__float2half_rn(v[i]));
        ll[i] = v[i] - hh[i];
    }
    __half2 fh0 = __floats2half2_rn(hh[0], hh[1]);
    __half2 fh1 = __floats2half2_rn(hh[2], hh[3]);
    __half2 fl0 = __floats2half2_rn(ll[0], ll[1]);
    __half2 fl1 = __floats2half2_rn(ll[2], ll[3]);
    uint2 fp, fl;
    fp.x = *(uint32_t*)&fh0; fp.y = *(uint32_t*)&fh1;
    fl.x = *(uint32_t*)&fl0; fl.y = *(uint32_t*)&fl1;
    size_t ob2 = (size_t)r * K2 + c4 * 4;
    *(uint2*)(Y2 + ob2)      = fp;
    *(uint2*)(Y2 + ob2 + DM) = fl;
    __half2 s0 = __floats2half2_rn(v[0] * v[0], v[1] * v[1]);
    __half2 s1 = __floats2half2_rn(v[2] * v[2], v[3] * v[3]);
    uint2 sq;
    sq.x = *(uint32_t*)&s0;
    sq.y = *(uint32_t*)&s1;
    *(uint2*)(Ysq + (size_t)r * DM + c4 * 4) = sq;
}

// fp16 dup-convert of 4 weight matrices to [hi|hi] (K2 wide); grid (DM, 4)
__global__ void wdup4_kernel(const float* __restrict__ W0, const float* __restrict__ W1,
                             const float* __restrict__ W2, const float* __restrict__ W3,
                             __half* __restrict__ Y0, __half* __restrict__ Y1,
                             __half* __restrict__ Y2, __half* __restrict__ Y3) {
    int z = blockIdx.y;
    const float* X = (z == 0) ? W0 : (z == 1) ? W1 : (z == 2) ? W2 : W3;
    __half* Y      = (z == 0) ? Y0 : (z == 1) ? Y1 : (z == 2) ? Y2 : Y3;
    int r  = blockIdx.x;
    int c4 = threadIdx.x;
    float4 x = *(const float4*)(X + (size_t)r * DM + c4 * 4);
    __half2 h0 = __floats2half2_rn(x.x, x.y);
    __half2 h1 = __floats2half2_rn(x.z, x.w);
    uint2 p;
    p.x = *(uint32_t*)&h0;
    p.y = *(uint32_t*)&h1;
    size_t ob = (size_t)r * K2 + c4 * 4;
    *(uint2*)(Y + ob)      = p;
    *(uint2*)(Y + ob + DM) = p;
}

// fp16 softplus^2 convert of both rho weights; grid (DM, 2)
__global__ void f16w2_kernel(const float* __restrict__ W0, const float* __restrict__ W1,
                             __half* __restrict__ Y0, __half* __restrict__ Y1) {
    int z = blockIdx.y;
    const float* X = (z == 0) ? W0 : W1;
    __half* Y      = (z == 0) ? Y0 : Y1;
    int row = blockIdx.x;
    int c4  = threadIdx.x;
    float4 x = *(const float4*)(X + (size_t)row * DM + c4 * 4);
    float v[4] = {x.x, x.y, x.z, x.w};
    #pragma unroll
    for (int i = 0; i < 4; ++i) {
        float sp = (v[i] > 15.f) ? v[i] : log1pf(__expf(v[i]));
        v[i] = sp * sp;
    }
    __half2 h0 = __floats2half2_rn(v[0], v[1]);
    __half2 h1 = __floats2half2_rn(v[2], v[3]);
    uint2 p;
    p.x = *(uint32_t*)&h0;
    p.y = *(uint32_t*)&h1;
    *(uint2*)(Y + (size_t)row * DM + c4 * 4) = p;
}

// ---------------------------------------------------------------------------
// fp16 GEMM mainloop with NITER k-chunks (stride NITER*BK per row)
// ---------------------------------------------------------------------------
template<int NITER>
__device__ __forceinline__ void gemm_main_h(
    const __half* __restrict__ A, const __half* __restrict__ B,
    char* smem, int mBase, int nBase, float acc[4][4][4]) {
    const uint32_t sb = smem_u32(smem);
    const int t    = threadIdx.x;
    const int wid  = t >> 5;
    const int lane = t & 31;
    const int wm   = wid & 1;
    const int wn   = wid >> 1;
    const int STRIDE = NITER * BK;

    const int r  = t >> 1;
    const int uc = (t & 1) * 4;
    const __half* aRow = A + (size_t)(mBase + r) * STRIDE + uc * 8;
    const __half* bRow = B + (size_t)(nBase + r) * STRIDE + uc * 8;

    auto load_stage = [&](int buf, int c) {
        uint32_t sA = sb + buf * STAGE_BYTES;
        uint32_t sB = sA + BM * 128;
        const __half* ga = aRow + c * BK;
        const __half* gb = bRow + c * BK;
        #pragma unroll
        for (int i = 0; i < 4; ++i) {
            uint32_t bo = r * 128 + (uc + i) * 16;
            cp16(sA + SWZ(bo), ga + i * 8);
            cp16(sB + SWZ(bo), gb + i * 8);
        }
        CP_COMMIT();
    };

    const int aRowSel = (lane & 7) | (((lane >> 3) & 1) << 3);
    const int aKSel   = (lane >> 4) << 4;
    const int bNSel   = (lane & 7) | ((lane >> 4) << 3);
    const int bKSel   = ((lane >> 3) & 1) << 4;

    load_stage(0, 0);
    load_stage(1, 1);

    for (int kt = 0; kt < NITER; ++kt) {
        const int buf = kt % STAGES;
        if (kt == NITER - 1) asm volatile("cp.async.wait_group 0;" ::: "memory");
        else                 asm volatile("cp.async.wait_group 1;" ::: "memory");
        __syncthreads();

        if (kt + 2 < NITER) load_stage((kt + 2) % STAGES, kt + 2);

        uint32_t sA = sb + buf * STAGE_BYTES;
        uint32_t sB = sA + BM * 128;
        #pragma unroll
        for (int ks = 0; ks < 4; ++ks) {
            uint32_t af[4][4], bfr2[2][4];
            #pragma unroll
            for (int mi = 0; mi < 4; ++mi) {
                uint32_t bo = (uint32_t)((wm * 64 + mi * 16 + aRowSel) * 128
                                         + ks * 32 + aKSel);
                ldsm4(af[mi], sA + SWZ(bo));
            }
            #pragma unroll
            for (int pi = 0; pi < 2; ++pi) {
                uint32_t bo = (uint32_t)((wn * 32 + pi * 16 + bNSel) * 128
                                         + ks * 32 + bKSel);
                ldsm4(bfr2[pi], sB + SWZ(bo));
            }
            #pragma unroll
            for (int mi = 0; mi < 4; ++mi)
                #pragma unroll
                for (int ni = 0; ni < 4; ++ni)
                    mma16816h(acc[mi][ni], af[mi], &bfr2[ni >> 1][(ni & 1) * 2]);
        }
        __syncthreads();
    }
}

// ---------------------------------------------------------------------------
// fused projection GEMM (all fp16): z=0/1/2 -> Q/K/V (fp16x2, 64-wide fp16
// head-major epilogue), z=3 -> V-variance (fp16x1). grid (8, 64, 4).
// ---------------------------------------------------------------------------
__global__ void __launch_bounds__(256, 2)
gemm_proj(const __half* __restrict__ hH2,
          const __half* __restrict__ hWq2, const __half* __restrict__ hWk2,
          const __half* __restrict__ hWv2,
          const __half* __restrict__ hA2, const __half* __restrict__ hVs,
          const float* __restrict__ bq, const float* __restrict__ bk,
          const float* __restrict__ bv, const float* __restrict__ bvs2,
          __half* __restrict__ q2, __half* __restrict__ k2,
          __half* __restrict__ v2h, __half* __restrict__ vv2h) {
    extern __shared__ __align__(1024) char smem[];
    const int z = blockIdx.z;
    const int mBase = blockIdx.y * BM;
    const int nBase = blockIdx.x * BNT;
    float acc[4][4][4] = {};

    if (z == 0)      gemm_main_h<32>(hH2, hWq2, smem, mBase, nBase, acc);
    else if (z == 1) gemm_main_h<32>(hH2, hWk2, smem, mBase, nBase, acc);
    else if (z == 2) gemm_main_h<32>(hH2, hWv2, smem, mBase, nBase, acc);
    else             gemm_main_h<16>(hA2, hVs, smem, mBase, nBase, acc);

    const float* bias = (z == 0) ? bq : (z == 1) ? bk : (z == 2) ? bv : bvs2;
    __half* dst0 = (z == 0) ? q2 : (z == 1) ? k2 : (z == 2) ? v2h : vv2h;
    const int wid  = threadIdx.x >> 5;
    const int lane = threadIdx.x & 31;
    const int lr = lane >> 2;
    const int lc = (lane & 3) * 2;
    const int rB = mBase + (wid & 1) * 64;
    const int cB = nBase + (wid >> 1) * 32;
    #pragma unroll
    for (int mi = 0; mi < 4; ++mi) {
        #pragma unroll
        for (int ni = 0; ni < 4; ++ni) {
            int col  = cB + ni * 8 + lc;
            int row0 = rB + mi * 16 + lr;
            int h = col >> 6, dl = col & 63;
            float2 bi = *(const float2*)(bias + col);
            float vx[2][2] = {{acc[mi][ni][0] + bi.x, acc[mi][ni][1] + bi.y},
                              {acc[mi][ni][2] + bi.x, acc[mi][ni][3] + bi.y}};
            #pragma unroll
            for (int rr2 = 0; rr2 < 2; ++rr2) {
                int row = row0 + rr2 * 8;
                int b = row >> 10, n = row & 1023;
                __half2 hv = __floats2half2_rn(vx[rr2][0], vx[rr2][1]);
                *(uint32_t*)(dst0 + ((size_t)(b * NH + h) * NSEQ + n) * 64 + dl)
                    = *(uint32_t*)&hv;
            }
        }
    }
}

// ---------------------------------------------------------------------------
// fused output GEMM: z=0 -> out_mean (fp16x2), z=1 -> out_var (fp16x1 + add).
// ---------------------------------------------------------------------------
__global__ void __launch_bounds__(256, 2)
gemm_out(const __half* __restrict__ a2h, const __half* __restrict__ hWo2,
         const float* __restrict__ bo,
         const __half* __restrict__ hC2, const __half* __restrict__ hOs,
         const float* __restrict__ bos2, const float* __restrict__ var,
         float* __restrict__ out_mean, float* __restrict__ out_var) {
    extern __shared__ __align__(1024) char smem[];
    const int z = blockIdx.z;
    const int mBase = blockIdx.y * BM;
    const int nBase = blockIdx.x * BNT;
    float acc[4][4][4] = {};

    if (z == 0) gemm_main_h<32>(a2h, hWo2, smem, mBase, nBase, acc);
    else        gemm_main_h<16>(hC2, hOs, smem, mBase, nBase, acc);

    const float* bias = (z == 0) ? bo : bos2;
    float* C          = (z == 0) ? out_mean : out_var;
    const int wid  = threadIdx.x >> 5;
    const int lane = threadIdx.x & 31;
    const int lr = lane >> 2;
    const int lc = (lane & 3) * 2;
    const int rB = mBase + (wid & 1) * 64;
    const int cB = nBase + (wid >> 1) * 32;
    #pragma unroll
    for (int mi = 0; mi < 4; ++mi) {
        #pragma unroll
        for (int ni = 0; ni < 4; ++ni) {
            int col  = cB + ni * 8 + lc;
            int row0 = rB + mi * 16 + lr;
            float2 bi = *(const float2*)(bias + col);
            float vx[2][2] = {{acc[mi][ni][0] + bi.x, acc[mi][ni][1] + bi.y},
                              {acc[mi][ni][2] + bi.x, acc[mi][ni][3] + bi.y}};
            #pragma unroll
            for (int rr2 = 0; rr2 < 2; ++rr2) {
                size_t o = (size_t)(row0 + rr2 * 8) * DM + col;
                if (z == 1) {
                    float2 a2 = *(const float2*)(var + o);
                    vx[rr2][0] += a2.x; vx[rr2][1] += a2.y;
                }
                *(float2*)(C + o) = make_float2(vx[rr2][0], vx[rr2][1]);
            }
        }
    }
}

// ---------------------------------------------------------------------------
// dist2: output fp16
// ---------------------------------------------------------------------------
__global__ void dist2_kernel(const float* __restrict__ xr, __half* __restrict__ d2) {
    __shared__ float xm[64][17];
    __shared__ float xn[64][17];
    __shared__ float x2m[64];
    __shared__ float x2n[64];

    const int t  = threadIdx.x;
    const int b  = blockIdx.z;
    const int mi = blockIdx.y * 64;
    const int nj = blockIdx.x * 64;

    for (int idx = t; idx < 64 * 4; idx += 256) {
        int r = idx >> 2, c = (idx & 3) * 4;
        float4 a = *(const float4*)(xr + ((size_t)b * NSEQ + mi + r) * 16 + c);
        xm[r][c] = a.x; xm[r][c+1] = a.y; xm[r][c+2] = a.z; xm[r][c+3] = a.w;
        float4 bb = *(const float4*)(xr + ((size_t)b * NSEQ + nj + r) * 16 + c);
        xn[r][c] = bb.x; xn[r][c+1] = bb.y; xn[r][c+2] = bb.z; xn[r][c+3] = bb.w;
    }
    __syncthreads();

    if (t < 64) {
        float s = 0.f;
        #pragma unroll
        for (int c = 0; c < 16; ++c) s += xm[t][c] * xm[t][c];
        x2m[t] = s;
    } else if (t < 128) {
        int r = t - 64;
        float s = 0.f;
        #pragma unroll
        for (int c = 0; c < 16; ++c) s += xn[r][c] * xn[r][c];
        x2n[r] = s;
    }
    __syncthreads();

    const int tx = t & 15, ty = t >> 4;
    #pragma unroll
    for (int i = 0; i < 4; ++i) {
        int row = ty * 4 + i;
        float out4[4];
        #pragma unroll
        for (int j = 0; j < 4; ++j) {
            int col = tx * 4 + j;
            float dot = 0.f;
            #pragma unroll
            for (int c = 0; c < 16; ++c) dot += xm[row][c] * xn[col][c];
            out4[j] = fmaxf(x2m[row] + x2n[col] - 2.f * dot, 0.f);
        }
        __half2 o0 = __floats2half2_rn(out4[0], out4[1]);
        __half2 o1 = __floats2half2_rn(out4[2], out4[3]);
        uint2 p;
        p.x = *(uint32_t*)&o0;
        p.y = *(uint32_t*)&o1;
        *(uint2*)(d2 + ((size_t)b * NSEQ + mi + row) * NSEQ + nj + tx * 4) = p;
    }
}

// ---------------------------------------------------------------------------
// Tensor-core flash attention, KT=128. S fp16 (Q x K over 64 dims);
// PV fp16 hi-only (P x256); P^2 Vv fp16 hi-only (P^2 x1024). d2 fp16.
// Epilogue writes a2h (fp16x2 ctx), hC2 (fp16 ctx^2), var (fp32).
// ---------------------------------------------------------------------------
__global__ void __launch_bounds__(256, 1)
attn_tc(const __half* __restrict__ q2, const __half* __restrict__ k2,
        const __half* __restrict__ v2h, const __half* __restrict__ vv2h,
        const __half* __restrict__ d2g,
        const float* __restrict__ lsf, const float* __restrict__ lll,
        __half* __restrict__ a2h, __half* __restrict__ hC2,
        float* __restrict__ var) {
    extern __shared__ __align__(1024) char smem[];
    const uint32_t sb = smem_u32(smem);
    const int t    = threadIdx.x;
    const int wid  = t >> 5;
    const int lane = t & 31;
    const int qb   = blockIdx.x * QB;
    const int bh   = blockIdx.y;
    const int b    = bh >> 4, hh = bh & 15;

    const float sigma_f2 = __expf(2.f * lsf[hh]);
    const float coef     = 0.5f * __expf(-2.f * lll[hh]);

    const __half* Qg  = q2   + ((size_t)bh * NSEQ + qb) * 64;
    const __half* Kg  = k2   + (size_t)bh * NSEQ * 64;
    const __half* Vg  = v2h  + (size_t)bh * NSEQ * 64;
    const __half* VVg = vv2h + (size_t)bh * NSEQ * 64;

    // Q load: 128 rows x 8 units (64 fp16 = 128B per row)
    for (int i = t; i < QB * 8; i += 256) {
        int row = i >> 3, u = i & 7;
        cp16(sb + SM_Q + SWZ((uint32_t)(row * 128 + u * 16)),
             Qg + (size_t)row * 64 + u * 8);
    }

    auto load_kv = [&](int buf, int kt) {
        const __half* kg = Kg  + (size_t)kt * KT * 64;
        const __half* vg = Vg  + (size_t)kt * KT * 64;
        const __half* wg = VVg + (size_t)kt * KT * 64;
        for (int i = t; i < KT * 8; i += 256) {
            int row = i >> 3, u = i & 7;
            uint32_t so = SWZ((uint32_t)(row * 128 + u * 16));
            cp16(sb + SM_K  + buf * 16384 + so, kg + (size_t)row * 64 + u * 8);
            cp16(sb + SM_V  + buf * 16384 + so, vg + (size_t)row * 64 + u * 8);
            cp16(sb + SM_VV + buf * 16384 + so, wg + (size_t)row * 64 + u * 8);
        }
        CP_COMMIT();
    };
    load_kv(0, 0);

    const int l15 = lane & 15;
    const int lHi = (lane >> 4) << 4;
    const uint32_t aRowOff = (uint32_t)((wid * 16 + l15) * 128 + lHi);
    const int g    = lane >> 3;
    const int keyl = ((g >> 1) << 3) + (lane & 7);
    const uint32_t kCol = (uint32_t)((g & 1) << 4);
    const int rr    = lane >> 2;
    const int cpair = (lane & 3) * 2;

    float accC[8][4] = {}, accV[8][4] = {};
    float rm0 = -1e30f, rm1 = -1e30f, rl0 = 0.f, rl1 = 0.f;

    for (int kt = 0; kt < NSEQ / KT; ++kt) {
        if (kt + 1 < NSEQ / KT) { __syncthreads(); load_kv((kt + 1) & 1, kt + 1); }
        if (kt + 1 < NSEQ / KT) asm volatile("cp.async.wait_group 1;" ::: "memory");
        else                    asm volatile("cp.async.wait_group 0;" ::: "memory");
        __syncthreads();

        const int buf = kt & 1;
        const uint32_t kB  = sb + SM_K  + buf * 16384;
        const uint32_t vB  = sb + SM_V  + buf * 16384;
        const uint32_t vvB = sb + SM_VV + buf * 16384;

        float sacc[16][4];
        #pragma unroll
        for (int j = 0; j < 16; ++j)
            #pragma unroll
            for (int e = 0; e < 4; ++e) sacc[j][e] = 0.f;

        // ---- S = Q . K^T over 64 fp16 dims (4 k-steps) ----
        #pragma unroll
        for (int ks = 0; ks < 4; ++ks) {
            uint32_t a[4];
            ldsm4(a, sb + SM_Q + SWZ(aRowOff + ks * 32));
            #pragma unroll
            for (int n0 = 0; n0 < 8; ++n0) {
                uint32_t kb4[4];
                ldsm4(kb4, kB + SWZ((uint32_t)((n0 * 16 + keyl) * 128) + ks * 32 + kCol));
                mma16816h(sacc[2 * n0],     a, kb4);
                mma16816h(sacc[2 * n0 + 1], a, kb4 + 2);
            }
        }

        const int kb0 = kt * KT;
        const __half* d2r0 = d2g + (size_t)b * NSEQ * NSEQ
                           + (size_t)(qb + wid * 16 + rr) * NSEQ + kb0;
        const __half* d2r1 = d2r0 + 8 * NSEQ;
        #pragma unroll
        for (int j = 0; j < 16; ++j) {
            float2 da = __half22float2(*(const __half2*)(d2r0 + j * 8 + cpair));
            float2 db = __half22float2(*(const __half2*)(d2r1 + j * 8 + cpair));
            sacc[j][0] = sacc[j][0] * QSCALE + sigma_f2 * __expf(-da.x * coef);
            sacc[j][1] = sacc[j][1] * QSCALE + sigma_f2 * __expf(-da.y * coef);
            sacc[j][2] = sacc[j][2] * QSCALE + sigma_f2 * __expf(-db.x * coef);
            sacc[j][3] = sacc[j][3] * QSCALE + sigma_f2 * __expf(-db.y * coef);
        }
        float mx0 = -1e30f, mx1 = -1e30f;
        #pragma unroll
        for (int j = 0; j < 16; ++j) {
            mx0 = fmaxf(mx0, fmaxf(sacc[j][0], sacc[j][1]));
            mx1 = fmaxf(mx1, fmaxf(sacc[j][2], sacc[j][3]));
        }
        mx0 = fmaxf(mx0, __shfl_xor_sync(0xffffffffu, mx0, 1));
        mx0 = fmaxf(mx0, __shfl_xor_sync(0xffffffffu, mx0, 2));
        mx1 = fmaxf(mx1, __shfl_xor_sync(0xffffffffu, mx1, 1));
        mx1 = fmaxf(mx1, __shfl_xor_sync(0xffffffffu, mx1, 2));
        float m0n = fmaxf(rm0, mx0), m1n = fmaxf(rm1, mx1);
        float f0 = __expf(rm0 - m0n), f1 = __expf(rm1 - m1n);
        rm0 = m0n; rm1 = m1n;
        float sum0 = 0.f, sum1 = 0.f;
        #pragma unroll
        for (int j = 0; j < 16; ++j) {
            sacc[j][0] = __expf(sacc[j][0] - m0n); sum0 += sacc[j][0];
            sacc[j][1] = __expf(sacc[j][1] - m0n); sum0 += sacc[j][1];
            sacc[j][2] = __expf(sacc[j][2] - m1n); sum1 += sacc[j][2];
            sacc[j][3] = __expf(sacc[j][3] - m1n); sum1 += sacc[j][3];
        }
        sum0 += __shfl_xor_sync(0xffffffffu, sum0, 1);
        sum0 += __shfl_xor_sync(0xffffffffu, sum0, 2);
        sum1 += __shfl_xor_sync(0xffffffffu, sum1, 1);
        sum1 += __shfl_xor_sync(0xffffffffu, sum1, 2);
        rl0 = rl0 * f0 + sum0;
        rl1 = rl1 * f1 + sum1;
        float f02 = f0 * f0, f12 = f1 * f1;
        #pragma unroll
        for (int j = 0; j < 8; ++j) {
            accC[j][0] *= f0;  accC[j][1] *= f0;
            accC[j][2] *= f1;  accC[j][3] *= f1;
            accV[j][0] *= f02; accV[j][1] *= f02;
            accV[j][2] *= f12; accV[j][3] *= f12;
        }

        // ---- PV and P^2 Vv: fp16 hi-only (P x256, P^2 x1024) ----
        #pragma unroll
        for (int tt = 0; tt < 8; ++tt) {
            float p8[8], q8[8];
            #pragma unroll
            for (int e = 0; e < 4; ++e) {
                float p0 = sacc[2 * tt][e], p1 = sacc[2 * tt + 1][e];
                p8[e]     = p0 * 256.f;
                p8[4 + e] = p1 * 256.f;
                q8[e]     = p0 * p0 * 1024.f;
                q8[4 + e] = p1 * p1 * 1024.f;
            }
            uint32_t phi[4], p2h[4];
            #pragma unroll
            for (int e = 0; e < 4; ++e) {
                __half2 a = __floats2half2_rn(p8[2 * e], p8[2 * e + 1]);
                __half2 c = __floats2half2_rn(q8[2 * e], q8[2 * e + 1]);
                phi[e] = *(uint32_t*)&a;
                p2h[e] = *(uint32_t*)&c;
            }

            const uint32_t rowOff = (uint32_t)((tt * 16 + l15) * 128 + lHi);
            uint32_t vb[16];
            #pragma unroll
            for (int w = 0; w < 4; ++w) ldsm4t(vb + 4 * w, vB + SWZ(rowOff + w * 32));
            #pragma unroll
            for (int j = 0; j < 8; ++j)
                mma16816h(accC[j], phi, &vb[(j >> 1) * 4 + (j & 1) * 2]);
            #pragma unroll
            for (int w = 0; w < 4; ++w) ldsm4t(vb + 4 * w, vvB + SWZ(rowOff + w * 32));
            #pragma unroll
            for (int j = 0; j < 8; ++j)
                mma16816h(accV[j], p2h, &vb[(j >> 1) * 4 + (j & 1) * 2]);
        }
    }

    // ---- epilogue: write a2h (fp16x2 ctx), hC2 (fp16 ctx^2), var (fp32) ----
    const float i0 = 1.f / (256.f * rl0), i1 = 1.f / (256.f * rl1);
    const float w0 = 1.f / (1024.f * rl0 * rl0), w1 = 1.f / (1024.f * rl1 * rl1);
    const int row0 = qb + wid * 16 + rr;
    #pragma unroll
    for (int j = 0; j < 8; ++j) {
        int off = j * 8 + cpair;
        int col = hh * 64 + off;
        float cv[2][2] = {{accC[j][0] * i0, accC[j][1] * i0},
                          {accC[j][2] * i1, accC[j][3] * i1}};
        float uv[2][2] = {{accV[j][0] * w0, accV[j][1] * w0},
                          {accV[j][2] * w1, accV[j][3] * w1}};
        #pragma unroll
        for (int rr2 = 0; rr2 < 2; ++rr2) {
            size_t bn = (size_t)b * NSEQ + row0 + rr2 * 8;
            float c0 = cv[rr2][0], c1 = cv[rr2][1];
            float h0 = __half2float(__float2half_rn(c0));
            float h1 = __half2float(__float2half_rn(c1));
            __half2 hpk = __floats2half2_rn(h0, h1);
            __half2 lpk = __floats2half2_rn(c0 - h0, c1 - h1);
            __half* dst = a2h + bn * K2 + col;
            *(uint32_t*)dst          = *(uint32_t*)&hpk;
            *(uint32_t*)(dst + 1024) = *(uint32_t*)&lpk;
            __half2 hc = __floats2half2_rn(c0 * c0, c1 * c1);
            *(uint32_t*)(hC2 + bn * DM + col) = *(uint32_t*)&hc;
            *(float2*)(var + bn * DM + col) = make_float2(uv[rr2][0], uv[rr2][1]);
        }
    }
}

// ---------------------------------------------------------------------------
// Launcher
// ---------------------------------------------------------------------------
extern "C" void kernel_launch(void* const* d_in, const int* in_sizes, int n_in,
                              void* d_out, int out_size) {
    const float* H      = (const float*)d_in[0];
    const float* xr     = (const float*)d_in[1];
    const float* Wq     = (const float*)d_in[2];
    const float* bq     = (const float*)d_in[4];
    const float* Wk     = (const float*)d_in[6];
    const float* bk     = (const float*)d_in[8];
    const float* Wv     = (const float*)d_in[10];
    const float* Wv_rho = (const float*)d_in[11];
    const float* bv     = (const float*)d_in[12];
    const float* bv_rho = (const float*)d_in[13];
    const float* Wo     = (const float*)d_in[14];
    const float* Wo_rho = (const float*)d_in[15];
    const float* bo     = (const float*)d_in[16];
    const float* bo_rho = (const float*)d_in[17];
    const float* lsf    = (const float*)d_in[18];
    const float* lll    = (const float*)d_in[19];

    float *var, *bvs2, *bos2;
    __half *d2, *hH2, *a2hp, *hWq2, *hWk2, *hWv2, *hWo2, *hA2, *hC2, *hVs, *hOs;
    __half *q2p, *k2p, *v2hp, *vv2hp;
    cudaGetSymbolAddress((void**)&var,  g_var);
    cudaGetSymbolAddress((void**)&d2,   g_d2);
    cudaGetSymbolAddress((void**)&bvs2, g_bvs2);
    cudaGetSymbolAddress((void**)&bos2, g_bos2);
    cudaGetSymbolAddress((void**)&hH2,  g_hH2);
    cudaGetSymbolAddress((void**)&a2hp, g_a2h);
    cudaGetSymbolAddress((void**)&hWq2, g_hWq2);
    cudaGetSymbolAddress((void**)&hWk2, g_hWk2);
    cudaGetSymbolAddress((void**)&hWv2, g_hWv2);
    cudaGetSymbolAddress((void**)&hWo2, g_hWo2);
    cudaGetSymbolAddress((void**)&hA2,  g_hA_H2);
    cudaGetSymbolAddress((void**)&hC2,  g_hC2);
    cudaGetSymbolAddress((void**)&hVs,  g_hB_vs2);
    cudaGetSymbolAddress((void**)&hOs,  g_hB_os2);
    cudaGetSymbolAddress((void**)&q2p,  g_q2);
    cudaGetSymbolAddress((void**)&k2p,  g_k2);
    cudaGetSymbolAddress((void**)&v2hp, g_v2h);
    cudaGetSymbolAddress((void**)&vv2hp, g_vv2h);

    cudaFuncSetAttribute(gemm_proj, cudaFuncAttributeMaxDynamicSharedMemorySize, SMEM_GEMM);
    cudaFuncSetAttribute(gemm_out,  cudaFuncAttributeMaxDynamicSharedMemorySize, SMEM_GEMM);
    cudaFuncSetAttribute(attn_tc,   cudaFuncAttributeMaxDynamicSharedMemorySize, ATTN_SMEM);

    // [0] both bias softplus^2
    bias2_kernel<<<8, 256>>>(bv_rho, bo_rho, bvs2, bos2);
    // [1] fused H prep: fp16x2 + fp16 H^2 (one read)
    splitH_kernel<<<BN, 256>>>(H, hH2, hA2);
    // [2] Wq/Wk/Wv/Wo fp16 dup, [3] rho fp16 converts
    wdup4_kernel<<<dim3(DM, 4), 256>>>(Wq, Wk, Wv, Wo, hWq2, hWk2, hWv2, hWo2);
    f16w2_kernel<<<dim3(DM, 2), 256>>>(Wv_rho, Wo_rho, hVs, hOs);
    // [4] fused projection GEMM (all fp16): Q/K/V fp16x2, Vv fp16x1
    gemm_proj<<<dim3(DM / BNT, BN / BM, 4), 256, SMEM_GEMM>>>(
        hH2, hWq2, hWk2, hWv2, hA2, hVs, bq, bk, bv, bvs2,
        q2p, k2p, v2hp, vv2hp);
    // [5] pairwise squared distances (fp16)
    dist2_kernel<<<dim3(16, 16, BATCH), 256>>>(xr, d2);
    // [6] attention -> a2h / hC2 / var directly
    attn_tc<<<dim3(NSEQ / QB, BATCH * NH), 256, ATTN_SMEM>>>(
        q2p, k2p, v2hp, vv2hp, d2, lsf, lll, a2hp, hC2, var);
    // [7] fused output GEMM: out_mean fp16x2, out_var fp16x1 + var add
    float* out_mean = (float*)d_out;
    float* out_var  = out_mean + (size_t)BN * DM;
    gemm_out<<<dim3(DM / BNT, BN / BM, 2), 256, SMEM_GEMM>>>(
        a2hp, hWo2, bo, hC2, hOs, bos2, var, out_mean, out_var);
}

// round 16
// speedup vs baseline: 6.3048x; 1.3362x over previous
#include <cuda_runtime.h>
#include <cuda_fp16.h>
#include <math.h>
#include <stdint.h>

#define DM    1024
#define BATCH 8
#define NSEQ  1024
#define BN    (BATCH * NSEQ)
#define NH    16
#define DK    64
#define QSCALE 0.125f

#define BK      64
#define BM      128
#define BNT     128
#define STAGES  3
#define STAGE_BYTES ((BM + BNT) * 128)
#define SMEM_GEMM (STAGES * STAGE_BYTES)        // 96 KB

// attention tiling / smem (KT=128; Q/K/V/VV fp16 64-wide)
#define QB 128
#define KT 128
#define SM_Q   0                  // 128 x 128B = 16384
#define SM_K   16384              // 2 bufs x 128 x 128B = 32768
#define SM_V   49152              // 32768
#define SM_VV  81920              // 32768
#define ATTN_SMEM 114688

// ---------------------------------------------------------------------------
// Scratch
// ---------------------------------------------------------------------------
__device__ float  g_var [BN * DM];
__device__ __half g_d2  [BATCH * NSEQ * NSEQ];
__device__ float  g_bvs2[DM];
__device__ float  g_bos2[DM];

__device__ __half g_hH  [BN * DM];          // fp16 H (Q/K/V GEMM A)
__device__ __half g_hCtx[BN * DM];          // fp16 ctx (out_mean A)
__device__ __half g_hA_H2[BN * DM];         // fp16 H^2 (Vv A)
__device__ __half g_hC2 [BN * DM];          // fp16 ctx^2 (out_var A)
__device__ __half g_hWq [DM * DM];
__device__ __half g_hWk [DM * DM];
__device__ __half g_hWv [DM * DM];
__device__ __half g_hWo [DM * DM];
__device__ __half g_hVs [DM * DM];          // fp16 softplus^2(Wv_rho)
__device__ __half g_hOs [DM * DM];          // fp16 softplus^2(Wo_rho)

__device__ __half g_q2 [BATCH * NH * NSEQ * 64];    // Q fp16 head-major
__device__ __half g_k2 [BATCH * NH * NSEQ * 64];    // K fp16 head-major
__device__ __half g_v2h [BATCH * NH * NSEQ * 64];
__device__ __half g_vv2h[BATCH * NH * NSEQ * 64];

// ---------------------------------------------------------------------------
// PTX helpers
// ---------------------------------------------------------------------------
__device__ __forceinline__ uint32_t smem_u32(const void* p) {
    uint32_t a;
    asm("{ .reg .u64 t; cvta.to.shared.u64 t, %1; cvt.u32.u64 %0, t; }"
        : "=r"(a) : "l"(p));
    return a;
}
#define SWZ(off) ((off) ^ (((off) >> 3) & 0x70))

__device__ __forceinline__ void cp16(uint32_t dst, const void* src) {
    asm volatile("cp.async.cg.shared.global [%0], [%1], 16;"
                 :: "r"(dst), "l"(src) : "memory");
}
#define CP_COMMIT() asm volatile("cp.async.commit_group;" ::: "memory")

__device__ __forceinline__ void ldsm4(uint32_t* r, uint32_t addr) {
    asm volatile("ldmatrix.sync.aligned.m8n8.x4.shared.b16 {%0,%1,%2,%3}, [%4];"
                 : "=r"(r[0]), "=r"(r[1]), "=r"(r[2]), "=r"(r[3]) : "r"(addr));
}
__device__ __forceinline__ void ldsm4t(uint32_t* r, uint32_t addr) {
    asm volatile("ldmatrix.sync.aligned.m8n8.x4.trans.shared.b16 {%0,%1,%2,%3}, [%4];"
                 : "=r"(r[0]), "=r"(r[1]), "=r"(r[2]), "=r"(r[3]) : "r"(addr));
}
__device__ __forceinline__ void mma16816h(float* c, const uint32_t* a, const uint32_t* b) {
    asm volatile("mma.sync.aligned.m16n8k16.row.col.f32.f16.f16.f32 "
                 "{%0,%1,%2,%3}, {%4,%5,%6,%7}, {%8,%9}, {%0,%1,%2,%3};"
                 : "+f"(c[0]), "+f"(c[1]), "+f"(c[2]), "+f"(c[3])
                 : "r"(a[0]), "r"(a[1]), "r"(a[2]), "r"(a[3]), "r"(b[0]), "r"(b[1]));
}

// ---------------------------------------------------------------------------
// elementwise prep kernels
// ---------------------------------------------------------------------------
__global__ void bias2_kernel(const float* __restrict__ a, const float* __restrict__ b,
                             float* __restrict__ oa, float* __restrict__ ob) {
    int i = blockIdx.x * 256 + threadIdx.x;
    const float* in  = (i < DM) ? a  : b;
    float*       out = (i < DM) ? oa : ob;
    int j = i & (DM - 1);
    float x  = in[j];
    float sp = (x > 15.f) ? x : log1pf(__expf(x));
    out[j] = sp * sp;
}

// fused H prep: fp16 H + fp16 H^2 (one read of H)
__global__ void splitH_kernel(const float* __restrict__ X,
                              __half* __restrict__ Yh, __half* __restrict__ Ysq) {
    int r  = blockIdx.x;
    int c4 = threadIdx.x;
    float4 x = *(const float4*)(X + (size_t)r * DM + c4 * 4);
    __half2 h0 = __floats2half2_rn(x.x, x.y);
    __half2 h1 = __floats2half2_rn(x.z, x.w);
    uint2 p;
    p.x = *(uint32_t*)&h0;
    p.y = *(uint32_t*)&h1;
    *(uint2*)(Yh + (size_t)r * DM + c4 * 4) = p;
    __half2 s0 = __floats2half2_rn(x.x * x.x, x.y * x.y);
    __half2 s1 = __floats2half2_rn(x.z * x.z, x.w * x.w);
    uint2 sq;
    sq.x = *(uint32_t*)&s0;
    sq.y = *(uint32_t*)&s1;
    *(uint2*)(Ysq + (size_t)r * DM + c4 * 4) = sq;
}

// fp16 convert of 6 weight matrices; z<4 plain, z>=4 softplus^2. grid (DM, 6)
__global__ void wconv6_kernel(const float* __restrict__ W0, const float* __restrict__ W1,
                              const float* __restrict__ W2, const float* __restrict__ W3,
                              const float* __restrict__ W4, const float* __restrict__ W5,
                              __half* __restrict__ Y0, __half* __restrict__ Y1,
                              __half* __restrict__ Y2, __half* __restrict__ Y3,
                              __half* __restrict__ Y4, __half* __restrict__ Y5) {
    int z = blockIdx.y;
    const float* X = (z == 0) ? W0 : (z == 1) ? W1 : (z == 2) ? W2
                   : (z == 3) ? W3 : (z == 4) ? W4 : W5;
    __half* Y      = (z == 0) ? Y0 : (z == 1) ? Y1 : (z == 2) ? Y2
                   : (z == 3) ? Y3 : (z == 4) ? Y4 : Y5;
    int r  = blockIdx.x;
    int c4 = threadIdx.x;
    float4 x = *(const float4*)(X + (size_t)r * DM + c4 * 4);
    float v[4] = {x.x, x.y, x.z, x.w};
    if (z >= 4) {
        #pragma unroll
        for (int i = 0; i < 4; ++i) {
            float sp = (v[i] > 15.f) ? v[i] : log1pf(__expf(v[i]));
            v[i] = sp * sp;
        }
    }
    __half2 h0 = __floats2half2_rn(v[0], v[1]);
    __half2 h1 = __floats2half2_rn(v[2], v[3]);
    uint2 p;
    p.x = *(uint32_t*)&h0;
    p.y = *(uint32_t*)&h1;
    *(uint2*)(Y + (size_t)r * DM + c4 * 4) = p;
}

// ---------------------------------------------------------------------------
// fp16 GEMM mainloop, K = 1024 (16 k-chunks)
// ---------------------------------------------------------------------------
__device__ __forceinline__ void gemm_main_h(
    const __half* __restrict__ A, const __half* __restrict__ B,
    char* smem, int mBase, int nBase, float acc[4][4][4]) {
    const uint32_t sb = smem_u32(smem);
    const int t    = threadIdx.x;
    const int wid  = t >> 5;
    const int lane = t & 31;
    const int wm   = wid & 1;
    const int wn   = wid >> 1;
    const int NITER = 16;

    const int r  = t >> 1;
    const int uc = (t & 1) * 4;
    const __half* aRow = A + (size_t)(mBase + r) * DM + uc * 8;
    const __half* bRow = B + (size_t)(nBase + r) * DM + uc * 8;

    auto load_stage = [&](int buf, int c) {
        uint32_t sA = sb + buf * STAGE_BYTES;
        uint32_t sB = sA + BM * 128;
        const __half* ga = aRow + c * BK;
        const __half* gb = bRow + c * BK;
        #pragma unroll
        for (int i = 0; i < 4; ++i) {
            uint32_t bo = r * 128 + (uc + i) * 16;
            cp16(sA + SWZ(bo), ga + i * 8);
            cp16(sB + SWZ(bo), gb + i * 8);
        }
        CP_COMMIT();
    };

    const int aRowSel = (lane & 7) | (((lane >> 3) & 1) << 3);
    const int aKSel   = (lane >> 4) << 4;
    const int bNSel   = (lane & 7) | ((lane >> 4) << 3);
    const int bKSel   = ((lane >> 3) & 1) << 4;

    load_stage(0, 0);
    load_stage(1, 1);

    for (int kt = 0; kt < NITER; ++kt) {
        const int buf = kt % STAGES;
        if (kt == NITER - 1) asm volatile("cp.async.wait_group 0;" ::: "memory");
        else                 asm volatile("cp.async.wait_group 1;" ::: "memory");
        __syncthreads();

        if (kt + 2 < NITER) load_stage((kt + 2) % STAGES, kt + 2);

        uint32_t sA = sb + buf * STAGE_BYTES;
        uint32_t sB = sA + BM * 128;
        #pragma unroll
        for (int ks = 0; ks < 4; ++ks) {
            uint32_t af[4][4], bfr2[2][4];
            #pragma unroll
            for (int mi = 0; mi < 4; ++mi) {
                uint32_t bo = (uint32_t)((wm * 64 + mi * 16 + aRowSel) * 128
                                         + ks * 32 + aKSel);
                ldsm4(af[mi], sA + SWZ(bo));
            }
            #pragma unroll
            for (int pi = 0; pi < 2; ++pi) {
                uint32_t bo = (uint32_t)((wn * 32 + pi * 16 + bNSel) * 128
                                         + ks * 32 + bKSel);
                ldsm4(bfr2[pi], sB + SWZ(bo));
            }
            #pragma unroll
            for (int mi = 0; mi < 4; ++mi)
                #pragma unroll
                for (int ni = 0; ni < 4; ++ni)
                    mma16816h(acc[mi][ni], af[mi], &bfr2[ni >> 1][(ni & 1) * 2]);
        }
        __syncthreads();
    }
}

// ---------------------------------------------------------------------------
// fused projection GEMM (all fp16, K=1024): z=0/1/2/3 -> Q/K/V/Vv,
// fp16 64-wide head-major epilogue. grid (8, 64, 4).
// ---------------------------------------------------------------------------
__global__ void __launch_bounds__(256, 2)
gemm_proj(const __half* __restrict__ hH, const __half* __restrict__ hA2,
          const __half* __restrict__ hWq, const __half* __restrict__ hWk,
          const __half* __restrict__ hWv, const __half* __restrict__ hVs,
          const float* __restrict__ bq, const float* __restrict__ bk,
          const float* __restrict__ bv, const float* __restrict__ bvs2,
          __half* __restrict__ q2, __half* __restrict__ k2,
          __half* __restrict__ v2h, __half* __restrict__ vv2h) {
    extern __shared__ __align__(1024) char smem[];
    const int z = blockIdx.z;
    const int mBase = blockIdx.y * BM;
    const int nBase = blockIdx.x * BNT;
    float acc[4][4][4] = {};

    const __half* A = (z == 3) ? hA2 : hH;
    const __half* B = (z == 0) ? hWq : (z == 1) ? hWk : (z == 2) ? hWv : hVs;
    gemm_main_h(A, B, smem, mBase, nBase, acc);

    const float* bias = (z == 0) ? bq : (z == 1) ? bk : (z == 2) ? bv : bvs2;
    __half* dst0 = (z == 0) ? q2 : (z == 1) ? k2 : (z == 2) ? v2h : vv2h;
    const int wid  = threadIdx.x >> 5;
    const int lane = threadIdx.x & 31;
    const int lr = lane >> 2;
    const int lc = (lane & 3) * 2;
    const int rB = mBase + (wid & 1) * 64;
    const int cB = nBase + (wid >> 1) * 32;
    #pragma unroll
    for (int mi = 0; mi < 4; ++mi) {
        #pragma unroll
        for (int ni = 0; ni < 4; ++ni) {
            int col  = cB + ni * 8 + lc;
            int row0 = rB + mi * 16 + lr;
            int h = col >> 6, dl = col & 63;
            float2 bi = *(const float2*)(bias + col);
            float vx[2][2] = {{acc[mi][ni][0] + bi.x, acc[mi][ni][1] + bi.y},
                              {acc[mi][ni][2] + bi.x, acc[mi][ni][3] + bi.y}};
            #pragma unroll
            for (int rr2 = 0; rr2 < 2; ++rr2) {
                int row = row0 + rr2 * 8;
                int b = row >> 10, n = row & 1023;
                __half2 hv = __floats2half2_rn(vx[rr2][0], vx[rr2][1]);
                *(uint32_t*)(dst0 + ((size_t)(b * NH + h) * NSEQ + n) * 64 + dl)
                    = *(uint32_t*)&hv;
            }
        }
    }
}

// ---------------------------------------------------------------------------
// fused output GEMM (K=1024): z=0 -> out_mean, z=1 -> out_var (+ add).
// ---------------------------------------------------------------------------
__global__ void __launch_bounds__(256, 2)
gemm_out(const __half* __restrict__ hCtx, const __half* __restrict__ hWo,
         const float* __restrict__ bo,
         const __half* __restrict__ hC2, const __half* __restrict__ hOs,
         const float* __restrict__ bos2, const float* __restrict__ var,
         float* __restrict__ out_mean, float* __restrict__ out_var) {
    extern __shared__ __align__(1024) char smem[];
    const int z = blockIdx.z;
    const int mBase = blockIdx.y * BM;
    const int nBase = blockIdx.x * BNT;
    float acc[4][4][4] = {};

    if (z == 0) gemm_main_h(hCtx, hWo, smem, mBase, nBase, acc);
    else        gemm_main_h(hC2, hOs, smem, mBase, nBase, acc);

    const float* bias = (z == 0) ? bo : bos2;
    float* C          = (z == 0) ? out_mean : out_var;
    const int wid  = threadIdx.x >> 5;
    const int lane = threadIdx.x & 31;
    const int lr = lane >> 2;
    const int lc = (lane & 3) * 2;
    const int rB = mBase + (wid & 1) * 64;
    const int cB = nBase + (wid >> 1) * 32;
    #pragma unroll
    for (int mi = 0; mi < 4; ++mi) {
        #pragma unroll
        for (int ni = 0; ni < 4; ++ni) {
            int col  = cB + ni * 8 + lc;
            int row0 = rB + mi * 16 + lr;
            float2 bi = *(const float2*)(bias + col);
            float vx[2][2] = {{acc[mi][ni][0] + bi.x, acc[mi][ni][1] + bi.y},
                              {acc[mi][ni][2] + bi.x, acc[mi][ni][3] + bi.y}};
            #pragma unroll
            for (int rr2 = 0; rr2 < 2; ++rr2) {
                size_t o = (size_t)(row0 + rr2 * 8) * DM + col;
                if (z == 1) {
                    float2 a2 = *(const float2*)(var + o);
                    vx[rr2][0] += a2.x; vx[rr2][1] += a2.y;
                }
                *(float2*)(C + o) = make_float2(vx[rr2][0], vx[rr2][1]);
            }
        }
    }
}

// ---------------------------------------------------------------------------
// dist2: output fp16
// ---------------------------------------------------------------------------
__global__ void dist2_kernel(const float* __restrict__ xr, __half* __restrict__ d2) {
    __shared__ float xm[64][17];
    __shared__ float xn[64][17];
    __shared__ float x2m[64];
    __shared__ float x2n[64];

    const int t  = threadIdx.x;
    const int b  = blockIdx.z;
    const int mi = blockIdx.y * 64;
    const int nj = blockIdx.x * 64;

    for (int idx = t; idx < 64 * 4; idx += 256) {
        int r = idx >> 2, c = (idx & 3) * 4;
        float4 a = *(const float4*)(xr + ((size_t)b * NSEQ + mi + r) * 16 + c);
        xm[r][c] = a.x; xm[r][c+1] = a.y; xm[r][c+2] = a.z; xm[r][c+3] = a.w;
        float4 bb = *(const float4*)(xr + ((size_t)b * NSEQ + nj + r) * 16 + c);
        xn[r][c] = bb.x; xn[r][c+1] = bb.y; xn[r][c+2] = bb.z; xn[r][c+3] = bb.w;
    }
    __syncthreads();

    if (t < 64) {
        float s = 0.f;
        #pragma unroll
        for (int c = 0; c < 16; ++c) s += xm[t][c] * xm[t][c];
        x2m[t] = s;
    } else if (t < 128) {
        int r = t - 64;
        float s = 0.f;
        #pragma unroll
        for (int c = 0; c < 16; ++c) s += xn[r][c] * xn[r][c];
        x2n[r] = s;
    }
    __syncthreads();

    const int tx = t & 15, ty = t >> 4;
    #pragma unroll
    for (int i = 0; i < 4; ++i) {
        int row = ty * 4 + i;
        float out4[4];
        #pragma unroll
        for (int j = 0; j < 4; ++j) {
            int col = tx * 4 + j;
            float dot = 0.f;
            #pragma unroll
            for (int c = 0; c < 16; ++c) dot += xm[row][c] * xn[col][c];
            out4[j] = fmaxf(x2m[row] + x2n[col] - 2.f * dot, 0.f);
        }
        __half2 o0 = __floats2half2_rn(out4[0], out4[1]);
        __half2 o1 = __floats2half2_rn(out4[2], out4[3]);
        uint2 p;
        p.x = *(uint32_t*)&o0;
        p.y = *(uint32_t*)&o1;
        *(uint2*)(d2 + ((size_t)b * NSEQ + mi + row) * NSEQ + nj + tx * 4) = p;
    }
}

// ---------------------------------------------------------------------------
// Tensor-core flash attention, KT=128. S fp16 (Q x K over 64 dims);
// PV fp16 hi-only (P x256); P^2 Vv fp16 hi-only (P^2 x1024). d2 fp16.
// Epilogue writes hCtx (fp16 ctx), hC2 (fp16 ctx^2), var (fp32).
// ---------------------------------------------------------------------------
__global__ void __launch_bounds__(256, 1)
attn_tc(const __half* __restrict__ q2, const __half* __restrict__ k2,
        const __half* __restrict__ v2h, const __half* __restrict__ vv2h,
        const __half* __restrict__ d2g,
        const float* __restrict__ lsf, const float* __restrict__ lll,
        __half* __restrict__ hCtx, __half* __restrict__ hC2,
        float* __restrict__ var) {
    extern __shared__ __align__(1024) char smem[];
    const uint32_t sb = smem_u32(smem);
    const int t    = threadIdx.x;
    const int wid  = t >> 5;
    const int lane = t & 31;
    const int qb   = blockIdx.x * QB;
    const int bh   = blockIdx.y;
    const int b    = bh >> 4, hh = bh & 15;

    const float sigma_f2 = __expf(2.f * lsf[hh]);
    const float coef     = 0.5f * __expf(-2.f * lll[hh]);

    const __half* Qg  = q2   + ((size_t)bh * NSEQ + qb) * 64;
    const __half* Kg  = k2   + (size_t)bh * NSEQ * 64;
    const __half* Vg  = v2h  + (size_t)bh * NSEQ * 64;
    const __half* VVg = vv2h + (size_t)bh * NSEQ * 64;

    for (int i = t; i < QB * 8; i += 256) {
        int row = i >> 3, u = i & 7;
        cp16(sb + SM_Q + SWZ((uint32_t)(row * 128 + u * 16)),
             Qg + (size_t)row * 64 + u * 8);
    }

    auto load_kv = [&](int buf, int kt) {
        const __half* kg = Kg  + (size_t)kt * KT * 64;
        const __half* vg = Vg  + (size_t)kt * KT * 64;
        const __half* wg = VVg + (size_t)kt * KT * 64;
        for (int i = t; i < KT * 8; i += 256) {
            int row = i >> 3, u = i & 7;
            uint32_t so = SWZ((uint32_t)(row * 128 + u * 16));
            cp16(sb + SM_K  + buf * 16384 + so, kg + (size_t)row * 64 + u * 8);
            cp16(sb + SM_V  + buf * 16384 + so, vg + (size_t)row * 64 + u * 8);
            cp16(sb + SM_VV + buf * 16384 + so, wg + (size_t)row * 64 + u * 8);
        }
        CP_COMMIT();
    };
    load_kv(0, 0);

    const int l15 = lane & 15;
    const int lHi = (lane >> 4) << 4;
    const uint32_t aRowOff = (uint32_t)((wid * 16 + l15) * 128 + lHi);
    const int g    = lane >> 3;
    const int keyl = ((g >> 1) << 3) + (lane & 7);
    const uint32_t kCol = (uint32_t)((g & 1) << 4);
    const int rr    = lane >> 2;
    const int cpair = (lane & 3) * 2;

    float accC[8][4] = {}, accV[8][4] = {};
    float rm0 = -1e30f, rm1 = -1e30f, rl0 = 0.f, rl1 = 0.f;

    for (int kt = 0; kt < NSEQ / KT; ++kt) {
        if (kt + 1 < NSEQ / KT) { __syncthreads(); load_kv((kt + 1) & 1, kt + 1); }
        if (kt + 1 < NSEQ / KT) asm volatile("cp.async.wait_group 1;" ::: "memory");
        else                    asm volatile("cp.async.wait_group 0;" ::: "memory");
        __syncthreads();

        const int buf = kt & 1;
        const uint32_t kB  = sb + SM_K  + buf * 16384;
        const uint32_t vB  = sb + SM_V  + buf * 16384;
        const uint32_t vvB = sb + SM_VV + buf * 16384;

        float sacc[16][4];
        #pragma unroll
        for (int j = 0; j < 16; ++j)
            #pragma unroll
            for (int e = 0; e < 4; ++e) sacc[j][e] = 0.f;

        #pragma unroll
        for (int ks = 0; ks < 4; ++ks) {
            uint32_t a[4];
            ldsm4(a, sb + SM_Q + SWZ(aRowOff + ks * 32));
            #pragma unroll
            for (int n0 = 0; n0 < 8; ++n0) {
                uint32_t kb4[4];
                ldsm4(kb4, kB + SWZ((uint32_t)((n0 * 16 + keyl) * 128) + ks * 32 + kCol));
                mma16816h(sacc[2 * n0],     a, kb4);
                mma16816h(sacc[2 * n0 + 1], a, kb4 + 2);
            }
        }

        const int kb0 = kt * KT;
        const __half* d2r0 = d2g + (size_t)b * NSEQ * NSEQ
                           + (size_t)(qb + wid * 16 + rr) * NSEQ + kb0;
        const __half* d2r1 = d2r0 + 8 * NSEQ;
        #pragma unroll
        for (int j = 0; j < 16; ++j) {
            float2 da = __half22float2(*(const __half2*)(d2r0 + j * 8 + cpair));
            float2 db = __half22float2(*(const __half2*)(d2r1 + j * 8 + cpair));
            sacc[j][0] = sacc[j][0] * QSCALE + sigma_f2 * __expf(-da.x * coef);
            sacc[j][1] = sacc[j][1] * QSCALE + sigma_f2 * __expf(-da.y * coef);
            sacc[j][2] = sacc[j][2] * QSCALE + sigma_f2 * __expf(-db.x * coef);
            sacc[j][3] = sacc[j][3] * QSCALE + sigma_f2 * __expf(-db.y * coef);
        }
        float mx0 = -1e30f, mx1 = -1e30f;
        #pragma unroll
        for (int j = 0; j < 16; ++j) {
            mx0 = fmaxf(mx0, fmaxf(sacc[j][0], sacc[j][1]));
            mx1 = fmaxf(mx1, fmaxf(sacc[j][2], sacc[j][3]));
        }
        mx0 = fmaxf(mx0, __shfl_xor_sync(0xffffffffu, mx0, 1));
        mx0 = fmaxf(mx0, __shfl_xor_sync(0xffffffffu, mx0, 2));
        mx1 = fmaxf(mx1, __shfl_xor_sync(0xffffffffu, mx1, 1));
        mx1 = fmaxf(mx1, __shfl_xor_sync(0xffffffffu, mx1, 2));
        float m0n = fmaxf(rm0, mx0), m1n = fmaxf(rm1, mx1);
        float f0 = __expf(rm0 - m0n), f1 = __expf(rm1 - m1n);
        rm0 = m0n; rm1 = m1n;
        float sum0 = 0.f, sum1 = 0.f;
        #pragma unroll
        for (int j = 0; j < 16; ++j) {
            sacc[j][0] = __expf(sacc[j][0] - m0n); sum0 += sacc[j][0];
            sacc[j][1] = __expf(sacc[j][1] - m0n); sum0 += sacc[j][1];
            sacc[j][2] = __expf(sacc[j][2] - m1n); sum1 += sacc[j][2];
            sacc[j][3] = __expf(sacc[j][3] - m1n); sum1 += sacc[j][3];
        }
        sum0 += __shfl_xor_sync(0xffffffffu, sum0, 1);
        sum0 += __shfl_xor_sync(0xffffffffu, sum0, 2);
        sum1 += __shfl_xor_sync(0xffffffffu, sum1, 1);
        sum1 += __shfl_xor_sync(0xffffffffu, sum1, 2);
        rl0 = rl0 * f0 + sum0;
        rl1 = rl1 * f1 + sum1;
        float f02 = f0 * f0, f12 = f1 * f1;
        #pragma unroll
        for (int j = 0; j < 8; ++j) {
            accC[j][0] *= f0;  accC[j][1] *= f0;
            accC[j][2] *= f1;  accC[j][3] *= f1;
            accV[j][0] *= f02; accV[j][1] *= f02;
            accV[j][2] *= f12; accV[j][3] *= f12;
        }

        #pragma unroll
        for (int tt = 0; tt < 8; ++tt) {
            float p8[8], q8[8];
            #pragma unroll
            for (int e = 0; e < 4; ++e) {
                float p0 = sacc[2 * tt][e], p1 = sacc[2 * tt + 1][e];
                p8[e]     = p0 * 256.f;
                p8[4 + e] = p1 * 256.f;
                q8[e]     = p0 * p0 * 1024.f;
                q8[4 + e] = p1 * p1 * 1024.f;
            }
            uint32_t phi[4], p2h[4];
            #pragma unroll
            for (int e = 0; e < 4; ++e) {
                __half2 a = __floats2half2_rn(p8[2 * e], p8[2 * e + 1]);
                __half2 c = __floats2half2_rn(q8[2 * e], q8[2 * e + 1]);
                phi[e] = *(uint32_t*)&a;
                p2h[e] = *(uint32_t*)&c;
            }

            const uint32_t rowOff = (uint32_t)((tt * 16 + l15) * 128 + lHi);
            uint32_t vb[16];
            #pragma unroll
            for (int w = 0; w < 4; ++w) ldsm4t(vb + 4 * w, vB + SWZ(rowOff + w * 32));
            #pragma unroll
            for (int j = 0; j < 8; ++j)
                mma16816h(accC[j], phi, &vb[(j >> 1) * 4 + (j & 1) * 2]);
            #pragma unroll
            for (int w = 0; w < 4; ++w) ldsm4t(vb + 4 * w, vvB + SWZ(rowOff + w * 32));
            #pragma unroll
            for (int j = 0; j < 8; ++j)
                mma16816h(accV[j], p2h, &vb[(j >> 1) * 4 + (j & 1) * 2]);
        }
    }

    // ---- epilogue: write hCtx (fp16 ctx), hC2 (fp16 ctx^2), var (fp32) ----
    const float i0 = 1.f / (256.f * rl0), i1 = 1.f / (256.f * rl1);
    const float w0 = 1.f / (1024.f * rl0 * rl0), w1 = 1.f / (1024.f * rl1 * rl1);
    const int row0 = qb + wid * 16 + rr;
    #pragma unroll
    for (int j = 0; j < 8; ++j) {
        int off = j * 8 + cpair;
        int col = hh * 64 + off;
        float cv[2][2] = {{accC[j][0] * i0, accC[j][1] * i0},
                          {accC[j][2] * i1, accC[j][3] * i1}};
        float uv[2][2] = {{accV[j][0] * w0, accV[j][1] * w0},
                          {accV[j][2] * w1, accV[j][3] * w1}};
        #pragma unroll
        for (int rr2 = 0; rr2 < 2; ++rr2) {
            size_t bn = (size_t)b * NSEQ + row0 + rr2 * 8;
            float c0 = cv[rr2][0], c1 = cv[rr2][1];
            __half2 hpk = __floats2half2_rn(c0, c1);
            *(uint32_t*)(hCtx + bn * DM + col) = *(uint32_t*)&hpk;
            __half2 hc = __floats2half2_rn(c0 * c0, c1 * c1);
            *(uint32_t*)(hC2 + bn * DM + col) = *(uint32_t*)&hc;
            *(float2*)(var + bn * DM + col) = make_float2(uv[rr2][0], uv[rr2][1]);
        }
    }
}

// ---------------------------------------------------------------------------
// Launcher
// ---------------------------------------------------------------------------
extern "C" void kernel_launch(void* const* d_in, const int* in_sizes, int n_in,
                              void* d_out, int out_size) {
    const float* H      = (const float*)d_in[0];
    const float* xr     = (const float*)d_in[1];
    const float* Wq     = (const float*)d_in[2];
    const float* bq     = (const float*)d_in[4];
    const float* Wk     = (const float*)d_in[6];
    const float* bk     = (const float*)d_in[8];
    const float* Wv     = (const float*)d_in[10];
    const float* Wv_rho = (const float*)d_in[11];
    const float* bv     = (const float*)d_in[12];
    const float* bv_rho = (const float*)d_in[13];
    const float* Wo     = (const float*)d_in[14];
    const float* Wo_rho = (const float*)d_in[15];
    const float* bo     = (const float*)d_in[16];
    const float* bo_rho = (const float*)d_in[17];
    const float* lsf    = (const float*)d_in[18];
    const float* lll    = (const float*)d_in[19];

    float *var, *bvs2, *bos2;
    __half *d2, *hH, *hCtx, *hA2, *hC2, *hWq, *hWk, *hWv, *hWo, *hVs, *hOs;
    __half *q2p, *k2p, *v2hp, *vv2hp;
    cudaGetSymbolAddress((void**)&var,  g_var);
    cudaGetSymbolAddress((void**)&d2,   g_d2);
    cudaGetSymbolAddress((void**)&bvs2, g_bvs2);
    cudaGetSymbolAddress((void**)&bos2, g_bos2);
    cudaGetSymbolAddress((void**)&hH,   g_hH);
    cudaGetSymbolAddress((void**)&hCtx, g_hCtx);
    cudaGetSymbolAddress((void**)&hA2,  g_hA_H2);
    cudaGetSymbolAddress((void**)&hC2,  g_hC2);
    cudaGetSymbolAddress((void**)&hWq,  g_hWq);
    cudaGetSymbolAddress((void**)&hWk,  g_hWk);
    cudaGetSymbolAddress((void**)&hWv,  g_hWv);
    cudaGetSymbolAddress((void**)&hWo,  g_hWo);
    cudaGetSymbolAddress((void**)&hVs,  g_hVs);
    cudaGetSymbolAddress((void**)&hOs,  g_hOs);
    cudaGetSymbolAddress((void**)&q2p,  g_q2);
    cudaGetSymbolAddress((void**)&k2p,  g_k2);
    cudaGetSymbolAddress((void**)&v2hp, g_v2h);
    cudaGetSymbolAddress((void**)&vv2hp, g_vv2h);

    cudaFuncSetAttribute(gemm_proj, cudaFuncAttributeMaxDynamicSharedMemorySize, SMEM_GEMM);
    cudaFuncSetAttribute(gemm_out,  cudaFuncAttributeMaxDynamicSharedMemorySize, SMEM_GEMM);
    cudaFuncSetAttribute(attn_tc,   cudaFuncAttributeMaxDynamicSharedMemorySize, ATTN_SMEM);

    // [0] both bias softplus^2
    bias2_kernel<<<8, 256>>>(bv_rho, bo_rho, bvs2, bos2);
    // [1] fused H prep: fp16 H + fp16 H^2 (one read)
    splitH_kernel<<<BN, 256>>>(H, hH, hA2);
    // [2] all 6 weight converts (4 plain + 2 softplus^2)
    wconv6_kernel<<<dim3(DM, 6), 256>>>(Wq, Wk, Wv, Wo, Wv_rho, Wo_rho,
                                        hWq, hWk, hWv, hWo, hVs, hOs);
    // [3] fused projection GEMM (all fp16, K=1024): Q/K/V/Vv
    gemm_proj<<<dim3(DM / BNT, BN / BM, 4), 256, SMEM_GEMM>>>(
        hH, hA2, hWq, hWk, hWv, hVs, bq, bk, bv, bvs2,
        q2p, k2p, v2hp, vv2hp);
    // [4] pairwise squared distances (fp16)
    dist2_kernel<<<dim3(16, 16, BATCH), 256>>>(xr, d2);
    // [5] attention -> hCtx / hC2 / var directly
    attn_tc<<<dim3(NSEQ / QB, BATCH * NH), 256, ATTN_SMEM>>>(
        q2p, k2p, v2hp, vv2hp, d2, lsf, lll, hCtx, hC2, var);
    // [6] fused output GEMM (K=1024): out_mean + out_var (+ var add)
    float* out_mean = (float*)d_out;
    float* out_var  = out_mean + (size_t)BN * DM;
    gemm_out<<<dim3(DM / BNT, BN / BM, 2), 256, SMEM_GEMM>>>(
        hCtx, hWo, bo, hC2, hOs, bos2, var, out_mean, out_var);
}

// round 17
// speedup vs baseline: 6.3398x; 1.0055x over previous
#include <cuda_runtime.h>
#include <cuda_fp16.h>
#include <math.h>
#include <stdint.h>

#define DM    1024
#define BATCH 8
#define NSEQ  1024
#define BN    (BATCH * NSEQ)
#define NH    16
#define DK    64
#define QSCALE 0.125f

#define BK      64
#define BM      128
#define BNT     128
#define STAGES  3
#define STAGE_BYTES ((BM + BNT) * 128)
#define SMEM_GEMM (STAGES * STAGE_BYTES)        // 96 KB

// attention tiling / smem
#define QB 128
#define KT 128
#define SM_Q   0
#define SM_K   16384
#define SM_V   49152
#define SM_VV  81920
#define ATTN_SMEM 114688

// ---------------------------------------------------------------------------
// Scratch
// ---------------------------------------------------------------------------
__device__ __half g_var [BN * DM];          // fp16 var_attn scratch
__device__ __half g_d2  [BATCH * NSEQ * NSEQ];
__device__ float  g_bvs2[DM];
__device__ float  g_bos2[DM];

__device__ __half g_hH  [BN * DM];
__device__ __half g_hCtx[BN * DM];
__device__ __half g_hA_H2[BN * DM];
__device__ __half g_hC2 [BN * DM];
__device__ __half g_hWq [DM * DM];
__device__ __half g_hWk [DM * DM];
__device__ __half g_hWv [DM * DM];
__device__ __half g_hWo [DM * DM];
__device__ __half g_hVs [DM * DM];
__device__ __half g_hOs [DM * DM];

__device__ __half g_q2 [BATCH * NH * NSEQ * 64];
__device__ __half g_k2 [BATCH * NH * NSEQ * 64];
__device__ __half g_v2h [BATCH * NH * NSEQ * 64];
__device__ __half g_vv2h[BATCH * NH * NSEQ * 64];

// ---------------------------------------------------------------------------
// PTX helpers
// ---------------------------------------------------------------------------
__device__ __forceinline__ uint32_t smem_u32(const void* p) {
    uint32_t a;
    asm("{ .reg .u64 t; cvta.to.shared.u64 t, %1; cvt.u32.u64 %0, t; }"
        : "=r"(a) : "l"(p));
    return a;
}
#define SWZ(off) ((off) ^ (((off) >> 3) & 0x70))

__device__ __forceinline__ void cp16(uint32_t dst, const void* src) {
    asm volatile("cp.async.cg.shared.global [%0], [%1], 16;"
                 :: "r"(dst), "l"(src) : "memory");
}
#define CP_COMMIT() asm volatile("cp.async.commit_group;" ::: "memory")

__device__ __forceinline__ void ldsm4(uint32_t* r, uint32_t addr) {
    asm volatile("ldmatrix.sync.aligned.m8n8.x4.shared.b16 {%0,%1,%2,%3}, [%4];"
                 : "=r"(r[0]), "=r"(r[1]), "=r"(r[2]), "=r"(r[3]) : "r"(addr));
}
__device__ __forceinline__ void ldsm4t(uint32_t* r, uint32_t addr) {
    asm volatile("ldmatrix.sync.aligned.m8n8.x4.trans.shared.b16 {%0,%1,%2,%3}, [%4];"
                 : "=r"(r[0]), "=r"(r[1]), "=r"(r[2]), "=r"(r[3]) : "r"(addr));
}
__device__ __forceinline__ void mma16816h(float* c, const uint32_t* a, const uint32_t* b) {
    asm volatile("mma.sync.aligned.m16n8k16.row.col.f32.f16.f16.f32 "
                 "{%0,%1,%2,%3}, {%4,%5,%6,%7}, {%8,%9}, {%0,%1,%2,%3};"
                 : "+f"(c[0]), "+f"(c[1]), "+f"(c[2]), "+f"(c[3])
                 : "r"(a[0]), "r"(a[1]), "r"(a[2]), "r"(a[3]), "r"(b[0]), "r"(b[1]));
}

// ---------------------------------------------------------------------------
// fused prep kernel: blocks [0,BN) -> splitH rows; [BN, BN+6*DM) -> weight
// converts (4 plain + 2 softplus^2); [BN+6*DM, +8) -> bias softplus^2.
// ---------------------------------------------------------------------------
__global__ void prep_kernel(const float* __restrict__ H,
                            const float* __restrict__ W0, const float* __restrict__ W1,
                            const float* __restrict__ W2, const float* __restrict__ W3,
                            const float* __restrict__ W4, const float* __restrict__ W5,
                            const float* __restrict__ bvr, const float* __restrict__ bor,
                            __half* __restrict__ hH, __half* __restrict__ hA2,
                            __half* __restrict__ Y0, __half* __restrict__ Y1,
                            __half* __restrict__ Y2, __half* __restrict__ Y3,
                            __half* __restrict__ Y4, __half* __restrict__ Y5,
                            float* __restrict__ bvs2, float* __restrict__ bos2) {
    int bid = blockIdx.x;
    int c4  = threadIdx.x;
    if (bid < BN) {
        // splitH: fp16 H + fp16 H^2
        float4 x = *(const float4*)(H + (size_t)bid * DM + c4 * 4);
        __half2 h0 = __floats2half2_rn(x.x, x.y);
        __half2 h1 = __floats2half2_rn(x.z, x.w);
        uint2 p;
        p.x = *(uint32_t*)&h0;
        p.y = *(uint32_t*)&h1;
        *(uint2*)(hH + (size_t)bid * DM + c4 * 4) = p;
        __half2 s0 = __floats2half2_rn(x.x * x.x, x.y * x.y);
        __half2 s1 = __floats2half2_rn(x.z * x.z, x.w * x.w);
        uint2 sq;
        sq.x = *(uint32_t*)&s0;
        sq.y = *(uint32_t*)&s1;
        *(uint2*)(hA2 + (size_t)bid * DM + c4 * 4) = sq;
    } else if (bid < BN + 6 * DM) {
        int idx = bid - BN;
        int z = idx >> 10, r = idx & (DM - 1);
        const float* X = (z == 0) ? W0 : (z == 1) ? W1 : (z == 2) ? W2
                       : (z == 3) ? W3 : (z == 4) ? W4 : W5;
        __half* Y      = (z == 0) ? Y0 : (z == 1) ? Y1 : (z == 2) ? Y2
                       : (z == 3) ? Y3 : (z == 4) ? Y4 : Y5;
        float4 x = *(const float4*)(X + (size_t)r * DM + c4 * 4);
        float v[4] = {x.x, x.y, x.z, x.w};
        if (z >= 4) {
            #pragma unroll
            for (int i = 0; i < 4; ++i) {
                float sp = (v[i] > 15.f) ? v[i] : log1pf(__expf(v[i]));
                v[i] = sp * sp;
            }
        }
        __half2 h0 = __floats2half2_rn(v[0], v[1]);
        __half2 h1 = __floats2half2_rn(v[2], v[3]);
        uint2 p;
        p.x = *(uint32_t*)&h0;
        p.y = *(uint32_t*)&h1;
        *(uint2*)(Y + (size_t)r * DM + c4 * 4) = p;
    } else {
        int i = (bid - BN - 6 * DM) * 256 + c4;      // 0..2047
        const float* in  = (i < DM) ? bvr  : bor;
        float*       out = (i < DM) ? bvs2 : bos2;
        int j = i & (DM - 1);
        float x  = in[j];
        float sp = (x > 15.f) ? x : log1pf(__expf(x));
        out[j] = sp * sp;
    }
}

// ---------------------------------------------------------------------------
// fp16 GEMM mainloop, K = 1024 (16 k-chunks)
// ---------------------------------------------------------------------------
__device__ __forceinline__ void gemm_main_h(
    const __half* __restrict__ A, const __half* __restrict__ B,
    char* smem, int mBase, int nBase, float acc[4][4][4]) {
    const uint32_t sb = smem_u32(smem);
    const int t    = threadIdx.x;
    const int wid  = t >> 5;
    const int lane = t & 31;
    const int wm   = wid & 1;
    const int wn   = wid >> 1;
    const int NITER = 16;

    const int r  = t >> 1;
    const int uc = (t & 1) * 4;
    const __half* aRow = A + (size_t)(mBase + r) * DM + uc * 8;
    const __half* bRow = B + (size_t)(nBase + r) * DM + uc * 8;

    auto load_stage = [&](int buf, int c) {
        uint32_t sA = sb + buf * STAGE_BYTES;
        uint32_t sB = sA + BM * 128;
        const __half* ga = aRow + c * BK;
        const __half* gb = bRow + c * BK;
        #pragma unroll
        for (int i = 0; i < 4; ++i) {
            uint32_t bo = r * 128 + (uc + i) * 16;
            cp16(sA + SWZ(bo), ga + i * 8);
            cp16(sB + SWZ(bo), gb + i * 8);
        }
        CP_COMMIT();
    };

    const int aRowSel = (lane & 7) | (((lane >> 3) & 1) << 3);
    const int aKSel   = (lane >> 4) << 4;
    const int bNSel   = (lane & 7) | ((lane >> 4) << 3);
    const int bKSel   = ((lane >> 3) & 1) << 4;

    load_stage(0, 0);
    load_stage(1, 1);

    for (int kt = 0; kt < NITER; ++kt) {
        const int buf = kt % STAGES;
        if (kt == NITER - 1) asm volatile("cp.async.wait_group 0;" ::: "memory");
        else                 asm volatile("cp.async.wait_group 1;" ::: "memory");
        __syncthreads();

        if (kt + 2 < NITER) load_stage((kt + 2) % STAGES, kt + 2);

        uint32_t sA = sb + buf * STAGE_BYTES;
        uint32_t sB = sA + BM * 128;
        #pragma unroll
        for (int ks = 0; ks < 4; ++ks) {
            uint32_t af[4][4], bfr2[2][4];
            #pragma unroll
            for (int mi = 0; mi < 4; ++mi) {
                uint32_t bo = (uint32_t)((wm * 64 + mi * 16 + aRowSel) * 128
                                         + ks * 32 + aKSel);
                ldsm4(af[mi], sA + SWZ(bo));
            }
            #pragma unroll
            for (int pi = 0; pi < 2; ++pi) {
                uint32_t bo = (uint32_t)((wn * 32 + pi * 16 + bNSel) * 128
                                         + ks * 32 + bKSel);
                ldsm4(bfr2[pi], sB + SWZ(bo));
            }
            #pragma unroll
            for (int mi = 0; mi < 4; ++mi)
                #pragma unroll
                for (int ni = 0; ni < 4; ++ni)
                    mma16816h(acc[mi][ni], af[mi], &bfr2[ni >> 1][(ni & 1) * 2]);
        }
        __syncthreads();
    }
}

// ---------------------------------------------------------------------------
// fused projection GEMM: z=0/1/2/3 -> Q/K/V/Vv (fp16 head-major epilogue)
// ---------------------------------------------------------------------------
__global__ void __launch_bounds__(256, 2)
gemm_proj(const __half* __restrict__ hH, const __half* __restrict__ hA2,
          const __half* __restrict__ hWq, const __half* __restrict__ hWk,
          const __half* __restrict__ hWv, const __half* __restrict__ hVs,
          const float* __restrict__ bq, const float* __restrict__ bk,
          const float* __restrict__ bv, const float* __restrict__ bvs2,
          __half* __restrict__ q2, __half* __restrict__ k2,
          __half* __restrict__ v2h, __half* __restrict__ vv2h) {
    extern __shared__ __align__(1024) char smem[];
    const int z = blockIdx.z;
    const int mBase = blockIdx.y * BM;
    const int nBase = blockIdx.x * BNT;
    float acc[4][4][4] = {};

    const __half* A = (z == 3) ? hA2 : hH;
    const __half* B = (z == 0) ? hWq : (z == 1) ? hWk : (z == 2) ? hWv : hVs;
    gemm_main_h(A, B, smem, mBase, nBase, acc);

    const float* bias = (z == 0) ? bq : (z == 1) ? bk : (z == 2) ? bv : bvs2;
    __half* dst0 = (z == 0) ? q2 : (z == 1) ? k2 : (z == 2) ? v2h : vv2h;
    const int wid  = threadIdx.x >> 5;
    const int lane = threadIdx.x & 31;
    const int lr = lane >> 2;
    const int lc = (lane & 3) * 2;
    const int rB = mBase + (wid & 1) * 64;
    const int cB = nBase + (wid >> 1) * 32;
    #pragma unroll
    for (int mi = 0; mi < 4; ++mi) {
        #pragma unroll
        for (int ni = 0; ni < 4; ++ni) {
            int col  = cB + ni * 8 + lc;
            int row0 = rB + mi * 16 + lr;
            int h = col >> 6, dl = col & 63;
            float2 bi = *(const float2*)(bias + col);
            float vx[2][2] = {{acc[mi][ni][0] + bi.x, acc[mi][ni][1] + bi.y},
                              {acc[mi][ni][2] + bi.x, acc[mi][ni][3] + bi.y}};
            #pragma unroll
            for (int rr2 = 0; rr2 < 2; ++rr2) {
                int row = row0 + rr2 * 8;
                int b = row >> 10, n = row & 1023;
                __half2 hv = __floats2half2_rn(vx[rr2][0], vx[rr2][1]);
                *(uint32_t*)(dst0 + ((size_t)(b * NH + h) * NSEQ + n) * 64 + dl)
                    = *(uint32_t*)&hv;
            }
        }
    }
}

// ---------------------------------------------------------------------------
// fused output GEMM: z=0 -> out_mean, z=1 -> out_var (+ fp16 var add).
// ---------------------------------------------------------------------------
__global__ void __launch_bounds__(256, 2)
gemm_out(const __half* __restrict__ hCtx, const __half* __restrict__ hWo,
         const float* __restrict__ bo,
         const __half* __restrict__ hC2, const __half* __restrict__ hOs,
         const float* __restrict__ bos2, const __half* __restrict__ varh,
         float* __restrict__ out_mean, float* __restrict__ out_var) {
    extern __shared__ __align__(1024) char smem[];
    const int z = blockIdx.z;
    const int mBase = blockIdx.y * BM;
    const int nBase = blockIdx.x * BNT;
    float acc[4][4][4] = {};

    if (z == 0) gemm_main_h(hCtx, hWo, smem, mBase, nBase, acc);
    else        gemm_main_h(hC2, hOs, smem, mBase, nBase, acc);

    const float* bias = (z == 0) ? bo : bos2;
    float* C          = (z == 0) ? out_mean : out_var;
    const int wid  = threadIdx.x >> 5;
    const int lane = threadIdx.x & 31;
    const int lr = lane >> 2;
    const int lc = (lane & 3) * 2;
    const int rB = mBase + (wid & 1) * 64;
    const int cB = nBase + (wid >> 1) * 32;
    #pragma unroll
    for (int mi = 0; mi < 4; ++mi) {
        #pragma unroll
        for (int ni = 0; ni < 4; ++ni) {
            int col  = cB + ni * 8 + lc;
            int row0 = rB + mi * 16 + lr;
            float2 bi = *(const float2*)(bias + col);
            float vx[2][2] = {{acc[mi][ni][0] + bi.x, acc[mi][ni][1] + bi.y},
                              {acc[mi][ni][2] + bi.x, acc[mi][ni][3] + bi.y}};
            #pragma unroll
            for (int rr2 = 0; rr2 < 2; ++rr2) {
                size_t o = (size_t)(row0 + rr2 * 8) * DM + col;
                if (z == 1) {
                    float2 a2 = __half22float2(*(const __half2*)(varh + o));
                    vx[rr2][0] += a2.x; vx[rr2][1] += a2.y;
                }
                *(float2*)(C + o) = make_float2(vx[rr2][0], vx[rr2][1]);
            }
        }
    }
}

// ---------------------------------------------------------------------------
// dist2: output fp16
// ---------------------------------------------------------------------------
__global__ void dist2_kernel(const float* __restrict__ xr, __half* __restrict__ d2) {
    __shared__ float xm[64][17];
    __shared__ float xn[64][17];
    __shared__ float x2m[64];
    __shared__ float x2n[64];

    const int t  = threadIdx.x;
    const int b  = blockIdx.z;
    const int mi = blockIdx.y * 64;
    const int nj = blockIdx.x * 64;

    for (int idx = t; idx < 64 * 4; idx += 256) {
        int r = idx >> 2, c = (idx & 3) * 4;
        float4 a = *(const float4*)(xr + ((size_t)b * NSEQ + mi + r) * 16 + c);
        xm[r][c] = a.x; xm[r][c+1] = a.y; xm[r][c+2] = a.z; xm[r][c+3] = a.w;
        float4 bb = *(const float4*)(xr + ((size_t)b * NSEQ + nj + r) * 16 + c);
        xn[r][c] = bb.x; xn[r][c+1] = bb.y; xn[r][c+2] = bb.z; xn[r][c+3] = bb.w;
    }
    __syncthreads();

    if (t < 64) {
        float s = 0.f;
        #pragma unroll
        for (int c = 0; c < 16; ++c) s += xm[t][c] * xm[t][c];
        x2m[t] = s;
    } else if (t < 128) {
        int r = t - 64;
        float s = 0.f;
        #pragma unroll
        for (int c = 0; c < 16; ++c) s += xn[r][c] * xn[r][c];
        x2n[r] = s;
    }
    __syncthreads();

    const int tx = t & 15, ty = t >> 4;
    #pragma unroll
    for (int i = 0; i < 4; ++i) {
        int row = ty * 4 + i;
        float out4[4];
        #pragma unroll
        for (int j = 0; j < 4; ++j) {
            int col = tx * 4 + j;
            float dot = 0.f;
            #pragma unroll
            for (int c = 0; c < 16; ++c) dot += xm[row][c] * xn[col][c];
            out4[j] = fmaxf(x2m[row] + x2n[col] - 2.f * dot, 0.f);
        }
        __half2 o0 = __floats2half2_rn(out4[0], out4[1]);
        __half2 o1 = __floats2half2_rn(out4[2], out4[3]);
        uint2 p;
        p.x = *(uint32_t*)&o0;
        p.y = *(uint32_t*)&o1;
        *(uint2*)(d2 + ((size_t)b * NSEQ + mi + row) * NSEQ + nj + tx * 4) = p;
    }
}

// ---------------------------------------------------------------------------
// Tensor-core flash attention (unchanged except fp16 var store)
// ---------------------------------------------------------------------------
__global__ void __launch_bounds__(256, 1)
attn_tc(const __half* __restrict__ q2, const __half* __restrict__ k2,
        const __half* __restrict__ v2h, const __half* __restrict__ vv2h,
        const __half* __restrict__ d2g,
        const float* __restrict__ lsf, const float* __restrict__ lll,
        __half* __restrict__ hCtx, __half* __restrict__ hC2,
        __half* __restrict__ varh) {
    extern __shared__ __align__(1024) char smem[];
    const uint32_t sb = smem_u32(smem);
    const int t    = threadIdx.x;
    const int wid  = t >> 5;
    const int lane = t & 31;
    const int qb   = blockIdx.x * QB;
    const int bh   = blockIdx.y;
    const int b    = bh >> 4, hh = bh & 15;

    const float sigma_f2 = __expf(2.f * lsf[hh]);
    const float coef     = 0.5f * __expf(-2.f * lll[hh]);

    const __half* Qg  = q2   + ((size_t)bh * NSEQ + qb) * 64;
    const __half* Kg  = k2   + (size_t)bh * NSEQ * 64;
    const __half* Vg  = v2h  + (size_t)bh * NSEQ * 64;
    const __half* VVg = vv2h + (size_t)bh * NSEQ * 64;

    for (int i = t; i < QB * 8; i += 256) {
        int row = i >> 3, u = i & 7;
        cp16(sb + SM_Q + SWZ((uint32_t)(row * 128 + u * 16)),
             Qg + (size_t)row * 64 + u * 8);
    }

    auto load_kv = [&](int buf, int kt) {
        const __half* kg = Kg  + (size_t)kt * KT * 64;
        const __half* vg = Vg  + (size_t)kt * KT * 64;
        const __half* wg = VVg + (size_t)kt * KT * 64;
        for (int i = t; i < KT * 8; i += 256) {
            int row = i >> 3, u = i & 7;
            uint32_t so = SWZ((uint32_t)(row * 128 + u * 16));
            cp16(sb + SM_K  + buf * 16384 + so, kg + (size_t)row * 64 + u * 8);
            cp16(sb + SM_V  + buf * 16384 + so, vg + (size_t)row * 64 + u * 8);
            cp16(sb + SM_VV + buf * 16384 + so, wg + (size_t)row * 64 + u * 8);
        }
        CP_COMMIT();
    };
    load_kv(0, 0);

    const int l15 = lane & 15;
    const int lHi = (lane >> 4) << 4;
    const uint32_t aRowOff = (uint32_t)((wid * 16 + l15) * 128 + lHi);
    const int g    = lane >> 3;
    const int keyl = ((g >> 1) << 3) + (lane & 7);
    const uint32_t kCol = (uint32_t)((g & 1) << 4);
    const int rr    = lane >> 2;
    const int cpair = (lane & 3) * 2;

    float accC[8][4] = {}, accV[8][4] = {};
    float rm0 = -1e30f, rm1 = -1e30f, rl0 = 0.f, rl1 = 0.f;

    for (int kt = 0; kt < NSEQ / KT; ++kt) {
        if (kt + 1 < NSEQ / KT) { __syncthreads(); load_kv((kt + 1) & 1, kt + 1); }
        if (kt + 1 < NSEQ / KT) asm volatile("cp.async.wait_group 1;" ::: "memory");
        else                    asm volatile("cp.async.wait_group 0;" ::: "memory");
        __syncthreads();

        const int buf = kt & 1;
        const uint32_t kB  = sb + SM_K  + buf * 16384;
        const uint32_t vB  = sb + SM_V  + buf * 16384;
        const uint32_t vvB = sb + SM_VV + buf * 16384;

        float sacc[16][4];
        #pragma unroll
        for (int j = 0; j < 16; ++j)
            #pragma unroll
            for (int e = 0; e < 4; ++e) sacc[j][e] = 0.f;

        #pragma unroll
        for (int ks = 0; ks < 4; ++ks) {
            uint32_t a[4];
            ldsm4(a, sb + SM_Q + SWZ(aRowOff + ks * 32));
            #pragma unroll
            for (int n0 = 0; n0 < 8; ++n0) {
                uint32_t kb4[4];
                ldsm4(kb4, kB + SWZ((uint32_t)((n0 * 16 + keyl) * 128) + ks * 32 + kCol));
                mma16816h(sacc[2 * n0],     a, kb4);
                mma16816h(sacc[2 * n0 + 1], a, kb4 + 2);
            }
        }

        const int kb0 = kt * KT;
        const __half* d2r0 = d2g + (size_t)b * NSEQ * NSEQ
                           + (size_t)(qb + wid * 16 + rr) * NSEQ + kb0;
        const __half* d2r1 = d2r0 + 8 * NSEQ;
        #pragma unroll
        for (int j = 0; j < 16; ++j) {
            float2 da = __half22float2(*(const __half2*)(d2r0 + j * 8 + cpair));
            float2 db = __half22float2(*(const __half2*)(d2r1 + j * 8 + cpair));
            sacc[j][0] = sacc[j][0] * QSCALE + sigma_f2 * __expf(-da.x * coef);
            sacc[j][1] = sacc[j][1] * QSCALE + sigma_f2 * __expf(-da.y * coef);
            sacc[j][2] = sacc[j][2] * QSCALE + sigma_f2 * __expf(-db.x * coef);
            sacc[j][3] = sacc[j][3] * QSCALE + sigma_f2 * __expf(-db.y * coef);
        }
        float mx0 = -1e30f, mx1 = -1e30f;
        #pragma unroll
        for (int j = 0; j < 16; ++j) {
            mx0 = fmaxf(mx0, fmaxf(sacc[j][0], sacc[j][1]));
            mx1 = fmaxf(mx1, fmaxf(sacc[j][2], sacc[j][3]));
        }
        mx0 = fmaxf(mx0, __shfl_xor_sync(0xffffffffu, mx0, 1));
        mx0 = fmaxf(mx0, __shfl_xor_sync(0xffffffffu, mx0, 2));
        mx1 = fmaxf(mx1, __shfl_xor_sync(0xffffffffu, mx1, 1));
        mx1 = fmaxf(mx1, __shfl_xor_sync(0xffffffffu, mx1, 2));
        float m0n = fmaxf(rm0, mx0), m1n = fmaxf(rm1, mx1);
        float f0 = __expf(rm0 - m0n), f1 = __expf(rm1 - m1n);
        rm0 = m0n; rm1 = m1n;
        float sum0 = 0.f, sum1 = 0.f;
        #pragma unroll
        for (int j = 0; j < 16; ++j) {
            sacc[j][0] = __expf(sacc[j][0] - m0n); sum0 += sacc[j][0];
            sacc[j][1] = __expf(sacc[j][1] - m0n); sum0 += sacc[j][1];
            sacc[j][2] = __expf(sacc[j][2] - m1n); sum1 += sacc[j][2];
            sacc[j][3] = __expf(sacc[j][3] - m1n); sum1 += sacc[j][3];
        }
        sum0 += __shfl_xor_sync(0xffffffffu, sum0, 1);
        sum0 += __shfl_xor_sync(0xffffffffu, sum0, 2);
        sum1 += __shfl_xor_sync(0xffffffffu, sum1, 1);
        sum1 += __shfl_xor_sync(0xffffffffu, sum1, 2);
        rl0 = rl0 * f0 + sum0;
        rl1 = rl1 * f1 + sum1;
        float f02 = f0 * f0, f12 = f1 * f1;
        #pragma unroll
        for (int j = 0; j < 8; ++j) {
            accC[j][0] *= f0;  accC[j][1] *= f0;
            accC[j][2] *= f1;  accC[j][3] *= f1;
            accV[j][0] *= f02; accV[j][1] *= f02;
            accV[j][2] *= f12; accV[j][3] *= f12;
        }

        #pragma unroll
        for (int tt = 0; tt < 8; ++tt) {
            float p8[8], q8[8];
            #pragma unroll
            for (int e = 0; e < 4; ++e) {
                float p0 = sacc[2 * tt][e], p1 = sacc[2 * tt + 1][e];
                p8[e]     = p0 * 256.f;
                p8[4 + e] = p1 * 256.f;
                q8[e]     = p0 * p0 * 1024.f;
                q8[4 + e] = p1 * p1 * 1024.f;
            }
            uint32_t phi[4], p2h[4];
            #pragma unroll
            for (int e = 0; e < 4; ++e) {
                __half2 a = __floats2half2_rn(p8[2 * e], p8[2 * e + 1]);
                __half2 c = __floats2half2_rn(q8[2 * e], q8[2 * e + 1]);
                phi[e] = *(uint32_t*)&a;
                p2h[e] = *(uint32_t*)&c;
            }

            const uint32_t rowOff = (uint32_t)((tt * 16 + l15) * 128 + lHi);
            uint32_t vb[16];
            #pragma unroll
            for (int w = 0; w < 4; ++w) ldsm4t(vb + 4 * w, vB + SWZ(rowOff + w * 32));
            #pragma unroll
            for (int j = 0; j < 8; ++j)
                mma16816h(accC[j], phi, &vb[(j >> 1) * 4 + (j & 1) * 2]);
            #pragma unroll
            for (int w = 0; w < 4; ++w) ldsm4t(vb + 4 * w, vvB + SWZ(rowOff + w * 32));
            #pragma unroll
            for (int j = 0; j < 8; ++j)
                mma16816h(accV[j], p2h, &vb[(j >> 1) * 4 + (j & 1) * 2]);
        }
    }

    // ---- epilogue: write hCtx (fp16), hC2 (fp16), varh (fp16) ----
    const float i0 = 1.f / (256.f * rl0), i1 = 1.f / (256.f * rl1);
    const float w0 = 1.f / (1024.f * rl0 * rl0), w1 = 1.f / (1024.f * rl1 * rl1);
    const int row0 = qb + wid * 16 + rr;
    #pragma unroll
    for (int j = 0; j < 8; ++j) {
        int off = j * 8 + cpair;
        int col = hh * 64 + off;
        float cv[2][2] = {{accC[j][0] * i0, accC[j][1] * i0},
                          {accC[j][2] * i1, accC[j][3] * i1}};
        float uv[2][2] = {{accV[j][0] * w0, accV[j][1] * w0},
                          {accV[j][2] * w1, accV[j][3] * w1}};
        #pragma unroll
        for (int rr2 = 0; rr2 < 2; ++rr2) {
            size_t bn = (size_t)b * NSEQ + row0 + rr2 * 8;
            float c0 = cv[rr2][0], c1 = cv[rr2][1];
            __half2 hpk = __floats2half2_rn(c0, c1);
            *(uint32_t*)(hCtx + bn * DM + col) = *(uint32_t*)&hpk;
            __half2 hc = __floats2half2_rn(c0 * c0, c1 * c1);
            *(uint32_t*)(hC2 + bn * DM + col) = *(uint32_t*)&hc;
            __half2 uvp = __floats2half2_rn(uv[rr2][0], uv[rr2][1]);
            *(uint32_t*)(varh + bn * DM + col) = *(uint32_t*)&uvp;
        }
    }
}

// ---------------------------------------------------------------------------
// Launcher
// ---------------------------------------------------------------------------
extern "C" void kernel_launch(void* const* d_in, const int* in_sizes, int n_in,
                              void* d_out, int out_size) {
    const float* H      = (const float*)d_in[0];
    const float* xr     = (const float*)d_in[1];
    const float* Wq     = (const float*)d_in[2];
    const float* bq     = (const float*)d_in[4];
    const float* Wk     = (const float*)d_in[6];
    const float* bk     = (const float*)d_in[8];
    const float* Wv     = (const float*)d_in[10];
    const float* Wv_rho = (const float*)d_in[11];
    const float* bv     = (const float*)d_in[12];
    const float* bv_rho = (const float*)d_in[13];
    const float* Wo     = (const float*)d_in[14];
    const float* Wo_rho = (const float*)d_in[15];
    const float* bo     = (const float*)d_in[16];
    const float* bo_rho = (const float*)d_in[17];
    const float* lsf    = (const float*)d_in[18];
    const float* lll    = (const float*)d_in[19];

    float *bvs2, *bos2;
    __half *varh, *d2, *hH, *hCtx, *hA2, *hC2, *hWq, *hWk, *hWv, *hWo, *hVs, *hOs;
    __half *q2p, *k2p, *v2hp, *vv2hp;
    cudaGetSymbolAddress((void**)&varh, g_var);
    cudaGetSymbolAddress((void**)&d2,   g_d2);
    cudaGetSymbolAddress((void**)&bvs2, g_bvs2);
    cudaGetSymbolAddress((void**)&bos2, g_bos2);
    cudaGetSymbolAddress((void**)&hH,   g_hH);
    cudaGetSymbolAddress((void**)&hCtx, g_hCtx);
    cudaGetSymbolAddress((void**)&hA2,  g_hA_H2);
    cudaGetSymbolAddress((void**)&hC2,  g_hC2);
    cudaGetSymbolAddress((void**)&hWq,  g_hWq);
    cudaGetSymbolAddress((void**)&hWk,  g_hWk);
    cudaGetSymbolAddress((void**)&hWv,  g_hWv);
    cudaGetSymbolAddress((void**)&hWo,  g_hWo);
    cudaGetSymbolAddress((void**)&hVs,  g_hVs);
    cudaGetSymbolAddress((void**)&hOs,  g_hOs);
    cudaGetSymbolAddress((void**)&q2p,  g_q2);
    cudaGetSymbolAddress((void**)&k2p,  g_k2);
    cudaGetSymbolAddress((void**)&v2hp, g_v2h);
    cudaGetSymbolAddress((void**)&vv2hp, g_vv2h);

    cudaFuncSetAttribute(gemm_proj, cudaFuncAttributeMaxDynamicSharedMemorySize, SMEM_GEMM);
    cudaFuncSetAttribute(gemm_out,  cudaFuncAttributeMaxDynamicSharedMemorySize, SMEM_GEMM);
    cudaFuncSetAttribute(attn_tc,   cudaFuncAttributeMaxDynamicSharedMemorySize, ATTN_SMEM);

    // [0] fused prep: H split + 6 weight converts + both biases
    prep_kernel<<<BN + 6 * DM + 8, 256>>>(
        H, Wq, Wk, Wv, Wo, Wv_rho, Wo_rho, bv_rho, bo_rho,
        hH, hA2, hWq, hWk, hWv, hWo, hVs, hOs, bvs2, bos2);
    // [1] fused projection GEMM: Q/K/V/Vv
    gemm_proj<<<dim3(DM / BNT, BN / BM, 4), 256, SMEM_GEMM>>>(
        hH, hA2, hWq, hWk, hWv, hVs, bq, bk, bv, bvs2,
        q2p, k2p, v2hp, vv2hp);
    // [2] pairwise squared distances (fp16)
    dist2_kernel<<<dim3(16, 16, BATCH), 256>>>(xr, d2);
    // [3] attention -> hCtx / hC2 / varh
    attn_tc<<<dim3(NSEQ / QB, BATCH * NH), 256, ATTN_SMEM>>>(
        q2p, k2p, v2hp, vv2hp, d2, lsf, lll, hCtx, hC2, varh);
    // [4] fused output GEMM: out_mean + out_var (+ fp16 var add)
    float* out_mean = (float*)d_out;
    float* out_var  = out_mean + (size_t)BN * DM;
    gemm_out<<<dim3(DM / BNT, BN / BM, 2), 256, SMEM_GEMM>>>(
        hCtx, hWo, bo, hC2, hOs, bos2, varh, out_mean, out_var);
}